// round 1
// baseline (speedup 1.0000x reference)
#include <cuda_runtime.h>
#include <math.h>

#define N_ATOMS 32768
#define MNBR    12
#define ORIG    92
#define EDGE    41
#define FDIM    128
#define HDIM    256
#define NCONV   3
#define NCRY    128
#define APC     256

// ---- scratch (static device arrays; no allocation allowed) ----
__device__ float g_x [N_ATOMS * FDIM];
__device__ float g_pc[N_ATOMS * FDIM];
__device__ float g_yn[N_ATOMS * FDIM];
__device__ float g_site[N_ATOMS];

__device__ __forceinline__ float softplusf(float x) {
    return fmaxf(x, 0.f) + log1pf(expf(-fabsf(x)));
}
__device__ __forceinline__ float sigmoidf(float x) {
    return 1.f / (1.f + expf(-x));
}

// ============================================================================
// Kernel 1: embedding  x = atom_fea @ W_embed + b      [N,92] @ [92,128]
// grid 256 x 256 threads; W in smem; 2 rows per iteration
// ============================================================================
__global__ void k_embed(const float* __restrict__ atom_fea,
                        const float* __restrict__ W,
                        const float* __restrict__ b) {
    __shared__ float Ws[ORIG * FDIM];     // 47104 B
    __shared__ float rows[2 * ORIG];
    int tid = threadIdx.x;
    for (int i = tid; i < ORIG * FDIM; i += 256) Ws[i] = W[i];
    __syncthreads();
    int base = blockIdx.x * 128;
    int half = tid >> 7, f = tid & 127;
    for (int it = 0; it < 64; ++it) {
        int r0 = base + it * 2;
        for (int j = tid; j < 2 * ORIG; j += 256)
            rows[j] = atom_fea[r0 * ORIG + j];
        __syncthreads();
        float acc = b[f];
        const float* rp = rows + half * ORIG;
        #pragma unroll 4
        for (int e = 0; e < ORIG; e++)
            acc = fmaf(rp[e], Ws[e * FDIM + f], acc);
        g_x[(r0 + half) * FDIM + f] = acc;
        __syncthreads();
    }
}

// ============================================================================
// Kernel 2: convA  [phi_c | y_nbr] = x @ [Wc | Wn] + [bc | bn]
// GEMM: M=32768, K=128, N=256.  64x64 tile, BK=16, 256 threads, 4x4 microtile
// blockIdx.x in [0,4): col tile (0,1 -> center; 2,3 -> nbr)
// ============================================================================
__global__ void k_convA(const float* __restrict__ Wc, const float* __restrict__ bc,
                        const float* __restrict__ Wn, const float* __restrict__ bn) {
    __shared__ float As[16 * 68];  // transposed A tile, pitch 68
    __shared__ float Bs[16 * 64];
    int tid = threadIdx.x;
    int tx = tid & 15, ty = tid >> 4;
    int m0 = blockIdx.y * 64;
    int n0 = blockIdx.x * 64;
    const float* W  = (n0 < FDIM) ? Wc : Wn;
    const float* bb = (n0 < FDIM) ? bc : bn;
    int colbase = n0 & (FDIM - 1);

    float c00=0,c01=0,c02=0,c03=0, c10=0,c11=0,c12=0,c13=0;
    float c20=0,c21=0,c22=0,c23=0, c30=0,c31=0,c32=0,c33=0;

    int arow = tid >> 2, ac4 = tid & 3;
    int brow = tid >> 4, bc4 = tid & 15;

    for (int kt = 0; kt < 8; ++kt) {
        int k0 = kt * 16;
        float4 av = *(const float4*)&g_x[(m0 + arow) * FDIM + k0 + ac4 * 4];
        float4 bv = *(const float4*)&W[(k0 + brow) * FDIM + colbase + bc4 * 4];
        __syncthreads();
        As[(ac4*4+0)*68 + arow] = av.x;
        As[(ac4*4+1)*68 + arow] = av.y;
        As[(ac4*4+2)*68 + arow] = av.z;
        As[(ac4*4+3)*68 + arow] = av.w;
        *(float4*)&Bs[brow * 64 + bc4 * 4] = bv;
        __syncthreads();
        #pragma unroll
        for (int k = 0; k < 16; k++) {
            float4 a = *(const float4*)&As[k * 68 + ty * 4];
            float4 b = *(const float4*)&Bs[k * 64 + tx * 4];
            c00=fmaf(a.x,b.x,c00); c01=fmaf(a.x,b.y,c01); c02=fmaf(a.x,b.z,c02); c03=fmaf(a.x,b.w,c03);
            c10=fmaf(a.y,b.x,c10); c11=fmaf(a.y,b.y,c11); c12=fmaf(a.y,b.z,c12); c13=fmaf(a.y,b.w,c13);
            c20=fmaf(a.z,b.x,c20); c21=fmaf(a.z,b.y,c21); c22=fmaf(a.z,b.z,c22); c23=fmaf(a.z,b.w,c23);
            c30=fmaf(a.w,b.x,c30); c31=fmaf(a.w,b.y,c31); c32=fmaf(a.w,b.z,c32); c33=fmaf(a.w,b.w,c33);
        }
    }
    float* dst = (n0 < FDIM) ? g_pc : g_yn;
    float cr[4][4] = {{c00,c01,c02,c03},{c10,c11,c12,c13},{c20,c21,c22,c23},{c30,c31,c32,c33}};
    #pragma unroll
    for (int ii = 0; ii < 4; ii++) {
        int r = m0 + ty * 4 + ii;
        #pragma unroll
        for (int jj = 0; jj < 4; jj++) {
            int j = colbase + tx * 4 + jj;
            dst[r * FDIM + j] = cr[ii][jj] + bb[j];
        }
    }
}

// ============================================================================
// Kernel 3: convB — fully fused neighbor message pass
// Per atom: gather y_nbr, phi_e GEMV (41->128), inter = pc*pn*pe,
//           gate/mag GEMVs (128->128 each), sigmoid*softplus sum over m,
//           LayerNorm, residual into g_x.
// Persistent: grid ~152 CTAs x 256 threads, 2 atoms per CTA per iteration.
// Dynamic smem: weights (Wg/Wm transposed, pitch 132) + W_edge + scratch.
// ============================================================================
#define CB_WGT   0
#define CB_WMT   16896
#define CB_WE    33792
#define CB_BG    39040
#define CB_BM    39168
#define CB_BE    39296
#define CB_LNS   39424
#define CB_LNB   39552
#define CB_INTER 39680
#define CB_SNBR  42752
#define CB_RED   43736
#define CB_SIDX  43752
#define CB_FLOATS 43776
#define CONVB_SMEM (CB_FLOATS * 4)

extern __shared__ float sm[];

__global__ void k_convB(const float* __restrict__ nbr_fea, const int* __restrict__ nbr_idx,
                        const float* __restrict__ Wg, const float* __restrict__ bg,
                        const float* __restrict__ Wm, const float* __restrict__ bm,
                        const float* __restrict__ We, const float* __restrict__ be,
                        const float* __restrict__ lns, const float* __restrict__ lnb) {
    float* WgT    = sm + CB_WGT;
    float* WmT    = sm + CB_WMT;
    float* WeS    = sm + CB_WE;
    float* bgS    = sm + CB_BG;
    float* bmS    = sm + CB_BM;
    float* beS    = sm + CB_BE;
    float* lnsS   = sm + CB_LNS;
    float* lnbS   = sm + CB_LNB;
    float* interS = sm + CB_INTER;   // [2][12][128]
    float* snbr   = sm + CB_SNBR;    // [2][12*41]
    float* red    = sm + CB_RED;     // [2][4][2]
    int*   sidx   = (int*)(sm + CB_SIDX); // [2][12]

    int tid = threadIdx.x;
    for (int i = tid; i < FDIM * FDIM; i += 256) {
        int k = i >> 7, f = i & 127;
        WgT[f * 132 + k] = Wg[i];
        WmT[f * 132 + k] = Wm[i];
    }
    for (int i = tid; i < EDGE * FDIM; i += 256) WeS[i] = We[i];
    if (tid < FDIM) {
        bgS[tid] = bg[tid]; bmS[tid] = bm[tid]; beS[tid] = be[tid];
        lnsS[tid] = lns[tid]; lnbS[tid] = lnb[tid];
    }
    __syncthreads();

    int half = tid >> 7, f = tid & 127;
    int lw = (tid & 127) >> 5;   // warp within half
    int lane = tid & 31;
    const float4* wgp = (const float4*)(WgT + f * 132);
    const float4* wmp = (const float4*)(WmT + f * 132);

    for (int p = blockIdx.x; p < N_ATOMS / 2; p += gridDim.x) {
        int n = p * 2 + half;
        // stage neighbor indices + edge features
        if (f < MNBR) sidx[half * MNBR + f] = nbr_idx[n * MNBR + f];
        for (int j = f; j < MNBR * EDGE; j += 128)
            snbr[half * MNBR * EDGE + j] = nbr_fea[n * MNBR * EDGE + j];
        __syncthreads();

        float pc = g_pc[n * FDIM + f];
        float yn[MNBR];
        #pragma unroll
        for (int m = 0; m < MNBR; m++)
            yn[m] = g_yn[sidx[half * MNBR + m] * FDIM + f];

        float pe[MNBR];
        #pragma unroll
        for (int m = 0; m < MNBR; m++) pe[m] = beS[f];
        const float* sn = snbr + half * MNBR * EDGE;
        for (int e = 0; e < EDGE; e++) {
            float w = WeS[e * FDIM + f];
            #pragma unroll
            for (int m = 0; m < MNBR; m++)
                pe[m] = fmaf(sn[m * EDGE + e], w, pe[m]);
        }
        #pragma unroll
        for (int m = 0; m < MNBR; m++)
            interS[(half * MNBR + m) * FDIM + f] = pc * yn[m] * pe[m];
        __syncthreads();

        float ag[MNBR], am[MNBR];
        #pragma unroll
        for (int m = 0; m < MNBR; m++) { ag[m] = bgS[f]; am[m] = bmS[f]; }
        const float4* ivbase = (const float4*)(interS + half * MNBR * FDIM);
        #pragma unroll 2
        for (int k4 = 0; k4 < FDIM / 4; k4++) {
            float4 wg = wgp[k4];
            float4 wm = wmp[k4];
            #pragma unroll
            for (int m = 0; m < MNBR; m++) {
                float4 iv = ivbase[m * (FDIM / 4) + k4];
                ag[m] = fmaf(iv.x, wg.x, ag[m]); ag[m] = fmaf(iv.y, wg.y, ag[m]);
                ag[m] = fmaf(iv.z, wg.z, ag[m]); ag[m] = fmaf(iv.w, wg.w, ag[m]);
                am[m] = fmaf(iv.x, wm.x, am[m]); am[m] = fmaf(iv.y, wm.y, am[m]);
                am[m] = fmaf(iv.z, wm.z, am[m]); am[m] = fmaf(iv.w, wm.w, am[m]);
            }
        }
        float ns = 0.f;
        #pragma unroll
        for (int m = 0; m < MNBR; m++)
            ns += sigmoidf(ag[m]) * softplusf(am[m]);

        // LayerNorm over f (128 threads of this half)
        float s = ns, sq = ns * ns;
        #pragma unroll
        for (int o = 16; o > 0; o >>= 1) {
            s  += __shfl_xor_sync(0xffffffffu, s,  o);
            sq += __shfl_xor_sync(0xffffffffu, sq, o);
        }
        if (lane == 0) { red[(half * 4 + lw) * 2] = s; red[(half * 4 + lw) * 2 + 1] = sq; }
        __syncthreads();
        s  = red[half * 8 + 0] + red[half * 8 + 2] + red[half * 8 + 4] + red[half * 8 + 6];
        sq = red[half * 8 + 1] + red[half * 8 + 3] + red[half * 8 + 5] + red[half * 8 + 7];
        float mu = s * (1.f / FDIM);
        float var = sq * (1.f / FDIM) - mu * mu;
        float rstd = rsqrtf(var + 1e-6f);
        g_x[n * FDIM + f] += (ns - mu) * rstd * lnsS[f] + lnbS[f];
        __syncthreads();   // protect smem reuse next iteration
    }
}

// ============================================================================
// Kernel 4: readout  E_site[n] = softplus(x @ W_h + b_h) . W_out + b_out
// Persistent: 152 CTAs x 256 threads; W_h transposed in smem (pitch 132)
// ============================================================================
#define RO_WHT  0
#define RO_WO   33792
#define RO_BH   34048
#define RO_XR   34304
#define RO_RED  34432
#define RO_FLOATS 34440
#define RO_SMEM (RO_FLOATS * 4)

__global__ void k_readout(const float* __restrict__ Wh, const float* __restrict__ bh,
                          const float* __restrict__ Wout, const float* __restrict__ bout) {
    float* WhT = sm + RO_WHT;   // [256][132]
    float* WoS = sm + RO_WO;    // 256
    float* bhS = sm + RO_BH;    // 256
    float* xr  = sm + RO_XR;    // 128
    float* red = sm + RO_RED;   // 8
    int tid = threadIdx.x;
    for (int i = tid; i < FDIM * HDIM; i += 256) {
        int k = i >> 8, j = i & 255;
        WhT[j * 132 + k] = Wh[i];
    }
    WoS[tid] = Wout[tid];
    bhS[tid] = bh[tid];
    __syncthreads();
    float b0 = bout[0];
    const float4* wp = (const float4*)(WhT + tid * 132);

    for (int n = blockIdx.x; n < N_ATOMS; n += gridDim.x) {
        if (tid < FDIM) xr[tid] = g_x[n * FDIM + tid];
        __syncthreads();
        float acc = bhS[tid];
        #pragma unroll 4
        for (int k4 = 0; k4 < FDIM / 4; k4++) {
            float4 w = wp[k4];
            float4 xv = *(const float4*)(xr + k4 * 4);
            acc = fmaf(w.x, xv.x, acc); acc = fmaf(w.y, xv.y, acc);
            acc = fmaf(w.z, xv.z, acc); acc = fmaf(w.w, xv.w, acc);
        }
        float pcontrib = softplusf(acc) * WoS[tid];
        #pragma unroll
        for (int o = 16; o > 0; o >>= 1)
            pcontrib += __shfl_xor_sync(0xffffffffu, pcontrib, o);
        if ((tid & 31) == 0) red[tid >> 5] = pcontrib;
        __syncthreads();
        if (tid == 0) {
            float ssum = 0.f;
            #pragma unroll
            for (int w8 = 0; w8 < 8; w8++) ssum += red[w8];
            g_site[n] = ssum + b0;
        }
        __syncthreads();
    }
}

// ============================================================================
// Kernel 5: deterministic per-crystal sum  out[c] = sum_{a<256} E_site
// ============================================================================
__global__ void k_crystal(float* __restrict__ out) {
    __shared__ float red[8];
    int c = blockIdx.x, tid = threadIdx.x;
    float v = g_site[c * APC + tid];
    #pragma unroll
    for (int o = 16; o > 0; o >>= 1)
        v += __shfl_xor_sync(0xffffffffu, v, o);
    if ((tid & 31) == 0) red[tid >> 5] = v;
    __syncthreads();
    if (tid == 0) {
        float s = 0.f;
        #pragma unroll
        for (int i = 0; i < 8; i++) s += red[i];
        out[c] = s;
    }
}

// ============================================================================
extern "C" void kernel_launch(void* const* d_in, const int* in_sizes, int n_in,
                              void* d_out, int out_size) {
    const float* atom_fea = (const float*)d_in[0];
    const float* nbr_fea  = (const float*)d_in[1];
    const int*   nbr_idx  = (const int*)  d_in[2];
    const float* W_embed  = (const float*)d_in[3];
    const float* b_embed  = (const float*)d_in[4];
    const float* W_center = (const float*)d_in[5];
    const float* b_center = (const float*)d_in[6];
    const float* W_nbr    = (const float*)d_in[7];
    const float* b_nbr    = (const float*)d_in[8];
    const float* W_edge   = (const float*)d_in[9];
    const float* b_edge   = (const float*)d_in[10];
    const float* W_gate   = (const float*)d_in[11];
    const float* b_gate   = (const float*)d_in[12];
    const float* W_mag    = (const float*)d_in[13];
    const float* b_mag    = (const float*)d_in[14];
    const float* ln_scale = (const float*)d_in[15];
    const float* ln_bias  = (const float*)d_in[16];
    const float* W_h      = (const float*)d_in[17];
    const float* b_h      = (const float*)d_in[18];
    const float* W_out    = (const float*)d_in[19];
    const float* b_out    = (const float*)d_in[20];
    float* out = (float*)d_out;

    cudaFuncSetAttribute(k_convB,   cudaFuncAttributeMaxDynamicSharedMemorySize, CONVB_SMEM);
    cudaFuncSetAttribute(k_readout, cudaFuncAttributeMaxDynamicSharedMemorySize, RO_SMEM);

    k_embed<<<256, 256>>>(atom_fea, W_embed, b_embed);
    for (int l = 0; l < NCONV; l++) {
        dim3 gA(4, 512);
        k_convA<<<gA, 256>>>(W_center + l * FDIM * FDIM, b_center + l * FDIM,
                             W_nbr    + l * FDIM * FDIM, b_nbr    + l * FDIM);
        k_convB<<<152, 256, CONVB_SMEM>>>(nbr_fea, nbr_idx,
                                          W_gate + l * FDIM * FDIM, b_gate + l * FDIM,
                                          W_mag  + l * FDIM * FDIM, b_mag  + l * FDIM,
                                          W_edge + l * EDGE * FDIM, b_edge + l * FDIM,
                                          ln_scale + l * FDIM, ln_bias + l * FDIM);
    }
    k_readout<<<152, 256, RO_SMEM>>>(W_h, b_h, W_out, b_out);
    k_crystal<<<NCRY, 256>>>(out);
}

// round 3
// speedup vs baseline: 1.9091x; 1.9091x over previous
#include <cuda_runtime.h>
#include <math.h>
#include <cstdint>

#define N_ATOMS 32768
#define MNBR    12
#define PROWS   16                       // padded rows per atom (12 real + 4 zero)
#define ORIG    92
#define EDGE    41
#define FDIM    128
#define HDIM    256
#define NCONV   3
#define NCRY    128
#define APC     256
#define GT_ATOMS 4
#define GT_ROWS  (GT_ATOMS * PROWS)      // 64 rows per MMA tile
#define NTILE    (N_ATOMS / GT_ATOMS)    // 8192

// ---- scratch (static device arrays; zero-initialized, no allocation) ----
__device__ float g_x [N_ATOMS * FDIM];
__device__ float g_pc[N_ATOMS * FDIM];
__device__ float g_yn[N_ATOMS * FDIM];
__device__ float g_inter[(size_t)N_ATOMS * PROWS * FDIM];   // 268 MB, tf32-rounded
__device__ float g_site[N_ATOMS];

__device__ __forceinline__ float softplusf(float x) {
    return fmaxf(x, 0.f) + log1pf(expf(-fabsf(x)));
}
__device__ __forceinline__ float tf32r(float x) {
    uint32_t u;
    asm("cvt.rna.tf32.f32 %0, %1;" : "=r"(u) : "f"(x));
    return __uint_as_float(u);
}
__device__ __forceinline__ uint32_t smem_u32(const void* p) {
    uint32_t a;
    asm("{ .reg .u64 t; cvta.to.shared.u64 t, %1; cvt.u32.u64 %0, t; }" : "=r"(a) : "l"(p));
    return a;
}
__device__ __forceinline__ void mma_tf32(float c[4], const uint32_t a[4], const uint32_t b[2]) {
    asm volatile("mma.sync.aligned.m16n8k8.row.col.f32.tf32.tf32.f32 "
        "{%0,%1,%2,%3}, {%4,%5,%6,%7}, {%8,%9}, {%0,%1,%2,%3};"
        : "+f"(c[0]), "+f"(c[1]), "+f"(c[2]), "+f"(c[3])
        : "r"(a[0]), "r"(a[1]), "r"(a[2]), "r"(a[3]), "r"(b[0]), "r"(b[1]));
}
// gate*mag activation: sigmoid(g) * softplus(m), fast-math MUFU path
__device__ __forceinline__ float act(float g, float m) {
    float sig = __fdividef(1.f, 1.f + __expf(-g));
    float sp  = fmaxf(m, 0.f) + __logf(1.f + __expf(-fabsf(m)));
    return sig * sp;
}

// ============================================================================
// Kernel 1: embedding  x = atom_fea @ W_embed + b      [N,92]@[92,128]
// ============================================================================
__global__ void k_embed(const float* __restrict__ atom_fea,
                        const float* __restrict__ W,
                        const float* __restrict__ b) {
    __shared__ float Ws[ORIG * FDIM];
    __shared__ float rows[2 * ORIG];
    int tid = threadIdx.x;
    for (int i = tid; i < ORIG * FDIM; i += 256) Ws[i] = W[i];
    __syncthreads();
    int base = blockIdx.x * 128;
    int half = tid >> 7, f = tid & 127;
    for (int it = 0; it < 64; ++it) {
        int r0 = base + it * 2;
        for (int j = tid; j < 2 * ORIG; j += 256)
            rows[j] = atom_fea[r0 * ORIG + j];
        __syncthreads();
        float acc = b[f];
        const float* rp = rows + half * ORIG;
        #pragma unroll 4
        for (int e = 0; e < ORIG; e++)
            acc = fmaf(rp[e], Ws[e * FDIM + f], acc);
        g_x[(r0 + half) * FDIM + f] = acc;
        __syncthreads();
    }
}

// ============================================================================
// Kernel 2: convA  [phi_c | y_nbr] = x @ [Wc | Wn] + [bc | bn]
// ============================================================================
__global__ void k_convA(const float* __restrict__ Wc, const float* __restrict__ bc,
                        const float* __restrict__ Wn, const float* __restrict__ bn) {
    __shared__ float As[16 * 68];
    __shared__ float Bs[16 * 64];
    int tid = threadIdx.x;
    int tx = tid & 15, ty = tid >> 4;
    int m0 = blockIdx.y * 64;
    int n0 = blockIdx.x * 64;
    const float* W  = (n0 < FDIM) ? Wc : Wn;
    const float* bb = (n0 < FDIM) ? bc : bn;
    int colbase = n0 & (FDIM - 1);

    float c00=0,c01=0,c02=0,c03=0, c10=0,c11=0,c12=0,c13=0;
    float c20=0,c21=0,c22=0,c23=0, c30=0,c31=0,c32=0,c33=0;
    int arow = tid >> 2, ac4 = tid & 3;
    int brow = tid >> 4, bc4 = tid & 15;

    for (int kt = 0; kt < 8; ++kt) {
        int k0 = kt * 16;
        float4 av = *(const float4*)&g_x[(m0 + arow) * FDIM + k0 + ac4 * 4];
        float4 bv = *(const float4*)&W[(k0 + brow) * FDIM + colbase + bc4 * 4];
        __syncthreads();
        As[(ac4*4+0)*68 + arow] = av.x;
        As[(ac4*4+1)*68 + arow] = av.y;
        As[(ac4*4+2)*68 + arow] = av.z;
        As[(ac4*4+3)*68 + arow] = av.w;
        *(float4*)&Bs[brow * 64 + bc4 * 4] = bv;
        __syncthreads();
        #pragma unroll
        for (int k = 0; k < 16; k++) {
            float4 a = *(const float4*)&As[k * 68 + ty * 4];
            float4 b = *(const float4*)&Bs[k * 64 + tx * 4];
            c00=fmaf(a.x,b.x,c00); c01=fmaf(a.x,b.y,c01); c02=fmaf(a.x,b.z,c02); c03=fmaf(a.x,b.w,c03);
            c10=fmaf(a.y,b.x,c10); c11=fmaf(a.y,b.y,c11); c12=fmaf(a.y,b.z,c12); c13=fmaf(a.y,b.w,c13);
            c20=fmaf(a.z,b.x,c20); c21=fmaf(a.z,b.y,c21); c22=fmaf(a.z,b.z,c22); c23=fmaf(a.z,b.w,c23);
            c30=fmaf(a.w,b.x,c30); c31=fmaf(a.w,b.y,c31); c32=fmaf(a.w,b.z,c32); c33=fmaf(a.w,b.w,c33);
        }
    }
    float* dst = (n0 < FDIM) ? g_pc : g_yn;
    float cr[4][4] = {{c00,c01,c02,c03},{c10,c11,c12,c13},{c20,c21,c22,c23},{c30,c31,c32,c33}};
    #pragma unroll
    for (int ii = 0; ii < 4; ii++) {
        int r = m0 + ty * 4 + ii;
        #pragma unroll
        for (int jj = 0; jj < 4; jj++) {
            int j = colbase + tx * 4 + jj;
            dst[r * FDIM + j] = cr[ii][jj] + bb[j];
        }
    }
}

// ============================================================================
// Kernel 3a: k_inter — inter[(n,m),f] = pc * yn[idx] * phi_e, tf32-rounded,
// written to padded layout (16 rows/atom; rows 12-15 stay zero).
// ============================================================================
__global__ void k_inter(const float* __restrict__ nbr_fea, const int* __restrict__ nbr_idx,
                        const float* __restrict__ We, const float* __restrict__ be) {
    __shared__ float WeS[EDGE * FDIM];
    __shared__ float beS[FDIM];
    __shared__ float snbr[2 * MNBR * EDGE];
    __shared__ int   sidx[2 * MNBR];
    int tid = threadIdx.x;
    for (int i = tid; i < EDGE * FDIM; i += 256) WeS[i] = We[i];
    if (tid < FDIM) beS[tid] = be[tid];
    __syncthreads();

    int half = tid >> 7, f = tid & 127;
    for (int p = blockIdx.x; p < N_ATOMS / 2; p += gridDim.x) {
        int n = p * 2 + half;
        if (f < MNBR) sidx[half * MNBR + f] = nbr_idx[n * MNBR + f];
        for (int j = f; j < MNBR * EDGE; j += 128)
            snbr[half * MNBR * EDGE + j] = nbr_fea[n * MNBR * EDGE + j];
        __syncthreads();

        float pc = g_pc[n * FDIM + f];
        float yn[MNBR];
        #pragma unroll
        for (int m = 0; m < MNBR; m++)
            yn[m] = g_yn[sidx[half * MNBR + m] * FDIM + f];

        float pe[MNBR];
        #pragma unroll
        for (int m = 0; m < MNBR; m++) pe[m] = beS[f];
        const float* sn = snbr + half * MNBR * EDGE;
        for (int e = 0; e < EDGE; e++) {
            float w = WeS[e * FDIM + f];
            #pragma unroll
            for (int m = 0; m < MNBR; m++)
                pe[m] = fmaf(sn[m * EDGE + e], w, pe[m]);
        }
        size_t rb = (size_t)n * PROWS * FDIM + f;
        #pragma unroll
        for (int m = 0; m < MNBR; m++)
            g_inter[rb + (size_t)m * FDIM] = tf32r(pc * yn[m] * pe[m]);
        __syncthreads();
    }
}

// ============================================================================
// Kernel 3b: k_gm — mma.sync tf32 persistent GEMM + fused epilogue
//   C[r, f] (gate) and C[r, f] (mag) for 64 rows x 128 f per tile,
//   then sigmoid*softplus, masked per-atom row sum, LayerNorm, residual.
// smem: B weights [128k][264] (gate cols 0-127, mag 128-255) | A x2 [64][132]
// ============================================================================
#define S_B    0
#define S_A0   33792
#define S_A1   42240
#define S_BIAS 50688
#define S_RED  51200
#define S_TOT  51712
#define GM_SMEM (S_TOT * 4)

extern __shared__ float sm[];

__device__ __forceinline__ void gm_load_a(uint32_t dst, int t, int tid) {
    const char* src = (const char*)(g_inter + (size_t)t * GT_ROWS * FDIM);
    #pragma unroll
    for (int q = 0; q < 8; q++) {
        int i = tid + q * 256;            // 16B chunk, 0..2047
        int r = i >> 5, c4 = i & 31;
        uint32_t d = dst + (uint32_t)(r * 132 + c4 * 4) * 4;
        asm volatile("cp.async.ca.shared.global [%0], [%1], 16;"
                     :: "r"(d), "l"(src + (size_t)i * 16) : "memory");
    }
}

__global__ void __launch_bounds__(256, 1)
k_gm(const float* __restrict__ Wg, const float* __restrict__ bg,
     const float* __restrict__ Wm, const float* __restrict__ bm,
     const float* __restrict__ lns, const float* __restrict__ lnb) {
    int tid = threadIdx.x, wid = tid >> 5, lane = tid & 31;
    uint32_t* smu = (uint32_t*)sm;

    // resident weights, tf32-rounded: B[k][n], n<128 gate, n>=128 mag
    for (int i = tid; i < FDIM * FDIM; i += 256) {
        int k = i >> 7, n = i & 127;
        smu[S_B + k * 264 + n]       = __float_as_uint(tf32r(Wg[i]));
        smu[S_B + k * 264 + 128 + n] = __float_as_uint(tf32r(Wm[i]));
    }
    if (tid < FDIM) {
        sm[S_BIAS + tid]       = bg[tid];
        sm[S_BIAS + 128 + tid] = bm[tid];
        sm[S_BIAS + 256 + tid] = lns[tid];
        sm[S_BIAS + 384 + tid] = lnb[tid];
    }
    __syncthreads();

    int wr = wid >> 2, wc = wid & 3;       // warp grid 2(row) x 4(col)
    int tig = lane & 3, grp = lane >> 2;
    // per-warp bias registers (f columns fixed for all tiles)
    float bgr[4][2], bmr[4][2];
    #pragma unroll
    for (int j = 0; j < 4; j++) {
        int f0 = wc * 32 + j * 8 + 2 * tig;
        bgr[j][0] = sm[S_BIAS + f0];       bgr[j][1] = sm[S_BIAS + f0 + 1];
        bmr[j][0] = sm[S_BIAS + 128 + f0]; bmr[j][1] = sm[S_BIAS + 128 + f0 + 1];
    }
    float4 lns4 = make_float4(0,0,0,0), lnb4 = make_float4(0,0,0,0);
    if (wid < 4) {
        lns4 = *(const float4*)&sm[S_BIAS + 256 + lane * 4];
        lnb4 = *(const float4*)&sm[S_BIAS + 384 + lane * 4];
    }

    uint32_t abuf[2] = { smem_u32(sm + S_A0), smem_u32(sm + S_A1) };
    int stride = gridDim.x;
    int t0 = blockIdx.x;
    gm_load_a(abuf[0], t0, tid);
    asm volatile("cp.async.commit_group;" ::: "memory");
    int cur = 0;

    for (int t = t0; t < NTILE; t += stride) {
        if (t + stride < NTILE) {
            gm_load_a(abuf[cur ^ 1], t + stride, tid);
            asm volatile("cp.async.commit_group;" ::: "memory");
            asm volatile("cp.async.wait_group 1;" ::: "memory");
        } else {
            asm volatile("cp.async.wait_group 0;" ::: "memory");
        }
        __syncthreads();

        const uint32_t* Asu = smu + (cur ? S_A1 : S_A0);
        float cg[2][4][4] = {}, cm[2][4][4] = {};
        #pragma unroll
        for (int ks = 0; ks < 16; ks++) {
            int k0 = ks * 8;
            uint32_t a[2][4];
            #pragma unroll
            for (int rt = 0; rt < 2; rt++) {
                int r = wr * 32 + rt * 16 + grp;
                a[rt][0] = Asu[r * 132 + k0 + tig];
                a[rt][1] = Asu[(r + 8) * 132 + k0 + tig];
                a[rt][2] = Asu[r * 132 + k0 + 4 + tig];
                a[rt][3] = Asu[(r + 8) * 132 + k0 + 4 + tig];
            }
            #pragma unroll
            for (int j = 0; j < 4; j++) {
                int n = wc * 32 + j * 8 + grp;
                uint32_t bgf[2] = { Asu[0], 0 };  // placeholder overwritten below
                bgf[0] = smu[S_B + (k0 + tig) * 264 + n];
                bgf[1] = smu[S_B + (k0 + 4 + tig) * 264 + n];
                uint32_t bmf[2];
                bmf[0] = smu[S_B + (k0 + tig) * 264 + 128 + n];
                bmf[1] = smu[S_B + (k0 + 4 + tig) * 264 + 128 + n];
                #pragma unroll
                for (int rt = 0; rt < 2; rt++) {
                    mma_tf32(cg[rt][j], a[rt], bgf);
                    mma_tf32(cm[rt][j], a[rt], bmf);
                }
            }
        }

        // epilogue: activations, masked per-atom (12 of 16 rows) column sums
        bool notpad = (grp < 4);          // c2/c3 rows (grp+8) pad when grp>=4
        #pragma unroll
        for (int rt = 0; rt < 2; rt++) {
            int atom = wr * 2 + rt;
            #pragma unroll
            for (int j = 0; j < 4; j++) {
                float p0 = act(cg[rt][j][0] + bgr[j][0], cm[rt][j][0] + bmr[j][0]);
                float p1 = act(cg[rt][j][1] + bgr[j][1], cm[rt][j][1] + bmr[j][1]);
                if (notpad) {
                    p0 += act(cg[rt][j][2] + bgr[j][0], cm[rt][j][2] + bmr[j][0]);
                    p1 += act(cg[rt][j][3] + bgr[j][1], cm[rt][j][3] + bmr[j][1]);
                }
                #pragma unroll
                for (int o = 4; o < 32; o <<= 1) {
                    p0 += __shfl_xor_sync(0xffffffffu, p0, o);
                    p1 += __shfl_xor_sync(0xffffffffu, p1, o);
                }
                if (grp == 0) {
                    int f0 = wc * 32 + j * 8 + 2 * tig;
                    sm[S_RED + atom * 128 + f0]     = p0;
                    sm[S_RED + atom * 128 + f0 + 1] = p1;
                }
            }
        }
        __syncthreads();

        if (wid < 4) {      // one warp per atom: LayerNorm + residual
            float4 v = *(const float4*)&sm[S_RED + wid * 128 + lane * 4];
            float s = v.x + v.y + v.z + v.w;
            float q = v.x*v.x + v.y*v.y + v.z*v.z + v.w*v.w;
            #pragma unroll
            for (int o = 16; o > 0; o >>= 1) {
                s += __shfl_xor_sync(0xffffffffu, s, o);
                q += __shfl_xor_sync(0xffffffffu, q, o);
            }
            float mu = s * (1.f / FDIM);
            float var = q * (1.f / FDIM) - mu * mu;
            float rstd = rsqrtf(var + 1e-6f);
            int n = t * GT_ATOMS + wid;
            float4 x = *(float4*)&g_x[n * FDIM + lane * 4];
            x.x += (v.x - mu) * rstd * lns4.x + lnb4.x;
            x.y += (v.y - mu) * rstd * lns4.y + lnb4.y;
            x.z += (v.z - mu) * rstd * lns4.z + lnb4.z;
            x.w += (v.w - mu) * rstd * lns4.w + lnb4.w;
            *(float4*)&g_x[n * FDIM + lane * 4] = x;
        }
        cur ^= 1;
    }
}

// ============================================================================
// Kernel 4: readout
// ============================================================================
#define RO_WHT  0
#define RO_WO   33792
#define RO_BH   34048
#define RO_XR   34304
#define RO_RED  34432
#define RO_FLOATS 34440
#define RO_SMEM (RO_FLOATS * 4)

__global__ void k_readout(const float* __restrict__ Wh, const float* __restrict__ bh,
                          const float* __restrict__ Wout, const float* __restrict__ bout) {
    float* WhT = sm + RO_WHT;
    float* WoS = sm + RO_WO;
    float* bhS = sm + RO_BH;
    float* xr  = sm + RO_XR;
    float* red = sm + RO_RED;
    int tid = threadIdx.x;
    for (int i = tid; i < FDIM * HDIM; i += 256) {
        int k = i >> 8, j = i & 255;
        WhT[j * 132 + k] = Wh[i];
    }
    WoS[tid] = Wout[tid];
    bhS[tid] = bh[tid];
    __syncthreads();
    float b0 = bout[0];
    const float4* wp = (const float4*)(WhT + tid * 132);

    for (int n = blockIdx.x; n < N_ATOMS; n += gridDim.x) {
        if (tid < FDIM) xr[tid] = g_x[n * FDIM + tid];
        __syncthreads();
        float acc = bhS[tid];
        #pragma unroll 4
        for (int k4 = 0; k4 < FDIM / 4; k4++) {
            float4 w = wp[k4];
            float4 xv = *(const float4*)(xr + k4 * 4);
            acc = fmaf(w.x, xv.x, acc); acc = fmaf(w.y, xv.y, acc);
            acc = fmaf(w.z, xv.z, acc); acc = fmaf(w.w, xv.w, acc);
        }
        float pcontrib = softplusf(acc) * WoS[tid];
        #pragma unroll
        for (int o = 16; o > 0; o >>= 1)
            pcontrib += __shfl_xor_sync(0xffffffffu, pcontrib, o);
        if ((tid & 31) == 0) red[tid >> 5] = pcontrib;
        __syncthreads();
        if (tid == 0) {
            float ssum = 0.f;
            #pragma unroll
            for (int w8 = 0; w8 < 8; w8++) ssum += red[w8];
            g_site[n] = ssum + b0;
        }
        __syncthreads();
    }
}

// ============================================================================
// Kernel 5: per-crystal sum
// ============================================================================
__global__ void k_crystal(float* __restrict__ out) {
    __shared__ float red[8];
    int c = blockIdx.x, tid = threadIdx.x;
    float v = g_site[c * APC + tid];
    #pragma unroll
    for (int o = 16; o > 0; o >>= 1)
        v += __shfl_xor_sync(0xffffffffu, v, o);
    if ((tid & 31) == 0) red[tid >> 5] = v;
    __syncthreads();
    if (tid == 0) {
        float s = 0.f;
        #pragma unroll
        for (int i = 0; i < 8; i++) s += red[i];
        out[c] = s;
    }
}

// ============================================================================
extern "C" void kernel_launch(void* const* d_in, const int* in_sizes, int n_in,
                              void* d_out, int out_size) {
    const float* atom_fea = (const float*)d_in[0];
    const float* nbr_fea  = (const float*)d_in[1];
    const int*   nbr_idx  = (const int*)  d_in[2];
    const float* W_embed  = (const float*)d_in[3];
    const float* b_embed  = (const float*)d_in[4];
    const float* W_center = (const float*)d_in[5];
    const float* b_center = (const float*)d_in[6];
    const float* W_nbr    = (const float*)d_in[7];
    const float* b_nbr    = (const float*)d_in[8];
    const float* W_edge   = (const float*)d_in[9];
    const float* b_edge   = (const float*)d_in[10];
    const float* W_gate   = (const float*)d_in[11];
    const float* b_gate   = (const float*)d_in[12];
    const float* W_mag    = (const float*)d_in[13];
    const float* b_mag    = (const float*)d_in[14];
    const float* ln_scale = (const float*)d_in[15];
    const float* ln_bias  = (const float*)d_in[16];
    const float* W_h      = (const float*)d_in[17];
    const float* b_h      = (const float*)d_in[18];
    const float* W_out    = (const float*)d_in[19];
    const float* b_out    = (const float*)d_in[20];
    float* out = (float*)d_out;

    cudaFuncSetAttribute(k_gm,      cudaFuncAttributeMaxDynamicSharedMemorySize, GM_SMEM);
    cudaFuncSetAttribute(k_readout, cudaFuncAttributeMaxDynamicSharedMemorySize, RO_SMEM);

    k_embed<<<256, 256>>>(atom_fea, W_embed, b_embed);
    for (int l = 0; l < NCONV; l++) {
        dim3 gA(4, 512);
        k_convA<<<gA, 256>>>(W_center + l * FDIM * FDIM, b_center + l * FDIM,
                             W_nbr    + l * FDIM * FDIM, b_nbr    + l * FDIM);
        k_inter<<<592, 256>>>(nbr_fea, nbr_idx,
                              W_edge + l * EDGE * FDIM, b_edge + l * FDIM);
        k_gm<<<148, 256, GM_SMEM>>>(W_gate + l * FDIM * FDIM, b_gate + l * FDIM,
                                    W_mag  + l * FDIM * FDIM, b_mag  + l * FDIM,
                                    ln_scale + l * FDIM, ln_bias + l * FDIM);
    }
    k_readout<<<152, 256, RO_SMEM>>>(W_h, b_h, W_out, b_out);
    k_crystal<<<NCRY, 256>>>(out);
}

// round 4
// speedup vs baseline: 2.5572x; 1.3395x over previous
#include <cuda_runtime.h>
#include <math.h>
#include <cstdint>

#define N_ATOMS 32768
#define MNBR    12
#define PROWS   16
#define ORIG    92
#define EDGE    41
#define EK      48                        // padded edge-K
#define FDIM    128
#define HDIM    256
#define NCONV   3
#define NCRY    128
#define APC     256
#define GT_ATOMS 4
#define GT_ROWS  (GT_ATOMS * PROWS)       // 64
#define NTILE    (N_ATOMS / GT_ATOMS)     // 8192

// ---- scratch ----
__device__ float g_x [N_ATOMS * FDIM];
__device__ float g_pc[N_ATOMS * FDIM];
__device__ float g_yn[N_ATOMS * FDIM];
__device__ float g_site[N_ATOMS];

__device__ __forceinline__ float softplusf(float x) {
    return fmaxf(x, 0.f) + log1pf(expf(-fabsf(x)));
}
__device__ __forceinline__ float tf32r(float x) {
    uint32_t u;
    asm("cvt.rna.tf32.f32 %0, %1;" : "=r"(u) : "f"(x));
    return __uint_as_float(u);
}
__device__ __forceinline__ void mma_tf32(float c[4], const uint32_t a[4], const uint32_t b[2]) {
    asm volatile("mma.sync.aligned.m16n8k8.row.col.f32.tf32.tf32.f32 "
        "{%0,%1,%2,%3}, {%4,%5,%6,%7}, {%8,%9}, {%0,%1,%2,%3};"
        : "+f"(c[0]), "+f"(c[1]), "+f"(c[2]), "+f"(c[3])
        : "r"(a[0]), "r"(a[1]), "r"(a[2]), "r"(a[3]), "r"(b[0]), "r"(b[1]));
}
__device__ __forceinline__ float act(float g, float m) {
    float sig = __fdividef(1.f, 1.f + __expf(-g));
    float sp  = fmaxf(m, 0.f) + __logf(1.f + __expf(-fabsf(m)));
    return sig * sp;
}

// ============================================================================
// Kernel 1: embedding
// ============================================================================
__global__ void k_embed(const float* __restrict__ atom_fea,
                        const float* __restrict__ W,
                        const float* __restrict__ b) {
    __shared__ float Ws[ORIG * FDIM];
    __shared__ float rows[2 * ORIG];
    int tid = threadIdx.x;
    for (int i = tid; i < ORIG * FDIM; i += 256) Ws[i] = W[i];
    __syncthreads();
    int base = blockIdx.x * 128;
    int half = tid >> 7, f = tid & 127;
    for (int it = 0; it < 64; ++it) {
        int r0 = base + it * 2;
        for (int j = tid; j < 2 * ORIG; j += 256)
            rows[j] = atom_fea[r0 * ORIG + j];
        __syncthreads();
        float acc = b[f];
        const float* rp = rows + half * ORIG;
        #pragma unroll 4
        for (int e = 0; e < ORIG; e++)
            acc = fmaf(rp[e], Ws[e * FDIM + f], acc);
        g_x[(r0 + half) * FDIM + f] = acc;
        __syncthreads();
    }
}

// ============================================================================
// Kernel 2: convA  [phi_c | y_nbr] = x @ [Wc | Wn] + [bc | bn]
// ============================================================================
__global__ void k_convA(const float* __restrict__ Wc, const float* __restrict__ bc,
                        const float* __restrict__ Wn, const float* __restrict__ bn) {
    __shared__ float As[16 * 68];
    __shared__ float Bs[16 * 64];
    int tid = threadIdx.x;
    int tx = tid & 15, ty = tid >> 4;
    int m0 = blockIdx.y * 64;
    int n0 = blockIdx.x * 64;
    const float* W  = (n0 < FDIM) ? Wc : Wn;
    const float* bb = (n0 < FDIM) ? bc : bn;
    int colbase = n0 & (FDIM - 1);

    float c00=0,c01=0,c02=0,c03=0, c10=0,c11=0,c12=0,c13=0;
    float c20=0,c21=0,c22=0,c23=0, c30=0,c31=0,c32=0,c33=0;
    int arow = tid >> 2, ac4 = tid & 3;
    int brow = tid >> 4, bc4 = tid & 15;

    for (int kt = 0; kt < 8; ++kt) {
        int k0 = kt * 16;
        float4 av = *(const float4*)&g_x[(m0 + arow) * FDIM + k0 + ac4 * 4];
        float4 bv = *(const float4*)&W[(k0 + brow) * FDIM + colbase + bc4 * 4];
        __syncthreads();
        As[(ac4*4+0)*68 + arow] = av.x;
        As[(ac4*4+1)*68 + arow] = av.y;
        As[(ac4*4+2)*68 + arow] = av.z;
        As[(ac4*4+3)*68 + arow] = av.w;
        *(float4*)&Bs[brow * 64 + bc4 * 4] = bv;
        __syncthreads();
        #pragma unroll
        for (int k = 0; k < 16; k++) {
            float4 a = *(const float4*)&As[k * 68 + ty * 4];
            float4 b = *(const float4*)&Bs[k * 64 + tx * 4];
            c00=fmaf(a.x,b.x,c00); c01=fmaf(a.x,b.y,c01); c02=fmaf(a.x,b.z,c02); c03=fmaf(a.x,b.w,c03);
            c10=fmaf(a.y,b.x,c10); c11=fmaf(a.y,b.y,c11); c12=fmaf(a.y,b.z,c12); c13=fmaf(a.y,b.w,c13);
            c20=fmaf(a.z,b.x,c20); c21=fmaf(a.z,b.y,c21); c22=fmaf(a.z,b.z,c22); c23=fmaf(a.z,b.w,c23);
            c30=fmaf(a.w,b.x,c30); c31=fmaf(a.w,b.y,c31); c32=fmaf(a.w,b.z,c32); c33=fmaf(a.w,b.w,c33);
        }
    }
    float* dst = (n0 < FDIM) ? g_pc : g_yn;
    float cr[4][4] = {{c00,c01,c02,c03},{c10,c11,c12,c13},{c20,c21,c22,c23},{c30,c31,c32,c33}};
    #pragma unroll
    for (int ii = 0; ii < 4; ii++) {
        int r = m0 + ty * 4 + ii;
        #pragma unroll
        for (int jj = 0; jj < 4; jj++) {
            int j = colbase + tx * 4 + jj;
            dst[r * FDIM + j] = cr[ii][jj] + bb[j];
        }
    }
}

// ============================================================================
// Kernel 3: k_conv — FUSED per-layer conv: phi_e mma + inter build + gate/mag
//           mma + activation + LayerNorm + residual.  Persistent, 148 CTAs.
// smem (floats):
//   S_W    [128k][264]  gate|mag weights (tf32)      33792
//   S_AGM  [64][132]    inter tile (A of gm mma)      8448
//   S_AE   [64][52]     nbr_fea tile (A of edge mma)  3328
//   S_WE   [48][132]    W_edge (tf32, K padded)       6336
//   S_BIAS bg|bm|lns|lnb|be                            640
//   S_RED                                              512
//   S_IDX  48 ints                                      64
// ============================================================================
#define S_W    0
#define S_AGM  33792
#define S_AE   42240
#define S_WE   45568
#define S_BIAS 51904
#define S_RED  52544
#define S_IDX  53056
#define S_TOT  53120
#define CV_SMEM (S_TOT * 4)

extern __shared__ float sm[];

__global__ void __launch_bounds__(256, 1)
k_conv(const float* __restrict__ nbr_fea, const int* __restrict__ nbr_idx,
       const float* __restrict__ Wg, const float* __restrict__ bg,
       const float* __restrict__ Wm, const float* __restrict__ bm,
       const float* __restrict__ We, const float* __restrict__ be,
       const float* __restrict__ lns, const float* __restrict__ lnb) {
    int tid = threadIdx.x, wid = tid >> 5, lane = tid & 31;
    uint32_t* smu = (uint32_t*)sm;
    int* sidx = (int*)(sm + S_IDX);

    // ---- init resident weights (tf32) ----
    for (int i = tid; i < FDIM * FDIM; i += 256) {
        int k = i >> 7, n = i & 127;
        smu[S_W + k * 264 + n]       = __float_as_uint(tf32r(Wg[i]));
        smu[S_W + k * 264 + 128 + n] = __float_as_uint(tf32r(Wm[i]));
    }
    for (int i = tid; i < EK * 132; i += 256) sm[S_WE + i] = 0.f;     // zero padded W_edge
    for (int i = tid; i < 8448; i += 256) sm[S_AGM + i] = 0.f;        // zero A_gm (pad rows stay 0)
    for (int i = tid; i < 3328; i += 256) sm[S_AE + i] = 0.f;         // zero A_e  (pads stay 0)
    __syncthreads();
    for (int i = tid; i < EDGE * FDIM; i += 256) {
        int k = i >> 7, n = i & 127;
        sm[S_WE + k * 132 + n] = tf32r(We[i]);
    }
    if (tid < FDIM) {
        sm[S_BIAS + tid]       = bg[tid];
        sm[S_BIAS + 128 + tid] = bm[tid];
        sm[S_BIAS + 256 + tid] = lns[tid];
        sm[S_BIAS + 384 + tid] = lnb[tid];
        sm[S_BIAS + 512 + tid] = be[tid];
    }
    __syncthreads();

    int wr = wid >> 2, wc = wid & 3;        // 2(row) x 4(col) warp grid
    int tig = lane & 3, grp = lane >> 2;
    bool notpad = (grp < 4);                // rows grp+8 real only when grp<4

    float bgr[4][2], bmr[4][2], ber[4][2];
    #pragma unroll
    for (int j = 0; j < 4; j++) {
        int f0 = wc * 32 + j * 8 + 2 * tig;
        bgr[j][0] = sm[S_BIAS + f0];        bgr[j][1] = sm[S_BIAS + f0 + 1];
        bmr[j][0] = sm[S_BIAS + 128 + f0];  bmr[j][1] = sm[S_BIAS + 128 + f0 + 1];
        ber[j][0] = sm[S_BIAS + 512 + f0];  ber[j][1] = sm[S_BIAS + 512 + f0 + 1];
    }
    float4 lns4 = make_float4(0,0,0,0), lnb4 = make_float4(0,0,0,0);
    if (wid < 4) {
        lns4 = *(const float4*)&sm[S_BIAS + 256 + lane * 4];
        lnb4 = *(const float4*)&sm[S_BIAS + 384 + lane * 4];
    }

    for (int t = blockIdx.x; t < NTILE; t += gridDim.x) {
        // ---- stage: neighbor indices + edge features (48 contiguous rows) ----
        if (tid < 48) sidx[tid] = nbr_idx[t * 48 + tid];
        {
            const float* nf = nbr_fea + (size_t)t * 48 * EDGE;
            #pragma unroll
            for (int q = 0; q < 8; q++) {
                int i = tid + q * 256;
                if (i < 48 * EDGE) {
                    int mr = i / EDGE, e = i - mr * EDGE;
                    int a = mr / MNBR, m = mr - a * MNBR;
                    sm[S_AE + (a * PROWS + m) * 52 + e] = tf32r(nf[i]);
                }
            }
        }
        __syncthreads();

        // ---- prefetch yn / pc operand pairs from L2 ----
        float2 yn0[2][4], yn1[2][4], pcp[2][4];
        #pragma unroll
        for (int rt = 0; rt < 2; rt++) {
            int a = wr * 2 + rt;
            int i0 = sidx[a * MNBR + grp];                            // m = grp (<12)
            int i1 = notpad ? sidx[a * MNBR + grp + 8] : 0;
            #pragma unroll
            for (int j = 0; j < 4; j++) {
                int f0 = wc * 32 + j * 8 + 2 * tig;
                yn0[rt][j] = *(const float2*)&g_yn[i0 * FDIM + f0];
                yn1[rt][j] = notpad ? *(const float2*)&g_yn[i1 * FDIM + f0]
                                    : make_float2(0.f, 0.f);
                pcp[rt][j] = *(const float2*)&g_pc[(t * GT_ATOMS + a) * FDIM + f0];
            }
        }

        // ---- phi_e mma: C[r,f] = A_e @ W_e  (M=64, N=128, K=48) ----
        float ce[2][4][4] = {};
        #pragma unroll
        for (int ks = 0; ks < 6; ks++) {
            int k0 = ks * 8;
            uint32_t a[2][4];
            #pragma unroll
            for (int rt = 0; rt < 2; rt++) {
                int r = wr * 32 + rt * 16 + grp;
                a[rt][0] = smu[S_AE + r * 52 + k0 + tig];
                a[rt][1] = smu[S_AE + (r + 8) * 52 + k0 + tig];
                a[rt][2] = smu[S_AE + r * 52 + k0 + 4 + tig];
                a[rt][3] = smu[S_AE + (r + 8) * 52 + k0 + 4 + tig];
            }
            #pragma unroll
            for (int j = 0; j < 4; j++) {
                int n = wc * 32 + j * 8 + grp;
                uint32_t b[2];
                b[0] = smu[S_WE + (k0 + tig) * 132 + n];
                b[1] = smu[S_WE + (k0 + 4 + tig) * 132 + n];
                #pragma unroll
                for (int rt = 0; rt < 2; rt++)
                    mma_tf32(ce[rt][j], a[rt], b);
            }
        }

        // ---- build inter tile in smem: A_gm[r,f] = tf32(pc*yn*(pe+be)) ----
        #pragma unroll
        for (int rt = 0; rt < 2; rt++) {
            int r = wr * 32 + rt * 16 + grp;
            #pragma unroll
            for (int j = 0; j < 4; j++) {
                int f0 = wc * 32 + j * 8 + 2 * tig;
                float2 o0;
                o0.x = tf32r(pcp[rt][j].x * yn0[rt][j].x * (ce[rt][j][0] + ber[j][0]));
                o0.y = tf32r(pcp[rt][j].y * yn0[rt][j].y * (ce[rt][j][1] + ber[j][1]));
                *(float2*)&sm[S_AGM + r * 132 + f0] = o0;
                if (notpad) {
                    float2 o1;
                    o1.x = tf32r(pcp[rt][j].x * yn1[rt][j].x * (ce[rt][j][2] + ber[j][0]));
                    o1.y = tf32r(pcp[rt][j].y * yn1[rt][j].y * (ce[rt][j][3] + ber[j][1]));
                    *(float2*)&sm[S_AGM + (r + 8) * 132 + f0] = o1;
                }
            }
        }
        __syncthreads();

        // ---- gate/mag mma: K=128 over inter tile ----
        float cg[2][4][4] = {}, cmm[2][4][4] = {};
        #pragma unroll
        for (int ks = 0; ks < 16; ks++) {
            int k0 = ks * 8;
            uint32_t a[2][4];
            #pragma unroll
            for (int rt = 0; rt < 2; rt++) {
                int r = wr * 32 + rt * 16 + grp;
                a[rt][0] = smu[S_AGM + r * 132 + k0 + tig];
                a[rt][1] = smu[S_AGM + (r + 8) * 132 + k0 + tig];
                a[rt][2] = smu[S_AGM + r * 132 + k0 + 4 + tig];
                a[rt][3] = smu[S_AGM + (r + 8) * 132 + k0 + 4 + tig];
            }
            #pragma unroll
            for (int j = 0; j < 4; j++) {
                int n = wc * 32 + j * 8 + grp;
                uint32_t bgf[2], bmf[2];
                bgf[0] = smu[S_W + (k0 + tig) * 264 + n];
                bgf[1] = smu[S_W + (k0 + 4 + tig) * 264 + n];
                bmf[0] = smu[S_W + (k0 + tig) * 264 + 128 + n];
                bmf[1] = smu[S_W + (k0 + 4 + tig) * 264 + 128 + n];
                #pragma unroll
                for (int rt = 0; rt < 2; rt++) {
                    mma_tf32(cg[rt][j], a[rt], bgf);
                    mma_tf32(cmm[rt][j], a[rt], bmf);
                }
            }
        }

        // ---- activation + masked per-atom column sums ----
        #pragma unroll
        for (int rt = 0; rt < 2; rt++) {
            int atom = wr * 2 + rt;
            #pragma unroll
            for (int j = 0; j < 4; j++) {
                float p0 = act(cg[rt][j][0] + bgr[j][0], cmm[rt][j][0] + bmr[j][0]);
                float p1 = act(cg[rt][j][1] + bgr[j][1], cmm[rt][j][1] + bmr[j][1]);
                if (notpad) {
                    p0 += act(cg[rt][j][2] + bgr[j][0], cmm[rt][j][2] + bmr[j][0]);
                    p1 += act(cg[rt][j][3] + bgr[j][1], cmm[rt][j][3] + bmr[j][1]);
                }
                #pragma unroll
                for (int o = 4; o < 32; o <<= 1) {
                    p0 += __shfl_xor_sync(0xffffffffu, p0, o);
                    p1 += __shfl_xor_sync(0xffffffffu, p1, o);
                }
                if (grp == 0) {
                    int f0 = wc * 32 + j * 8 + 2 * tig;
                    sm[S_RED + atom * 128 + f0]     = p0;
                    sm[S_RED + atom * 128 + f0 + 1] = p1;
                }
            }
        }
        __syncthreads();

        // ---- LayerNorm + residual (one warp per atom) ----
        if (wid < 4) {
            float4 v = *(const float4*)&sm[S_RED + wid * 128 + lane * 4];
            float s = v.x + v.y + v.z + v.w;
            float q = v.x*v.x + v.y*v.y + v.z*v.z + v.w*v.w;
            #pragma unroll
            for (int o = 16; o > 0; o >>= 1) {
                s += __shfl_xor_sync(0xffffffffu, s, o);
                q += __shfl_xor_sync(0xffffffffu, q, o);
            }
            float mu = s * (1.f / FDIM);
            float var = q * (1.f / FDIM) - mu * mu;
            float rstd = rsqrtf(var + 1e-6f);
            int n = t * GT_ATOMS + wid;
            float4 x = *(float4*)&g_x[n * FDIM + lane * 4];
            x.x += (v.x - mu) * rstd * lns4.x + lnb4.x;
            x.y += (v.y - mu) * rstd * lns4.y + lnb4.y;
            x.z += (v.z - mu) * rstd * lns4.z + lnb4.z;
            x.w += (v.w - mu) * rstd * lns4.w + lnb4.w;
            *(float4*)&g_x[n * FDIM + lane * 4] = x;
        }
        __syncthreads();
    }
}

// ============================================================================
// Kernel 4: readout
// ============================================================================
#define RO_WHT  0
#define RO_WO   33792
#define RO_BH   34048
#define RO_XR   34304
#define RO_RED  34432
#define RO_FLOATS 34440
#define RO_SMEM (RO_FLOATS * 4)

__global__ void k_readout(const float* __restrict__ Wh, const float* __restrict__ bh,
                          const float* __restrict__ Wout, const float* __restrict__ bout) {
    float* WhT = sm + RO_WHT;
    float* WoS = sm + RO_WO;
    float* bhS = sm + RO_BH;
    float* xr  = sm + RO_XR;
    float* red = sm + RO_RED;
    int tid = threadIdx.x;
    for (int i = tid; i < FDIM * HDIM; i += 256) {
        int k = i >> 8, j = i & 255;
        WhT[j * 132 + k] = Wh[i];
    }
    WoS[tid] = Wout[tid];
    bhS[tid] = bh[tid];
    __syncthreads();
    float b0 = bout[0];
    const float4* wp = (const float4*)(WhT + tid * 132);

    for (int n = blockIdx.x; n < N_ATOMS; n += gridDim.x) {
        if (tid < FDIM) xr[tid] = g_x[n * FDIM + tid];
        __syncthreads();
        float acc = bhS[tid];
        #pragma unroll 4
        for (int k4 = 0; k4 < FDIM / 4; k4++) {
            float4 w = wp[k4];
            float4 xv = *(const float4*)(xr + k4 * 4);
            acc = fmaf(w.x, xv.x, acc); acc = fmaf(w.y, xv.y, acc);
            acc = fmaf(w.z, xv.z, acc); acc = fmaf(w.w, xv.w, acc);
        }
        float pcontrib = softplusf(acc) * WoS[tid];
        #pragma unroll
        for (int o = 16; o > 0; o >>= 1)
            pcontrib += __shfl_xor_sync(0xffffffffu, pcontrib, o);
        if ((tid & 31) == 0) red[tid >> 5] = pcontrib;
        __syncthreads();
        if (tid == 0) {
            float ssum = 0.f;
            #pragma unroll
            for (int w8 = 0; w8 < 8; w8++) ssum += red[w8];
            g_site[n] = ssum + b0;
        }
        __syncthreads();
    }
}

// ============================================================================
// Kernel 5: per-crystal sum
// ============================================================================
__global__ void k_crystal(float* __restrict__ out) {
    __shared__ float red[8];
    int c = blockIdx.x, tid = threadIdx.x;
    float v = g_site[c * APC + tid];
    #pragma unroll
    for (int o = 16; o > 0; o >>= 1)
        v += __shfl_xor_sync(0xffffffffu, v, o);
    if ((tid & 31) == 0) red[tid >> 5] = v;
    __syncthreads();
    if (tid == 0) {
        float s = 0.f;
        #pragma unroll
        for (int i = 0; i < 8; i++) s += red[i];
        out[c] = s;
    }
}

// ============================================================================
extern "C" void kernel_launch(void* const* d_in, const int* in_sizes, int n_in,
                              void* d_out, int out_size) {
    const float* atom_fea = (const float*)d_in[0];
    const float* nbr_fea  = (const float*)d_in[1];
    const int*   nbr_idx  = (const int*)  d_in[2];
    const float* W_embed  = (const float*)d_in[3];
    const float* b_embed  = (const float*)d_in[4];
    const float* W_center = (const float*)d_in[5];
    const float* b_center = (const float*)d_in[6];
    const float* W_nbr    = (const float*)d_in[7];
    const float* b_nbr    = (const float*)d_in[8];
    const float* W_edge   = (const float*)d_in[9];
    const float* b_edge   = (const float*)d_in[10];
    const float* W_gate   = (const float*)d_in[11];
    const float* b_gate   = (const float*)d_in[12];
    const float* W_mag    = (const float*)d_in[13];
    const float* b_mag    = (const float*)d_in[14];
    const float* ln_scale = (const float*)d_in[15];
    const float* ln_bias  = (const float*)d_in[16];
    const float* W_h      = (const float*)d_in[17];
    const float* b_h      = (const float*)d_in[18];
    const float* W_out    = (const float*)d_in[19];
    const float* b_out    = (const float*)d_in[20];
    float* out = (float*)d_out;

    cudaFuncSetAttribute(k_conv,    cudaFuncAttributeMaxDynamicSharedMemorySize, CV_SMEM);
    cudaFuncSetAttribute(k_readout, cudaFuncAttributeMaxDynamicSharedMemorySize, RO_SMEM);

    k_embed<<<256, 256>>>(atom_fea, W_embed, b_embed);
    for (int l = 0; l < NCONV; l++) {
        dim3 gA(4, 512);
        k_convA<<<gA, 256>>>(W_center + l * FDIM * FDIM, b_center + l * FDIM,
                             W_nbr    + l * FDIM * FDIM, b_nbr    + l * FDIM);
        k_conv<<<148, 256, CV_SMEM>>>(nbr_fea, nbr_idx,
                                      W_gate + l * FDIM * FDIM, b_gate + l * FDIM,
                                      W_mag  + l * FDIM * FDIM, b_mag  + l * FDIM,
                                      W_edge + l * EDGE * FDIM, b_edge + l * FDIM,
                                      ln_scale + l * FDIM, ln_bias + l * FDIM);
    }
    k_readout<<<152, 256, RO_SMEM>>>(W_h, b_h, W_out, b_out);
    k_crystal<<<NCRY, 256>>>(out);
}

// round 5
// speedup vs baseline: 2.6111x; 1.0211x over previous
#include <cuda_runtime.h>
#include <math.h>
#include <cstdint>

#define N_ATOMS 32768
#define MNBR    12
#define PROWS   16
#define ORIG    92
#define EDGE    41
#define EK      48
#define FDIM    128
#define HDIM    256
#define NCONV   3
#define NCRY    128
#define APC     256
#define GT_ATOMS 4
#define GT_ROWS  (GT_ATOMS * PROWS)       // 64
#define NTILE    (N_ATOMS / GT_ATOMS)     // 8192
#define ATILE    (N_ATOMS / 64)           // 512

// ---- scratch ----
__device__ float g_x [N_ATOMS * FDIM];
__device__ float g_pc[N_ATOMS * FDIM];
__device__ float g_yn[N_ATOMS * FDIM];
__device__ float g_site[N_ATOMS];

__device__ __forceinline__ float softplusf(float x) {
    return fmaxf(x, 0.f) + log1pf(expf(-fabsf(x)));
}
__device__ __forceinline__ float tf32r(float x) {
    uint32_t u;
    asm("cvt.rna.tf32.f32 %0, %1;" : "=r"(u) : "f"(x));
    return __uint_as_float(u);
}
__device__ __forceinline__ uint32_t smem_u32(const void* p) {
    uint32_t a;
    asm("{ .reg .u64 t; cvta.to.shared.u64 t, %1; cvt.u32.u64 %0, t; }" : "=r"(a) : "l"(p));
    return a;
}
__device__ __forceinline__ void mma_tf32(float c[4], const uint32_t a[4], const uint32_t b[2]) {
    asm volatile("mma.sync.aligned.m16n8k8.row.col.f32.tf32.tf32.f32 "
        "{%0,%1,%2,%3}, {%4,%5,%6,%7}, {%8,%9}, {%0,%1,%2,%3};"
        : "+f"(c[0]), "+f"(c[1]), "+f"(c[2]), "+f"(c[3])
        : "r"(a[0]), "r"(a[1]), "r"(a[2]), "r"(a[3]), "r"(b[0]), "r"(b[1]));
}
__device__ __forceinline__ float act(float g, float m) {
    float sig = __fdividef(1.f, 1.f + __expf(-g));
    float sp  = fmaxf(m, 0.f) + __logf(1.f + __expf(-fabsf(m)));
    return sig * sp;
}

extern __shared__ float sm[];

// ============================================================================
// Kernel 1: embedding
// ============================================================================
__global__ void k_embed(const float* __restrict__ atom_fea,
                        const float* __restrict__ W,
                        const float* __restrict__ b) {
    __shared__ float Ws[ORIG * FDIM];
    __shared__ float rows[2 * ORIG];
    int tid = threadIdx.x;
    for (int i = tid; i < ORIG * FDIM; i += 256) Ws[i] = W[i];
    __syncthreads();
    int base = blockIdx.x * 128;
    int half = tid >> 7, f = tid & 127;
    for (int it = 0; it < 64; ++it) {
        int r0 = base + it * 2;
        for (int j = tid; j < 2 * ORIG; j += 256)
            rows[j] = atom_fea[r0 * ORIG + j];
        __syncthreads();
        float acc = b[f];
        const float* rp = rows + half * ORIG;
        #pragma unroll 4
        for (int e = 0; e < ORIG; e++)
            acc = fmaf(rp[e], Ws[e * FDIM + f], acc);
        g_x[(r0 + half) * FDIM + f] = acc;
        __syncthreads();
    }
}

// ============================================================================
// Kernel 2: k_convA — tf32 mma GEMM: [phi_c|y_nbr] = x @ [Wc|Wn] + bias
// Persistent, 148 CTAs. smem: W [128k][264] tf32, A [64][132] tf32, bias.
// ============================================================================
#define A2_W    0
#define A2_A    33792
#define A2_BIAS 42240
#define A2_TOT  42496
#define A2_SMEM (A2_TOT * 4)

__global__ void __launch_bounds__(256, 1)
k_convA(const float* __restrict__ Wc, const float* __restrict__ bc,
        const float* __restrict__ Wn, const float* __restrict__ bn) {
    int tid = threadIdx.x, wid = tid >> 5, lane = tid & 31;
    uint32_t* smu = (uint32_t*)sm;
    for (int i = tid; i < FDIM * FDIM; i += 256) {
        int k = i >> 7, n = i & 127;
        smu[A2_W + k * 264 + n]       = __float_as_uint(tf32r(Wc[i]));
        smu[A2_W + k * 264 + 128 + n] = __float_as_uint(tf32r(Wn[i]));
    }
    if (tid < 128) { sm[A2_BIAS + tid] = bc[tid]; sm[A2_BIAS + 128 + tid] = bn[tid]; }
    __syncthreads();

    int wr = wid >> 2, wc = wid & 3;
    int tig = lane & 3, grp = lane >> 2;
    float bcr[4][2], bnr[4][2];
    #pragma unroll
    for (int j = 0; j < 4; j++) {
        int f0 = wc * 32 + j * 8 + 2 * tig;
        bcr[j][0] = sm[A2_BIAS + f0];       bcr[j][1] = sm[A2_BIAS + f0 + 1];
        bnr[j][0] = sm[A2_BIAS + 128 + f0]; bnr[j][1] = sm[A2_BIAS + 128 + f0 + 1];
    }

    for (int t = blockIdx.x; t < ATILE; t += gridDim.x) {
        // stage A tile (tf32-rounded)
        #pragma unroll
        for (int q = 0; q < 8; q++) {
            int ch = tid + q * 256;
            int r = ch >> 5, c4 = ch & 31;
            float4 v = *(const float4*)&g_x[(t * 64 + r) * FDIM + c4 * 4];
            sm[A2_A + r * 132 + c4 * 4 + 0] = tf32r(v.x);
            sm[A2_A + r * 132 + c4 * 4 + 1] = tf32r(v.y);
            sm[A2_A + r * 132 + c4 * 4 + 2] = tf32r(v.z);
            sm[A2_A + r * 132 + c4 * 4 + 3] = tf32r(v.w);
        }
        __syncthreads();

        float cpc[2][4][4] = {}, cyn[2][4][4] = {};
        #pragma unroll
        for (int ks = 0; ks < 16; ks++) {
            int k0 = ks * 8;
            uint32_t a[2][4];
            #pragma unroll
            for (int rt = 0; rt < 2; rt++) {
                int r = wr * 32 + rt * 16 + grp;
                a[rt][0] = smu[A2_A + r * 132 + k0 + tig];
                a[rt][1] = smu[A2_A + (r + 8) * 132 + k0 + tig];
                a[rt][2] = smu[A2_A + r * 132 + k0 + 4 + tig];
                a[rt][3] = smu[A2_A + (r + 8) * 132 + k0 + 4 + tig];
            }
            #pragma unroll
            for (int j = 0; j < 4; j++) {
                int n = wc * 32 + j * 8 + grp;
                uint32_t bcf[2], bnf[2];
                bcf[0] = smu[A2_W + (k0 + tig) * 264 + n];
                bcf[1] = smu[A2_W + (k0 + 4 + tig) * 264 + n];
                bnf[0] = smu[A2_W + (k0 + tig) * 264 + 128 + n];
                bnf[1] = smu[A2_W + (k0 + 4 + tig) * 264 + 128 + n];
                #pragma unroll
                for (int rt = 0; rt < 2; rt++) {
                    mma_tf32(cpc[rt][j], a[rt], bcf);
                    mma_tf32(cyn[rt][j], a[rt], bnf);
                }
            }
        }

        #pragma unroll
        for (int rt = 0; rt < 2; rt++) {
            int r0 = t * 64 + wr * 32 + rt * 16 + grp;
            #pragma unroll
            for (int j = 0; j < 4; j++) {
                int f0 = wc * 32 + j * 8 + 2 * tig;
                float2 v;
                v.x = cpc[rt][j][0] + bcr[j][0]; v.y = cpc[rt][j][1] + bcr[j][1];
                *(float2*)&g_pc[r0 * FDIM + f0] = v;
                v.x = cpc[rt][j][2] + bcr[j][0]; v.y = cpc[rt][j][3] + bcr[j][1];
                *(float2*)&g_pc[(r0 + 8) * FDIM + f0] = v;
                v.x = cyn[rt][j][0] + bnr[j][0]; v.y = cyn[rt][j][1] + bnr[j][1];
                *(float2*)&g_yn[r0 * FDIM + f0] = v;
                v.x = cyn[rt][j][2] + bnr[j][0]; v.y = cyn[rt][j][3] + bnr[j][1];
                *(float2*)&g_yn[(r0 + 8) * FDIM + f0] = v;
            }
        }
        __syncthreads();
    }
}

// ============================================================================
// Kernel 3: k_conv — fused conv layer, named-barrier groups + cp.async pipeline
// ============================================================================
#define S_W    0          // 33792
#define S_AGM  33792      //  8448
#define S_AE   42240      //  6656 (2 x 64x52)
#define S_WE   48896      //  6336 (48x132)
#define S_BIAS 55232      //   640
#define S_RED  55872      //   512
#define S_IDX  56384      //    96 (2 x 48 ints)
#define S_TOT  56480
#define CV_SMEM (S_TOT * 4)

__device__ __forceinline__ void stage_ae(uint32_t sA, const float* __restrict__ nf, int tid) {
    #pragma unroll
    for (int q = 0; q < 8; q++) {
        int i = tid + q * 256;
        if (i < 48 * EDGE) {
            int mr = i / EDGE, e = i - mr * EDGE;
            int a = mr / MNBR, m = mr - a * MNBR;
            uint32_t d = sA + (uint32_t)((a * PROWS + m) * 52 + e) * 4;
            asm volatile("cp.async.ca.shared.global [%0], [%1], 4;"
                         :: "r"(d), "l"(nf + i) : "memory");
        }
    }
}

__global__ void __launch_bounds__(256, 1)
k_conv(const float* __restrict__ nbr_fea, const int* __restrict__ nbr_idx,
       const float* __restrict__ Wg, const float* __restrict__ bg,
       const float* __restrict__ Wm, const float* __restrict__ bm,
       const float* __restrict__ We, const float* __restrict__ be,
       const float* __restrict__ lns, const float* __restrict__ lnb) {
    int tid = threadIdx.x, wid = tid >> 5, lane = tid & 31;
    uint32_t* smu = (uint32_t*)sm;
    int* sidx = (int*)(sm + S_IDX);

    for (int i = tid; i < FDIM * FDIM; i += 256) {
        int k = i >> 7, n = i & 127;
        smu[S_W + k * 264 + n]       = __float_as_uint(tf32r(Wg[i]));
        smu[S_W + k * 264 + 128 + n] = __float_as_uint(tf32r(Wm[i]));
    }
    for (int i = tid; i < 6336; i += 256) sm[S_WE + i] = 0.f;
    for (int i = tid; i < 8448; i += 256) sm[S_AGM + i] = 0.f;
    for (int i = tid; i < 6656; i += 256) sm[S_AE + i] = 0.f;
    __syncthreads();
    for (int i = tid; i < EDGE * FDIM; i += 256) {
        int k = i >> 7, n = i & 127;
        sm[S_WE + k * 132 + n] = tf32r(We[i]);
    }
    if (tid < FDIM) {
        sm[S_BIAS + tid]       = bg[tid];
        sm[S_BIAS + 128 + tid] = bm[tid];
        sm[S_BIAS + 256 + tid] = lns[tid];
        sm[S_BIAS + 384 + tid] = lnb[tid];
        sm[S_BIAS + 512 + tid] = be[tid];
    }

    int wr = wid >> 2, wc = wid & 3;
    int tig = lane & 3, grp = lane >> 2;
    bool notpad = (grp < 4);
    int barid = wr + 1;

    float bgr[4][2], bmr[4][2], ber[4][2];
    float4 lns4, lnb4;
    uint32_t ae0 = smem_u32(sm + S_AE), ae1 = smem_u32(sm + S_AE + 3328);

    // prologue: stage first tile
    int stride = gridDim.x;
    int t0 = blockIdx.x;
    if (tid < 48) sidx[tid] = nbr_idx[t0 * 48 + tid];
    stage_ae(ae0, nbr_fea + (size_t)t0 * 48 * EDGE, tid);
    asm volatile("cp.async.commit_group;" ::: "memory");
    asm volatile("cp.async.wait_group 0;" ::: "memory");
    __syncthreads();

    #pragma unroll
    for (int j = 0; j < 4; j++) {
        int f0 = wc * 32 + j * 8 + 2 * tig;
        bgr[j][0] = sm[S_BIAS + f0];        bgr[j][1] = sm[S_BIAS + f0 + 1];
        bmr[j][0] = sm[S_BIAS + 128 + f0];  bmr[j][1] = sm[S_BIAS + 128 + f0 + 1];
        ber[j][0] = sm[S_BIAS + 512 + f0];  ber[j][1] = sm[S_BIAS + 512 + f0 + 1];
    }
    lns4 = *(const float4*)&sm[S_BIAS + 256 + lane * 4];
    lnb4 = *(const float4*)&sm[S_BIAS + 384 + lane * 4];

    int buf = 0;
    for (int t = t0; t < NTILE; t += stride) {
        const int* sx = sidx + buf * 48;
        int aeB = S_AE + buf * 3328;

        // ---- prefetch yn/pc from L2 ----
        float2 yn0[2][4], yn1[2][4], pcp[2][4];
        #pragma unroll
        for (int rt = 0; rt < 2; rt++) {
            int a = wr * 2 + rt;
            int i0 = sx[a * MNBR + grp];
            int i1 = notpad ? sx[a * MNBR + grp + 8] : 0;
            #pragma unroll
            for (int j = 0; j < 4; j++) {
                int f0 = wc * 32 + j * 8 + 2 * tig;
                yn0[rt][j] = *(const float2*)&g_yn[i0 * FDIM + f0];
                yn1[rt][j] = notpad ? *(const float2*)&g_yn[i1 * FDIM + f0]
                                    : make_float2(0.f, 0.f);
                pcp[rt][j] = *(const float2*)&g_pc[(t * GT_ATOMS + a) * FDIM + f0];
            }
        }

        // ---- issue prefetch of NEXT tile ----
        int tn = t + stride;
        if (tn < NTILE) {
            if (tid < 48) sidx[(buf ^ 1) * 48 + tid] = nbr_idx[tn * 48 + tid];
            stage_ae(buf ? ae0 : ae1, nbr_fea + (size_t)tn * 48 * EDGE, tid);
        }
        asm volatile("cp.async.commit_group;" ::: "memory");

        // ---- phi_e mma (M=64, N=128, K=48) ----
        float ce[2][4][4] = {};
        #pragma unroll
        for (int ks = 0; ks < 6; ks++) {
            int k0 = ks * 8;
            uint32_t a[2][4];
            #pragma unroll
            for (int rt = 0; rt < 2; rt++) {
                int r = wr * 32 + rt * 16 + grp;
                a[rt][0] = smu[aeB + r * 52 + k0 + tig];
                a[rt][1] = smu[aeB + (r + 8) * 52 + k0 + tig];
                a[rt][2] = smu[aeB + r * 52 + k0 + 4 + tig];
                a[rt][3] = smu[aeB + (r + 8) * 52 + k0 + 4 + tig];
            }
            #pragma unroll
            for (int j = 0; j < 4; j++) {
                int n = wc * 32 + j * 8 + grp;
                uint32_t b[2];
                b[0] = smu[S_WE + (k0 + tig) * 132 + n];
                b[1] = smu[S_WE + (k0 + 4 + tig) * 132 + n];
                #pragma unroll
                for (int rt = 0; rt < 2; rt++)
                    mma_tf32(ce[rt][j], a[rt], b);
            }
        }

        // ---- build inter tile ----
        #pragma unroll
        for (int rt = 0; rt < 2; rt++) {
            int r = wr * 32 + rt * 16 + grp;
            #pragma unroll
            for (int j = 0; j < 4; j++) {
                int f0 = wc * 32 + j * 8 + 2 * tig;
                float2 o0;
                o0.x = tf32r(pcp[rt][j].x * yn0[rt][j].x * (ce[rt][j][0] + ber[j][0]));
                o0.y = tf32r(pcp[rt][j].y * yn0[rt][j].y * (ce[rt][j][1] + ber[j][1]));
                *(float2*)&sm[S_AGM + r * 132 + f0] = o0;
                if (notpad) {
                    float2 o1;
                    o1.x = tf32r(pcp[rt][j].x * yn1[rt][j].x * (ce[rt][j][2] + ber[j][0]));
                    o1.y = tf32r(pcp[rt][j].y * yn1[rt][j].y * (ce[rt][j][3] + ber[j][1]));
                    *(float2*)&sm[S_AGM + (r + 8) * 132 + f0] = o1;
                }
            }
        }
        asm volatile("bar.sync %0, %1;" :: "r"(barid), "r"(128) : "memory");

        // ---- gate/mag mma (K=128) ----
        float cg[2][4][4] = {}, cmm[2][4][4] = {};
        #pragma unroll
        for (int ks = 0; ks < 16; ks++) {
            int k0 = ks * 8;
            uint32_t a[2][4];
            #pragma unroll
            for (int rt = 0; rt < 2; rt++) {
                int r = wr * 32 + rt * 16 + grp;
                a[rt][0] = smu[S_AGM + r * 132 + k0 + tig];
                a[rt][1] = smu[S_AGM + (r + 8) * 132 + k0 + tig];
                a[rt][2] = smu[S_AGM + r * 132 + k0 + 4 + tig];
                a[rt][3] = smu[S_AGM + (r + 8) * 132 + k0 + 4 + tig];
            }
            #pragma unroll
            for (int j = 0; j < 4; j++) {
                int n = wc * 32 + j * 8 + grp;
                uint32_t bgf[2], bmf[2];
                bgf[0] = smu[S_W + (k0 + tig) * 264 + n];
                bgf[1] = smu[S_W + (k0 + 4 + tig) * 264 + n];
                bmf[0] = smu[S_W + (k0 + tig) * 264 + 128 + n];
                bmf[1] = smu[S_W + (k0 + 4 + tig) * 264 + 128 + n];
                #pragma unroll
                for (int rt = 0; rt < 2; rt++) {
                    mma_tf32(cg[rt][j], a[rt], bgf);
                    mma_tf32(cmm[rt][j], a[rt], bmf);
                }
            }
        }

        // ---- activation + masked per-atom column sums ----
        #pragma unroll
        for (int rt = 0; rt < 2; rt++) {
            int atom = wr * 2 + rt;
            #pragma unroll
            for (int j = 0; j < 4; j++) {
                float p0 = act(cg[rt][j][0] + bgr[j][0], cmm[rt][j][0] + bmr[j][0]);
                float p1 = act(cg[rt][j][1] + bgr[j][1], cmm[rt][j][1] + bmr[j][1]);
                if (notpad) {
                    p0 += act(cg[rt][j][2] + bgr[j][0], cmm[rt][j][2] + bmr[j][0]);
                    p1 += act(cg[rt][j][3] + bgr[j][1], cmm[rt][j][3] + bmr[j][1]);
                }
                #pragma unroll
                for (int o = 4; o < 32; o <<= 1) {
                    p0 += __shfl_xor_sync(0xffffffffu, p0, o);
                    p1 += __shfl_xor_sync(0xffffffffu, p1, o);
                }
                if (grp == 0) {
                    int f0 = wc * 32 + j * 8 + 2 * tig;
                    sm[S_RED + atom * 128 + f0]     = p0;
                    sm[S_RED + atom * 128 + f0 + 1] = p1;
                }
            }
        }
        asm volatile("bar.sync %0, %1;" :: "r"(barid), "r"(128) : "memory");

        // ---- LayerNorm + residual (warps 0,1 of each group) ----
        if ((wid & 3) < 2) {
            int atom = wr * 2 + (wid & 3);
            float4 v = *(const float4*)&sm[S_RED + atom * 128 + lane * 4];
            float s = v.x + v.y + v.z + v.w;
            float q = v.x*v.x + v.y*v.y + v.z*v.z + v.w*v.w;
            #pragma unroll
            for (int o = 16; o > 0; o >>= 1) {
                s += __shfl_xor_sync(0xffffffffu, s, o);
                q += __shfl_xor_sync(0xffffffffu, q, o);
            }
            float mu = s * (1.f / FDIM);
            float var = q * (1.f / FDIM) - mu * mu;
            float rstd = rsqrtf(var + 1e-6f);
            int n = t * GT_ATOMS + atom;
            float4 x = *(float4*)&g_x[n * FDIM + lane * 4];
            x.x += (v.x - mu) * rstd * lns4.x + lnb4.x;
            x.y += (v.y - mu) * rstd * lns4.y + lnb4.y;
            x.z += (v.z - mu) * rstd * lns4.z + lnb4.z;
            x.w += (v.w - mu) * rstd * lns4.w + lnb4.w;
            *(float4*)&g_x[n * FDIM + lane * 4] = x;
        }

        asm volatile("cp.async.wait_group 0;" ::: "memory");
        __syncthreads();
        buf ^= 1;
    }
}

// ============================================================================
// Kernel 4: readout
// ============================================================================
#define RO_WHT  0
#define RO_WO   33792
#define RO_BH   34048
#define RO_XR   34304
#define RO_RED  34432
#define RO_FLOATS 34440
#define RO_SMEM (RO_FLOATS * 4)

__global__ void k_readout(const float* __restrict__ Wh, const float* __restrict__ bh,
                          const float* __restrict__ Wout, const float* __restrict__ bout) {
    float* WhT = sm + RO_WHT;
    float* WoS = sm + RO_WO;
    float* bhS = sm + RO_BH;
    float* xr  = sm + RO_XR;
    float* red = sm + RO_RED;
    int tid = threadIdx.x;
    for (int i = tid; i < FDIM * HDIM; i += 256) {
        int k = i >> 8, j = i & 255;
        WhT[j * 132 + k] = Wh[i];
    }
    WoS[tid] = Wout[tid];
    bhS[tid] = bh[tid];
    __syncthreads();
    float b0 = bout[0];
    const float4* wp = (const float4*)(WhT + tid * 132);

    for (int n = blockIdx.x; n < N_ATOMS; n += gridDim.x) {
        if (tid < FDIM) xr[tid] = g_x[n * FDIM + tid];
        __syncthreads();
        float acc = bhS[tid];
        #pragma unroll 4
        for (int k4 = 0; k4 < FDIM / 4; k4++) {
            float4 w = wp[k4];
            float4 xv = *(const float4*)(xr + k4 * 4);
            acc = fmaf(w.x, xv.x, acc); acc = fmaf(w.y, xv.y, acc);
            acc = fmaf(w.z, xv.z, acc); acc = fmaf(w.w, xv.w, acc);
        }
        float pcontrib = softplusf(acc) * WoS[tid];
        #pragma unroll
        for (int o = 16; o > 0; o >>= 1)
            pcontrib += __shfl_xor_sync(0xffffffffu, pcontrib, o);
        if ((tid & 31) == 0) red[tid >> 5] = pcontrib;
        __syncthreads();
        if (tid == 0) {
            float ssum = 0.f;
            #pragma unroll
            for (int w8 = 0; w8 < 8; w8++) ssum += red[w8];
            g_site[n] = ssum + b0;
        }
        __syncthreads();
    }
}

// ============================================================================
// Kernel 5: per-crystal sum
// ============================================================================
__global__ void k_crystal(float* __restrict__ out) {
    __shared__ float red[8];
    int c = blockIdx.x, tid = threadIdx.x;
    float v = g_site[c * APC + tid];
    #pragma unroll
    for (int o = 16; o > 0; o >>= 1)
        v += __shfl_xor_sync(0xffffffffu, v, o);
    if ((tid & 31) == 0) red[tid >> 5] = v;
    __syncthreads();
    if (tid == 0) {
        float s = 0.f;
        #pragma unroll
        for (int i = 0; i < 8; i++) s += red[i];
        out[c] = s;
    }
}

// ============================================================================
extern "C" void kernel_launch(void* const* d_in, const int* in_sizes, int n_in,
                              void* d_out, int out_size) {
    const float* atom_fea = (const float*)d_in[0];
    const float* nbr_fea  = (const float*)d_in[1];
    const int*   nbr_idx  = (const int*)  d_in[2];
    const float* W_embed  = (const float*)d_in[3];
    const float* b_embed  = (const float*)d_in[4];
    const float* W_center = (const float*)d_in[5];
    const float* b_center = (const float*)d_in[6];
    const float* W_nbr    = (const float*)d_in[7];
    const float* b_nbr    = (const float*)d_in[8];
    const float* W_edge   = (const float*)d_in[9];
    const float* b_edge   = (const float*)d_in[10];
    const float* W_gate   = (const float*)d_in[11];
    const float* b_gate   = (const float*)d_in[12];
    const float* W_mag    = (const float*)d_in[13];
    const float* b_mag    = (const float*)d_in[14];
    const float* ln_scale = (const float*)d_in[15];
    const float* ln_bias  = (const float*)d_in[16];
    const float* W_h      = (const float*)d_in[17];
    const float* b_h      = (const float*)d_in[18];
    const float* W_out    = (const float*)d_in[19];
    const float* b_out    = (const float*)d_in[20];
    float* out = (float*)d_out;

    cudaFuncSetAttribute(k_convA,   cudaFuncAttributeMaxDynamicSharedMemorySize, A2_SMEM);
    cudaFuncSetAttribute(k_conv,    cudaFuncAttributeMaxDynamicSharedMemorySize, CV_SMEM);
    cudaFuncSetAttribute(k_readout, cudaFuncAttributeMaxDynamicSharedMemorySize, RO_SMEM);

    k_embed<<<256, 256>>>(atom_fea, W_embed, b_embed);
    for (int l = 0; l < NCONV; l++) {
        k_convA<<<148, 256, A2_SMEM>>>(W_center + l * FDIM * FDIM, b_center + l * FDIM,
                                       W_nbr    + l * FDIM * FDIM, b_nbr    + l * FDIM);
        k_conv<<<148, 256, CV_SMEM>>>(nbr_fea, nbr_idx,
                                      W_gate + l * FDIM * FDIM, b_gate + l * FDIM,
                                      W_mag  + l * FDIM * FDIM, b_mag  + l * FDIM,
                                      W_edge + l * EDGE * FDIM, b_edge + l * FDIM,
                                      ln_scale + l * FDIM, ln_bias + l * FDIM);
    }
    k_readout<<<152, 256, RO_SMEM>>>(W_h, b_h, W_out, b_out);
    k_crystal<<<NCRY, 256>>>(out);
}

// round 6
// speedup vs baseline: 2.6229x; 1.0045x over previous
#include <cuda_runtime.h>
#include <math.h>
#include <cstdint>

#define N_ATOMS 32768
#define MNBR    12
#define PROWS   16
#define ORIG    92
#define EDGE    41
#define FDIM    128
#define HDIM    256
#define NCONV   3
#define NCRY    128
#define APC     256
#define NT2     (N_ATOMS / 2)             // 16384 atom-pair tiles
#define ATILE   (N_ATOMS / 64)            // 512 (convA tiles)

// ---- scratch ----
__device__ float g_x [N_ATOMS * FDIM];
__device__ float g_pc[N_ATOMS * FDIM];
__device__ float g_yn[N_ATOMS * FDIM];
__device__ float g_site[N_ATOMS];

__device__ __forceinline__ float softplusf(float x) {
    return fmaxf(x, 0.f) + log1pf(expf(-fabsf(x)));
}
__device__ __forceinline__ float tf32r(float x) {
    uint32_t u;
    asm("cvt.rna.tf32.f32 %0, %1;" : "=r"(u) : "f"(x));
    return __uint_as_float(u);
}
__device__ __forceinline__ uint32_t smem_u32(const void* p) {
    uint32_t a;
    asm("{ .reg .u64 t; cvta.to.shared.u64 t, %1; cvt.u32.u64 %0, t; }" : "=r"(a) : "l"(p));
    return a;
}
__device__ __forceinline__ void mma_tf32(float c[4], const uint32_t a[4], const uint32_t b[2]) {
    asm volatile("mma.sync.aligned.m16n8k8.row.col.f32.tf32.tf32.f32 "
        "{%0,%1,%2,%3}, {%4,%5,%6,%7}, {%8,%9}, {%0,%1,%2,%3};"
        : "+f"(c[0]), "+f"(c[1]), "+f"(c[2]), "+f"(c[3])
        : "r"(a[0]), "r"(a[1]), "r"(a[2]), "r"(a[3]), "r"(b[0]), "r"(b[1]));
}
__device__ __forceinline__ float act(float g, float m) {
    float sig = __fdividef(1.f, 1.f + __expf(-g));
    float sp  = fmaxf(m, 0.f) + __logf(1.f + __expf(-fabsf(m)));
    return sig * sp;
}

extern __shared__ float sm[];

// ============================================================================
// Kernel 1: embedding
// ============================================================================
__global__ void k_embed(const float* __restrict__ atom_fea,
                        const float* __restrict__ W,
                        const float* __restrict__ b) {
    __shared__ float Ws[ORIG * FDIM];
    __shared__ float rows[2 * ORIG];
    int tid = threadIdx.x;
    for (int i = tid; i < ORIG * FDIM; i += 256) Ws[i] = W[i];
    __syncthreads();
    int base = blockIdx.x * 128;
    int half = tid >> 7, f = tid & 127;
    for (int it = 0; it < 64; ++it) {
        int r0 = base + it * 2;
        for (int j = tid; j < 2 * ORIG; j += 256)
            rows[j] = atom_fea[r0 * ORIG + j];
        __syncthreads();
        float acc = b[f];
        const float* rp = rows + half * ORIG;
        #pragma unroll 4
        for (int e = 0; e < ORIG; e++)
            acc = fmaf(rp[e], Ws[e * FDIM + f], acc);
        g_x[(r0 + half) * FDIM + f] = acc;
        __syncthreads();
    }
}

// ============================================================================
// Kernel 2: k_convA — tf32 mma GEMM: [phi_c|y_nbr] = x @ [Wc|Wn] + bias
// ============================================================================
#define A2_W    0
#define A2_A    33792
#define A2_BIAS 42240
#define A2_TOT  42496
#define A2_SMEM (A2_TOT * 4)

__global__ void __launch_bounds__(256, 1)
k_convA(const float* __restrict__ Wc, const float* __restrict__ bc,
        const float* __restrict__ Wn, const float* __restrict__ bn) {
    int tid = threadIdx.x, wid = tid >> 5, lane = tid & 31;
    uint32_t* smu = (uint32_t*)sm;
    for (int i = tid; i < FDIM * FDIM; i += 256) {
        int k = i >> 7, n = i & 127;
        smu[A2_W + k * 264 + n]       = __float_as_uint(tf32r(Wc[i]));
        smu[A2_W + k * 264 + 128 + n] = __float_as_uint(tf32r(Wn[i]));
    }
    if (tid < 128) { sm[A2_BIAS + tid] = bc[tid]; sm[A2_BIAS + 128 + tid] = bn[tid]; }
    __syncthreads();

    int wr = wid >> 2, wc = wid & 3;
    int tig = lane & 3, grp = lane >> 2;
    float bcr[4][2], bnr[4][2];
    #pragma unroll
    for (int j = 0; j < 4; j++) {
        int f0 = wc * 32 + j * 8 + 2 * tig;
        bcr[j][0] = sm[A2_BIAS + f0];       bcr[j][1] = sm[A2_BIAS + f0 + 1];
        bnr[j][0] = sm[A2_BIAS + 128 + f0]; bnr[j][1] = sm[A2_BIAS + 128 + f0 + 1];
    }

    for (int t = blockIdx.x; t < ATILE; t += gridDim.x) {
        #pragma unroll
        for (int q = 0; q < 8; q++) {
            int ch = tid + q * 256;
            int r = ch >> 5, c4 = ch & 31;
            float4 v = *(const float4*)&g_x[(t * 64 + r) * FDIM + c4 * 4];
            sm[A2_A + r * 132 + c4 * 4 + 0] = tf32r(v.x);
            sm[A2_A + r * 132 + c4 * 4 + 1] = tf32r(v.y);
            sm[A2_A + r * 132 + c4 * 4 + 2] = tf32r(v.z);
            sm[A2_A + r * 132 + c4 * 4 + 3] = tf32r(v.w);
        }
        __syncthreads();

        float cpc[2][4][4] = {}, cyn[2][4][4] = {};
        #pragma unroll
        for (int ks = 0; ks < 16; ks++) {
            int k0 = ks * 8;
            uint32_t a[2][4];
            #pragma unroll
            for (int rt = 0; rt < 2; rt++) {
                int r = wr * 32 + rt * 16 + grp;
                a[rt][0] = smu[A2_A + r * 132 + k0 + tig];
                a[rt][1] = smu[A2_A + (r + 8) * 132 + k0 + tig];
                a[rt][2] = smu[A2_A + r * 132 + k0 + 4 + tig];
                a[rt][3] = smu[A2_A + (r + 8) * 132 + k0 + 4 + tig];
            }
            #pragma unroll
            for (int j = 0; j < 4; j++) {
                int n = wc * 32 + j * 8 + grp;
                uint32_t bcf[2], bnf[2];
                bcf[0] = smu[A2_W + (k0 + tig) * 264 + n];
                bcf[1] = smu[A2_W + (k0 + 4 + tig) * 264 + n];
                bnf[0] = smu[A2_W + (k0 + tig) * 264 + 128 + n];
                bnf[1] = smu[A2_W + (k0 + 4 + tig) * 264 + 128 + n];
                #pragma unroll
                for (int rt = 0; rt < 2; rt++) {
                    mma_tf32(cpc[rt][j], a[rt], bcf);
                    mma_tf32(cyn[rt][j], a[rt], bnf);
                }
            }
        }

        #pragma unroll
        for (int rt = 0; rt < 2; rt++) {
            int r0 = t * 64 + wr * 32 + rt * 16 + grp;
            #pragma unroll
            for (int j = 0; j < 4; j++) {
                int f0 = wc * 32 + j * 8 + 2 * tig;
                float2 v;
                v.x = cpc[rt][j][0] + bcr[j][0]; v.y = cpc[rt][j][1] + bcr[j][1];
                *(float2*)&g_pc[r0 * FDIM + f0] = v;
                v.x = cpc[rt][j][2] + bcr[j][0]; v.y = cpc[rt][j][3] + bcr[j][1];
                *(float2*)&g_pc[(r0 + 8) * FDIM + f0] = v;
                v.x = cyn[rt][j][0] + bnr[j][0]; v.y = cyn[rt][j][1] + bnr[j][1];
                *(float2*)&g_yn[r0 * FDIM + f0] = v;
                v.x = cyn[rt][j][2] + bnr[j][0]; v.y = cyn[rt][j][3] + bnr[j][1];
                *(float2*)&g_yn[(r0 + 8) * FDIM + f0] = v;
            }
        }
        __syncthreads();
    }
}

// ============================================================================
// Kernel 3: k_conv — fused conv layer; TWO fully independent 128-thread
// pipelines per CTA (private smem, private tile stream, group barriers only).
// Per-group tile = 2 atoms (32 padded rows).
// ============================================================================
#define S_W     0          // 33792 (shared, read-only)
#define S_WE    33792      //  6336 (shared, read-only)
#define S_BIAS  40128      //   640 (shared, read-only)
#define S_GRP   40768      // per-group regions
#define GRPSZ   7856
#define GP_AGM  0          // 32x132            = 4224
#define GP_AE   4224       // 2 x (32x52=1664)  = 3328
#define GP_RED  7552       // 2 atoms x 128     =  256
#define GP_IDX  7808       // 2 buf x 24 ints   =   48
#define S_TOT   (S_GRP + 2 * GRPSZ)    // 56480 floats
#define CV_SMEM (S_TOT * 4)            // 225920 B

__device__ __forceinline__ void stage_ae2(uint32_t dstbase, const float* __restrict__ nf,
                                          int gtid) {
    #pragma unroll
    for (int q = 0; q < 8; q++) {
        int i = gtid + q * 128;
        if (i < 24 * EDGE) {
            int mr = i / EDGE, e = i - mr * EDGE;
            int a = mr / MNBR, m = mr - a * MNBR;
            uint32_t d = dstbase + (uint32_t)((a * PROWS + m) * 52 + e) * 4;
            asm volatile("cp.async.ca.shared.global [%0], [%1], 4;"
                         :: "r"(d), "l"(nf + i) : "memory");
        }
    }
}

__global__ void __launch_bounds__(256, 1)
k_conv(const float* __restrict__ nbr_fea, const int* __restrict__ nbr_idx,
       const float* __restrict__ Wg, const float* __restrict__ bg,
       const float* __restrict__ Wm, const float* __restrict__ bm,
       const float* __restrict__ We, const float* __restrict__ be,
       const float* __restrict__ lns, const float* __restrict__ lnb) {
    int tid = threadIdx.x, wid = tid >> 5, lane = tid & 31;
    int half = wid >> 2, wg = wid & 3, gtid = tid & 127;
    uint32_t* smu = (uint32_t*)sm;

    // ---- shared read-only weights ----
    for (int i = tid; i < FDIM * FDIM; i += 256) {
        int k = i >> 7, n = i & 127;
        smu[S_W + k * 264 + n]       = __float_as_uint(tf32r(Wg[i]));
        smu[S_W + k * 264 + 128 + n] = __float_as_uint(tf32r(Wm[i]));
    }
    for (int i = tid; i < 6336; i += 256) sm[S_WE + i] = 0.f;
    for (int i = tid; i < 2 * GRPSZ; i += 256) sm[S_GRP + i] = 0.f;   // zero group regions (pads stay 0)
    __syncthreads();
    for (int i = tid; i < EDGE * FDIM; i += 256) {
        int k = i >> 7, n = i & 127;
        sm[S_WE + k * 132 + n] = tf32r(We[i]);
    }
    if (tid < FDIM) {
        sm[S_BIAS + tid]       = bg[tid];
        sm[S_BIAS + 128 + tid] = bm[tid];
        sm[S_BIAS + 256 + tid] = lns[tid];
        sm[S_BIAS + 384 + tid] = lnb[tid];
        sm[S_BIAS + 512 + tid] = be[tid];
    }

    int gbase = S_GRP + half * GRPSZ;
    int* sidx = (int*)(sm + gbase + GP_IDX);
    uint32_t aeRaw = smem_u32(sm + gbase + GP_AE);
    int tig = lane & 3, grp = lane >> 2;
    bool notpad = (grp < 4);
    int barid = half + 1;
    int wc = wg;                         // warp covers f columns wc*32..wc*32+31

    // ---- per-group tile stream ----
    int stride = 2 * gridDim.x;
    int s0 = blockIdx.x * 2 + half;

    // prologue: stage first tile into buffer 0 (per-group threads)
    if (s0 < NT2) {
        if (gtid < 24) sidx[gtid] = nbr_idx[s0 * 24 + gtid];
        stage_ae2(aeRaw, nbr_fea + (size_t)s0 * 24 * EDGE, gtid);
    }
    asm volatile("cp.async.commit_group;" ::: "memory");
    asm volatile("cp.async.wait_group 0;" ::: "memory");
    __syncthreads();   // weights + first stage visible to everyone

    float bgr[4][2], bmr[4][2], ber[4][2];
    #pragma unroll
    for (int j = 0; j < 4; j++) {
        int f0 = wc * 32 + j * 8 + 2 * tig;
        bgr[j][0] = sm[S_BIAS + f0];        bgr[j][1] = sm[S_BIAS + f0 + 1];
        bmr[j][0] = sm[S_BIAS + 128 + f0];  bmr[j][1] = sm[S_BIAS + 128 + f0 + 1];
        ber[j][0] = sm[S_BIAS + 512 + f0];  ber[j][1] = sm[S_BIAS + 512 + f0 + 1];
    }
    float4 lns4 = *(const float4*)&sm[S_BIAS + 256 + lane * 4];
    float4 lnb4 = *(const float4*)&sm[S_BIAS + 384 + lane * 4];

    int buf = 0;
    for (int t = s0; t < NT2; t += stride) {
        const int* sx = sidx + buf * 24;
        int aeB = gbase + GP_AE + buf * 1664;

        // ---- prefetch yn/pc (L2) ----
        float2 yn0[2][4], yn1[2][4], pcp[2][4];
        #pragma unroll
        for (int rt = 0; rt < 2; rt++) {
            int i0 = sx[rt * MNBR + grp];
            int i1 = notpad ? sx[rt * MNBR + grp + 8] : 0;
            #pragma unroll
            for (int j = 0; j < 4; j++) {
                int f0 = wc * 32 + j * 8 + 2 * tig;
                yn0[rt][j] = *(const float2*)&g_yn[i0 * FDIM + f0];
                yn1[rt][j] = notpad ? *(const float2*)&g_yn[i1 * FDIM + f0]
                                    : make_float2(0.f, 0.f);
                pcp[rt][j] = *(const float2*)&g_pc[(t * 2 + rt) * FDIM + f0];
            }
        }

        // ---- issue next-tile staging (private buffers) ----
        int tn = t + stride;
        if (tn < NT2) {
            if (gtid < 24) sidx[(buf ^ 1) * 24 + gtid] = nbr_idx[tn * 24 + gtid];
            stage_ae2(aeRaw + (uint32_t)(buf ^ 1) * 1664 * 4,
                      nbr_fea + (size_t)tn * 24 * EDGE, gtid);
        }
        asm volatile("cp.async.commit_group;" ::: "memory");

        // ---- phi_e mma (M=32, N=128, K=48) ----
        float ce[2][4][4] = {};
        #pragma unroll
        for (int ks = 0; ks < 6; ks++) {
            int k0 = ks * 8;
            uint32_t a[2][4];
            #pragma unroll
            for (int rt = 0; rt < 2; rt++) {
                int r = rt * 16 + grp;
                a[rt][0] = smu[aeB + r * 52 + k0 + tig];
                a[rt][1] = smu[aeB + (r + 8) * 52 + k0 + tig];
                a[rt][2] = smu[aeB + r * 52 + k0 + 4 + tig];
                a[rt][3] = smu[aeB + (r + 8) * 52 + k0 + 4 + tig];
            }
            #pragma unroll
            for (int j = 0; j < 4; j++) {
                int n = wc * 32 + j * 8 + grp;
                uint32_t b[2];
                b[0] = smu[S_WE + (k0 + tig) * 132 + n];
                b[1] = smu[S_WE + (k0 + 4 + tig) * 132 + n];
                #pragma unroll
                for (int rt = 0; rt < 2; rt++)
                    mma_tf32(ce[rt][j], a[rt], b);
            }
        }

        // ---- build inter tile (private AGM) ----
        #pragma unroll
        for (int rt = 0; rt < 2; rt++) {
            int r = rt * 16 + grp;
            #pragma unroll
            for (int j = 0; j < 4; j++) {
                int f0 = wc * 32 + j * 8 + 2 * tig;
                float2 o0;
                o0.x = tf32r(pcp[rt][j].x * yn0[rt][j].x * (ce[rt][j][0] + ber[j][0]));
                o0.y = tf32r(pcp[rt][j].y * yn0[rt][j].y * (ce[rt][j][1] + ber[j][1]));
                *(float2*)&sm[gbase + GP_AGM + r * 132 + f0] = o0;
                if (notpad) {
                    float2 o1;
                    o1.x = tf32r(pcp[rt][j].x * yn1[rt][j].x * (ce[rt][j][2] + ber[j][0]));
                    o1.y = tf32r(pcp[rt][j].y * yn1[rt][j].y * (ce[rt][j][3] + ber[j][1]));
                    *(float2*)&sm[gbase + GP_AGM + (r + 8) * 132 + f0] = o1;
                }
            }
        }
        asm volatile("bar.sync %0, %1;" :: "r"(barid), "r"(128) : "memory");

        // ---- gate/mag mma (M=32, N=256, K=128) ----
        float cg[2][4][4] = {}, cmm[2][4][4] = {};
        #pragma unroll
        for (int ks = 0; ks < 16; ks++) {
            int k0 = ks * 8;
            uint32_t a[2][4];
            #pragma unroll
            for (int rt = 0; rt < 2; rt++) {
                int r = rt * 16 + grp;
                a[rt][0] = smu[gbase + GP_AGM + r * 132 + k0 + tig];
                a[rt][1] = smu[gbase + GP_AGM + (r + 8) * 132 + k0 + tig];
                a[rt][2] = smu[gbase + GP_AGM + r * 132 + k0 + 4 + tig];
                a[rt][3] = smu[gbase + GP_AGM + (r + 8) * 132 + k0 + 4 + tig];
            }
            #pragma unroll
            for (int j = 0; j < 4; j++) {
                int n = wc * 32 + j * 8 + grp;
                uint32_t bgf[2], bmf[2];
                bgf[0] = smu[S_W + (k0 + tig) * 264 + n];
                bgf[1] = smu[S_W + (k0 + 4 + tig) * 264 + n];
                bmf[0] = smu[S_W + (k0 + tig) * 264 + 128 + n];
                bmf[1] = smu[S_W + (k0 + 4 + tig) * 264 + 128 + n];
                #pragma unroll
                for (int rt = 0; rt < 2; rt++) {
                    mma_tf32(cg[rt][j], a[rt], bgf);
                    mma_tf32(cmm[rt][j], a[rt], bmf);
                }
            }
        }

        // ---- activation + masked per-atom column sums ----
        #pragma unroll
        for (int rt = 0; rt < 2; rt++) {
            #pragma unroll
            for (int j = 0; j < 4; j++) {
                float p0 = act(cg[rt][j][0] + bgr[j][0], cmm[rt][j][0] + bmr[j][0]);
                float p1 = act(cg[rt][j][1] + bgr[j][1], cmm[rt][j][1] + bmr[j][1]);
                if (notpad) {
                    p0 += act(cg[rt][j][2] + bgr[j][0], cmm[rt][j][2] + bmr[j][0]);
                    p1 += act(cg[rt][j][3] + bgr[j][1], cmm[rt][j][3] + bmr[j][1]);
                }
                #pragma unroll
                for (int o = 4; o < 32; o <<= 1) {
                    p0 += __shfl_xor_sync(0xffffffffu, p0, o);
                    p1 += __shfl_xor_sync(0xffffffffu, p1, o);
                }
                if (grp == 0) {
                    int f0 = wc * 32 + j * 8 + 2 * tig;
                    sm[gbase + GP_RED + rt * 128 + f0]     = p0;
                    sm[gbase + GP_RED + rt * 128 + f0 + 1] = p1;
                }
            }
        }
        // drain own staging, then group barrier = RED visibility + stage visibility
        asm volatile("cp.async.wait_group 0;" ::: "memory");
        asm volatile("bar.sync %0, %1;" :: "r"(barid), "r"(128) : "memory");

        // ---- LayerNorm + residual (warps 0,1 of group) ----
        if (wg < 2) {
            float4 v = *(const float4*)&sm[gbase + GP_RED + wg * 128 + lane * 4];
            float s = v.x + v.y + v.z + v.w;
            float q = v.x*v.x + v.y*v.y + v.z*v.z + v.w*v.w;
            #pragma unroll
            for (int o = 16; o > 0; o >>= 1) {
                s += __shfl_xor_sync(0xffffffffu, s, o);
                q += __shfl_xor_sync(0xffffffffu, q, o);
            }
            float mu = s * (1.f / FDIM);
            float var = q * (1.f / FDIM) - mu * mu;
            float rstd = rsqrtf(var + 1e-6f);
            int n = t * 2 + wg;
            float4 x = *(float4*)&g_x[n * FDIM + lane * 4];
            x.x += (v.x - mu) * rstd * lns4.x + lnb4.x;
            x.y += (v.y - mu) * rstd * lns4.y + lnb4.y;
            x.z += (v.z - mu) * rstd * lns4.z + lnb4.z;
            x.w += (v.w - mu) * rstd * lns4.w + lnb4.w;
            *(float4*)&g_x[n * FDIM + lane * 4] = x;
        }
        buf ^= 1;
    }
}

// ============================================================================
// Kernel 4: readout
// ============================================================================
#define RO_WHT  0
#define RO_WO   33792
#define RO_BH   34048
#define RO_XR   34304
#define RO_RED  34432
#define RO_FLOATS 34440
#define RO_SMEM (RO_FLOATS * 4)

__global__ void k_readout(const float* __restrict__ Wh, const float* __restrict__ bh,
                          const float* __restrict__ Wout, const float* __restrict__ bout) {
    float* WhT = sm + RO_WHT;
    float* WoS = sm + RO_WO;
    float* bhS = sm + RO_BH;
    float* xr  = sm + RO_XR;
    float* red = sm + RO_RED;
    int tid = threadIdx.x;
    for (int i = tid; i < FDIM * HDIM; i += 256) {
        int k = i >> 8, j = i & 255;
        WhT[j * 132 + k] = Wh[i];
    }
    WoS[tid] = Wout[tid];
    bhS[tid] = bh[tid];
    __syncthreads();
    float b0 = bout[0];
    const float4* wp = (const float4*)(WhT + tid * 132);

    for (int n = blockIdx.x; n < N_ATOMS; n += gridDim.x) {
        if (tid < FDIM) xr[tid] = g_x[n * FDIM + tid];
        __syncthreads();
        float acc = bhS[tid];
        #pragma unroll 4
        for (int k4 = 0; k4 < FDIM / 4; k4++) {
            float4 w = wp[k4];
            float4 xv = *(const float4*)(xr + k4 * 4);
            acc = fmaf(w.x, xv.x, acc); acc = fmaf(w.y, xv.y, acc);
            acc = fmaf(w.z, xv.z, acc); acc = fmaf(w.w, xv.w, acc);
        }
        float pcontrib = softplusf(acc) * WoS[tid];
        #pragma unroll
        for (int o = 16; o > 0; o >>= 1)
            pcontrib += __shfl_xor_sync(0xffffffffu, pcontrib, o);
        if ((tid & 31) == 0) red[tid >> 5] = pcontrib;
        __syncthreads();
        if (tid == 0) {
            float ssum = 0.f;
            #pragma unroll
            for (int w8 = 0; w8 < 8; w8++) ssum += red[w8];
            g_site[n] = ssum + b0;
        }
        __syncthreads();
    }
}

// ============================================================================
// Kernel 5: per-crystal sum
// ============================================================================
__global__ void k_crystal(float* __restrict__ out) {
    __shared__ float red[8];
    int c = blockIdx.x, tid = threadIdx.x;
    float v = g_site[c * APC + tid];
    #pragma unroll
    for (int o = 16; o > 0; o >>= 1)
        v += __shfl_xor_sync(0xffffffffu, v, o);
    if ((tid & 31) == 0) red[tid >> 5] = v;
    __syncthreads();
    if (tid == 0) {
        float s = 0.f;
        #pragma unroll
        for (int i = 0; i < 8; i++) s += red[i];
        out[c] = s;
    }
}

// ============================================================================
extern "C" void kernel_launch(void* const* d_in, const int* in_sizes, int n_in,
                              void* d_out, int out_size) {
    const float* atom_fea = (const float*)d_in[0];
    const float* nbr_fea  = (const float*)d_in[1];
    const int*   nbr_idx  = (const int*)  d_in[2];
    const float* W_embed  = (const float*)d_in[3];
    const float* b_embed  = (const float*)d_in[4];
    const float* W_center = (const float*)d_in[5];
    const float* b_center = (const float*)d_in[6];
    const float* W_nbr    = (const float*)d_in[7];
    const float* b_nbr    = (const float*)d_in[8];
    const float* W_edge   = (const float*)d_in[9];
    const float* b_edge   = (const float*)d_in[10];
    const float* W_gate   = (const float*)d_in[11];
    const float* b_gate   = (const float*)d_in[12];
    const float* W_mag    = (const float*)d_in[13];
    const float* b_mag    = (const float*)d_in[14];
    const float* ln_scale = (const float*)d_in[15];
    const float* ln_bias  = (const float*)d_in[16];
    const float* W_h      = (const float*)d_in[17];
    const float* b_h      = (const float*)d_in[18];
    const float* W_out    = (const float*)d_in[19];
    const float* b_out    = (const float*)d_in[20];
    float* out = (float*)d_out;

    cudaFuncSetAttribute(k_convA,   cudaFuncAttributeMaxDynamicSharedMemorySize, A2_SMEM);
    cudaFuncSetAttribute(k_conv,    cudaFuncAttributeMaxDynamicSharedMemorySize, CV_SMEM);
    cudaFuncSetAttribute(k_readout, cudaFuncAttributeMaxDynamicSharedMemorySize, RO_SMEM);

    k_embed<<<256, 256>>>(atom_fea, W_embed, b_embed);
    for (int l = 0; l < NCONV; l++) {
        k_convA<<<148, 256, A2_SMEM>>>(W_center + l * FDIM * FDIM, b_center + l * FDIM,
                                       W_nbr    + l * FDIM * FDIM, b_nbr    + l * FDIM);
        k_conv<<<148, 256, CV_SMEM>>>(nbr_fea, nbr_idx,
                                      W_gate + l * FDIM * FDIM, b_gate + l * FDIM,
                                      W_mag  + l * FDIM * FDIM, b_mag  + l * FDIM,
                                      W_edge + l * EDGE * FDIM, b_edge + l * FDIM,
                                      ln_scale + l * FDIM, ln_bias + l * FDIM);
    }
    k_readout<<<152, 256, RO_SMEM>>>(W_h, b_h, W_out, b_out);
    k_crystal<<<NCRY, 256>>>(out);
}

// round 8
// speedup vs baseline: 2.9976x; 1.1429x over previous
#include <cuda_runtime.h>
#include <cuda_fp16.h>
#include <math.h>
#include <cstdint>

#define N_ATOMS 32768
#define MNBR    12
#define PROWS   16
#define ORIG    92
#define EDGE    41
#define FDIM    128
#define HDIM    256
#define NCONV   3
#define NCRY    128
#define APC     256
#define NT2     (N_ATOMS / 2)             // 16384 atom-pair tiles
#define ATILE   (N_ATOMS / 64)            // 512 (convA tiles)

// ---- scratch ----
__device__ float    g_x [N_ATOMS * FDIM];
__device__ float    g_pc[N_ATOMS * FDIM];
__device__ float    g_yn[N_ATOMS * FDIM];
__device__ uint32_t g_nbrh[N_ATOMS * MNBR * 24];   // fp16-packed nbr_fea (k2=24), 37.7 MB
__device__ float    g_site[N_ATOMS];

__device__ __forceinline__ float softplusf(float x) {
    return fmaxf(x, 0.f) + log1pf(expf(-fabsf(x)));
}
__device__ __forceinline__ float tf32r(float x) {
    uint32_t u;
    asm("cvt.rna.tf32.f32 %0, %1;" : "=r"(u) : "f"(x));
    return __uint_as_float(u);
}
__device__ __forceinline__ uint32_t smem_u32(const void* p) {
    uint32_t a;
    asm("{ .reg .u64 t; cvta.to.shared.u64 t, %1; cvt.u32.u64 %0, t; }" : "=r"(a) : "l"(p));
    return a;
}
__device__ __forceinline__ uint32_t packh2(float a, float b) {
    __half2 h = __floats2half2_rn(a, b);
    return *(uint32_t*)&h;
}
__device__ __forceinline__ void mma_tf32(float c[4], const uint32_t a[4], const uint32_t b[2]) {
    asm volatile("mma.sync.aligned.m16n8k8.row.col.f32.tf32.tf32.f32 "
        "{%0,%1,%2,%3}, {%4,%5,%6,%7}, {%8,%9}, {%0,%1,%2,%3};"
        : "+f"(c[0]), "+f"(c[1]), "+f"(c[2]), "+f"(c[3])
        : "r"(a[0]), "r"(a[1]), "r"(a[2]), "r"(a[3]), "r"(b[0]), "r"(b[1]));
}
__device__ __forceinline__ void mma_f16(float c[4], const uint32_t a[4], const uint32_t b[2]) {
    asm volatile("mma.sync.aligned.m16n8k16.row.col.f32.f16.f16.f32 "
        "{%0,%1,%2,%3}, {%4,%5,%6,%7}, {%8,%9}, {%0,%1,%2,%3};"
        : "+f"(c[0]), "+f"(c[1]), "+f"(c[2]), "+f"(c[3])
        : "r"(a[0]), "r"(a[1]), "r"(a[2]), "r"(a[3]), "r"(b[0]), "r"(b[1]));
}
__device__ __forceinline__ float act(float g, float m) {
    float sig = __fdividef(1.f, 1.f + __expf(-g));
    float sp  = fmaxf(m, 0.f) + __logf(1.f + __expf(-fabsf(m)));
    return sig * sp;
}

extern __shared__ float sm[];

// ============================================================================
// Kernel 0: pack nbr_fea -> fp16 k-pair layout [atom][m][24 u32] (zeros padded)
// ============================================================================
__global__ void k_pack(const float* __restrict__ nbr_fea) {
    int total = N_ATOMS * MNBR * 24;
    for (int idx = blockIdx.x * 256 + threadIdx.x; idx < total; idx += gridDim.x * 256) {
        int row = idx / 24, c = idx - row * 24;      // row = atom*12+m
        int k0 = 2 * c, k1 = 2 * c + 1;
        float v0 = (k0 < EDGE) ? nbr_fea[row * EDGE + k0] : 0.f;
        float v1 = (k1 < EDGE) ? nbr_fea[row * EDGE + k1] : 0.f;
        g_nbrh[idx] = packh2(v0, v1);
    }
}

// ============================================================================
// Kernel 1: embedding
// ============================================================================
__global__ void k_embed(const float* __restrict__ atom_fea,
                        const float* __restrict__ W,
                        const float* __restrict__ b) {
    __shared__ float Ws[ORIG * FDIM];
    __shared__ float rows[2 * ORIG];
    int tid = threadIdx.x;
    for (int i = tid; i < ORIG * FDIM; i += 256) Ws[i] = W[i];
    __syncthreads();
    int base = blockIdx.x * 128;
    int half = tid >> 7, f = tid & 127;
    for (int it = 0; it < 64; ++it) {
        int r0 = base + it * 2;
        for (int j = tid; j < 2 * ORIG; j += 256)
            rows[j] = atom_fea[r0 * ORIG + j];
        __syncthreads();
        float acc = b[f];
        const float* rp = rows + half * ORIG;
        #pragma unroll 4
        for (int e = 0; e < ORIG; e++)
            acc = fmaf(rp[e], Ws[e * FDIM + f], acc);
        g_x[(r0 + half) * FDIM + f] = acc;
        __syncthreads();
    }
}

// ============================================================================
// Kernel 2: k_convA — tf32 mma GEMM (pitch 265: 2-way instead of 8-way B loads)
// ============================================================================
#define A2_W    0
#define A2_A    33920           // 128*265
#define A2_BIAS 42368
#define A2_TOT  42624
#define A2_SMEM (A2_TOT * 4)

__global__ void __launch_bounds__(256, 1)
k_convA(const float* __restrict__ Wc, const float* __restrict__ bc,
        const float* __restrict__ Wn, const float* __restrict__ bn) {
    int tid = threadIdx.x, wid = tid >> 5, lane = tid & 31;
    uint32_t* smu = (uint32_t*)sm;
    for (int i = tid; i < FDIM * FDIM; i += 256) {
        int k = i >> 7, n = i & 127;
        smu[A2_W + k * 265 + n]       = __float_as_uint(tf32r(Wc[i]));
        smu[A2_W + k * 265 + 128 + n] = __float_as_uint(tf32r(Wn[i]));
    }
    if (tid < 128) { sm[A2_BIAS + tid] = bc[tid]; sm[A2_BIAS + 128 + tid] = bn[tid]; }
    __syncthreads();

    int wr = wid >> 2, wc = wid & 3;
    int tig = lane & 3, grp = lane >> 2;
    float bcr[4][2], bnr[4][2];
    #pragma unroll
    for (int j = 0; j < 4; j++) {
        int f0 = wc * 32 + j * 8 + 2 * tig;
        bcr[j][0] = sm[A2_BIAS + f0];       bcr[j][1] = sm[A2_BIAS + f0 + 1];
        bnr[j][0] = sm[A2_BIAS + 128 + f0]; bnr[j][1] = sm[A2_BIAS + 128 + f0 + 1];
    }

    for (int t = blockIdx.x; t < ATILE; t += gridDim.x) {
        #pragma unroll
        for (int q = 0; q < 8; q++) {
            int ch = tid + q * 256;
            int r = ch >> 5, c4 = ch & 31;
            float4 v = *(const float4*)&g_x[(t * 64 + r) * FDIM + c4 * 4];
            sm[A2_A + r * 132 + c4 * 4 + 0] = tf32r(v.x);
            sm[A2_A + r * 132 + c4 * 4 + 1] = tf32r(v.y);
            sm[A2_A + r * 132 + c4 * 4 + 2] = tf32r(v.z);
            sm[A2_A + r * 132 + c4 * 4 + 3] = tf32r(v.w);
        }
        __syncthreads();

        float cpc[2][4][4] = {}, cyn[2][4][4] = {};
        #pragma unroll
        for (int ks = 0; ks < 16; ks++) {
            int k0 = ks * 8;
            uint32_t a[2][4];
            #pragma unroll
            for (int rt = 0; rt < 2; rt++) {
                int r = wr * 32 + rt * 16 + grp;
                a[rt][0] = smu[A2_A + r * 132 + k0 + tig];
                a[rt][1] = smu[A2_A + (r + 8) * 132 + k0 + tig];
                a[rt][2] = smu[A2_A + r * 132 + k0 + 4 + tig];
                a[rt][3] = smu[A2_A + (r + 8) * 132 + k0 + 4 + tig];
            }
            #pragma unroll
            for (int j = 0; j < 4; j++) {
                int n = wc * 32 + j * 8 + grp;
                uint32_t bcf[2], bnf[2];
                bcf[0] = smu[A2_W + (k0 + tig) * 265 + n];
                bcf[1] = smu[A2_W + (k0 + 4 + tig) * 265 + n];
                bnf[0] = smu[A2_W + (k0 + tig) * 265 + 128 + n];
                bnf[1] = smu[A2_W + (k0 + 4 + tig) * 265 + 128 + n];
                #pragma unroll
                for (int rt = 0; rt < 2; rt++) {
                    mma_tf32(cpc[rt][j], a[rt], bcf);
                    mma_tf32(cyn[rt][j], a[rt], bnf);
                }
            }
        }

        #pragma unroll
        for (int rt = 0; rt < 2; rt++) {
            int r0 = t * 64 + wr * 32 + rt * 16 + grp;
            #pragma unroll
            for (int j = 0; j < 4; j++) {
                int f0 = wc * 32 + j * 8 + 2 * tig;
                float2 v;
                v.x = cpc[rt][j][0] + bcr[j][0]; v.y = cpc[rt][j][1] + bcr[j][1];
                *(float2*)&g_pc[r0 * FDIM + f0] = v;
                v.x = cpc[rt][j][2] + bcr[j][0]; v.y = cpc[rt][j][3] + bcr[j][1];
                *(float2*)&g_pc[(r0 + 8) * FDIM + f0] = v;
                v.x = cyn[rt][j][0] + bnr[j][0]; v.y = cyn[rt][j][1] + bnr[j][1];
                *(float2*)&g_yn[r0 * FDIM + f0] = v;
                v.x = cyn[rt][j][2] + bnr[j][0]; v.y = cyn[rt][j][3] + bnr[j][1];
                *(float2*)&g_yn[(r0 + 8) * FDIM + f0] = v;
            }
        }
        __syncthreads();
    }
}

// ============================================================================
// Kernel 3: k_conv — fused conv layer, fp16 m16n8k16, two independent
// 128-thread pipelines. All smem offsets in 32-bit words.
//   S_W   Wp u32[64 k2][265]  (gate n<128 | mag n>=128)   16960
//   S_WE  WEp u32[24 k2][133]                              3192
//   S_BIAS bg|bm|lns|lnb|be fp32                            640
//   per group: AGM u32[32][68]=2176 | AE 2x u32[32][28]=1792 | RED 256 | IDX 48
// ============================================================================
#define S_W     0
#define S_WE    16960
#define S_BIAS  20152
#define S_GRP   20792
#define GRPSZ   4272
#define GP_AGM  0
#define GP_AE   2176
#define GP_RED  3968
#define GP_IDX  4224
#define S_TOT   (S_GRP + 2 * GRPSZ)     // 29336 words
#define CV_SMEM (S_TOT * 4)

__device__ __forceinline__ void stage_ae_h(uint32_t dstbase, const char* __restrict__ src,
                                           int gtid) {
    #pragma unroll
    for (int q = 0; q < 2; q++) {
        int i = gtid + q * 128;                      // 144 chunks of 16B
        if (i < 144) {
            int a = i / 72, rem = i - a * 72;
            int m = rem / 6, c = rem - m * 6;
            uint32_t d = dstbase + (uint32_t)((a * PROWS + m) * 28 + c * 4) * 4;
            asm volatile("cp.async.ca.shared.global [%0], [%1], 16;"
                         :: "r"(d), "l"(src + (size_t)i * 16) : "memory");
        }
    }
}

__global__ void __launch_bounds__(256, 1)
k_conv(const int* __restrict__ nbr_idx,
       const float* __restrict__ Wg, const float* __restrict__ bg,
       const float* __restrict__ Wm, const float* __restrict__ bm,
       const float* __restrict__ We, const float* __restrict__ be,
       const float* __restrict__ lns, const float* __restrict__ lnb) {
    int tid = threadIdx.x, wid = tid >> 5, lane = tid & 31;
    int half = wid >> 2, wg = wid & 3, gtid = tid & 127;
    uint32_t* smu = (uint32_t*)sm;

    // ---- pack resident weights to fp16 k-pairs ----
    for (int i = tid; i < 64 * 256; i += 256) {
        int k2 = i >> 8, n = i & 255;
        const float* W = (n < 128) ? Wg : Wm;
        int nn = n & 127;
        smu[S_W + k2 * 265 + n] = packh2(W[(2 * k2) * FDIM + nn], W[(2 * k2 + 1) * FDIM + nn]);
    }
    for (int i = tid; i < 24 * 128; i += 256) {
        int k2 = i >> 7, n = i & 127;
        float v0 = (2 * k2     < EDGE) ? We[(2 * k2) * FDIM + n]     : 0.f;
        float v1 = (2 * k2 + 1 < EDGE) ? We[(2 * k2 + 1) * FDIM + n] : 0.f;
        smu[S_WE + k2 * 133 + n] = packh2(v0, v1);
    }
    for (int i = tid; i < 2 * GRPSZ; i += 256) sm[S_GRP + i] = 0.f;  // pads stay zero
    if (tid < FDIM) {
        sm[S_BIAS + tid]       = bg[tid];
        sm[S_BIAS + 128 + tid] = bm[tid];
        sm[S_BIAS + 256 + tid] = lns[tid];
        sm[S_BIAS + 384 + tid] = lnb[tid];
        sm[S_BIAS + 512 + tid] = be[tid];
    }

    int gbase = S_GRP + half * GRPSZ;
    int* sidx = (int*)(sm + gbase + GP_IDX);
    uint32_t aeRaw = smem_u32(sm + gbase + GP_AE);
    int tig = lane & 3, grp = lane >> 2;
    bool notpad = (grp < 4);
    int barid = half + 1;
    int wc = wg;

    int stride = 2 * gridDim.x;
    int s0 = blockIdx.x * 2 + half;

    __syncthreads();    // weights + zeroed regions visible before staging

    // prologue: stage first tile into buffer 0
    if (gtid < 24) sidx[gtid] = nbr_idx[s0 * 24 + gtid];
    stage_ae_h(aeRaw, (const char*)(g_nbrh + (size_t)s0 * 576), gtid);
    asm volatile("cp.async.commit_group;" ::: "memory");

    float bgr[4][2], bmr[4][2], ber[4][2];
    #pragma unroll
    for (int j = 0; j < 4; j++) {
        int f0 = wc * 32 + j * 8 + 2 * tig;
        bgr[j][0] = sm[S_BIAS + f0];        bgr[j][1] = sm[S_BIAS + f0 + 1];
        bmr[j][0] = sm[S_BIAS + 128 + f0];  bmr[j][1] = sm[S_BIAS + 128 + f0 + 1];
        ber[j][0] = sm[S_BIAS + 512 + f0];  ber[j][1] = sm[S_BIAS + 512 + f0 + 1];
    }
    float4 lns4 = *(const float4*)&sm[S_BIAS + 256 + lane * 4];
    float4 lnb4 = *(const float4*)&sm[S_BIAS + 384 + lane * 4];

    asm volatile("cp.async.wait_group 0;" ::: "memory");
    asm volatile("bar.sync %0, %1;" :: "r"(barid), "r"(128) : "memory");

    int buf = 0;
    for (int t = s0; t < NT2; t += stride) {
        const int* sx = sidx + buf * 24;
        int aeB = gbase + GP_AE + buf * 896;

        // ---- prefetch yn/pc (fp32, L2) ----
        float2 yn0[2][4], yn1[2][4], pcp[2][4];
        #pragma unroll
        for (int rt = 0; rt < 2; rt++) {
            int i0 = sx[rt * MNBR + grp];
            int i1 = notpad ? sx[rt * MNBR + grp + 8] : 0;
            #pragma unroll
            for (int j = 0; j < 4; j++) {
                int f0 = wc * 32 + j * 8 + 2 * tig;
                yn0[rt][j] = *(const float2*)&g_yn[i0 * FDIM + f0];
                yn1[rt][j] = notpad ? *(const float2*)&g_yn[i1 * FDIM + f0]
                                    : make_float2(0.f, 0.f);
                pcp[rt][j] = *(const float2*)&g_pc[(t * 2 + rt) * FDIM + f0];
            }
        }

        // ---- issue next-tile staging ----
        int tn = t + stride;
        if (tn < NT2) {
            if (gtid < 24) sidx[(buf ^ 1) * 24 + gtid] = nbr_idx[tn * 24 + gtid];
            stage_ae_h(aeRaw + (uint32_t)(buf ^ 1) * 896 * 4,
                       (const char*)(g_nbrh + (size_t)tn * 576), gtid);
        }
        asm volatile("cp.async.commit_group;" ::: "memory");

        // ---- phi_e mma: fp16 k16, K=48 -> 3 steps ----
        float ce[2][4][4] = {};
        #pragma unroll
        for (int ks = 0; ks < 3; ks++) {
            int k0 = ks * 8;                         // k2 units
            uint32_t a[2][4];
            #pragma unroll
            for (int rt = 0; rt < 2; rt++) {
                int r = rt * 16 + grp;
                a[rt][0] = smu[aeB + r * 28 + k0 + tig];
                a[rt][1] = smu[aeB + (r + 8) * 28 + k0 + tig];
                a[rt][2] = smu[aeB + r * 28 + k0 + 4 + tig];
                a[rt][3] = smu[aeB + (r + 8) * 28 + k0 + 4 + tig];
            }
            #pragma unroll
            for (int j = 0; j < 4; j++) {
                int n = wc * 32 + j * 8 + grp;
                uint32_t b[2];
                b[0] = smu[S_WE + (k0 + tig) * 133 + n];
                b[1] = smu[S_WE + (k0 + 4 + tig) * 133 + n];
                #pragma unroll
                for (int rt = 0; rt < 2; rt++)
                    mma_f16(ce[rt][j], a[rt], b);
            }
        }

        // ---- build inter tile (packed fp16) ----
        #pragma unroll
        for (int rt = 0; rt < 2; rt++) {
            int r = rt * 16 + grp;
            #pragma unroll
            for (int j = 0; j < 4; j++) {
                int kk = wc * 16 + j * 4 + tig;      // k2 index = f0/2
                smu[gbase + GP_AGM + r * 68 + kk] =
                    packh2(pcp[rt][j].x * yn0[rt][j].x * (ce[rt][j][0] + ber[j][0]),
                           pcp[rt][j].y * yn0[rt][j].y * (ce[rt][j][1] + ber[j][1]));
                if (notpad) {
                    smu[gbase + GP_AGM + (r + 8) * 68 + kk] =
                        packh2(pcp[rt][j].x * yn1[rt][j].x * (ce[rt][j][2] + ber[j][0]),
                               pcp[rt][j].y * yn1[rt][j].y * (ce[rt][j][3] + ber[j][1]));
                }
            }
        }
        asm volatile("bar.sync %0, %1;" :: "r"(barid), "r"(128) : "memory");

        // ---- gate/mag mma: fp16 k16, K=128 -> 8 steps ----
        float cg[2][4][4] = {}, cmm[2][4][4] = {};
        #pragma unroll
        for (int ks = 0; ks < 8; ks++) {
            int k0 = ks * 8;                         // k2 units
            uint32_t a[2][4];
            #pragma unroll
            for (int rt = 0; rt < 2; rt++) {
                int r = rt * 16 + grp;
                a[rt][0] = smu[gbase + GP_AGM + r * 68 + k0 + tig];
                a[rt][1] = smu[gbase + GP_AGM + (r + 8) * 68 + k0 + tig];
                a[rt][2] = smu[gbase + GP_AGM + r * 68 + k0 + 4 + tig];
                a[rt][3] = smu[gbase + GP_AGM + (r + 8) * 68 + k0 + 4 + tig];
            }
            #pragma unroll
            for (int j = 0; j < 4; j++) {
                int n = wc * 32 + j * 8 + grp;
                uint32_t bgf[2], bmf[2];
                bgf[0] = smu[S_W + (k0 + tig) * 265 + n];
                bgf[1] = smu[S_W + (k0 + 4 + tig) * 265 + n];
                bmf[0] = smu[S_W + (k0 + tig) * 265 + 128 + n];
                bmf[1] = smu[S_W + (k0 + 4 + tig) * 265 + 128 + n];
                #pragma unroll
                for (int rt = 0; rt < 2; rt++) {
                    mma_f16(cg[rt][j], a[rt], bgf);
                    mma_f16(cmm[rt][j], a[rt], bmf);
                }
            }
        }

        // ---- activation + masked per-atom column sums ----
        #pragma unroll
        for (int rt = 0; rt < 2; rt++) {
            #pragma unroll
            for (int j = 0; j < 4; j++) {
                float p0 = act(cg[rt][j][0] + bgr[j][0], cmm[rt][j][0] + bmr[j][0]);
                float p1 = act(cg[rt][j][1] + bgr[j][1], cmm[rt][j][1] + bmr[j][1]);
                if (notpad) {
                    p0 += act(cg[rt][j][2] + bgr[j][0], cmm[rt][j][2] + bmr[j][0]);
                    p1 += act(cg[rt][j][3] + bgr[j][1], cmm[rt][j][3] + bmr[j][1]);
                }
                #pragma unroll
                for (int o = 4; o < 32; o <<= 1) {
                    p0 += __shfl_xor_sync(0xffffffffu, p0, o);
                    p1 += __shfl_xor_sync(0xffffffffu, p1, o);
                }
                if (grp == 0) {
                    int f0 = wc * 32 + j * 8 + 2 * tig;
                    sm[gbase + GP_RED + rt * 128 + f0]     = p0;
                    sm[gbase + GP_RED + rt * 128 + f0 + 1] = p1;
                }
            }
        }
        asm volatile("cp.async.wait_group 0;" ::: "memory");
        asm volatile("bar.sync %0, %1;" :: "r"(barid), "r"(128) : "memory");

        // ---- LayerNorm + residual (warps 0,1 of group) ----
        if (wg < 2) {
            float4 v = *(const float4*)&sm[gbase + GP_RED + wg * 128 + lane * 4];
            float s = v.x + v.y + v.z + v.w;
            float q = v.x*v.x + v.y*v.y + v.z*v.z + v.w*v.w;
            #pragma unroll
            for (int o = 16; o > 0; o >>= 1) {
                s += __shfl_xor_sync(0xffffffffu, s, o);
                q += __shfl_xor_sync(0xffffffffu, q, o);
            }
            float mu = s * (1.f / FDIM);
            float var = q * (1.f / FDIM) - mu * mu;
            float rstd = rsqrtf(var + 1e-6f);
            int n = t * 2 + wg;
            float4 x = *(float4*)&g_x[n * FDIM + lane * 4];
            x.x += (v.x - mu) * rstd * lns4.x + lnb4.x;
            x.y += (v.y - mu) * rstd * lns4.y + lnb4.y;
            x.z += (v.z - mu) * rstd * lns4.z + lnb4.z;
            x.w += (v.w - mu) * rstd * lns4.w + lnb4.w;
            *(float4*)&g_x[n * FDIM + lane * 4] = x;
        }
        buf ^= 1;
    }
}

// ============================================================================
// Kernel 4: readout
// ============================================================================
#define RO_WHT  0
#define RO_WO   33792
#define RO_BH   34048
#define RO_XR   34304
#define RO_RED  34432
#define RO_FLOATS 34440
#define RO_SMEM (RO_FLOATS * 4)

__global__ void k_readout(const float* __restrict__ Wh, const float* __restrict__ bh,
                          const float* __restrict__ Wout, const float* __restrict__ bout) {
    float* WhT = sm + RO_WHT;
    float* WoS = sm + RO_WO;
    float* bhS = sm + RO_BH;
    float* xr  = sm + RO_XR;
    float* red = sm + RO_RED;
    int tid = threadIdx.x;
    for (int i = tid; i < FDIM * HDIM; i += 256) {
        int k = i >> 8, j = i & 255;
        WhT[j * 132 + k] = Wh[i];
    }
    WoS[tid] = Wout[tid];
    bhS[tid] = bh[tid];
    __syncthreads();
    float b0 = bout[0];
    const float4* wp = (const float4*)(WhT + tid * 132);

    for (int n = blockIdx.x; n < N_ATOMS; n += gridDim.x) {
        if (tid < FDIM) xr[tid] = g_x[n * FDIM + tid];
        __syncthreads();
        float acc = bhS[tid];
        #pragma unroll 4
        for (int k4 = 0; k4 < FDIM / 4; k4++) {
            float4 w = wp[k4];
            float4 xv = *(const float4*)(xr + k4 * 4);
            acc = fmaf(w.x, xv.x, acc); acc = fmaf(w.y, xv.y, acc);
            acc = fmaf(w.z, xv.z, acc); acc = fmaf(w.w, xv.w, acc);
        }
        float pcontrib = softplusf(acc) * WoS[tid];
        #pragma unroll
        for (int o = 16; o > 0; o >>= 1)
            pcontrib += __shfl_xor_sync(0xffffffffu, pcontrib, o);
        if ((tid & 31) == 0) red[tid >> 5] = pcontrib;
        __syncthreads();
        if (tid == 0) {
            float ssum = 0.f;
            #pragma unroll
            for (int w8 = 0; w8 < 8; w8++) ssum += red[w8];
            g_site[n] = ssum + b0;
        }
        __syncthreads();
    }
}

// ============================================================================
// Kernel 5: per-crystal sum
// ============================================================================
__global__ void k_crystal(float* __restrict__ out) {
    __shared__ float red[8];
    int c = blockIdx.x, tid = threadIdx.x;
    float v = g_site[c * APC + tid];
    #pragma unroll
    for (int o = 16; o > 0; o >>= 1)
        v += __shfl_xor_sync(0xffffffffu, v, o);
    if ((tid & 31) == 0) red[tid >> 5] = v;
    __syncthreads();
    if (tid == 0) {
        float s = 0.f;
        #pragma unroll
        for (int i = 0; i < 8; i++) s += red[i];
        out[c] = s;
    }
}

// ============================================================================
extern "C" void kernel_launch(void* const* d_in, const int* in_sizes, int n_in,
                              void* d_out, int out_size) {
    const float* atom_fea = (const float*)d_in[0];
    const float* nbr_fea  = (const float*)d_in[1];
    const int*   nbr_idx  = (const int*)  d_in[2];
    const float* W_embed  = (const float*)d_in[3];
    const float* b_embed  = (const float*)d_in[4];
    const float* W_center = (const float*)d_in[5];
    const float* b_center = (const float*)d_in[6];
    const float* W_nbr    = (const float*)d_in[7];
    const float* b_nbr    = (const float*)d_in[8];
    const float* W_edge   = (const float*)d_in[9];
    const float* b_edge   = (const float*)d_in[10];
    const float* W_gate   = (const float*)d_in[11];
    const float* b_gate   = (const float*)d_in[12];
    const float* W_mag    = (const float*)d_in[13];
    const float* b_mag    = (const float*)d_in[14];
    const float* ln_scale = (const float*)d_in[15];
    const float* ln_bias  = (const float*)d_in[16];
    const float* W_h      = (const float*)d_in[17];
    const float* b_h      = (const float*)d_in[18];
    const float* W_out    = (const float*)d_in[19];
    const float* b_out    = (const float*)d_in[20];
    float* out = (float*)d_out;

    cudaFuncSetAttribute(k_convA,   cudaFuncAttributeMaxDynamicSharedMemorySize, A2_SMEM);
    cudaFuncSetAttribute(k_conv,    cudaFuncAttributeMaxDynamicSharedMemorySize, CV_SMEM);
    cudaFuncSetAttribute(k_readout, cudaFuncAttributeMaxDynamicSharedMemorySize, RO_SMEM);

    k_pack<<<2048, 256>>>(nbr_fea);
    k_embed<<<256, 256>>>(atom_fea, W_embed, b_embed);
    for (int l = 0; l < NCONV; l++) {
        k_convA<<<148, 256, A2_SMEM>>>(W_center + l * FDIM * FDIM, b_center + l * FDIM,
                                       W_nbr    + l * FDIM * FDIM, b_nbr    + l * FDIM);
        k_conv<<<148, 256, CV_SMEM>>>(nbr_idx,
                                      W_gate + l * FDIM * FDIM, b_gate + l * FDIM,
                                      W_mag  + l * FDIM * FDIM, b_mag  + l * FDIM,
                                      W_edge + l * EDGE * FDIM, b_edge + l * FDIM,
                                      ln_scale + l * FDIM, ln_bias + l * FDIM);
    }
    k_readout<<<152, 256, RO_SMEM>>>(W_h, b_h, W_out, b_out);
    k_crystal<<<NCRY, 256>>>(out);
}

// round 9
// speedup vs baseline: 3.3345x; 1.1124x over previous
#include <cuda_runtime.h>
#include <cuda_fp16.h>
#include <math.h>
#include <cstdint>

#define N_ATOMS 32768
#define MNBR    12
#define PROWS   16
#define ORIG    92
#define EDGE    41
#define FDIM    128
#define HDIM    256
#define NCONV   3
#define NCRY    128
#define APC     256
#define NT2     (N_ATOMS / 2)             // 16384 atom-pair tiles
#define ATILE   (N_ATOMS / 64)            // 512 (convA tiles)

// ---- scratch ----
__device__ float    g_x [N_ATOMS * FDIM];
__device__ float    g_pc[N_ATOMS * FDIM];
__device__ float    g_yn[N_ATOMS * FDIM];
__device__ uint32_t g_nbrh[N_ATOMS * MNBR * 24];   // fp16-packed nbr_fea (k2=24)
__device__ float    g_site[N_ATOMS];

__device__ __forceinline__ float softplusf(float x) {
    return fmaxf(x, 0.f) + log1pf(expf(-fabsf(x)));
}
__device__ __forceinline__ float tf32r(float x) {
    uint32_t u;
    asm("cvt.rna.tf32.f32 %0, %1;" : "=r"(u) : "f"(x));
    return __uint_as_float(u);
}
__device__ __forceinline__ uint32_t smem_u32(const void* p) {
    uint32_t a;
    asm("{ .reg .u64 t; cvta.to.shared.u64 t, %1; cvt.u32.u64 %0, t; }" : "=r"(a) : "l"(p));
    return a;
}
__device__ __forceinline__ uint32_t packh2(float a, float b) {
    __half2 h = __floats2half2_rn(a, b);
    return *(uint32_t*)&h;
}
__device__ __forceinline__ void mma_tf32(float c[4], const uint32_t a[4], const uint32_t b[2]) {
    asm volatile("mma.sync.aligned.m16n8k8.row.col.f32.tf32.tf32.f32 "
        "{%0,%1,%2,%3}, {%4,%5,%6,%7}, {%8,%9}, {%0,%1,%2,%3};"
        : "+f"(c[0]), "+f"(c[1]), "+f"(c[2]), "+f"(c[3])
        : "r"(a[0]), "r"(a[1]), "r"(a[2]), "r"(a[3]), "r"(b[0]), "r"(b[1]));
}
__device__ __forceinline__ void mma_f16(float c[4], const uint32_t a[4], const uint32_t b[2]) {
    asm volatile("mma.sync.aligned.m16n8k16.row.col.f32.f16.f16.f32 "
        "{%0,%1,%2,%3}, {%4,%5,%6,%7}, {%8,%9}, {%0,%1,%2,%3};"
        : "+f"(c[0]), "+f"(c[1]), "+f"(c[2]), "+f"(c[3])
        : "r"(a[0]), "r"(a[1]), "r"(a[2]), "r"(a[3]), "r"(b[0]), "r"(b[1]));
}
__device__ __forceinline__ float act(float g, float m) {
    float sig = __fdividef(1.f, 1.f + __expf(-g));
    float sp  = fmaxf(m, 0.f) + __logf(1.f + __expf(-fabsf(m)));
    return sig * sp;
}

extern __shared__ float sm[];

// ============================================================================
// Kernel 0: pack nbr_fea -> fp16 k-pair layout [atom][m][24 u32]
// ============================================================================
__global__ void k_pack(const float* __restrict__ nbr_fea) {
    int total = N_ATOMS * MNBR * 24;
    for (int idx = blockIdx.x * 256 + threadIdx.x; idx < total; idx += gridDim.x * 256) {
        int row = idx / 24, c = idx - row * 24;
        int k0 = 2 * c, k1 = 2 * c + 1;
        float v0 = (k0 < EDGE) ? nbr_fea[row * EDGE + k0] : 0.f;
        float v1 = (k1 < EDGE) ? nbr_fea[row * EDGE + k1] : 0.f;
        g_nbrh[idx] = packh2(v0, v1);
    }
}

// ============================================================================
// Kernel 1: embedding
// ============================================================================
__global__ void k_embed(const float* __restrict__ atom_fea,
                        const float* __restrict__ W,
                        const float* __restrict__ b) {
    __shared__ float Ws[ORIG * FDIM];
    __shared__ float rows[2 * ORIG];
    int tid = threadIdx.x;
    for (int i = tid; i < ORIG * FDIM; i += 256) Ws[i] = W[i];
    __syncthreads();
    int base = blockIdx.x * 128;
    int half = tid >> 7, f = tid & 127;
    for (int it = 0; it < 64; ++it) {
        int r0 = base + it * 2;
        for (int j = tid; j < 2 * ORIG; j += 256)
            rows[j] = atom_fea[r0 * ORIG + j];
        __syncthreads();
        float acc = b[f];
        const float* rp = rows + half * ORIG;
        #pragma unroll 4
        for (int e = 0; e < ORIG; e++)
            acc = fmaf(rp[e], Ws[e * FDIM + f], acc);
        g_x[(r0 + half) * FDIM + f] = acc;
        __syncthreads();
    }
}

// ============================================================================
// Kernel 2: k_convA — tf32 mma GEMM (pitch 265)
// ============================================================================
#define A2_W    0
#define A2_A    33920
#define A2_BIAS 42368
#define A2_TOT  42624
#define A2_SMEM (A2_TOT * 4)

__global__ void __launch_bounds__(256, 1)
k_convA(const float* __restrict__ Wc, const float* __restrict__ bc,
        const float* __restrict__ Wn, const float* __restrict__ bn) {
    int tid = threadIdx.x, wid = tid >> 5, lane = tid & 31;
    uint32_t* smu = (uint32_t*)sm;
    for (int i = tid; i < FDIM * FDIM; i += 256) {
        int k = i >> 7, n = i & 127;
        smu[A2_W + k * 265 + n]       = __float_as_uint(tf32r(Wc[i]));
        smu[A2_W + k * 265 + 128 + n] = __float_as_uint(tf32r(Wn[i]));
    }
    if (tid < 128) { sm[A2_BIAS + tid] = bc[tid]; sm[A2_BIAS + 128 + tid] = bn[tid]; }
    __syncthreads();

    int wr = wid >> 2, wc = wid & 3;
    int tig = lane & 3, grp = lane >> 2;
    float bcr[4][2], bnr[4][2];
    #pragma unroll
    for (int j = 0; j < 4; j++) {
        int f0 = wc * 32 + j * 8 + 2 * tig;
        bcr[j][0] = sm[A2_BIAS + f0];       bcr[j][1] = sm[A2_BIAS + f0 + 1];
        bnr[j][0] = sm[A2_BIAS + 128 + f0]; bnr[j][1] = sm[A2_BIAS + 128 + f0 + 1];
    }

    for (int t = blockIdx.x; t < ATILE; t += gridDim.x) {
        #pragma unroll
        for (int q = 0; q < 8; q++) {
            int ch = tid + q * 256;
            int r = ch >> 5, c4 = ch & 31;
            float4 v = *(const float4*)&g_x[(t * 64 + r) * FDIM + c4 * 4];
            sm[A2_A + r * 132 + c4 * 4 + 0] = tf32r(v.x);
            sm[A2_A + r * 132 + c4 * 4 + 1] = tf32r(v.y);
            sm[A2_A + r * 132 + c4 * 4 + 2] = tf32r(v.z);
            sm[A2_A + r * 132 + c4 * 4 + 3] = tf32r(v.w);
        }
        __syncthreads();

        float cpc[2][4][4] = {}, cyn[2][4][4] = {};
        #pragma unroll
        for (int ks = 0; ks < 16; ks++) {
            int k0 = ks * 8;
            uint32_t a[2][4];
            #pragma unroll
            for (int rt = 0; rt < 2; rt++) {
                int r = wr * 32 + rt * 16 + grp;
                a[rt][0] = smu[A2_A + r * 132 + k0 + tig];
                a[rt][1] = smu[A2_A + (r + 8) * 132 + k0 + tig];
                a[rt][2] = smu[A2_A + r * 132 + k0 + 4 + tig];
                a[rt][3] = smu[A2_A + (r + 8) * 132 + k0 + 4 + tig];
            }
            #pragma unroll
            for (int j = 0; j < 4; j++) {
                int n = wc * 32 + j * 8 + grp;
                uint32_t bcf[2], bnf[2];
                bcf[0] = smu[A2_W + (k0 + tig) * 265 + n];
                bcf[1] = smu[A2_W + (k0 + 4 + tig) * 265 + n];
                bnf[0] = smu[A2_W + (k0 + tig) * 265 + 128 + n];
                bnf[1] = smu[A2_W + (k0 + 4 + tig) * 265 + 128 + n];
                #pragma unroll
                for (int rt = 0; rt < 2; rt++) {
                    mma_tf32(cpc[rt][j], a[rt], bcf);
                    mma_tf32(cyn[rt][j], a[rt], bnf);
                }
            }
        }

        #pragma unroll
        for (int rt = 0; rt < 2; rt++) {
            int r0 = t * 64 + wr * 32 + rt * 16 + grp;
            #pragma unroll
            for (int j = 0; j < 4; j++) {
                int f0 = wc * 32 + j * 8 + 2 * tig;
                float2 v;
                v.x = cpc[rt][j][0] + bcr[j][0]; v.y = cpc[rt][j][1] + bcr[j][1];
                *(float2*)&g_pc[r0 * FDIM + f0] = v;
                v.x = cpc[rt][j][2] + bcr[j][0]; v.y = cpc[rt][j][3] + bcr[j][1];
                *(float2*)&g_pc[(r0 + 8) * FDIM + f0] = v;
                v.x = cyn[rt][j][0] + bnr[j][0]; v.y = cyn[rt][j][1] + bnr[j][1];
                *(float2*)&g_yn[r0 * FDIM + f0] = v;
                v.x = cyn[rt][j][2] + bnr[j][0]; v.y = cyn[rt][j][3] + bnr[j][1];
                *(float2*)&g_yn[(r0 + 8) * FDIM + f0] = v;
            }
        }
        __syncthreads();
    }
}

// ============================================================================
// Kernel 3: k_conv — fused conv layer, fp16 mma, 512 threads:
// 2 independent pipelines x 8 warps; each warp covers 16 f-cols (j=2).
// ============================================================================
#define S_W     0
#define S_WE    16960
#define S_BIAS  20152
#define S_GRP   20792
#define GRPSZ   4272
#define GP_AGM  0
#define GP_AE   2176
#define GP_RED  3968
#define GP_IDX  4224
#define S_TOT   (S_GRP + 2 * GRPSZ)     // 29336 words = 117.3 KB
#define CV_SMEM (S_TOT * 4)
#define CV_THREADS 512

__device__ __forceinline__ void stage_ae_h(uint32_t dstbase, const char* __restrict__ src,
                                           int gtid) {
    if (gtid < 144) {                              // 144 chunks of 16B
        int a = gtid / 72, rem = gtid - a * 72;
        int m = rem / 6, c = rem - m * 6;
        uint32_t d = dstbase + (uint32_t)((a * PROWS + m) * 28 + c * 4) * 4;
        asm volatile("cp.async.ca.shared.global [%0], [%1], 16;"
                     :: "r"(d), "l"(src + (size_t)gtid * 16) : "memory");
    }
}

__global__ void __launch_bounds__(CV_THREADS, 1)
k_conv(const int* __restrict__ nbr_idx,
       const float* __restrict__ Wg, const float* __restrict__ bg,
       const float* __restrict__ Wm, const float* __restrict__ bm,
       const float* __restrict__ We, const float* __restrict__ be,
       const float* __restrict__ lns, const float* __restrict__ lnb) {
    int tid = threadIdx.x, wid = tid >> 5, lane = tid & 31;
    int half = wid >> 3, wg = wid & 7, gtid = tid & 255;
    uint32_t* smu = (uint32_t*)sm;

    // ---- pack resident weights to fp16 k-pairs ----
    for (int i = tid; i < 64 * 256; i += CV_THREADS) {
        int k2 = i >> 8, n = i & 255;
        const float* W = (n < 128) ? Wg : Wm;
        int nn = n & 127;
        smu[S_W + k2 * 265 + n] = packh2(W[(2 * k2) * FDIM + nn], W[(2 * k2 + 1) * FDIM + nn]);
    }
    for (int i = tid; i < 24 * 128; i += CV_THREADS) {
        int k2 = i >> 7, n = i & 127;
        float v0 = (2 * k2     < EDGE) ? We[(2 * k2) * FDIM + n]     : 0.f;
        float v1 = (2 * k2 + 1 < EDGE) ? We[(2 * k2 + 1) * FDIM + n] : 0.f;
        smu[S_WE + k2 * 133 + n] = packh2(v0, v1);
    }
    for (int i = tid; i < 2 * GRPSZ; i += CV_THREADS) sm[S_GRP + i] = 0.f;
    if (tid < FDIM) {
        sm[S_BIAS + tid]       = bg[tid];
        sm[S_BIAS + 128 + tid] = bm[tid];
        sm[S_BIAS + 256 + tid] = lns[tid];
        sm[S_BIAS + 384 + tid] = lnb[tid];
        sm[S_BIAS + 512 + tid] = be[tid];
    }

    int gbase = S_GRP + half * GRPSZ;
    int* sidx = (int*)(sm + gbase + GP_IDX);
    uint32_t aeRaw = smem_u32(sm + gbase + GP_AE);
    int tig = lane & 3, grp = lane >> 2;
    bool notpad = (grp < 4);
    int barid = half + 1;

    int stride = 2 * gridDim.x;
    int s0 = blockIdx.x * 2 + half;

    __syncthreads();

    // prologue: stage first tile into buffer 0
    if (gtid < 24) sidx[gtid] = nbr_idx[s0 * 24 + gtid];
    stage_ae_h(aeRaw, (const char*)(g_nbrh + (size_t)s0 * 576), gtid);
    asm volatile("cp.async.commit_group;" ::: "memory");

    float bgr[2][2], bmr[2][2], ber[2][2];
    #pragma unroll
    for (int j = 0; j < 2; j++) {
        int f0 = wg * 16 + j * 8 + 2 * tig;
        bgr[j][0] = sm[S_BIAS + f0];        bgr[j][1] = sm[S_BIAS + f0 + 1];
        bmr[j][0] = sm[S_BIAS + 128 + f0];  bmr[j][1] = sm[S_BIAS + 128 + f0 + 1];
        ber[j][0] = sm[S_BIAS + 512 + f0];  ber[j][1] = sm[S_BIAS + 512 + f0 + 1];
    }
    float4 lns4 = *(const float4*)&sm[S_BIAS + 256 + lane * 4];
    float4 lnb4 = *(const float4*)&sm[S_BIAS + 384 + lane * 4];

    asm volatile("cp.async.wait_group 0;" ::: "memory");
    asm volatile("bar.sync %0, %1;" :: "r"(barid), "r"(256) : "memory");

    int buf = 0;
    for (int t = s0; t < NT2; t += stride) {
        const int* sx = sidx + buf * 24;
        int aeB = gbase + GP_AE + buf * 896;

        // ---- prefetch yn/pc (fp32, L2) ----
        float2 yn0[2][2], yn1[2][2], pcp[2][2];
        #pragma unroll
        for (int rt = 0; rt < 2; rt++) {
            int i0 = sx[rt * MNBR + grp];
            int i1 = notpad ? sx[rt * MNBR + grp + 8] : 0;
            #pragma unroll
            for (int j = 0; j < 2; j++) {
                int f0 = wg * 16 + j * 8 + 2 * tig;
                yn0[rt][j] = *(const float2*)&g_yn[i0 * FDIM + f0];
                yn1[rt][j] = notpad ? *(const float2*)&g_yn[i1 * FDIM + f0]
                                    : make_float2(0.f, 0.f);
                pcp[rt][j] = *(const float2*)&g_pc[(t * 2 + rt) * FDIM + f0];
            }
        }

        // ---- issue next-tile staging ----
        int tn = t + stride;
        if (tn < NT2) {
            if (gtid < 24) sidx[(buf ^ 1) * 24 + gtid] = nbr_idx[tn * 24 + gtid];
            stage_ae_h(aeRaw + (uint32_t)(buf ^ 1) * 896 * 4,
                       (const char*)(g_nbrh + (size_t)tn * 576), gtid);
        }
        asm volatile("cp.async.commit_group;" ::: "memory");

        // ---- phi_e mma: fp16 k16, K=48 -> 3 steps ----
        float ce[2][2][4] = {};
        #pragma unroll
        for (int ks = 0; ks < 3; ks++) {
            int k0 = ks * 8;
            uint32_t a[2][4];
            #pragma unroll
            for (int rt = 0; rt < 2; rt++) {
                int r = rt * 16 + grp;
                a[rt][0] = smu[aeB + r * 28 + k0 + tig];
                a[rt][1] = smu[aeB + (r + 8) * 28 + k0 + tig];
                a[rt][2] = smu[aeB + r * 28 + k0 + 4 + tig];
                a[rt][3] = smu[aeB + (r + 8) * 28 + k0 + 4 + tig];
            }
            #pragma unroll
            for (int j = 0; j < 2; j++) {
                int n = wg * 16 + j * 8 + grp;
                uint32_t b[2];
                b[0] = smu[S_WE + (k0 + tig) * 133 + n];
                b[1] = smu[S_WE + (k0 + 4 + tig) * 133 + n];
                #pragma unroll
                for (int rt = 0; rt < 2; rt++)
                    mma_f16(ce[rt][j], a[rt], b);
            }
        }

        // ---- build inter tile (packed fp16) ----
        #pragma unroll
        for (int rt = 0; rt < 2; rt++) {
            int r = rt * 16 + grp;
            #pragma unroll
            for (int j = 0; j < 2; j++) {
                int kk = wg * 8 + j * 4 + tig;        // k2 index = f0/2
                smu[gbase + GP_AGM + r * 68 + kk] =
                    packh2(pcp[rt][j].x * yn0[rt][j].x * (ce[rt][j][0] + ber[j][0]),
                           pcp[rt][j].y * yn0[rt][j].y * (ce[rt][j][1] + ber[j][1]));
                if (notpad) {
                    smu[gbase + GP_AGM + (r + 8) * 68 + kk] =
                        packh2(pcp[rt][j].x * yn1[rt][j].x * (ce[rt][j][2] + ber[j][0]),
                               pcp[rt][j].y * yn1[rt][j].y * (ce[rt][j][3] + ber[j][1]));
                }
            }
        }
        asm volatile("bar.sync %0, %1;" :: "r"(barid), "r"(256) : "memory");

        // ---- gate/mag mma: fp16 k16, K=128 -> 8 steps ----
        float cg[2][2][4] = {}, cmm[2][2][4] = {};
        #pragma unroll
        for (int ks = 0; ks < 8; ks++) {
            int k0 = ks * 8;
            uint32_t a[2][4];
            #pragma unroll
            for (int rt = 0; rt < 2; rt++) {
                int r = rt * 16 + grp;
                a[rt][0] = smu[gbase + GP_AGM + r * 68 + k0 + tig];
                a[rt][1] = smu[gbase + GP_AGM + (r + 8) * 68 + k0 + tig];
                a[rt][2] = smu[gbase + GP_AGM + r * 68 + k0 + 4 + tig];
                a[rt][3] = smu[gbase + GP_AGM + (r + 8) * 68 + k0 + 4 + tig];
            }
            #pragma unroll
            for (int j = 0; j < 2; j++) {
                int n = wg * 16 + j * 8 + grp;
                uint32_t bgf[2], bmf[2];
                bgf[0] = smu[S_W + (k0 + tig) * 265 + n];
                bgf[1] = smu[S_W + (k0 + 4 + tig) * 265 + n];
                bmf[0] = smu[S_W + (k0 + tig) * 265 + 128 + n];
                bmf[1] = smu[S_W + (k0 + 4 + tig) * 265 + 128 + n];
                #pragma unroll
                for (int rt = 0; rt < 2; rt++) {
                    mma_f16(cg[rt][j], a[rt], bgf);
                    mma_f16(cmm[rt][j], a[rt], bmf);
                }
            }
        }

        // ---- activation + masked per-atom column sums ----
        #pragma unroll
        for (int rt = 0; rt < 2; rt++) {
            #pragma unroll
            for (int j = 0; j < 2; j++) {
                float p0 = act(cg[rt][j][0] + bgr[j][0], cmm[rt][j][0] + bmr[j][0]);
                float p1 = act(cg[rt][j][1] + bgr[j][1], cmm[rt][j][1] + bmr[j][1]);
                if (notpad) {
                    p0 += act(cg[rt][j][2] + bgr[j][0], cmm[rt][j][2] + bmr[j][0]);
                    p1 += act(cg[rt][j][3] + bgr[j][1], cmm[rt][j][3] + bmr[j][1]);
                }
                #pragma unroll
                for (int o = 4; o < 32; o <<= 1) {
                    p0 += __shfl_xor_sync(0xffffffffu, p0, o);
                    p1 += __shfl_xor_sync(0xffffffffu, p1, o);
                }
                if (grp == 0) {
                    int f0 = wg * 16 + j * 8 + 2 * tig;
                    sm[gbase + GP_RED + rt * 128 + f0]     = p0;
                    sm[gbase + GP_RED + rt * 128 + f0 + 1] = p1;
                }
            }
        }
        asm volatile("cp.async.wait_group 0;" ::: "memory");
        asm volatile("bar.sync %0, %1;" :: "r"(barid), "r"(256) : "memory");

        // ---- LayerNorm + residual (warps 0,1 of group) ----
        if (wg < 2) {
            float4 v = *(const float4*)&sm[gbase + GP_RED + wg * 128 + lane * 4];
            float s = v.x + v.y + v.z + v.w;
            float q = v.x*v.x + v.y*v.y + v.z*v.z + v.w*v.w;
            #pragma unroll
            for (int o = 16; o > 0; o >>= 1) {
                s += __shfl_xor_sync(0xffffffffu, s, o);
                q += __shfl_xor_sync(0xffffffffu, q, o);
            }
            float mu = s * (1.f / FDIM);
            float var = q * (1.f / FDIM) - mu * mu;
            float rstd = rsqrtf(var + 1e-6f);
            int n = t * 2 + wg;
            float4 x = *(float4*)&g_x[n * FDIM + lane * 4];
            x.x += (v.x - mu) * rstd * lns4.x + lnb4.x;
            x.y += (v.y - mu) * rstd * lns4.y + lnb4.y;
            x.z += (v.z - mu) * rstd * lns4.z + lnb4.z;
            x.w += (v.w - mu) * rstd * lns4.w + lnb4.w;
            *(float4*)&g_x[n * FDIM + lane * 4] = x;
        }
        buf ^= 1;
    }
}

// ============================================================================
// Kernel 4: readout
// ============================================================================
#define RO_WHT  0
#define RO_WO   33792
#define RO_BH   34048
#define RO_XR   34304
#define RO_RED  34432
#define RO_FLOATS 34440
#define RO_SMEM (RO_FLOATS * 4)

__global__ void k_readout(const float* __restrict__ Wh, const float* __restrict__ bh,
                          const float* __restrict__ Wout, const float* __restrict__ bout) {
    float* WhT = sm + RO_WHT;
    float* WoS = sm + RO_WO;
    float* bhS = sm + RO_BH;
    float* xr  = sm + RO_XR;
    float* red = sm + RO_RED;
    int tid = threadIdx.x;
    for (int i = tid; i < FDIM * HDIM; i += 256) {
        int k = i >> 8, j = i & 255;
        WhT[j * 132 + k] = Wh[i];
    }
    WoS[tid] = Wout[tid];
    bhS[tid] = bh[tid];
    __syncthreads();
    float b0 = bout[0];
    const float4* wp = (const float4*)(WhT + tid * 132);

    for (int n = blockIdx.x; n < N_ATOMS; n += gridDim.x) {
        if (tid < FDIM) xr[tid] = g_x[n * FDIM + tid];
        __syncthreads();
        float acc = bhS[tid];
        #pragma unroll 4
        for (int k4 = 0; k4 < FDIM / 4; k4++) {
            float4 w = wp[k4];
            float4 xv = *(const float4*)(xr + k4 * 4);
            acc = fmaf(w.x, xv.x, acc); acc = fmaf(w.y, xv.y, acc);
            acc = fmaf(w.z, xv.z, acc); acc = fmaf(w.w, xv.w, acc);
        }
        float pcontrib = softplusf(acc) * WoS[tid];
        #pragma unroll
        for (int o = 16; o > 0; o >>= 1)
            pcontrib += __shfl_xor_sync(0xffffffffu, pcontrib, o);
        if ((tid & 31) == 0) red[tid >> 5] = pcontrib;
        __syncthreads();
        if (tid == 0) {
            float ssum = 0.f;
            #pragma unroll
            for (int w8 = 0; w8 < 8; w8++) ssum += red[w8];
            g_site[n] = ssum + b0;
        }
        __syncthreads();
    }
}

// ============================================================================
// Kernel 5: per-crystal sum
// ============================================================================
__global__ void k_crystal(float* __restrict__ out) {
    __shared__ float red[8];
    int c = blockIdx.x, tid = threadIdx.x;
    float v = g_site[c * APC + tid];
    #pragma unroll
    for (int o = 16; o > 0; o >>= 1)
        v += __shfl_xor_sync(0xffffffffu, v, o);
    if ((tid & 31) == 0) red[tid >> 5] = v;
    __syncthreads();
    if (tid == 0) {
        float s = 0.f;
        #pragma unroll
        for (int i = 0; i < 8; i++) s += red[i];
        out[c] = s;
    }
}

// ============================================================================
extern "C" void kernel_launch(void* const* d_in, const int* in_sizes, int n_in,
                              void* d_out, int out_size) {
    const float* atom_fea = (const float*)d_in[0];
    const float* nbr_fea  = (const float*)d_in[1];
    const int*   nbr_idx  = (const int*)  d_in[2];
    const float* W_embed  = (const float*)d_in[3];
    const float* b_embed  = (const float*)d_in[4];
    const float* W_center = (const float*)d_in[5];
    const float* b_center = (const float*)d_in[6];
    const float* W_nbr    = (const float*)d_in[7];
    const float* b_nbr    = (const float*)d_in[8];
    const float* W_edge   = (const float*)d_in[9];
    const float* b_edge   = (const float*)d_in[10];
    const float* W_gate   = (const float*)d_in[11];
    const float* b_gate   = (const float*)d_in[12];
    const float* W_mag    = (const float*)d_in[13];
    const float* b_mag    = (const float*)d_in[14];
    const float* ln_scale = (const float*)d_in[15];
    const float* ln_bias  = (const float*)d_in[16];
    const float* W_h      = (const float*)d_in[17];
    const float* b_h      = (const float*)d_in[18];
    const float* W_out    = (const float*)d_in[19];
    const float* b_out    = (const float*)d_in[20];
    float* out = (float*)d_out;

    cudaFuncSetAttribute(k_convA,   cudaFuncAttributeMaxDynamicSharedMemorySize, A2_SMEM);
    cudaFuncSetAttribute(k_conv,    cudaFuncAttributeMaxDynamicSharedMemorySize, CV_SMEM);
    cudaFuncSetAttribute(k_readout, cudaFuncAttributeMaxDynamicSharedMemorySize, RO_SMEM);

    k_pack<<<2048, 256>>>(nbr_fea);
    k_embed<<<256, 256>>>(atom_fea, W_embed, b_embed);
    for (int l = 0; l < NCONV; l++) {
        k_convA<<<148, 256, A2_SMEM>>>(W_center + l * FDIM * FDIM, b_center + l * FDIM,
                                       W_nbr    + l * FDIM * FDIM, b_nbr    + l * FDIM);
        k_conv<<<148, CV_THREADS, CV_SMEM>>>(nbr_idx,
                                      W_gate + l * FDIM * FDIM, b_gate + l * FDIM,
                                      W_mag  + l * FDIM * FDIM, b_mag  + l * FDIM,
                                      W_edge + l * EDGE * FDIM, b_edge + l * FDIM,
                                      ln_scale + l * FDIM, ln_bias + l * FDIM);
    }
    k_readout<<<152, 256, RO_SMEM>>>(W_h, b_h, W_out, b_out);
    k_crystal<<<NCRY, 256>>>(out);
}

// round 10
// speedup vs baseline: 3.6018x; 1.0802x over previous
#include <cuda_runtime.h>
#include <cuda_fp16.h>
#include <math.h>
#include <cstdint>

#define N_ATOMS 32768
#define MNBR    12
#define PROWS   16
#define ORIG    92
#define EDGE    41
#define FDIM    128
#define HDIM    256
#define NCONV   3
#define NCRY    128
#define APC     256
#define NT2     (N_ATOMS / 2)             // 16384 atom-pair tiles
#define ATILE   (N_ATOMS / 64)            // 512 (convA tiles)

// ---- scratch ----
__device__ float    g_x [N_ATOMS * FDIM];
__device__ float    g_pc[N_ATOMS * FDIM];
__device__ float    g_yn[N_ATOMS * FDIM];
__device__ uint32_t g_nbrh[N_ATOMS * MNBR * 24];   // fp16-packed nbr_fea (k2=24)
__device__ float    g_site[N_ATOMS];

__device__ __forceinline__ float softplusf(float x) {
    return fmaxf(x, 0.f) + log1pf(expf(-fabsf(x)));
}
__device__ __forceinline__ float tf32r(float x) {
    uint32_t u;
    asm("cvt.rna.tf32.f32 %0, %1;" : "=r"(u) : "f"(x));
    return __uint_as_float(u);
}
__device__ __forceinline__ uint32_t smem_u32(const void* p) {
    uint32_t a;
    asm("{ .reg .u64 t; cvta.to.shared.u64 t, %1; cvt.u32.u64 %0, t; }" : "=r"(a) : "l"(p));
    return a;
}
__device__ __forceinline__ uint32_t packh2(float a, float b) {
    __half2 h = __floats2half2_rn(a, b);
    return *(uint32_t*)&h;
}
__device__ __forceinline__ void mma_tf32(float c[4], const uint32_t a[4], const uint32_t b[2]) {
    asm volatile("mma.sync.aligned.m16n8k8.row.col.f32.tf32.tf32.f32 "
        "{%0,%1,%2,%3}, {%4,%5,%6,%7}, {%8,%9}, {%0,%1,%2,%3};"
        : "+f"(c[0]), "+f"(c[1]), "+f"(c[2]), "+f"(c[3])
        : "r"(a[0]), "r"(a[1]), "r"(a[2]), "r"(a[3]), "r"(b[0]), "r"(b[1]));
}
__device__ __forceinline__ void mma_f16(float c[4], const uint32_t a[4], const uint32_t b[2]) {
    asm volatile("mma.sync.aligned.m16n8k16.row.col.f32.f16.f16.f32 "
        "{%0,%1,%2,%3}, {%4,%5,%6,%7}, {%8,%9}, {%0,%1,%2,%3};"
        : "+f"(c[0]), "+f"(c[1]), "+f"(c[2]), "+f"(c[3])
        : "r"(a[0]), "r"(a[1]), "r"(a[2]), "r"(a[3]), "r"(b[0]), "r"(b[1]));
}
__device__ __forceinline__ float act(float g, float m) {
    float sig = __fdividef(1.f, 1.f + __expf(-g));
    float sp  = fmaxf(m, 0.f) + __logf(1.f + __expf(-fabsf(m)));
    return sig * sp;
}

extern __shared__ float sm[];

// ============================================================================
// Kernel 0: pack nbr_fea -> fp16 k-pair layout [atom][m][24 u32]
// ============================================================================
__global__ void k_pack(const float* __restrict__ nbr_fea) {
    int total = N_ATOMS * MNBR * 24;
    for (int idx = blockIdx.x * 256 + threadIdx.x; idx < total; idx += gridDim.x * 256) {
        int row = idx / 24, c = idx - row * 24;
        int k0 = 2 * c, k1 = 2 * c + 1;
        float v0 = (k0 < EDGE) ? nbr_fea[row * EDGE + k0] : 0.f;
        float v1 = (k1 < EDGE) ? nbr_fea[row * EDGE + k1] : 0.f;
        g_nbrh[idx] = packh2(v0, v1);
    }
}

// ============================================================================
// Kernel 1: embedding
// ============================================================================
__global__ void k_embed(const float* __restrict__ atom_fea,
                        const float* __restrict__ W,
                        const float* __restrict__ b) {
    __shared__ float Ws[ORIG * FDIM];
    __shared__ float rows[2 * ORIG];
    int tid = threadIdx.x;
    for (int i = tid; i < ORIG * FDIM; i += 256) Ws[i] = W[i];
    __syncthreads();
    int base = blockIdx.x * 128;
    int half = tid >> 7, f = tid & 127;
    for (int it = 0; it < 64; ++it) {
        int r0 = base + it * 2;
        for (int j = tid; j < 2 * ORIG; j += 256)
            rows[j] = atom_fea[r0 * ORIG + j];
        __syncthreads();
        float acc = b[f];
        const float* rp = rows + half * ORIG;
        #pragma unroll 4
        for (int e = 0; e < ORIG; e++)
            acc = fmaf(rp[e], Ws[e * FDIM + f], acc);
        g_x[(r0 + half) * FDIM + f] = acc;
        __syncthreads();
    }
}

// ============================================================================
// Kernel 2: k_convA — tf32 mma GEMM (pitch 265)
// ============================================================================
#define A2_W    0
#define A2_A    33920
#define A2_BIAS 42368
#define A2_TOT  42624
#define A2_SMEM (A2_TOT * 4)

__global__ void __launch_bounds__(256, 1)
k_convA(const float* __restrict__ Wc, const float* __restrict__ bc,
        const float* __restrict__ Wn, const float* __restrict__ bn) {
    int tid = threadIdx.x, wid = tid >> 5, lane = tid & 31;
    uint32_t* smu = (uint32_t*)sm;
    for (int i = tid; i < FDIM * FDIM; i += 256) {
        int k = i >> 7, n = i & 127;
        smu[A2_W + k * 265 + n]       = __float_as_uint(tf32r(Wc[i]));
        smu[A2_W + k * 265 + 128 + n] = __float_as_uint(tf32r(Wn[i]));
    }
    if (tid < 128) { sm[A2_BIAS + tid] = bc[tid]; sm[A2_BIAS + 128 + tid] = bn[tid]; }
    __syncthreads();

    int wr = wid >> 2, wc = wid & 3;
    int tig = lane & 3, grp = lane >> 2;
    float bcr[4][2], bnr[4][2];
    #pragma unroll
    for (int j = 0; j < 4; j++) {
        int f0 = wc * 32 + j * 8 + 2 * tig;
        bcr[j][0] = sm[A2_BIAS + f0];       bcr[j][1] = sm[A2_BIAS + f0 + 1];
        bnr[j][0] = sm[A2_BIAS + 128 + f0]; bnr[j][1] = sm[A2_BIAS + 128 + f0 + 1];
    }

    for (int t = blockIdx.x; t < ATILE; t += gridDim.x) {
        #pragma unroll
        for (int q = 0; q < 8; q++) {
            int ch = tid + q * 256;
            int r = ch >> 5, c4 = ch & 31;
            float4 v = *(const float4*)&g_x[(t * 64 + r) * FDIM + c4 * 4];
            sm[A2_A + r * 132 + c4 * 4 + 0] = tf32r(v.x);
            sm[A2_A + r * 132 + c4 * 4 + 1] = tf32r(v.y);
            sm[A2_A + r * 132 + c4 * 4 + 2] = tf32r(v.z);
            sm[A2_A + r * 132 + c4 * 4 + 3] = tf32r(v.w);
        }
        __syncthreads();

        float cpc[2][4][4] = {}, cyn[2][4][4] = {};
        #pragma unroll
        for (int ks = 0; ks < 16; ks++) {
            int k0 = ks * 8;
            uint32_t a[2][4];
            #pragma unroll
            for (int rt = 0; rt < 2; rt++) {
                int r = wr * 32 + rt * 16 + grp;
                a[rt][0] = smu[A2_A + r * 132 + k0 + tig];
                a[rt][1] = smu[A2_A + (r + 8) * 132 + k0 + tig];
                a[rt][2] = smu[A2_A + r * 132 + k0 + 4 + tig];
                a[rt][3] = smu[A2_A + (r + 8) * 132 + k0 + 4 + tig];
            }
            #pragma unroll
            for (int j = 0; j < 4; j++) {
                int n = wc * 32 + j * 8 + grp;
                uint32_t bcf[2], bnf[2];
                bcf[0] = smu[A2_W + (k0 + tig) * 265 + n];
                bcf[1] = smu[A2_W + (k0 + 4 + tig) * 265 + n];
                bnf[0] = smu[A2_W + (k0 + tig) * 265 + 128 + n];
                bnf[1] = smu[A2_W + (k0 + 4 + tig) * 265 + 128 + n];
                #pragma unroll
                for (int rt = 0; rt < 2; rt++) {
                    mma_tf32(cpc[rt][j], a[rt], bcf);
                    mma_tf32(cyn[rt][j], a[rt], bnf);
                }
            }
        }

        #pragma unroll
        for (int rt = 0; rt < 2; rt++) {
            int r0 = t * 64 + wr * 32 + rt * 16 + grp;
            #pragma unroll
            for (int j = 0; j < 4; j++) {
                int f0 = wc * 32 + j * 8 + 2 * tig;
                float2 v;
                v.x = cpc[rt][j][0] + bcr[j][0]; v.y = cpc[rt][j][1] + bcr[j][1];
                *(float2*)&g_pc[r0 * FDIM + f0] = v;
                v.x = cpc[rt][j][2] + bcr[j][0]; v.y = cpc[rt][j][3] + bcr[j][1];
                *(float2*)&g_pc[(r0 + 8) * FDIM + f0] = v;
                v.x = cyn[rt][j][0] + bnr[j][0]; v.y = cyn[rt][j][1] + bnr[j][1];
                *(float2*)&g_yn[r0 * FDIM + f0] = v;
                v.x = cyn[rt][j][2] + bnr[j][0]; v.y = cyn[rt][j][3] + bnr[j][1];
                *(float2*)&g_yn[(r0 + 8) * FDIM + f0] = v;
            }
        }
        __syncthreads();
    }
}

// ============================================================================
// Kernel 3: k_conv — fused conv layer, fp16 mma, 512 threads, 2 pipelines.
// yn/pc gather staged via cp.async ONE tile ahead (smem double buffer);
// sidx/AE staged TWO tiles ahead (triple buffer). Two commit groups per
// iteration; wait_group 1 leaves the 2-ahead group in flight.
// ============================================================================
#define S_W     0          // 16960 u32
#define S_WE    16960      //  3192
#define S_BIAS  20152      //   640
#define S_GRP   20792
#define GP_AGM  0          // 32x68            = 2176
#define GP_AE   2176       // 3 x 896          = 2688
#define GP_YN   4864       // 2 x (26x132)     = 6864
#define GP_RED  11728      //  256
#define GP_IDX  11984      // 3 x 24 ints (pad 96)
#define GRPSZ   12080
#define S_TOT   (S_GRP + 2 * GRPSZ)     // 44952 words = 179.8 KB
#define CV_SMEM (S_TOT * 4)
#define CV_THREADS 512

__device__ __forceinline__ void stage_ae_h(uint32_t dstbase, const char* __restrict__ src,
                                           int gtid) {
    if (gtid < 144) {                              // 144 chunks of 16B
        int a = gtid / 72, rem = gtid - a * 72;
        int m = rem / 6, c = rem - m * 6;
        uint32_t d = dstbase + (uint32_t)((a * PROWS + m) * 28 + c * 4) * 4;
        asm volatile("cp.async.ca.shared.global [%0], [%1], 16;"
                     :: "r"(d), "l"(src + (size_t)gtid * 16) : "memory");
    }
}

// stage 24 yn rows (gathered) + 2 pc rows into [26][132] fp32 smem tile
__device__ __forceinline__ void stage_yn(uint32_t dstbase, const int* __restrict__ sx,
                                         int tn, int gtid) {
    #pragma unroll
    for (int q = 0; q < 4; q++) {
        int i = gtid + q * 256;                    // 832 chunks of 16B
        if (i < 832) {
            int row = i >> 5, c = i & 31;
            const float* src = (row < 24)
                ? g_yn + (size_t)sx[row] * FDIM + c * 4
                : g_pc + ((size_t)tn * 2 + (row - 24)) * FDIM + c * 4;
            uint32_t d = dstbase + (uint32_t)(row * 132 + c * 4) * 4;
            asm volatile("cp.async.ca.shared.global [%0], [%1], 16;"
                         :: "r"(d), "l"(src) : "memory");
        }
    }
}

__global__ void __launch_bounds__(CV_THREADS, 1)
k_conv(const int* __restrict__ nbr_idx,
       const float* __restrict__ Wg, const float* __restrict__ bg,
       const float* __restrict__ Wm, const float* __restrict__ bm,
       const float* __restrict__ We, const float* __restrict__ be,
       const float* __restrict__ lns, const float* __restrict__ lnb) {
    int tid = threadIdx.x, wid = tid >> 5, lane = tid & 31;
    int half = wid >> 3, wg = wid & 7, gtid = tid & 255;
    uint32_t* smu = (uint32_t*)sm;

    // ---- pack resident weights to fp16 k-pairs ----
    for (int i = tid; i < 64 * 256; i += CV_THREADS) {
        int k2 = i >> 8, n = i & 255;
        const float* W = (n < 128) ? Wg : Wm;
        int nn = n & 127;
        smu[S_W + k2 * 265 + n] = packh2(W[(2 * k2) * FDIM + nn], W[(2 * k2 + 1) * FDIM + nn]);
    }
    for (int i = tid; i < 24 * 128; i += CV_THREADS) {
        int k2 = i >> 7, n = i & 127;
        float v0 = (2 * k2     < EDGE) ? We[(2 * k2) * FDIM + n]     : 0.f;
        float v1 = (2 * k2 + 1 < EDGE) ? We[(2 * k2 + 1) * FDIM + n] : 0.f;
        smu[S_WE + k2 * 133 + n] = packh2(v0, v1);
    }
    for (int i = tid; i < 2 * GRPSZ; i += CV_THREADS) sm[S_GRP + i] = 0.f;
    if (tid < FDIM) {
        sm[S_BIAS + tid]       = bg[tid];
        sm[S_BIAS + 128 + tid] = bm[tid];
        sm[S_BIAS + 256 + tid] = lns[tid];
        sm[S_BIAS + 384 + tid] = lnb[tid];
        sm[S_BIAS + 512 + tid] = be[tid];
    }

    int gbase = S_GRP + half * GRPSZ;
    int* sidx3 = (int*)(sm + gbase + GP_IDX);
    uint32_t aeRaw = smem_u32(sm + gbase + GP_AE);
    uint32_t ynRaw = smem_u32(sm + gbase + GP_YN);
    int tig = lane & 3, grp = lane >> 2;
    bool notpad = (grp < 4);
    int barid = half + 1;

    int stride = 2 * gridDim.x;
    int s0 = blockIdx.x * 2 + half;

    __syncthreads();

    // ---- prologue: sidx buf0/buf1, AE buf0/buf1, then YN buf0 ----
    if (gtid < 24) {
        sidx3[gtid] = nbr_idx[s0 * 24 + gtid];
        if (s0 + stride < NT2)
            sidx3[24 + gtid] = nbr_idx[(s0 + stride) * 24 + gtid];
    }
    stage_ae_h(aeRaw, (const char*)(g_nbrh + (size_t)s0 * 576), gtid);
    if (s0 + stride < NT2)
        stage_ae_h(aeRaw + 896u * 4, (const char*)(g_nbrh + (size_t)(s0 + stride) * 576), gtid);
    asm volatile("cp.async.commit_group;" ::: "memory");
    asm volatile("cp.async.wait_group 0;" ::: "memory");
    asm volatile("bar.sync %0, %1;" :: "r"(barid), "r"(256) : "memory");

    stage_yn(ynRaw, sidx3, s0, gtid);
    asm volatile("cp.async.commit_group;" ::: "memory");
    asm volatile("cp.async.wait_group 0;" ::: "memory");
    asm volatile("bar.sync %0, %1;" :: "r"(barid), "r"(256) : "memory");

    float bgr[2][2], bmr[2][2], ber[2][2];
    #pragma unroll
    for (int j = 0; j < 2; j++) {
        int f0 = wg * 16 + j * 8 + 2 * tig;
        bgr[j][0] = sm[S_BIAS + f0];        bgr[j][1] = sm[S_BIAS + f0 + 1];
        bmr[j][0] = sm[S_BIAS + 128 + f0];  bmr[j][1] = sm[S_BIAS + 128 + f0 + 1];
        ber[j][0] = sm[S_BIAS + 512 + f0];  ber[j][1] = sm[S_BIAS + 512 + f0 + 1];
    }
    float4 lns4 = *(const float4*)&sm[S_BIAS + 256 + lane * 4];
    float4 lnb4 = *(const float4*)&sm[S_BIAS + 384 + lane * 4];

    int b2 = 0;      // yn consume buffer
    int b3 = 0;      // ae/sidx consume buffer
    for (int t = s0; t < NT2; t += stride) {
        int aeB = gbase + GP_AE + b3 * 896;
        int ynB = gbase + GP_YN + b2 * 3432;

        // ---- commit A: stage yn/pc for t+stride (uses sidx buf (b3+1)%3) ----
        if (t + stride < NT2)
            stage_yn(ynRaw + (uint32_t)(b2 ^ 1) * 3432 * 4,
                     sidx3 + ((b3 + 1) % 3) * 24, t + stride, gtid);
        asm volatile("cp.async.commit_group;" ::: "memory");

        // ---- commit B: stage sidx/AE for t+2*stride ----
        int t2 = t + 2 * stride;
        if (t2 < NT2) {
            int ib = (b3 + 2) % 3;
            if (gtid < 24) sidx3[ib * 24 + gtid] = nbr_idx[t2 * 24 + gtid];
            stage_ae_h(aeRaw + (uint32_t)ib * 896 * 4,
                       (const char*)(g_nbrh + (size_t)t2 * 576), gtid);
        }
        asm volatile("cp.async.commit_group;" ::: "memory");

        // ---- phi_e mma: fp16 k16, K=48 -> 3 steps ----
        float ce[2][2][4] = {};
        #pragma unroll
        for (int ks = 0; ks < 3; ks++) {
            int k0 = ks * 8;
            uint32_t a[2][4];
            #pragma unroll
            for (int rt = 0; rt < 2; rt++) {
                int r = rt * 16 + grp;
                a[rt][0] = smu[aeB + r * 28 + k0 + tig];
                a[rt][1] = smu[aeB + (r + 8) * 28 + k0 + tig];
                a[rt][2] = smu[aeB + r * 28 + k0 + 4 + tig];
                a[rt][3] = smu[aeB + (r + 8) * 28 + k0 + 4 + tig];
            }
            #pragma unroll
            for (int j = 0; j < 2; j++) {
                int n = wg * 16 + j * 8 + grp;
                uint32_t b[2];
                b[0] = smu[S_WE + (k0 + tig) * 133 + n];
                b[1] = smu[S_WE + (k0 + 4 + tig) * 133 + n];
                #pragma unroll
                for (int rt = 0; rt < 2; rt++)
                    mma_f16(ce[rt][j], a[rt], b);
            }
        }

        // ---- build inter tile (yn/pc from smem) ----
        #pragma unroll
        for (int rt = 0; rt < 2; rt++) {
            int r = rt * 16 + grp;
            int yr0 = ynB + (rt * 12 + grp) * 132;
            int pr  = ynB + (24 + rt) * 132;
            #pragma unroll
            for (int j = 0; j < 2; j++) {
                int f0 = wg * 16 + j * 8 + 2 * tig;
                int kk = wg * 8 + j * 4 + tig;
                float2 pc2 = *(const float2*)&sm[pr + f0];
                float2 y0  = *(const float2*)&sm[yr0 + f0];
                smu[gbase + GP_AGM + r * 68 + kk] =
                    packh2(pc2.x * y0.x * (ce[rt][j][0] + ber[j][0]),
                           pc2.y * y0.y * (ce[rt][j][1] + ber[j][1]));
                if (notpad) {
                    float2 y1 = *(const float2*)&sm[yr0 + 8 * 132 + f0];
                    smu[gbase + GP_AGM + (r + 8) * 68 + kk] =
                        packh2(pc2.x * y1.x * (ce[rt][j][2] + ber[j][0]),
                               pc2.y * y1.y * (ce[rt][j][3] + ber[j][1]));
                }
            }
        }
        asm volatile("bar.sync %0, %1;" :: "r"(barid), "r"(256) : "memory");

        // ---- gate/mag mma: fp16 k16, K=128 -> 8 steps ----
        float cg[2][2][4] = {}, cmm[2][2][4] = {};
        #pragma unroll
        for (int ks = 0; ks < 8; ks++) {
            int k0 = ks * 8;
            uint32_t a[2][4];
            #pragma unroll
            for (int rt = 0; rt < 2; rt++) {
                int r = rt * 16 + grp;
                a[rt][0] = smu[gbase + GP_AGM + r * 68 + k0 + tig];
                a[rt][1] = smu[gbase + GP_AGM + (r + 8) * 68 + k0 + tig];
                a[rt][2] = smu[gbase + GP_AGM + r * 68 + k0 + 4 + tig];
                a[rt][3] = smu[gbase + GP_AGM + (r + 8) * 68 + k0 + 4 + tig];
            }
            #pragma unroll
            for (int j = 0; j < 2; j++) {
                int n = wg * 16 + j * 8 + grp;
                uint32_t bgf[2], bmf[2];
                bgf[0] = smu[S_W + (k0 + tig) * 265 + n];
                bgf[1] = smu[S_W + (k0 + 4 + tig) * 265 + n];
                bmf[0] = smu[S_W + (k0 + tig) * 265 + 128 + n];
                bmf[1] = smu[S_W + (k0 + 4 + tig) * 265 + 128 + n];
                #pragma unroll
                for (int rt = 0; rt < 2; rt++) {
                    mma_f16(cg[rt][j], a[rt], bgf);
                    mma_f16(cmm[rt][j], a[rt], bmf);
                }
            }
        }

        // ---- activation + masked per-atom column sums ----
        #pragma unroll
        for (int rt = 0; rt < 2; rt++) {
            #pragma unroll
            for (int j = 0; j < 2; j++) {
                float p0 = act(cg[rt][j][0] + bgr[j][0], cmm[rt][j][0] + bmr[j][0]);
                float p1 = act(cg[rt][j][1] + bgr[j][1], cmm[rt][j][1] + bmr[j][1]);
                if (notpad) {
                    p0 += act(cg[rt][j][2] + bgr[j][0], cmm[rt][j][2] + bmr[j][0]);
                    p1 += act(cg[rt][j][3] + bgr[j][1], cmm[rt][j][3] + bmr[j][1]);
                }
                #pragma unroll
                for (int o = 4; o < 32; o <<= 1) {
                    p0 += __shfl_xor_sync(0xffffffffu, p0, o);
                    p1 += __shfl_xor_sync(0xffffffffu, p1, o);
                }
                if (grp == 0) {
                    int f0 = wg * 16 + j * 8 + 2 * tig;
                    sm[gbase + GP_RED + rt * 128 + f0]     = p0;
                    sm[gbase + GP_RED + rt * 128 + f0 + 1] = p1;
                }
            }
        }
        // drain commit A (yn for next iter) + previous commit B; keep this B in flight
        asm volatile("cp.async.wait_group 1;" ::: "memory");
        asm volatile("bar.sync %0, %1;" :: "r"(barid), "r"(256) : "memory");

        // ---- LayerNorm + residual (warps 0,1 of group) ----
        if (wg < 2) {
            float4 v = *(const float4*)&sm[gbase + GP_RED + wg * 128 + lane * 4];
            float s = v.x + v.y + v.z + v.w;
            float q = v.x*v.x + v.y*v.y + v.z*v.z + v.w*v.w;
            #pragma unroll
            for (int o = 16; o > 0; o >>= 1) {
                s += __shfl_xor_sync(0xffffffffu, s, o);
                q += __shfl_xor_sync(0xffffffffu, q, o);
            }
            float mu = s * (1.f / FDIM);
            float var = q * (1.f / FDIM) - mu * mu;
            float rstd = rsqrtf(var + 1e-6f);
            int n = t * 2 + wg;
            float4 x = *(float4*)&g_x[n * FDIM + lane * 4];
            x.x += (v.x - mu) * rstd * lns4.x + lnb4.x;
            x.y += (v.y - mu) * rstd * lns4.y + lnb4.y;
            x.z += (v.z - mu) * rstd * lns4.z + lnb4.z;
            x.w += (v.w - mu) * rstd * lns4.w + lnb4.w;
            *(float4*)&g_x[n * FDIM + lane * 4] = x;
        }
        b2 ^= 1;
        b3 = (b3 + 1) % 3;
    }
}

// ============================================================================
// Kernel 4: readout
// ============================================================================
#define RO_WHT  0
#define RO_WO   33792
#define RO_BH   34048
#define RO_XR   34304
#define RO_RED  34432
#define RO_FLOATS 34440
#define RO_SMEM (RO_FLOATS * 4)

__global__ void k_readout(const float* __restrict__ Wh, const float* __restrict__ bh,
                          const float* __restrict__ Wout, const float* __restrict__ bout) {
    float* WhT = sm + RO_WHT;
    float* WoS = sm + RO_WO;
    float* bhS = sm + RO_BH;
    float* xr  = sm + RO_XR;
    float* red = sm + RO_RED;
    int tid = threadIdx.x;
    for (int i = tid; i < FDIM * HDIM; i += 256) {
        int k = i >> 8, j = i & 255;
        WhT[j * 132 + k] = Wh[i];
    }
    WoS[tid] = Wout[tid];
    bhS[tid] = bh[tid];
    __syncthreads();
    float b0 = bout[0];
    const float4* wp = (const float4*)(WhT + tid * 132);

    for (int n = blockIdx.x; n < N_ATOMS; n += gridDim.x) {
        if (tid < FDIM) xr[tid] = g_x[n * FDIM + tid];
        __syncthreads();
        float acc = bhS[tid];
        #pragma unroll 4
        for (int k4 = 0; k4 < FDIM / 4; k4++) {
            float4 w = wp[k4];
            float4 xv = *(const float4*)(xr + k4 * 4);
            acc = fmaf(w.x, xv.x, acc); acc = fmaf(w.y, xv.y, acc);
            acc = fmaf(w.z, xv.z, acc); acc = fmaf(w.w, xv.w, acc);
        }
        float pcontrib = softplusf(acc) * WoS[tid];
        #pragma unroll
        for (int o = 16; o > 0; o >>= 1)
            pcontrib += __shfl_xor_sync(0xffffffffu, pcontrib, o);
        if ((tid & 31) == 0) red[tid >> 5] = pcontrib;
        __syncthreads();
        if (tid == 0) {
            float ssum = 0.f;
            #pragma unroll
            for (int w8 = 0; w8 < 8; w8++) ssum += red[w8];
            g_site[n] = ssum + b0;
        }
        __syncthreads();
    }
}

// ============================================================================
// Kernel 5: per-crystal sum
// ============================================================================
__global__ void k_crystal(float* __restrict__ out) {
    __shared__ float red[8];
    int c = blockIdx.x, tid = threadIdx.x;
    float v = g_site[c * APC + tid];
    #pragma unroll
    for (int o = 16; o > 0; o >>= 1)
        v += __shfl_xor_sync(0xffffffffu, v, o);
    if ((tid & 31) == 0) red[tid >> 5] = v;
    __syncthreads();
    if (tid == 0) {
        float s = 0.f;
        #pragma unroll
        for (int i = 0; i < 8; i++) s += red[i];
        out[c] = s;
    }
}

// ============================================================================
extern "C" void kernel_launch(void* const* d_in, const int* in_sizes, int n_in,
                              void* d_out, int out_size) {
    const float* atom_fea = (const float*)d_in[0];
    const float* nbr_fea  = (const float*)d_in[1];
    const int*   nbr_idx  = (const int*)  d_in[2];
    const float* W_embed  = (const float*)d_in[3];
    const float* b_embed  = (const float*)d_in[4];
    const float* W_center = (const float*)d_in[5];
    const float* b_center = (const float*)d_in[6];
    const float* W_nbr    = (const float*)d_in[7];
    const float* b_nbr    = (const float*)d_in[8];
    const float* W_edge   = (const float*)d_in[9];
    const float* b_edge   = (const float*)d_in[10];
    const float* W_gate   = (const float*)d_in[11];
    const float* b_gate   = (const float*)d_in[12];
    const float* W_mag    = (const float*)d_in[13];
    const float* b_mag    = (const float*)d_in[14];
    const float* ln_scale = (const float*)d_in[15];
    const float* ln_bias  = (const float*)d_in[16];
    const float* W_h      = (const float*)d_in[17];
    const float* b_h      = (const float*)d_in[18];
    const float* W_out    = (const float*)d_in[19];
    const float* b_out    = (const float*)d_in[20];
    float* out = (float*)d_out;

    cudaFuncSetAttribute(k_convA,   cudaFuncAttributeMaxDynamicSharedMemorySize, A2_SMEM);
    cudaFuncSetAttribute(k_conv,    cudaFuncAttributeMaxDynamicSharedMemorySize, CV_SMEM);
    cudaFuncSetAttribute(k_readout, cudaFuncAttributeMaxDynamicSharedMemorySize, RO_SMEM);

    k_pack<<<2048, 256>>>(nbr_fea);
    k_embed<<<256, 256>>>(atom_fea, W_embed, b_embed);
    for (int l = 0; l < NCONV; l++) {
        k_convA<<<148, 256, A2_SMEM>>>(W_center + l * FDIM * FDIM, b_center + l * FDIM,
                                       W_nbr    + l * FDIM * FDIM, b_nbr    + l * FDIM);
        k_conv<<<148, CV_THREADS, CV_SMEM>>>(nbr_idx,
                                      W_gate + l * FDIM * FDIM, b_gate + l * FDIM,
                                      W_mag  + l * FDIM * FDIM, b_mag  + l * FDIM,
                                      W_edge + l * EDGE * FDIM, b_edge + l * FDIM,
                                      ln_scale + l * FDIM, ln_bias + l * FDIM);
    }
    k_readout<<<152, 256, RO_SMEM>>>(W_h, b_h, W_out, b_out);
    k_crystal<<<NCRY, 256>>>(out);
}

// round 11
// speedup vs baseline: 3.7140x; 1.0311x over previous
#include <cuda_runtime.h>
#include <cuda_fp16.h>
#include <math.h>
#include <cstdint>

#define N_ATOMS 32768
#define MNBR    12
#define PROWS   16
#define ORIG    92
#define EDGE    41
#define FDIM    128
#define HDIM    256
#define NCONV   3
#define NCRY    128
#define APC     256
#define NT2     (N_ATOMS / 2)             // 16384 atom-pair tiles
#define ATILE   (N_ATOMS / 64)            // 512 (convA tiles)

// ---- scratch ----
__device__ float    g_x [N_ATOMS * FDIM];
__device__ float    g_pc[N_ATOMS * FDIM];
__device__ float    g_yn[N_ATOMS * FDIM];
__device__ uint32_t g_nbrh[NT2 * 768];     // fp16 edge features, fragment order, 50.3 MB
__device__ float    g_site[N_ATOMS];

__device__ __forceinline__ float softplusf(float x) {
    return fmaxf(x, 0.f) + log1pf(expf(-fabsf(x)));
}
__device__ __forceinline__ float tf32r(float x) {
    uint32_t u;
    asm("cvt.rna.tf32.f32 %0, %1;" : "=r"(u) : "f"(x));
    return __uint_as_float(u);
}
__device__ __forceinline__ uint32_t smem_u32(const void* p) {
    uint32_t a;
    asm("{ .reg .u64 t; cvta.to.shared.u64 t, %1; cvt.u32.u64 %0, t; }" : "=r"(a) : "l"(p));
    return a;
}
__device__ __forceinline__ uint32_t packh2(float a, float b) {
    __half2 h = __floats2half2_rn(a, b);
    return *(uint32_t*)&h;
}
__device__ __forceinline__ void mma_tf32(float c[4], const uint32_t a[4], const uint32_t b[2]) {
    asm volatile("mma.sync.aligned.m16n8k8.row.col.f32.tf32.tf32.f32 "
        "{%0,%1,%2,%3}, {%4,%5,%6,%7}, {%8,%9}, {%0,%1,%2,%3};"
        : "+f"(c[0]), "+f"(c[1]), "+f"(c[2]), "+f"(c[3])
        : "r"(a[0]), "r"(a[1]), "r"(a[2]), "r"(a[3]), "r"(b[0]), "r"(b[1]));
}
__device__ __forceinline__ void mma_f16(float c[4], uint32_t a0, uint32_t a1,
                                        uint32_t a2, uint32_t a3,
                                        uint32_t b0, uint32_t b1) {
    asm volatile("mma.sync.aligned.m16n8k16.row.col.f32.f16.f16.f32 "
        "{%0,%1,%2,%3}, {%4,%5,%6,%7}, {%8,%9}, {%0,%1,%2,%3};"
        : "+f"(c[0]), "+f"(c[1]), "+f"(c[2]), "+f"(c[3])
        : "r"(a0), "r"(a1), "r"(a2), "r"(a3), "r"(b0), "r"(b1));
}
__device__ __forceinline__ float act(float g, float m) {
    float sig = __fdividef(1.f, 1.f + __expf(-g));
    float sp  = fmaxf(m, 0.f) + __logf(1.f + __expf(-fabsf(m)));
    return sig * sp;
}

extern __shared__ float sm[];

// ============================================================================
// Kernel 0: pack nbr_fea -> fp16 FRAGMENT-ORDER per 2-atom tile (768 u32):
//   f = ((rt*3+ks)*32 + lane)*4 + slot*2 + rowbit
//   lane = grp*4+tig ; m = grp + rowbit*8 ; k2 = ks*8 + slot*4 + tig
// ============================================================================
__global__ void k_pack(const float* __restrict__ nbr_fea) {
    int total = NT2 * 768;
    for (int idx = blockIdx.x * 256 + threadIdx.x; idx < total; idx += gridDim.x * 256) {
        int s = idx / 768, f = idx - s * 768;
        int c = f & 3, q = f >> 2;
        int lane = q & 31, rks = q >> 5;
        int rt = rks / 3, ks = rks - rt * 3;
        int tig = lane & 3, grp = lane >> 2;
        int slot = c >> 1, rowbit = c & 1;
        int m = grp + rowbit * 8;
        int k2 = ks * 8 + slot * 4 + tig;
        float v0 = 0.f, v1 = 0.f;
        if (m < MNBR) {
            size_t base = ((size_t)(s * 2 + rt) * MNBR + m) * EDGE;
            if (2 * k2     < EDGE) v0 = nbr_fea[base + 2 * k2];
            if (2 * k2 + 1 < EDGE) v1 = nbr_fea[base + 2 * k2 + 1];
        }
        g_nbrh[idx] = packh2(v0, v1);
    }
}

// ============================================================================
// Kernel 1: embedding
// ============================================================================
__global__ void k_embed(const float* __restrict__ atom_fea,
                        const float* __restrict__ W,
                        const float* __restrict__ b) {
    __shared__ float Ws[ORIG * FDIM];
    __shared__ float rows[2 * ORIG];
    int tid = threadIdx.x;
    for (int i = tid; i < ORIG * FDIM; i += 256) Ws[i] = W[i];
    __syncthreads();
    int base = blockIdx.x * 128;
    int half = tid >> 7, f = tid & 127;
    for (int it = 0; it < 64; ++it) {
        int r0 = base + it * 2;
        for (int j = tid; j < 2 * ORIG; j += 256)
            rows[j] = atom_fea[r0 * ORIG + j];
        __syncthreads();
        float acc = b[f];
        const float* rp = rows + half * ORIG;
        #pragma unroll 4
        for (int e = 0; e < ORIG; e++)
            acc = fmaf(rp[e], Ws[e * FDIM + f], acc);
        g_x[(r0 + half) * FDIM + f] = acc;
        __syncthreads();
    }
}

// ============================================================================
// Kernel 2: k_convA — tf32 mma GEMM (pitch 265)
// ============================================================================
#define A2_W    0
#define A2_A    33920
#define A2_BIAS 42368
#define A2_TOT  42624
#define A2_SMEM (A2_TOT * 4)

__global__ void __launch_bounds__(256, 1)
k_convA(const float* __restrict__ Wc, const float* __restrict__ bc,
        const float* __restrict__ Wn, const float* __restrict__ bn) {
    int tid = threadIdx.x, wid = tid >> 5, lane = tid & 31;
    uint32_t* smu = (uint32_t*)sm;
    for (int i = tid; i < FDIM * FDIM; i += 256) {
        int k = i >> 7, n = i & 127;
        smu[A2_W + k * 265 + n]       = __float_as_uint(tf32r(Wc[i]));
        smu[A2_W + k * 265 + 128 + n] = __float_as_uint(tf32r(Wn[i]));
    }
    if (tid < 128) { sm[A2_BIAS + tid] = bc[tid]; sm[A2_BIAS + 128 + tid] = bn[tid]; }
    __syncthreads();

    int wr = wid >> 2, wc = wid & 3;
    int tig = lane & 3, grp = lane >> 2;
    float bcr[4][2], bnr[4][2];
    #pragma unroll
    for (int j = 0; j < 4; j++) {
        int f0 = wc * 32 + j * 8 + 2 * tig;
        bcr[j][0] = sm[A2_BIAS + f0];       bcr[j][1] = sm[A2_BIAS + f0 + 1];
        bnr[j][0] = sm[A2_BIAS + 128 + f0]; bnr[j][1] = sm[A2_BIAS + 128 + f0 + 1];
    }

    for (int t = blockIdx.x; t < ATILE; t += gridDim.x) {
        #pragma unroll
        for (int q = 0; q < 8; q++) {
            int ch = tid + q * 256;
            int r = ch >> 5, c4 = ch & 31;
            float4 v = *(const float4*)&g_x[(t * 64 + r) * FDIM + c4 * 4];
            sm[A2_A + r * 132 + c4 * 4 + 0] = tf32r(v.x);
            sm[A2_A + r * 132 + c4 * 4 + 1] = tf32r(v.y);
            sm[A2_A + r * 132 + c4 * 4 + 2] = tf32r(v.z);
            sm[A2_A + r * 132 + c4 * 4 + 3] = tf32r(v.w);
        }
        __syncthreads();

        float cpc[2][4][4] = {}, cyn[2][4][4] = {};
        #pragma unroll
        for (int ks = 0; ks < 16; ks++) {
            int k0 = ks * 8;
            uint32_t a[2][4];
            #pragma unroll
            for (int rt = 0; rt < 2; rt++) {
                int r = wr * 32 + rt * 16 + grp;
                a[rt][0] = smu[A2_A + r * 132 + k0 + tig];
                a[rt][1] = smu[A2_A + (r + 8) * 132 + k0 + tig];
                a[rt][2] = smu[A2_A + r * 132 + k0 + 4 + tig];
                a[rt][3] = smu[A2_A + (r + 8) * 132 + k0 + 4 + tig];
            }
            #pragma unroll
            for (int j = 0; j < 4; j++) {
                int n = wc * 32 + j * 8 + grp;
                uint32_t bcf[2], bnf[2];
                bcf[0] = smu[A2_W + (k0 + tig) * 265 + n];
                bcf[1] = smu[A2_W + (k0 + 4 + tig) * 265 + n];
                bnf[0] = smu[A2_W + (k0 + tig) * 265 + 128 + n];
                bnf[1] = smu[A2_W + (k0 + 4 + tig) * 265 + 128 + n];
                #pragma unroll
                for (int rt = 0; rt < 2; rt++) {
                    mma_tf32(cpc[rt][j], a[rt], bcf);
                    mma_tf32(cyn[rt][j], a[rt], bnf);
                }
            }
        }

        #pragma unroll
        for (int rt = 0; rt < 2; rt++) {
            int r0 = t * 64 + wr * 32 + rt * 16 + grp;
            #pragma unroll
            for (int j = 0; j < 4; j++) {
                int f0 = wc * 32 + j * 8 + 2 * tig;
                float2 v;
                v.x = cpc[rt][j][0] + bcr[j][0]; v.y = cpc[rt][j][1] + bcr[j][1];
                *(float2*)&g_pc[r0 * FDIM + f0] = v;
                v.x = cpc[rt][j][2] + bcr[j][0]; v.y = cpc[rt][j][3] + bcr[j][1];
                *(float2*)&g_pc[(r0 + 8) * FDIM + f0] = v;
                v.x = cyn[rt][j][0] + bnr[j][0]; v.y = cyn[rt][j][1] + bnr[j][1];
                *(float2*)&g_yn[r0 * FDIM + f0] = v;
                v.x = cyn[rt][j][2] + bnr[j][0]; v.y = cyn[rt][j][3] + bnr[j][1];
                *(float2*)&g_yn[(r0 + 8) * FDIM + f0] = v;
            }
        }
        __syncthreads();
    }
}

// ============================================================================
// Kernel 3: k_conv — fused conv layer, fp16 mma, fragment-ordered operands.
//   S_W  [wg][ks(8)][j(2)][lane]{bg0,bg1,bm0,bm1}          16384 u32
//   S_WE [wg][ks(3)][j(2)][lane]{b0,b1}                     3072 u32
//   AGM  [rt(2)][ks(8)][lane]{a0,a1,a2,a3}                  2048 u32/tile
//   AE   [rt(2)][ks(3)][lane]{a0,a1,a2,a3}                   768 u32/tile
// ============================================================================
#define S_W     0          // 16384
#define S_WE    16384      //  3072
#define S_BIAS  19456      //   640
#define S_GRP   20096
#define GP_AGM  0          // 2048
#define GP_AE   2048       // 3 x 768 = 2304
#define GP_YN   4352       // 2 x 3432 = 6864
#define GP_RED  11216      //  256
#define GP_IDX  11472      //  96 (3 x 24 ints + pad)
#define GRPSZ   11568
#define S_TOT   (S_GRP + 2 * GRPSZ)     // 43232 words = 172.9 KB
#define CV_SMEM (S_TOT * 4)
#define CV_THREADS 512

__device__ __forceinline__ void stage_ae_h(uint32_t dstbase, const char* __restrict__ src,
                                           int gtid) {
    if (gtid < 192) {                              // 192 chunks of 16B, contiguous
        asm volatile("cp.async.ca.shared.global [%0], [%1], 16;"
                     :: "r"(dstbase + (uint32_t)gtid * 16),
                        "l"(src + (size_t)gtid * 16) : "memory");
    }
}

// stage 24 yn rows (gathered) + 2 pc rows into [26][132] fp32 smem tile
__device__ __forceinline__ void stage_yn(uint32_t dstbase, const int* __restrict__ sx,
                                         int tn, int gtid) {
    #pragma unroll
    for (int q = 0; q < 4; q++) {
        int i = gtid + q * 256;                    // 832 chunks of 16B
        if (i < 832) {
            int row = i >> 5, c = i & 31;
            const float* src = (row < 24)
                ? g_yn + (size_t)sx[row] * FDIM + c * 4
                : g_pc + ((size_t)tn * 2 + (row - 24)) * FDIM + c * 4;
            uint32_t d = dstbase + (uint32_t)(row * 132 + c * 4) * 4;
            asm volatile("cp.async.ca.shared.global [%0], [%1], 16;"
                         :: "r"(d), "l"(src) : "memory");
        }
    }
}

__global__ void __launch_bounds__(CV_THREADS, 1)
k_conv(const int* __restrict__ nbr_idx,
       const float* __restrict__ Wg, const float* __restrict__ bg,
       const float* __restrict__ Wm, const float* __restrict__ bm,
       const float* __restrict__ We, const float* __restrict__ be,
       const float* __restrict__ lns, const float* __restrict__ lnb) {
    int tid = threadIdx.x, wid = tid >> 5, lane = tid & 31;
    int half = wid >> 3, wg = wid & 7, gtid = tid & 255;
    uint32_t* smu = (uint32_t*)sm;

    // ---- pack resident weights to fragment order ----
    for (int i = tid; i < 16384; i += CV_THREADS) {
        int wgo = i >> 11, rem = i & 2047;
        int c = rem & 3, idx4 = rem >> 2;
        int ln = idx4 & 31, ksj = idx4 >> 5;
        int ks = ksj >> 1, j = ksj & 1;
        int tg = ln & 3, gp = ln >> 2;
        int n = wgo * 16 + j * 8 + gp;
        int k2 = ks * 8 + (c & 1) * 4 + tg;
        const float* W = (c < 2) ? Wg : Wm;
        smu[S_W + i] = packh2(W[(2 * k2) * FDIM + n], W[(2 * k2 + 1) * FDIM + n]);
    }
    for (int i = tid; i < 3072; i += CV_THREADS) {
        int wgo = i / 384, rem = i - wgo * 384;
        int c = rem & 1, idx2 = rem >> 1;
        int ln = idx2 & 31, ksj = idx2 >> 5;
        int ks = ksj >> 1, j = ksj & 1;
        int tg = ln & 3, gp = ln >> 2;
        int n = wgo * 16 + j * 8 + gp;
        int k2 = ks * 8 + c * 4 + tg;
        float v0 = (2 * k2     < EDGE) ? We[(2 * k2) * FDIM + n]     : 0.f;
        float v1 = (2 * k2 + 1 < EDGE) ? We[(2 * k2 + 1) * FDIM + n] : 0.f;
        smu[S_WE + i] = packh2(v0, v1);
    }
    if (tid < FDIM) {
        sm[S_BIAS + tid]       = bg[tid];
        sm[S_BIAS + 128 + tid] = bm[tid];
        sm[S_BIAS + 256 + tid] = lns[tid];
        sm[S_BIAS + 384 + tid] = lnb[tid];
        sm[S_BIAS + 512 + tid] = be[tid];
    }

    int gbase = S_GRP + half * GRPSZ;
    int* sidx3 = (int*)(sm + gbase + GP_IDX);
    uint32_t aeRaw = smem_u32(sm + gbase + GP_AE);
    uint32_t ynRaw = smem_u32(sm + gbase + GP_YN);
    int tig = lane & 3, grp = lane >> 2;
    bool notpad = (grp < 4);
    int barid = half + 1;

    int stride = 2 * gridDim.x;
    int s0 = blockIdx.x * 2 + half;

    __syncthreads();

    // ---- prologue ----
    if (gtid < 24) {
        sidx3[gtid] = nbr_idx[s0 * 24 + gtid];
        if (s0 + stride < NT2)
            sidx3[24 + gtid] = nbr_idx[(s0 + stride) * 24 + gtid];
    }
    stage_ae_h(aeRaw, (const char*)(g_nbrh + (size_t)s0 * 768), gtid);
    if (s0 + stride < NT2)
        stage_ae_h(aeRaw + 768u * 4, (const char*)(g_nbrh + (size_t)(s0 + stride) * 768), gtid);
    asm volatile("cp.async.commit_group;" ::: "memory");
    asm volatile("cp.async.wait_group 0;" ::: "memory");
    asm volatile("bar.sync %0, %1;" :: "r"(barid), "r"(256) : "memory");

    stage_yn(ynRaw, sidx3, s0, gtid);
    asm volatile("cp.async.commit_group;" ::: "memory");
    asm volatile("cp.async.wait_group 0;" ::: "memory");
    asm volatile("bar.sync %0, %1;" :: "r"(barid), "r"(256) : "memory");

    float bgr[2][2], bmr[2][2], ber[2][2];
    #pragma unroll
    for (int j = 0; j < 2; j++) {
        int f0 = wg * 16 + j * 8 + 2 * tig;
        bgr[j][0] = sm[S_BIAS + f0];        bgr[j][1] = sm[S_BIAS + f0 + 1];
        bmr[j][0] = sm[S_BIAS + 128 + f0];  bmr[j][1] = sm[S_BIAS + 128 + f0 + 1];
        ber[j][0] = sm[S_BIAS + 512 + f0];  ber[j][1] = sm[S_BIAS + 512 + f0 + 1];
    }
    float4 lns4 = *(const float4*)&sm[S_BIAS + 256 + lane * 4];
    float4 lnb4 = *(const float4*)&sm[S_BIAS + 384 + lane * 4];

    int b2 = 0;      // yn consume buffer
    int b3 = 0;      // ae/sidx consume buffer
    for (int t = s0; t < NT2; t += stride) {
        int aeB = gbase + GP_AE + b3 * 768;
        int ynB = gbase + GP_YN + b2 * 3432;

        // ---- commit A: stage yn/pc for t+stride ----
        if (t + stride < NT2)
            stage_yn(ynRaw + (uint32_t)(b2 ^ 1) * 3432 * 4,
                     sidx3 + ((b3 + 1) % 3) * 24, t + stride, gtid);
        asm volatile("cp.async.commit_group;" ::: "memory");

        // ---- commit B: stage sidx/AE for t+2*stride ----
        int t2 = t + 2 * stride;
        if (t2 < NT2) {
            int ib = (b3 + 2) % 3;
            if (gtid < 24) sidx3[ib * 24 + gtid] = nbr_idx[t2 * 24 + gtid];
            stage_ae_h(aeRaw + (uint32_t)ib * 768 * 4,
                       (const char*)(g_nbrh + (size_t)t2 * 768), gtid);
        }
        asm volatile("cp.async.commit_group;" ::: "memory");

        // ---- phi_e mma: fp16 k16, K=48 -> 3 steps (fragment LDS.128/.64) ----
        float ce[2][2][4] = {};
        #pragma unroll
        for (int ks = 0; ks < 3; ks++) {
            uint4 A[2];
            #pragma unroll
            for (int rt = 0; rt < 2; rt++)
                A[rt] = *(const uint4*)&smu[aeB + ((rt * 3 + ks) * 32 + lane) * 4];
            #pragma unroll
            for (int j = 0; j < 2; j++) {
                uint2 Bf = *(const uint2*)&smu[S_WE + wg * 384 + ((ks * 2 + j) * 32 + lane) * 2];
                #pragma unroll
                for (int rt = 0; rt < 2; rt++)
                    mma_f16(ce[rt][j], A[rt].x, A[rt].y, A[rt].z, A[rt].w, Bf.x, Bf.y);
            }
        }

        // ---- build inter tile in AGM fragment order (STS.64) ----
        #pragma unroll
        for (int rt = 0; rt < 2; rt++) {
            int yr0 = ynB + (rt * 12 + grp) * 132;
            int pr  = ynB + (24 + rt) * 132;
            #pragma unroll
            for (int j = 0; j < 2; j++) {
                int f0 = wg * 16 + j * 8 + 2 * tig;
                float2 pc2 = *(const float2*)&sm[pr + f0];
                float2 y0  = *(const float2*)&sm[yr0 + f0];
                uint32_t lo = packh2(pc2.x * y0.x * (ce[rt][j][0] + ber[j][0]),
                                     pc2.y * y0.y * (ce[rt][j][1] + ber[j][1]));
                uint32_t hi = 0u;
                if (notpad) {
                    float2 y1 = *(const float2*)&sm[yr0 + 8 * 132 + f0];
                    hi = packh2(pc2.x * y1.x * (ce[rt][j][2] + ber[j][0]),
                                pc2.y * y1.y * (ce[rt][j][3] + ber[j][1]));
                }
                // dest: [rt][ks=wg][lane]{slot=j*2 + rowbit}
                *(uint2*)&smu[gbase + GP_AGM + ((rt * 8 + wg) * 32 + lane) * 4 + j * 2] =
                    make_uint2(lo, hi);
            }
        }
        asm volatile("bar.sync %0, %1;" :: "r"(barid), "r"(256) : "memory");

        // ---- gate/mag mma: fp16 k16, K=128 -> 8 steps (fragment LDS.128) ----
        float cg[2][2][4] = {}, cmm[2][2][4] = {};
        #pragma unroll
        for (int ks = 0; ks < 8; ks++) {
            uint4 A[2];
            #pragma unroll
            for (int rt = 0; rt < 2; rt++)
                A[rt] = *(const uint4*)&smu[gbase + GP_AGM + ((rt * 8 + ks) * 32 + lane) * 4];
            #pragma unroll
            for (int j = 0; j < 2; j++) {
                uint4 Bf = *(const uint4*)&smu[S_W + wg * 2048 + ((ks * 2 + j) * 32 + lane) * 4];
                #pragma unroll
                for (int rt = 0; rt < 2; rt++) {
                    mma_f16(cg[rt][j],  A[rt].x, A[rt].y, A[rt].z, A[rt].w, Bf.x, Bf.y);
                    mma_f16(cmm[rt][j], A[rt].x, A[rt].y, A[rt].z, A[rt].w, Bf.z, Bf.w);
                }
            }
        }

        // ---- activation + masked per-atom column sums ----
        #pragma unroll
        for (int rt = 0; rt < 2; rt++) {
            #pragma unroll
            for (int j = 0; j < 2; j++) {
                float p0 = act(cg[rt][j][0] + bgr[j][0], cmm[rt][j][0] + bmr[j][0]);
                float p1 = act(cg[rt][j][1] + bgr[j][1], cmm[rt][j][1] + bmr[j][1]);
                if (notpad) {
                    p0 += act(cg[rt][j][2] + bgr[j][0], cmm[rt][j][2] + bmr[j][0]);
                    p1 += act(cg[rt][j][3] + bgr[j][1], cmm[rt][j][3] + bmr[j][1]);
                }
                #pragma unroll
                for (int o = 4; o < 32; o <<= 1) {
                    p0 += __shfl_xor_sync(0xffffffffu, p0, o);
                    p1 += __shfl_xor_sync(0xffffffffu, p1, o);
                }
                if (grp == 0) {
                    int f0 = wg * 16 + j * 8 + 2 * tig;
                    sm[gbase + GP_RED + rt * 128 + f0]     = p0;
                    sm[gbase + GP_RED + rt * 128 + f0 + 1] = p1;
                }
            }
        }
        // drain commit A (yn for next iter) + previous commit B
        asm volatile("cp.async.wait_group 1;" ::: "memory");
        asm volatile("bar.sync %0, %1;" :: "r"(barid), "r"(256) : "memory");

        // ---- LayerNorm + residual (warps 0,1 of group) ----
        if (wg < 2) {
            float4 v = *(const float4*)&sm[gbase + GP_RED + wg * 128 + lane * 4];
            float s = v.x + v.y + v.z + v.w;
            float q = v.x*v.x + v.y*v.y + v.z*v.z + v.w*v.w;
            #pragma unroll
            for (int o = 16; o > 0; o >>= 1) {
                s += __shfl_xor_sync(0xffffffffu, s, o);
                q += __shfl_xor_sync(0xffffffffu, q, o);
            }
            float mu = s * (1.f / FDIM);
            float var = q * (1.f / FDIM) - mu * mu;
            float rstd = rsqrtf(var + 1e-6f);
            int n = t * 2 + wg;
            float4 x = *(float4*)&g_x[n * FDIM + lane * 4];
            x.x += (v.x - mu) * rstd * lns4.x + lnb4.x;
            x.y += (v.y - mu) * rstd * lns4.y + lnb4.y;
            x.z += (v.z - mu) * rstd * lns4.z + lnb4.z;
            x.w += (v.w - mu) * rstd * lns4.w + lnb4.w;
            *(float4*)&g_x[n * FDIM + lane * 4] = x;
        }
        b2 ^= 1;
        b3 = (b3 + 1) % 3;
    }
}

// ============================================================================
// Kernel 4: readout
// ============================================================================
#define RO_WHT  0
#define RO_WO   33792
#define RO_BH   34048
#define RO_XR   34304
#define RO_RED  34432
#define RO_FLOATS 34440
#define RO_SMEM (RO_FLOATS * 4)

__global__ void k_readout(const float* __restrict__ Wh, const float* __restrict__ bh,
                          const float* __restrict__ Wout, const float* __restrict__ bout) {
    float* WhT = sm + RO_WHT;
    float* WoS = sm + RO_WO;
    float* bhS = sm + RO_BH;
    float* xr  = sm + RO_XR;
    float* red = sm + RO_RED;
    int tid = threadIdx.x;
    for (int i = tid; i < FDIM * HDIM; i += 256) {
        int k = i >> 8, j = i & 255;
        WhT[j * 132 + k] = Wh[i];
    }
    WoS[tid] = Wout[tid];
    bhS[tid] = bh[tid];
    __syncthreads();
    float b0 = bout[0];
    const float4* wp = (const float4*)(WhT + tid * 132);

    for (int n = blockIdx.x; n < N_ATOMS; n += gridDim.x) {
        if (tid < FDIM) xr[tid] = g_x[n * FDIM + tid];
        __syncthreads();
        float acc = bhS[tid];
        #pragma unroll 4
        for (int k4 = 0; k4 < FDIM / 4; k4++) {
            float4 w = wp[k4];
            float4 xv = *(const float4*)(xr + k4 * 4);
            acc = fmaf(w.x, xv.x, acc); acc = fmaf(w.y, xv.y, acc);
            acc = fmaf(w.z, xv.z, acc); acc = fmaf(w.w, xv.w, acc);
        }
        float pcontrib = softplusf(acc) * WoS[tid];
        #pragma unroll
        for (int o = 16; o > 0; o >>= 1)
            pcontrib += __shfl_xor_sync(0xffffffffu, pcontrib, o);
        if ((tid & 31) == 0) red[tid >> 5] = pcontrib;
        __syncthreads();
        if (tid == 0) {
            float ssum = 0.f;
            #pragma unroll
            for (int w8 = 0; w8 < 8; w8++) ssum += red[w8];
            g_site[n] = ssum + b0;
        }
        __syncthreads();
    }
}

// ============================================================================
// Kernel 5: per-crystal sum
// ============================================================================
__global__ void k_crystal(float* __restrict__ out) {
    __shared__ float red[8];
    int c = blockIdx.x, tid = threadIdx.x;
    float v = g_site[c * APC + tid];
    #pragma unroll
    for (int o = 16; o > 0; o >>= 1)
        v += __shfl_xor_sync(0xffffffffu, v, o);
    if ((tid & 31) == 0) red[tid >> 5] = v;
    __syncthreads();
    if (tid == 0) {
        float s = 0.f;
        #pragma unroll
        for (int i = 0; i < 8; i++) s += red[i];
        out[c] = s;
    }
}

// ============================================================================
extern "C" void kernel_launch(void* const* d_in, const int* in_sizes, int n_in,
                              void* d_out, int out_size) {
    const float* atom_fea = (const float*)d_in[0];
    const float* nbr_fea  = (const float*)d_in[1];
    const int*   nbr_idx  = (const int*)  d_in[2];
    const float* W_embed  = (const float*)d_in[3];
    const float* b_embed  = (const float*)d_in[4];
    const float* W_center = (const float*)d_in[5];
    const float* b_center = (const float*)d_in[6];
    const float* W_nbr    = (const float*)d_in[7];
    const float* b_nbr    = (const float*)d_in[8];
    const float* W_edge   = (const float*)d_in[9];
    const float* b_edge   = (const float*)d_in[10];
    const float* W_gate   = (const float*)d_in[11];
    const float* b_gate   = (const float*)d_in[12];
    const float* W_mag    = (const float*)d_in[13];
    const float* b_mag    = (const float*)d_in[14];
    const float* ln_scale = (const float*)d_in[15];
    const float* ln_bias  = (const float*)d_in[16];
    const float* W_h      = (const float*)d_in[17];
    const float* b_h      = (const float*)d_in[18];
    const float* W_out    = (const float*)d_in[19];
    const float* b_out    = (const float*)d_in[20];
    float* out = (float*)d_out;

    cudaFuncSetAttribute(k_convA,   cudaFuncAttributeMaxDynamicSharedMemorySize, A2_SMEM);
    cudaFuncSetAttribute(k_conv,    cudaFuncAttributeMaxDynamicSharedMemorySize, CV_SMEM);
    cudaFuncSetAttribute(k_readout, cudaFuncAttributeMaxDynamicSharedMemorySize, RO_SMEM);

    k_pack<<<2048, 256>>>(nbr_fea);
    k_embed<<<256, 256>>>(atom_fea, W_embed, b_embed);
    for (int l = 0; l < NCONV; l++) {
        k_convA<<<148, 256, A2_SMEM>>>(W_center + l * FDIM * FDIM, b_center + l * FDIM,
                                       W_nbr    + l * FDIM * FDIM, b_nbr    + l * FDIM);
        k_conv<<<148, CV_THREADS, CV_SMEM>>>(nbr_idx,
                                      W_gate + l * FDIM * FDIM, b_gate + l * FDIM,
                                      W_mag  + l * FDIM * FDIM, b_mag  + l * FDIM,
                                      W_edge + l * EDGE * FDIM, b_edge + l * FDIM,
                                      ln_scale + l * FDIM, ln_bias + l * FDIM);
    }
    k_readout<<<152, 256, RO_SMEM>>>(W_h, b_h, W_out, b_out);
    k_crystal<<<NCRY, 256>>>(out);
}

// round 12
// speedup vs baseline: 5.2893x; 1.4242x over previous
#include <cuda_runtime.h>
#include <cuda_fp16.h>
#include <math.h>
#include <cstdint>

#define N_ATOMS 32768
#define MNBR    12
#define PROWS   16
#define ORIG    92
#define EDGE    41
#define FDIM    128
#define HDIM    256
#define NCONV   3
#define NCRY    128
#define APC     256
#define NT2     (N_ATOMS / 2)             // 16384 atom-pair tiles
#define ATILE   (N_ATOMS / 64)            // 512

// ---- scratch ----
__device__ float    g_x [N_ATOMS * FDIM];
__device__ float    g_pc[N_ATOMS * FDIM];
__device__ float    g_yn[N_ATOMS * FDIM];
__device__ uint32_t g_nbrh[NT2 * 768];     // fp16 edge features, fragment order
__device__ float    g_site[N_ATOMS];

__device__ __forceinline__ float softplusf(float x) {
    return fmaxf(x, 0.f) + log1pf(expf(-fabsf(x)));
}
__device__ __forceinline__ float tf32r(float x) {
    uint32_t u;
    asm("cvt.rna.tf32.f32 %0, %1;" : "=r"(u) : "f"(x));
    return __uint_as_float(u);
}
__device__ __forceinline__ uint32_t smem_u32(const void* p) {
    uint32_t a;
    asm("{ .reg .u64 t; cvta.to.shared.u64 t, %1; cvt.u32.u64 %0, t; }" : "=r"(a) : "l"(p));
    return a;
}
__device__ __forceinline__ uint32_t packh2(float a, float b) {
    __half2 h = __floats2half2_rn(a, b);
    return *(uint32_t*)&h;
}
__device__ __forceinline__ void mma_tf32(float c[4], const uint32_t a[4], const uint32_t b[2]) {
    asm volatile("mma.sync.aligned.m16n8k8.row.col.f32.tf32.tf32.f32 "
        "{%0,%1,%2,%3}, {%4,%5,%6,%7}, {%8,%9}, {%0,%1,%2,%3};"
        : "+f"(c[0]), "+f"(c[1]), "+f"(c[2]), "+f"(c[3])
        : "r"(a[0]), "r"(a[1]), "r"(a[2]), "r"(a[3]), "r"(b[0]), "r"(b[1]));
}
__device__ __forceinline__ void mma_f16(float c[4], uint32_t a0, uint32_t a1,
                                        uint32_t a2, uint32_t a3,
                                        uint32_t b0, uint32_t b1) {
    asm volatile("mma.sync.aligned.m16n8k16.row.col.f32.f16.f16.f32 "
        "{%0,%1,%2,%3}, {%4,%5,%6,%7}, {%8,%9}, {%0,%1,%2,%3};"
        : "+f"(c[0]), "+f"(c[1]), "+f"(c[2]), "+f"(c[3])
        : "r"(a0), "r"(a1), "r"(a2), "r"(a3), "r"(b0), "r"(b1));
}
__device__ __forceinline__ float act(float g, float m) {
    float sig = __fdividef(1.f, 1.f + __expf(-g));
    float sp  = fmaxf(m, 0.f) + __logf(1.f + __expf(-fabsf(m)));
    return sig * sp;
}
__device__ __forceinline__ float spf(float x) {
    return fmaxf(x, 0.f) + __logf(1.f + __expf(-fabsf(x)));
}

extern __shared__ float sm[];

// ============================================================================
// Kernel 0: pack nbr_fea -> fp16 FRAGMENT-ORDER per 2-atom tile (768 u32)
// ============================================================================
__global__ void k_pack(const float* __restrict__ nbr_fea) {
    int total = NT2 * 768;
    for (int idx = blockIdx.x * 256 + threadIdx.x; idx < total; idx += gridDim.x * 256) {
        int s = idx / 768, f = idx - s * 768;
        int c = f & 3, q = f >> 2;
        int lane = q & 31, rks = q >> 5;
        int rt = rks / 3, ks = rks - rt * 3;
        int tig = lane & 3, grp = lane >> 2;
        int slot = c >> 1, rowbit = c & 1;
        int m = grp + rowbit * 8;
        int k2 = ks * 8 + slot * 4 + tig;
        float v0 = 0.f, v1 = 0.f;
        if (m < MNBR) {
            size_t base = ((size_t)(s * 2 + rt) * MNBR + m) * EDGE;
            if (2 * k2     < EDGE) v0 = nbr_fea[base + 2 * k2];
            if (2 * k2 + 1 < EDGE) v1 = nbr_fea[base + 2 * k2 + 1];
        }
        g_nbrh[idx] = packh2(v0, v1);
    }
}

// ============================================================================
// Kernel 1: k_embed — fp16 mma GEMM: x = atom_fea @ W_embed + b
//   M=64/tile, N=128, K=92 padded->96 (48 k2, 6 ks). Persistent 148 CTAs.
// ============================================================================
#define E_W    0        // 6144 u32, fragment order
#define E_A    6144     // 64 x 52 u32
#define E_BIAS 9472     // 128 f
#define E_TOT  9600
#define E_SMEM (E_TOT * 4)

__global__ void __launch_bounds__(256, 1)
k_embed(const float* __restrict__ atom_fea,
        const float* __restrict__ W, const float* __restrict__ b) {
    int tid = threadIdx.x, wid = tid >> 5, lane = tid & 31;
    uint32_t* smu = (uint32_t*)sm;
    // pack B fragment order: i = wc*1536 + ((ks*4+j)*32+ln)*2 + c
    for (int i = tid; i < 6144; i += 256) {
        int wc0 = i / 1536, rem = i - wc0 * 1536;
        int c = rem & 1, idx = rem >> 1;
        int ln = idx & 31, ksj = idx >> 5;
        int ks = ksj >> 2, j = ksj & 3;
        int tg = ln & 3, gp = ln >> 2;
        int n = wc0 * 32 + j * 8 + gp;
        int k2 = ks * 8 + c * 4 + tg;
        float v0 = (2 * k2     < ORIG) ? W[(2 * k2) * FDIM + n]     : 0.f;
        float v1 = (2 * k2 + 1 < ORIG) ? W[(2 * k2 + 1) * FDIM + n] : 0.f;
        smu[E_W + i] = packh2(v0, v1);
    }
    if (tid < FDIM) sm[E_BIAS + tid] = b[tid];
    __syncthreads();

    int wr = wid >> 2, wc = wid & 3;
    int tig = lane & 3, grp = lane >> 2;
    float br[4][2];
    #pragma unroll
    for (int j = 0; j < 4; j++) {
        int n0 = wc * 32 + j * 8 + 2 * tig;
        br[j][0] = sm[E_BIAS + n0]; br[j][1] = sm[E_BIAS + n0 + 1];
    }

    for (int t = blockIdx.x; t < ATILE; t += gridDim.x) {
        #pragma unroll
        for (int q = 0; q < 12; q++) {
            int i = tid + q * 256;                 // 3072 = 64 x 48
            int r = i / 48, k2 = i - r * 48;
            uint32_t v = 0u;
            if (k2 < 46) {
                float2 f2 = *(const float2*)&atom_fea[(size_t)(t * 64 + r) * ORIG + 2 * k2];
                v = packh2(f2.x, f2.y);
            }
            smu[E_A + r * 52 + k2] = v;
        }
        __syncthreads();

        float c[2][4][4] = {};
        #pragma unroll
        for (int ks = 0; ks < 6; ks++) {
            int k0 = ks * 8;
            uint32_t a[2][4];
            #pragma unroll
            for (int rt = 0; rt < 2; rt++) {
                int r = wr * 32 + rt * 16 + grp;
                a[rt][0] = smu[E_A + r * 52 + k0 + tig];
                a[rt][1] = smu[E_A + (r + 8) * 52 + k0 + tig];
                a[rt][2] = smu[E_A + r * 52 + k0 + 4 + tig];
                a[rt][3] = smu[E_A + (r + 8) * 52 + k0 + 4 + tig];
            }
            #pragma unroll
            for (int j = 0; j < 4; j++) {
                uint2 Bf = *(const uint2*)&smu[E_W + wc * 1536 + ((ks * 4 + j) * 32 + lane) * 2];
                #pragma unroll
                for (int rt = 0; rt < 2; rt++)
                    mma_f16(c[rt][j], a[rt][0], a[rt][1], a[rt][2], a[rt][3], Bf.x, Bf.y);
            }
        }

        #pragma unroll
        for (int rt = 0; rt < 2; rt++) {
            int r0 = t * 64 + wr * 32 + rt * 16 + grp;
            #pragma unroll
            for (int j = 0; j < 4; j++) {
                int n0 = wc * 32 + j * 8 + 2 * tig;
                *(float2*)&g_x[r0 * FDIM + n0] =
                    make_float2(c[rt][j][0] + br[j][0], c[rt][j][1] + br[j][1]);
                *(float2*)&g_x[(r0 + 8) * FDIM + n0] =
                    make_float2(c[rt][j][2] + br[j][0], c[rt][j][3] + br[j][1]);
            }
        }
        __syncthreads();
    }
}

// ============================================================================
// Kernel 2: k_convA — tf32 mma GEMM (pitch 265)
// ============================================================================
#define A2_W    0
#define A2_A    33920
#define A2_BIAS 42368
#define A2_TOT  42624
#define A2_SMEM (A2_TOT * 4)

__global__ void __launch_bounds__(256, 1)
k_convA(const float* __restrict__ Wc, const float* __restrict__ bc,
        const float* __restrict__ Wn, const float* __restrict__ bn) {
    int tid = threadIdx.x, wid = tid >> 5, lane = tid & 31;
    uint32_t* smu = (uint32_t*)sm;
    for (int i = tid; i < FDIM * FDIM; i += 256) {
        int k = i >> 7, n = i & 127;
        smu[A2_W + k * 265 + n]       = __float_as_uint(tf32r(Wc[i]));
        smu[A2_W + k * 265 + 128 + n] = __float_as_uint(tf32r(Wn[i]));
    }
    if (tid < 128) { sm[A2_BIAS + tid] = bc[tid]; sm[A2_BIAS + 128 + tid] = bn[tid]; }
    __syncthreads();

    int wr = wid >> 2, wc = wid & 3;
    int tig = lane & 3, grp = lane >> 2;
    float bcr[4][2], bnr[4][2];
    #pragma unroll
    for (int j = 0; j < 4; j++) {
        int f0 = wc * 32 + j * 8 + 2 * tig;
        bcr[j][0] = sm[A2_BIAS + f0];       bcr[j][1] = sm[A2_BIAS + f0 + 1];
        bnr[j][0] = sm[A2_BIAS + 128 + f0]; bnr[j][1] = sm[A2_BIAS + 128 + f0 + 1];
    }

    for (int t = blockIdx.x; t < ATILE; t += gridDim.x) {
        #pragma unroll
        for (int q = 0; q < 8; q++) {
            int ch = tid + q * 256;
            int r = ch >> 5, c4 = ch & 31;
            float4 v = *(const float4*)&g_x[(t * 64 + r) * FDIM + c4 * 4];
            sm[A2_A + r * 132 + c4 * 4 + 0] = tf32r(v.x);
            sm[A2_A + r * 132 + c4 * 4 + 1] = tf32r(v.y);
            sm[A2_A + r * 132 + c4 * 4 + 2] = tf32r(v.z);
            sm[A2_A + r * 132 + c4 * 4 + 3] = tf32r(v.w);
        }
        __syncthreads();

        float cpc[2][4][4] = {}, cyn[2][4][4] = {};
        #pragma unroll
        for (int ks = 0; ks < 16; ks++) {
            int k0 = ks * 8;
            uint32_t a[2][4];
            #pragma unroll
            for (int rt = 0; rt < 2; rt++) {
                int r = wr * 32 + rt * 16 + grp;
                a[rt][0] = smu[A2_A + r * 132 + k0 + tig];
                a[rt][1] = smu[A2_A + (r + 8) * 132 + k0 + tig];
                a[rt][2] = smu[A2_A + r * 132 + k0 + 4 + tig];
                a[rt][3] = smu[A2_A + (r + 8) * 132 + k0 + 4 + tig];
            }
            #pragma unroll
            for (int j = 0; j < 4; j++) {
                int n = wc * 32 + j * 8 + grp;
                uint32_t bcf[2], bnf[2];
                bcf[0] = smu[A2_W + (k0 + tig) * 265 + n];
                bcf[1] = smu[A2_W + (k0 + 4 + tig) * 265 + n];
                bnf[0] = smu[A2_W + (k0 + tig) * 265 + 128 + n];
                bnf[1] = smu[A2_W + (k0 + 4 + tig) * 265 + 128 + n];
                #pragma unroll
                for (int rt = 0; rt < 2; rt++) {
                    mma_tf32(cpc[rt][j], a[rt], bcf);
                    mma_tf32(cyn[rt][j], a[rt], bnf);
                }
            }
        }

        #pragma unroll
        for (int rt = 0; rt < 2; rt++) {
            int r0 = t * 64 + wr * 32 + rt * 16 + grp;
            #pragma unroll
            for (int j = 0; j < 4; j++) {
                int f0 = wc * 32 + j * 8 + 2 * tig;
                float2 v;
                v.x = cpc[rt][j][0] + bcr[j][0]; v.y = cpc[rt][j][1] + bcr[j][1];
                *(float2*)&g_pc[r0 * FDIM + f0] = v;
                v.x = cpc[rt][j][2] + bcr[j][0]; v.y = cpc[rt][j][3] + bcr[j][1];
                *(float2*)&g_pc[(r0 + 8) * FDIM + f0] = v;
                v.x = cyn[rt][j][0] + bnr[j][0]; v.y = cyn[rt][j][1] + bnr[j][1];
                *(float2*)&g_yn[r0 * FDIM + f0] = v;
                v.x = cyn[rt][j][2] + bnr[j][0]; v.y = cyn[rt][j][3] + bnr[j][1];
                *(float2*)&g_yn[(r0 + 8) * FDIM + f0] = v;
            }
        }
        __syncthreads();
    }
}

// ============================================================================
// Kernel 3: k_conv — fused conv layer (unchanged from round 11)
// ============================================================================
#define S_W     0
#define S_WE    16384
#define S_BIAS  19456
#define S_GRP   20096
#define GP_AGM  0
#define GP_AE   2048
#define GP_YN   4352
#define GP_RED  11216
#define GP_IDX  11472
#define GRPSZ   11568
#define S_TOT   (S_GRP + 2 * GRPSZ)
#define CV_SMEM (S_TOT * 4)
#define CV_THREADS 512

__device__ __forceinline__ void stage_ae_h(uint32_t dstbase, const char* __restrict__ src,
                                           int gtid) {
    if (gtid < 192) {
        asm volatile("cp.async.ca.shared.global [%0], [%1], 16;"
                     :: "r"(dstbase + (uint32_t)gtid * 16),
                        "l"(src + (size_t)gtid * 16) : "memory");
    }
}

__device__ __forceinline__ void stage_yn(uint32_t dstbase, const int* __restrict__ sx,
                                         int tn, int gtid) {
    #pragma unroll
    for (int q = 0; q < 4; q++) {
        int i = gtid + q * 256;
        if (i < 832) {
            int row = i >> 5, c = i & 31;
            const float* src = (row < 24)
                ? g_yn + (size_t)sx[row] * FDIM + c * 4
                : g_pc + ((size_t)tn * 2 + (row - 24)) * FDIM + c * 4;
            uint32_t d = dstbase + (uint32_t)(row * 132 + c * 4) * 4;
            asm volatile("cp.async.ca.shared.global [%0], [%1], 16;"
                         :: "r"(d), "l"(src) : "memory");
        }
    }
}

__global__ void __launch_bounds__(CV_THREADS, 1)
k_conv(const int* __restrict__ nbr_idx,
       const float* __restrict__ Wg, const float* __restrict__ bg,
       const float* __restrict__ Wm, const float* __restrict__ bm,
       const float* __restrict__ We, const float* __restrict__ be,
       const float* __restrict__ lns, const float* __restrict__ lnb) {
    int tid = threadIdx.x, wid = tid >> 5, lane = tid & 31;
    int half = wid >> 3, wg = wid & 7, gtid = tid & 255;
    uint32_t* smu = (uint32_t*)sm;

    for (int i = tid; i < 16384; i += CV_THREADS) {
        int wgo = i >> 11, rem = i & 2047;
        int c = rem & 3, idx4 = rem >> 2;
        int ln = idx4 & 31, ksj = idx4 >> 5;
        int ks = ksj >> 1, j = ksj & 1;
        int tg = ln & 3, gp = ln >> 2;
        int n = wgo * 16 + j * 8 + gp;
        int k2 = ks * 8 + (c & 1) * 4 + tg;
        const float* W = (c < 2) ? Wg : Wm;
        smu[S_W + i] = packh2(W[(2 * k2) * FDIM + n], W[(2 * k2 + 1) * FDIM + n]);
    }
    for (int i = tid; i < 3072; i += CV_THREADS) {
        int wgo = i / 384, rem = i - wgo * 384;
        int c = rem & 1, idx2 = rem >> 1;
        int ln = idx2 & 31, ksj = idx2 >> 5;
        int ks = ksj >> 1, j = ksj & 1;
        int tg = ln & 3, gp = ln >> 2;
        int n = wgo * 16 + j * 8 + gp;
        int k2 = ks * 8 + c * 4 + tg;
        float v0 = (2 * k2     < EDGE) ? We[(2 * k2) * FDIM + n]     : 0.f;
        float v1 = (2 * k2 + 1 < EDGE) ? We[(2 * k2 + 1) * FDIM + n] : 0.f;
        smu[S_WE + i] = packh2(v0, v1);
    }
    if (tid < FDIM) {
        sm[S_BIAS + tid]       = bg[tid];
        sm[S_BIAS + 128 + tid] = bm[tid];
        sm[S_BIAS + 256 + tid] = lns[tid];
        sm[S_BIAS + 384 + tid] = lnb[tid];
        sm[S_BIAS + 512 + tid] = be[tid];
    }

    int gbase = S_GRP + half * GRPSZ;
    int* sidx3 = (int*)(sm + gbase + GP_IDX);
    uint32_t aeRaw = smem_u32(sm + gbase + GP_AE);
    uint32_t ynRaw = smem_u32(sm + gbase + GP_YN);
    int tig = lane & 3, grp = lane >> 2;
    bool notpad = (grp < 4);
    int barid = half + 1;

    int stride = 2 * gridDim.x;
    int s0 = blockIdx.x * 2 + half;

    __syncthreads();

    if (gtid < 24) {
        sidx3[gtid] = nbr_idx[s0 * 24 + gtid];
        if (s0 + stride < NT2)
            sidx3[24 + gtid] = nbr_idx[(s0 + stride) * 24 + gtid];
    }
    stage_ae_h(aeRaw, (const char*)(g_nbrh + (size_t)s0 * 768), gtid);
    if (s0 + stride < NT2)
        stage_ae_h(aeRaw + 768u * 4, (const char*)(g_nbrh + (size_t)(s0 + stride) * 768), gtid);
    asm volatile("cp.async.commit_group;" ::: "memory");
    asm volatile("cp.async.wait_group 0;" ::: "memory");
    asm volatile("bar.sync %0, %1;" :: "r"(barid), "r"(256) : "memory");

    stage_yn(ynRaw, sidx3, s0, gtid);
    asm volatile("cp.async.commit_group;" ::: "memory");
    asm volatile("cp.async.wait_group 0;" ::: "memory");
    asm volatile("bar.sync %0, %1;" :: "r"(barid), "r"(256) : "memory");

    float bgr[2][2], bmr[2][2], ber[2][2];
    #pragma unroll
    for (int j = 0; j < 2; j++) {
        int f0 = wg * 16 + j * 8 + 2 * tig;
        bgr[j][0] = sm[S_BIAS + f0];        bgr[j][1] = sm[S_BIAS + f0 + 1];
        bmr[j][0] = sm[S_BIAS + 128 + f0];  bmr[j][1] = sm[S_BIAS + 128 + f0 + 1];
        ber[j][0] = sm[S_BIAS + 512 + f0];  ber[j][1] = sm[S_BIAS + 512 + f0 + 1];
    }
    float4 lns4 = *(const float4*)&sm[S_BIAS + 256 + lane * 4];
    float4 lnb4 = *(const float4*)&sm[S_BIAS + 384 + lane * 4];

    int b2 = 0, b3 = 0;
    for (int t = s0; t < NT2; t += stride) {
        int aeB = gbase + GP_AE + b3 * 768;
        int ynB = gbase + GP_YN + b2 * 3432;

        if (t + stride < NT2)
            stage_yn(ynRaw + (uint32_t)(b2 ^ 1) * 3432 * 4,
                     sidx3 + ((b3 + 1) % 3) * 24, t + stride, gtid);
        asm volatile("cp.async.commit_group;" ::: "memory");

        int t2 = t + 2 * stride;
        if (t2 < NT2) {
            int ib = (b3 + 2) % 3;
            if (gtid < 24) sidx3[ib * 24 + gtid] = nbr_idx[t2 * 24 + gtid];
            stage_ae_h(aeRaw + (uint32_t)ib * 768 * 4,
                       (const char*)(g_nbrh + (size_t)t2 * 768), gtid);
        }
        asm volatile("cp.async.commit_group;" ::: "memory");

        float ce[2][2][4] = {};
        #pragma unroll
        for (int ks = 0; ks < 3; ks++) {
            uint4 A[2];
            #pragma unroll
            for (int rt = 0; rt < 2; rt++)
                A[rt] = *(const uint4*)&smu[aeB + ((rt * 3 + ks) * 32 + lane) * 4];
            #pragma unroll
            for (int j = 0; j < 2; j++) {
                uint2 Bf = *(const uint2*)&smu[S_WE + wg * 384 + ((ks * 2 + j) * 32 + lane) * 2];
                #pragma unroll
                for (int rt = 0; rt < 2; rt++)
                    mma_f16(ce[rt][j], A[rt].x, A[rt].y, A[rt].z, A[rt].w, Bf.x, Bf.y);
            }
        }

        #pragma unroll
        for (int rt = 0; rt < 2; rt++) {
            int yr0 = ynB + (rt * 12 + grp) * 132;
            int pr  = ynB + (24 + rt) * 132;
            #pragma unroll
            for (int j = 0; j < 2; j++) {
                int f0 = wg * 16 + j * 8 + 2 * tig;
                float2 pc2 = *(const float2*)&sm[pr + f0];
                float2 y0  = *(const float2*)&sm[yr0 + f0];
                uint32_t lo = packh2(pc2.x * y0.x * (ce[rt][j][0] + ber[j][0]),
                                     pc2.y * y0.y * (ce[rt][j][1] + ber[j][1]));
                uint32_t hi = 0u;
                if (notpad) {
                    float2 y1 = *(const float2*)&sm[yr0 + 8 * 132 + f0];
                    hi = packh2(pc2.x * y1.x * (ce[rt][j][2] + ber[j][0]),
                                pc2.y * y1.y * (ce[rt][j][3] + ber[j][1]));
                }
                *(uint2*)&smu[gbase + GP_AGM + ((rt * 8 + wg) * 32 + lane) * 4 + j * 2] =
                    make_uint2(lo, hi);
            }
        }
        asm volatile("bar.sync %0, %1;" :: "r"(barid), "r"(256) : "memory");

        float cg[2][2][4] = {}, cmm[2][2][4] = {};
        #pragma unroll
        for (int ks = 0; ks < 8; ks++) {
            uint4 A[2];
            #pragma unroll
            for (int rt = 0; rt < 2; rt++)
                A[rt] = *(const uint4*)&smu[gbase + GP_AGM + ((rt * 8 + ks) * 32 + lane) * 4];
            #pragma unroll
            for (int j = 0; j < 2; j++) {
                uint4 Bf = *(const uint4*)&smu[S_W + wg * 2048 + ((ks * 2 + j) * 32 + lane) * 4];
                #pragma unroll
                for (int rt = 0; rt < 2; rt++) {
                    mma_f16(cg[rt][j],  A[rt].x, A[rt].y, A[rt].z, A[rt].w, Bf.x, Bf.y);
                    mma_f16(cmm[rt][j], A[rt].x, A[rt].y, A[rt].z, A[rt].w, Bf.z, Bf.w);
                }
            }
        }

        #pragma unroll
        for (int rt = 0; rt < 2; rt++) {
            #pragma unroll
            for (int j = 0; j < 2; j++) {
                float p0 = act(cg[rt][j][0] + bgr[j][0], cmm[rt][j][0] + bmr[j][0]);
                float p1 = act(cg[rt][j][1] + bgr[j][1], cmm[rt][j][1] + bmr[j][1]);
                if (notpad) {
                    p0 += act(cg[rt][j][2] + bgr[j][0], cmm[rt][j][2] + bmr[j][0]);
                    p1 += act(cg[rt][j][3] + bgr[j][1], cmm[rt][j][3] + bmr[j][1]);
                }
                #pragma unroll
                for (int o = 4; o < 32; o <<= 1) {
                    p0 += __shfl_xor_sync(0xffffffffu, p0, o);
                    p1 += __shfl_xor_sync(0xffffffffu, p1, o);
                }
                if (grp == 0) {
                    int f0 = wg * 16 + j * 8 + 2 * tig;
                    sm[gbase + GP_RED + rt * 128 + f0]     = p0;
                    sm[gbase + GP_RED + rt * 128 + f0 + 1] = p1;
                }
            }
        }
        asm volatile("cp.async.wait_group 1;" ::: "memory");
        asm volatile("bar.sync %0, %1;" :: "r"(barid), "r"(256) : "memory");

        if (wg < 2) {
            float4 v = *(const float4*)&sm[gbase + GP_RED + wg * 128 + lane * 4];
            float s = v.x + v.y + v.z + v.w;
            float q = v.x*v.x + v.y*v.y + v.z*v.z + v.w*v.w;
            #pragma unroll
            for (int o = 16; o > 0; o >>= 1) {
                s += __shfl_xor_sync(0xffffffffu, s, o);
                q += __shfl_xor_sync(0xffffffffu, q, o);
            }
            float mu = s * (1.f / FDIM);
            float var = q * (1.f / FDIM) - mu * mu;
            float rstd = rsqrtf(var + 1e-6f);
            int n = t * 2 + wg;
            float4 x = *(float4*)&g_x[n * FDIM + lane * 4];
            x.x += (v.x - mu) * rstd * lns4.x + lnb4.x;
            x.y += (v.y - mu) * rstd * lns4.y + lnb4.y;
            x.z += (v.z - mu) * rstd * lns4.z + lnb4.z;
            x.w += (v.w - mu) * rstd * lns4.w + lnb4.w;
            *(float4*)&g_x[n * FDIM + lane * 4] = x;
        }
        b2 ^= 1;
        b3 = (b3 + 1) % 3;
    }
}

// ============================================================================
// Kernel 4: k_readout — fp16 mma GEMM 32768x256x128 + fused softplus.Wout
//   M=64/tile, warps 2x4 (each 32 rows x 64 cols, j=0..7). Persistent.
// ============================================================================
#define R_W    0        // 16384 u32, fragment order
#define R_A    16384    // 64 x 68 u32
#define R_BH   20736    // 256 f
#define R_WO   20992    // 256 f
#define R_RED  21248    // 64 x 4 f
#define R_TOT  21504
#define R_SMEM (R_TOT * 4)

__global__ void __launch_bounds__(256, 1)
k_readout(const float* __restrict__ Wh, const float* __restrict__ bh,
          const float* __restrict__ Wout, const float* __restrict__ bout) {
    int tid = threadIdx.x, wid = tid >> 5, lane = tid & 31;
    uint32_t* smu = (uint32_t*)sm;
    // pack B: i = wc*4096 + ((ks*8+j)*32+ln)*2 + c
    for (int i = tid; i < 16384; i += 256) {
        int wc0 = i >> 12, rem = i & 4095;
        int c = rem & 1, idx = rem >> 1;
        int ln = idx & 31, ksj = idx >> 5;
        int ks = ksj >> 3, j = ksj & 7;
        int tg = ln & 3, gp = ln >> 2;
        int n = wc0 * 64 + j * 8 + gp;
        int k2 = ks * 8 + c * 4 + tg;
        smu[R_W + i] = packh2(Wh[(2 * k2) * HDIM + n], Wh[(2 * k2 + 1) * HDIM + n]);
    }
    sm[R_BH + tid] = bh[tid];
    sm[R_WO + tid] = Wout[tid];
    __syncthreads();

    int wr = wid >> 2, wc = wid & 3;
    int tig = lane & 3, grp = lane >> 2;
    float b0 = bout[0];
    float bhr[8][2], wor[8][2];
    #pragma unroll
    for (int j = 0; j < 8; j++) {
        int n0 = wc * 64 + j * 8 + 2 * tig;
        bhr[j][0] = sm[R_BH + n0]; bhr[j][1] = sm[R_BH + n0 + 1];
        wor[j][0] = sm[R_WO + n0]; wor[j][1] = sm[R_WO + n0 + 1];
    }

    for (int t = blockIdx.x; t < ATILE; t += gridDim.x) {
        #pragma unroll
        for (int q = 0; q < 16; q++) {
            int i = tid + q * 256;                 // 4096 = 64 x 64
            int r = i >> 6, k2 = i & 63;
            float2 f2 = *(const float2*)&g_x[(size_t)(t * 64 + r) * FDIM + 2 * k2];
            smu[R_A + r * 68 + k2] = packh2(f2.x, f2.y);
        }
        __syncthreads();

        float c[2][8][4] = {};
        #pragma unroll
        for (int ks = 0; ks < 8; ks++) {
            int k0 = ks * 8;
            uint32_t a[2][4];
            #pragma unroll
            for (int rt = 0; rt < 2; rt++) {
                int r = wr * 32 + rt * 16 + grp;
                a[rt][0] = smu[R_A + r * 68 + k0 + tig];
                a[rt][1] = smu[R_A + (r + 8) * 68 + k0 + tig];
                a[rt][2] = smu[R_A + r * 68 + k0 + 4 + tig];
                a[rt][3] = smu[R_A + (r + 8) * 68 + k0 + 4 + tig];
            }
            #pragma unroll
            for (int j = 0; j < 8; j++) {
                uint2 Bf = *(const uint2*)&smu[R_W + wc * 4096 + ((ks * 8 + j) * 32 + lane) * 2];
                #pragma unroll
                for (int rt = 0; rt < 2; rt++)
                    mma_f16(c[rt][j], a[rt][0], a[rt][1], a[rt][2], a[rt][3], Bf.x, Bf.y);
            }
        }

        // epilogue: softplus + Wout dot, reduce over this warp's 64 cols
        #pragma unroll
        for (int rt = 0; rt < 2; rt++) {
            float p0 = 0.f, p1 = 0.f;
            #pragma unroll
            for (int j = 0; j < 8; j++) {
                p0 += spf(c[rt][j][0] + bhr[j][0]) * wor[j][0]
                    + spf(c[rt][j][1] + bhr[j][1]) * wor[j][1];
                p1 += spf(c[rt][j][2] + bhr[j][0]) * wor[j][0]
                    + spf(c[rt][j][3] + bhr[j][1]) * wor[j][1];
            }
            p0 += __shfl_xor_sync(0xffffffffu, p0, 1);
            p0 += __shfl_xor_sync(0xffffffffu, p0, 2);
            p1 += __shfl_xor_sync(0xffffffffu, p1, 1);
            p1 += __shfl_xor_sync(0xffffffffu, p1, 2);
            if (tig == 0) {
                int r = wr * 32 + rt * 16 + grp;
                sm[R_RED + r * 4 + wc]       = p0;
                sm[R_RED + (r + 8) * 4 + wc] = p1;
            }
        }
        __syncthreads();
        if (tid < 64) {
            float4 s4 = *(const float4*)&sm[R_RED + tid * 4];
            g_site[t * 64 + tid] = s4.x + s4.y + s4.z + s4.w + b0;
        }
        __syncthreads();
    }
}

// ============================================================================
// Kernel 5: per-crystal sum
// ============================================================================
__global__ void k_crystal(float* __restrict__ out) {
    __shared__ float red[8];
    int c = blockIdx.x, tid = threadIdx.x;
    float v = g_site[c * APC + tid];
    #pragma unroll
    for (int o = 16; o > 0; o >>= 1)
        v += __shfl_xor_sync(0xffffffffu, v, o);
    if ((tid & 31) == 0) red[tid >> 5] = v;
    __syncthreads();
    if (tid == 0) {
        float s = 0.f;
        #pragma unroll
        for (int i = 0; i < 8; i++) s += red[i];
        out[c] = s;
    }
}

// ============================================================================
extern "C" void kernel_launch(void* const* d_in, const int* in_sizes, int n_in,
                              void* d_out, int out_size) {
    const float* atom_fea = (const float*)d_in[0];
    const float* nbr_fea  = (const float*)d_in[1];
    const int*   nbr_idx  = (const int*)  d_in[2];
    const float* W_embed  = (const float*)d_in[3];
    const float* b_embed  = (const float*)d_in[4];
    const float* W_center = (const float*)d_in[5];
    const float* b_center = (const float*)d_in[6];
    const float* W_nbr    = (const float*)d_in[7];
    const float* b_nbr    = (const float*)d_in[8];
    const float* W_edge   = (const float*)d_in[9];
    const float* b_edge   = (const float*)d_in[10];
    const float* W_gate   = (const float*)d_in[11];
    const float* b_gate   = (const float*)d_in[12];
    const float* W_mag    = (const float*)d_in[13];
    const float* b_mag    = (const float*)d_in[14];
    const float* ln_scale = (const float*)d_in[15];
    const float* ln_bias  = (const float*)d_in[16];
    const float* W_h      = (const float*)d_in[17];
    const float* b_h      = (const float*)d_in[18];
    const float* W_out    = (const float*)d_in[19];
    const float* b_out    = (const float*)d_in[20];
    float* out = (float*)d_out;

    cudaFuncSetAttribute(k_embed,   cudaFuncAttributeMaxDynamicSharedMemorySize, E_SMEM);
    cudaFuncSetAttribute(k_convA,   cudaFuncAttributeMaxDynamicSharedMemorySize, A2_SMEM);
    cudaFuncSetAttribute(k_conv,    cudaFuncAttributeMaxDynamicSharedMemorySize, CV_SMEM);
    cudaFuncSetAttribute(k_readout, cudaFuncAttributeMaxDynamicSharedMemorySize, R_SMEM);

    k_pack<<<2048, 256>>>(nbr_fea);
    k_embed<<<148, 256, E_SMEM>>>(atom_fea, W_embed, b_embed);
    for (int l = 0; l < NCONV; l++) {
        k_convA<<<148, 256, A2_SMEM>>>(W_center + l * FDIM * FDIM, b_center + l * FDIM,
                                       W_nbr    + l * FDIM * FDIM, b_nbr    + l * FDIM);
        k_conv<<<148, CV_THREADS, CV_SMEM>>>(nbr_idx,
                                      W_gate + l * FDIM * FDIM, b_gate + l * FDIM,
                                      W_mag  + l * FDIM * FDIM, b_mag  + l * FDIM,
                                      W_edge + l * EDGE * FDIM, b_edge + l * FDIM,
                                      ln_scale + l * FDIM, ln_bias + l * FDIM);
    }
    k_readout<<<148, 256, R_SMEM>>>(W_h, b_h, W_out, b_out);
    k_crystal<<<NCRY, 256>>>(out);
}

// round 13
// speedup vs baseline: 5.3465x; 1.0108x over previous
#include <cuda_runtime.h>
#include <cuda_fp16.h>
#include <math.h>
#include <cstdint>

#define N_ATOMS 32768
#define MNBR    12
#define PROWS   16
#define ORIG    92
#define EDGE    41
#define FDIM    128
#define HDIM    256
#define NCONV   3
#define NCRY    128
#define APC     256
#define NT2     (N_ATOMS / 2)             // 16384 atom-pair tiles
#define ATILE   (N_ATOMS / 64)            // 512

// ---- scratch ----
__device__ float    g_x [N_ATOMS * FDIM];
__device__ float    g_pc[N_ATOMS * FDIM];
__device__ float    g_yn[N_ATOMS * FDIM];
__device__ uint32_t g_nbrh[NT2 * 768];     // fp16 edge features, fragment order
__device__ float    g_site[N_ATOMS];

__device__ __forceinline__ uint32_t smem_u32(const void* p) {
    uint32_t a;
    asm("{ .reg .u64 t; cvta.to.shared.u64 t, %1; cvt.u32.u64 %0, t; }" : "=r"(a) : "l"(p));
    return a;
}
__device__ __forceinline__ uint32_t packh2(float a, float b) {
    __half2 h = __floats2half2_rn(a, b);
    return *(uint32_t*)&h;
}
__device__ __forceinline__ void mma_f16(float c[4], uint32_t a0, uint32_t a1,
                                        uint32_t a2, uint32_t a3,
                                        uint32_t b0, uint32_t b1) {
    asm volatile("mma.sync.aligned.m16n8k16.row.col.f32.f16.f16.f32 "
        "{%0,%1,%2,%3}, {%4,%5,%6,%7}, {%8,%9}, {%0,%1,%2,%3};"
        : "+f"(c[0]), "+f"(c[1]), "+f"(c[2]), "+f"(c[3])
        : "r"(a0), "r"(a1), "r"(a2), "r"(a3), "r"(b0), "r"(b1));
}
__device__ __forceinline__ float act(float g, float m) {
    float sig = __fdividef(1.f, 1.f + __expf(-g));
    float sp  = fmaxf(m, 0.f) + __logf(1.f + __expf(-fabsf(m)));
    return sig * sp;
}
__device__ __forceinline__ float spf(float x) {
    return fmaxf(x, 0.f) + __logf(1.f + __expf(-fabsf(x)));
}

extern __shared__ float sm[];

// ============================================================================
// Kernel 0: pack nbr_fea -> fp16 FRAGMENT-ORDER per 2-atom tile (768 u32)
// ============================================================================
__global__ void k_pack(const float* __restrict__ nbr_fea) {
    int total = NT2 * 768;
    for (int idx = blockIdx.x * 256 + threadIdx.x; idx < total; idx += gridDim.x * 256) {
        int s = idx / 768, f = idx - s * 768;
        int c = f & 3, q = f >> 2;
        int lane = q & 31, rks = q >> 5;
        int rt = rks / 3, ks = rks - rt * 3;
        int tig = lane & 3, grp = lane >> 2;
        int slot = c >> 1, rowbit = c & 1;
        int m = grp + rowbit * 8;
        int k2 = ks * 8 + slot * 4 + tig;
        float v0 = 0.f, v1 = 0.f;
        if (m < MNBR) {
            size_t base = ((size_t)(s * 2 + rt) * MNBR + m) * EDGE;
            if (2 * k2     < EDGE) v0 = nbr_fea[base + 2 * k2];
            if (2 * k2 + 1 < EDGE) v1 = nbr_fea[base + 2 * k2 + 1];
        }
        g_nbrh[idx] = packh2(v0, v1);
    }
}

// ============================================================================
// Kernel 1: k_embed — fp16 mma GEMM: x = atom_fea @ W_embed + b
// ============================================================================
#define E_W    0        // 6144 u32, fragment order
#define E_A    6144     // 64 x 52 u32
#define E_BIAS 9472     // 128 f
#define E_TOT  9600
#define E_SMEM (E_TOT * 4)

__global__ void __launch_bounds__(256, 1)
k_embed(const float* __restrict__ atom_fea,
        const float* __restrict__ W, const float* __restrict__ b) {
    int tid = threadIdx.x, wid = tid >> 5, lane = tid & 31;
    uint32_t* smu = (uint32_t*)sm;
    for (int i = tid; i < 6144; i += 256) {
        int wc0 = i / 1536, rem = i - wc0 * 1536;
        int c = rem & 1, idx = rem >> 1;
        int ln = idx & 31, ksj = idx >> 5;
        int ks = ksj >> 2, j = ksj & 3;
        int tg = ln & 3, gp = ln >> 2;
        int n = wc0 * 32 + j * 8 + gp;
        int k2 = ks * 8 + c * 4 + tg;
        float v0 = (2 * k2     < ORIG) ? W[(2 * k2) * FDIM + n]     : 0.f;
        float v1 = (2 * k2 + 1 < ORIG) ? W[(2 * k2 + 1) * FDIM + n] : 0.f;
        smu[E_W + i] = packh2(v0, v1);
    }
    if (tid < FDIM) sm[E_BIAS + tid] = b[tid];
    __syncthreads();

    int wr = wid >> 2, wc = wid & 3;
    int tig = lane & 3, grp = lane >> 2;
    float br[4][2];
    #pragma unroll
    for (int j = 0; j < 4; j++) {
        int n0 = wc * 32 + j * 8 + 2 * tig;
        br[j][0] = sm[E_BIAS + n0]; br[j][1] = sm[E_BIAS + n0 + 1];
    }

    for (int t = blockIdx.x; t < ATILE; t += gridDim.x) {
        #pragma unroll
        for (int q = 0; q < 12; q++) {
            int i = tid + q * 256;
            int r = i / 48, k2 = i - r * 48;
            uint32_t v = 0u;
            if (k2 < 46) {
                float2 f2 = *(const float2*)&atom_fea[(size_t)(t * 64 + r) * ORIG + 2 * k2];
                v = packh2(f2.x, f2.y);
            }
            smu[E_A + r * 52 + k2] = v;
        }
        __syncthreads();

        float c[2][4][4] = {};
        #pragma unroll
        for (int ks = 0; ks < 6; ks++) {
            int k0 = ks * 8;
            uint32_t a[2][4];
            #pragma unroll
            for (int rt = 0; rt < 2; rt++) {
                int r = wr * 32 + rt * 16 + grp;
                a[rt][0] = smu[E_A + r * 52 + k0 + tig];
                a[rt][1] = smu[E_A + (r + 8) * 52 + k0 + tig];
                a[rt][2] = smu[E_A + r * 52 + k0 + 4 + tig];
                a[rt][3] = smu[E_A + (r + 8) * 52 + k0 + 4 + tig];
            }
            #pragma unroll
            for (int j = 0; j < 4; j++) {
                uint2 Bf = *(const uint2*)&smu[E_W + wc * 1536 + ((ks * 4 + j) * 32 + lane) * 2];
                #pragma unroll
                for (int rt = 0; rt < 2; rt++)
                    mma_f16(c[rt][j], a[rt][0], a[rt][1], a[rt][2], a[rt][3], Bf.x, Bf.y);
            }
        }

        #pragma unroll
        for (int rt = 0; rt < 2; rt++) {
            int r0 = t * 64 + wr * 32 + rt * 16 + grp;
            #pragma unroll
            for (int j = 0; j < 4; j++) {
                int n0 = wc * 32 + j * 8 + 2 * tig;
                *(float2*)&g_x[r0 * FDIM + n0] =
                    make_float2(c[rt][j][0] + br[j][0], c[rt][j][1] + br[j][1]);
                *(float2*)&g_x[(r0 + 8) * FDIM + n0] =
                    make_float2(c[rt][j][2] + br[j][0], c[rt][j][3] + br[j][1]);
            }
        }
        __syncthreads();
    }
}

// ============================================================================
// Kernel 2: k_convA — fp16 mma GEMM: [phi_c|y_nbr] = x @ [Wc|Wn] + bias
//   M=64/tile, N=2x128, K=128. B fragment uint4 = {pc0,pc1,yn0,yn1}.
// ============================================================================
#define CA_W    0        // 16384 u32, fragment order
#define CA_A    16384    // 64 x 68 u32
#define CA_BIAS 20736    // 256 f
#define CA_TOT  20992
#define CA_SMEM (CA_TOT * 4)

__global__ void __launch_bounds__(256, 1)
k_convA(const float* __restrict__ Wc, const float* __restrict__ bc,
        const float* __restrict__ Wn, const float* __restrict__ bn) {
    int tid = threadIdx.x, wid = tid >> 5, lane = tid & 31;
    uint32_t* smu = (uint32_t*)sm;
    // pack B: i = wc*4096 + (((ks*4+j)*32+ln)*4 + c);  c<2 -> Wc, c>=2 -> Wn
    for (int i = tid; i < 16384; i += 256) {
        int wc0 = i >> 12, rem = i & 4095;
        int c = rem & 3, idx4 = rem >> 2;
        int ln = idx4 & 31, ksj = idx4 >> 5;
        int ks = ksj >> 2, j = ksj & 3;
        int tg = ln & 3, gp = ln >> 2;
        int n = wc0 * 32 + j * 8 + gp;
        int k2 = ks * 8 + (c & 1) * 4 + tg;
        const float* W = (c < 2) ? Wc : Wn;
        smu[CA_W + i] = packh2(W[(2 * k2) * FDIM + n], W[(2 * k2 + 1) * FDIM + n]);
    }
    if (tid < 128) { sm[CA_BIAS + tid] = bc[tid]; sm[CA_BIAS + 128 + tid] = bn[tid]; }
    __syncthreads();

    int wr = wid >> 2, wc = wid & 3;
    int tig = lane & 3, grp = lane >> 2;
    float bcr[4][2], bnr[4][2];
    #pragma unroll
    for (int j = 0; j < 4; j++) {
        int f0 = wc * 32 + j * 8 + 2 * tig;
        bcr[j][0] = sm[CA_BIAS + f0];       bcr[j][1] = sm[CA_BIAS + f0 + 1];
        bnr[j][0] = sm[CA_BIAS + 128 + f0]; bnr[j][1] = sm[CA_BIAS + 128 + f0 + 1];
    }

    for (int t = blockIdx.x; t < ATILE; t += gridDim.x) {
        // stage A tile as fp16 k-pairs, pitch 68
        #pragma unroll
        for (int q = 0; q < 16; q++) {
            int i = tid + q * 256;                 // 4096 = 64 x 64
            int r = i >> 6, k2 = i & 63;
            float2 f2 = *(const float2*)&g_x[(size_t)(t * 64 + r) * FDIM + 2 * k2];
            smu[CA_A + r * 68 + k2] = packh2(f2.x, f2.y);
        }
        __syncthreads();

        float cpc[2][4][4] = {}, cyn[2][4][4] = {};
        #pragma unroll
        for (int ks = 0; ks < 8; ks++) {
            int k0 = ks * 8;
            uint32_t a[2][4];
            #pragma unroll
            for (int rt = 0; rt < 2; rt++) {
                int r = wr * 32 + rt * 16 + grp;
                a[rt][0] = smu[CA_A + r * 68 + k0 + tig];
                a[rt][1] = smu[CA_A + (r + 8) * 68 + k0 + tig];
                a[rt][2] = smu[CA_A + r * 68 + k0 + 4 + tig];
                a[rt][3] = smu[CA_A + (r + 8) * 68 + k0 + 4 + tig];
            }
            #pragma unroll
            for (int j = 0; j < 4; j++) {
                uint4 Bf = *(const uint4*)&smu[CA_W + wc * 4096 + ((ks * 4 + j) * 32 + lane) * 4];
                #pragma unroll
                for (int rt = 0; rt < 2; rt++) {
                    mma_f16(cpc[rt][j], a[rt][0], a[rt][1], a[rt][2], a[rt][3], Bf.x, Bf.y);
                    mma_f16(cyn[rt][j], a[rt][0], a[rt][1], a[rt][2], a[rt][3], Bf.z, Bf.w);
                }
            }
        }

        #pragma unroll
        for (int rt = 0; rt < 2; rt++) {
            int r0 = t * 64 + wr * 32 + rt * 16 + grp;
            #pragma unroll
            for (int j = 0; j < 4; j++) {
                int f0 = wc * 32 + j * 8 + 2 * tig;
                *(float2*)&g_pc[r0 * FDIM + f0] =
                    make_float2(cpc[rt][j][0] + bcr[j][0], cpc[rt][j][1] + bcr[j][1]);
                *(float2*)&g_pc[(r0 + 8) * FDIM + f0] =
                    make_float2(cpc[rt][j][2] + bcr[j][0], cpc[rt][j][3] + bcr[j][1]);
                *(float2*)&g_yn[r0 * FDIM + f0] =
                    make_float2(cyn[rt][j][0] + bnr[j][0], cyn[rt][j][1] + bnr[j][1]);
                *(float2*)&g_yn[(r0 + 8) * FDIM + f0] =
                    make_float2(cyn[rt][j][2] + bnr[j][0], cyn[rt][j][3] + bnr[j][1]);
            }
        }
        __syncthreads();
    }
}

// ============================================================================
// Kernel 3: k_conv — fused conv layer (unchanged from round 12)
// ============================================================================
#define S_W     0
#define S_WE    16384
#define S_BIAS  19456
#define S_GRP   20096
#define GP_AGM  0
#define GP_AE   2048
#define GP_YN   4352
#define GP_RED  11216
#define GP_IDX  11472
#define GRPSZ   11568
#define S_TOT   (S_GRP + 2 * GRPSZ)
#define CV_SMEM (S_TOT * 4)
#define CV_THREADS 512

__device__ __forceinline__ void stage_ae_h(uint32_t dstbase, const char* __restrict__ src,
                                           int gtid) {
    if (gtid < 192) {
        asm volatile("cp.async.ca.shared.global [%0], [%1], 16;"
                     :: "r"(dstbase + (uint32_t)gtid * 16),
                        "l"(src + (size_t)gtid * 16) : "memory");
    }
}

__device__ __forceinline__ void stage_yn(uint32_t dstbase, const int* __restrict__ sx,
                                         int tn, int gtid) {
    #pragma unroll
    for (int q = 0; q < 4; q++) {
        int i = gtid + q * 256;
        if (i < 832) {
            int row = i >> 5, c = i & 31;
            const float* src = (row < 24)
                ? g_yn + (size_t)sx[row] * FDIM + c * 4
                : g_pc + ((size_t)tn * 2 + (row - 24)) * FDIM + c * 4;
            uint32_t d = dstbase + (uint32_t)(row * 132 + c * 4) * 4;
            asm volatile("cp.async.ca.shared.global [%0], [%1], 16;"
                         :: "r"(d), "l"(src) : "memory");
        }
    }
}

__global__ void __launch_bounds__(CV_THREADS, 1)
k_conv(const int* __restrict__ nbr_idx,
       const float* __restrict__ Wg, const float* __restrict__ bg,
       const float* __restrict__ Wm, const float* __restrict__ bm,
       const float* __restrict__ We, const float* __restrict__ be,
       const float* __restrict__ lns, const float* __restrict__ lnb) {
    int tid = threadIdx.x, wid = tid >> 5, lane = tid & 31;
    int half = wid >> 3, wg = wid & 7, gtid = tid & 255;
    uint32_t* smu = (uint32_t*)sm;

    for (int i = tid; i < 16384; i += CV_THREADS) {
        int wgo = i >> 11, rem = i & 2047;
        int c = rem & 3, idx4 = rem >> 2;
        int ln = idx4 & 31, ksj = idx4 >> 5;
        int ks = ksj >> 1, j = ksj & 1;
        int tg = ln & 3, gp = ln >> 2;
        int n = wgo * 16 + j * 8 + gp;
        int k2 = ks * 8 + (c & 1) * 4 + tg;
        const float* W = (c < 2) ? Wg : Wm;
        smu[S_W + i] = packh2(W[(2 * k2) * FDIM + n], W[(2 * k2 + 1) * FDIM + n]);
    }
    for (int i = tid; i < 3072; i += CV_THREADS) {
        int wgo = i / 384, rem = i - wgo * 384;
        int c = rem & 1, idx2 = rem >> 1;
        int ln = idx2 & 31, ksj = idx2 >> 5;
        int ks = ksj >> 1, j = ksj & 1;
        int tg = ln & 3, gp = ln >> 2;
        int n = wgo * 16 + j * 8 + gp;
        int k2 = ks * 8 + c * 4 + tg;
        float v0 = (2 * k2     < EDGE) ? We[(2 * k2) * FDIM + n]     : 0.f;
        float v1 = (2 * k2 + 1 < EDGE) ? We[(2 * k2 + 1) * FDIM + n] : 0.f;
        smu[S_WE + i] = packh2(v0, v1);
    }
    if (tid < FDIM) {
        sm[S_BIAS + tid]       = bg[tid];
        sm[S_BIAS + 128 + tid] = bm[tid];
        sm[S_BIAS + 256 + tid] = lns[tid];
        sm[S_BIAS + 384 + tid] = lnb[tid];
        sm[S_BIAS + 512 + tid] = be[tid];
    }

    int gbase = S_GRP + half * GRPSZ;
    int* sidx3 = (int*)(sm + gbase + GP_IDX);
    uint32_t aeRaw = smem_u32(sm + gbase + GP_AE);
    uint32_t ynRaw = smem_u32(sm + gbase + GP_YN);
    int tig = lane & 3, grp = lane >> 2;
    bool notpad = (grp < 4);
    int barid = half + 1;

    int stride = 2 * gridDim.x;
    int s0 = blockIdx.x * 2 + half;

    __syncthreads();

    if (gtid < 24) {
        sidx3[gtid] = nbr_idx[s0 * 24 + gtid];
        if (s0 + stride < NT2)
            sidx3[24 + gtid] = nbr_idx[(s0 + stride) * 24 + gtid];
    }
    stage_ae_h(aeRaw, (const char*)(g_nbrh + (size_t)s0 * 768), gtid);
    if (s0 + stride < NT2)
        stage_ae_h(aeRaw + 768u * 4, (const char*)(g_nbrh + (size_t)(s0 + stride) * 768), gtid);
    asm volatile("cp.async.commit_group;" ::: "memory");
    asm volatile("cp.async.wait_group 0;" ::: "memory");
    asm volatile("bar.sync %0, %1;" :: "r"(barid), "r"(256) : "memory");

    stage_yn(ynRaw, sidx3, s0, gtid);
    asm volatile("cp.async.commit_group;" ::: "memory");
    asm volatile("cp.async.wait_group 0;" ::: "memory");
    asm volatile("bar.sync %0, %1;" :: "r"(barid), "r"(256) : "memory");

    float bgr[2][2], bmr[2][2], ber[2][2];
    #pragma unroll
    for (int j = 0; j < 2; j++) {
        int f0 = wg * 16 + j * 8 + 2 * tig;
        bgr[j][0] = sm[S_BIAS + f0];        bgr[j][1] = sm[S_BIAS + f0 + 1];
        bmr[j][0] = sm[S_BIAS + 128 + f0];  bmr[j][1] = sm[S_BIAS + 128 + f0 + 1];
        ber[j][0] = sm[S_BIAS + 512 + f0];  ber[j][1] = sm[S_BIAS + 512 + f0 + 1];
    }
    float4 lns4 = *(const float4*)&sm[S_BIAS + 256 + lane * 4];
    float4 lnb4 = *(const float4*)&sm[S_BIAS + 384 + lane * 4];

    int b2 = 0, b3 = 0;
    for (int t = s0; t < NT2; t += stride) {
        int aeB = gbase + GP_AE + b3 * 768;
        int ynB = gbase + GP_YN + b2 * 3432;

        if (t + stride < NT2)
            stage_yn(ynRaw + (uint32_t)(b2 ^ 1) * 3432 * 4,
                     sidx3 + ((b3 + 1) % 3) * 24, t + stride, gtid);
        asm volatile("cp.async.commit_group;" ::: "memory");

        int t2 = t + 2 * stride;
        if (t2 < NT2) {
            int ib = (b3 + 2) % 3;
            if (gtid < 24) sidx3[ib * 24 + gtid] = nbr_idx[t2 * 24 + gtid];
            stage_ae_h(aeRaw + (uint32_t)ib * 768 * 4,
                       (const char*)(g_nbrh + (size_t)t2 * 768), gtid);
        }
        asm volatile("cp.async.commit_group;" ::: "memory");

        float ce[2][2][4] = {};
        #pragma unroll
        for (int ks = 0; ks < 3; ks++) {
            uint4 A[2];
            #pragma unroll
            for (int rt = 0; rt < 2; rt++)
                A[rt] = *(const uint4*)&smu[aeB + ((rt * 3 + ks) * 32 + lane) * 4];
            #pragma unroll
            for (int j = 0; j < 2; j++) {
                uint2 Bf = *(const uint2*)&smu[S_WE + wg * 384 + ((ks * 2 + j) * 32 + lane) * 2];
                #pragma unroll
                for (int rt = 0; rt < 2; rt++)
                    mma_f16(ce[rt][j], A[rt].x, A[rt].y, A[rt].z, A[rt].w, Bf.x, Bf.y);
            }
        }

        #pragma unroll
        for (int rt = 0; rt < 2; rt++) {
            int yr0 = ynB + (rt * 12 + grp) * 132;
            int pr  = ynB + (24 + rt) * 132;
            #pragma unroll
            for (int j = 0; j < 2; j++) {
                int f0 = wg * 16 + j * 8 + 2 * tig;
                float2 pc2 = *(const float2*)&sm[pr + f0];
                float2 y0  = *(const float2*)&sm[yr0 + f0];
                uint32_t lo = packh2(pc2.x * y0.x * (ce[rt][j][0] + ber[j][0]),
                                     pc2.y * y0.y * (ce[rt][j][1] + ber[j][1]));
                uint32_t hi = 0u;
                if (notpad) {
                    float2 y1 = *(const float2*)&sm[yr0 + 8 * 132 + f0];
                    hi = packh2(pc2.x * y1.x * (ce[rt][j][2] + ber[j][0]),
                                pc2.y * y1.y * (ce[rt][j][3] + ber[j][1]));
                }
                *(uint2*)&smu[gbase + GP_AGM + ((rt * 8 + wg) * 32 + lane) * 4 + j * 2] =
                    make_uint2(lo, hi);
            }
        }
        asm volatile("bar.sync %0, %1;" :: "r"(barid), "r"(256) : "memory");

        float cg[2][2][4] = {}, cmm[2][2][4] = {};
        #pragma unroll
        for (int ks = 0; ks < 8; ks++) {
            uint4 A[2];
            #pragma unroll
            for (int rt = 0; rt < 2; rt++)
                A[rt] = *(const uint4*)&smu[gbase + GP_AGM + ((rt * 8 + ks) * 32 + lane) * 4];
            #pragma unroll
            for (int j = 0; j < 2; j++) {
                uint4 Bf = *(const uint4*)&smu[S_W + wg * 2048 + ((ks * 2 + j) * 32 + lane) * 4];
                #pragma unroll
                for (int rt = 0; rt < 2; rt++) {
                    mma_f16(cg[rt][j],  A[rt].x, A[rt].y, A[rt].z, A[rt].w, Bf.x, Bf.y);
                    mma_f16(cmm[rt][j], A[rt].x, A[rt].y, A[rt].z, A[rt].w, Bf.z, Bf.w);
                }
            }
        }

        #pragma unroll
        for (int rt = 0; rt < 2; rt++) {
            #pragma unroll
            for (int j = 0; j < 2; j++) {
                float p0 = act(cg[rt][j][0] + bgr[j][0], cmm[rt][j][0] + bmr[j][0]);
                float p1 = act(cg[rt][j][1] + bgr[j][1], cmm[rt][j][1] + bmr[j][1]);
                if (notpad) {
                    p0 += act(cg[rt][j][2] + bgr[j][0], cmm[rt][j][2] + bmr[j][0]);
                    p1 += act(cg[rt][j][3] + bgr[j][1], cmm[rt][j][3] + bmr[j][1]);
                }
                #pragma unroll
                for (int o = 4; o < 32; o <<= 1) {
                    p0 += __shfl_xor_sync(0xffffffffu, p0, o);
                    p1 += __shfl_xor_sync(0xffffffffu, p1, o);
                }
                if (grp == 0) {
                    int f0 = wg * 16 + j * 8 + 2 * tig;
                    sm[gbase + GP_RED + rt * 128 + f0]     = p0;
                    sm[gbase + GP_RED + rt * 128 + f0 + 1] = p1;
                }
            }
        }
        asm volatile("cp.async.wait_group 1;" ::: "memory");
        asm volatile("bar.sync %0, %1;" :: "r"(barid), "r"(256) : "memory");

        if (wg < 2) {
            float4 v = *(const float4*)&sm[gbase + GP_RED + wg * 128 + lane * 4];
            float s = v.x + v.y + v.z + v.w;
            float q = v.x*v.x + v.y*v.y + v.z*v.z + v.w*v.w;
            #pragma unroll
            for (int o = 16; o > 0; o >>= 1) {
                s += __shfl_xor_sync(0xffffffffu, s, o);
                q += __shfl_xor_sync(0xffffffffu, q, o);
            }
            float mu = s * (1.f / FDIM);
            float var = q * (1.f / FDIM) - mu * mu;
            float rstd = rsqrtf(var + 1e-6f);
            int n = t * 2 + wg;
            float4 x = *(float4*)&g_x[n * FDIM + lane * 4];
            x.x += (v.x - mu) * rstd * lns4.x + lnb4.x;
            x.y += (v.y - mu) * rstd * lns4.y + lnb4.y;
            x.z += (v.z - mu) * rstd * lns4.z + lnb4.z;
            x.w += (v.w - mu) * rstd * lns4.w + lnb4.w;
            *(float4*)&g_x[n * FDIM + lane * 4] = x;
        }
        b2 ^= 1;
        b3 = (b3 + 1) % 3;
    }
}

// ============================================================================
// Kernel 4: k_readout — fp16 mma GEMM + fused softplus.Wout (unchanged)
// ============================================================================
#define R_W    0
#define R_A    16384
#define R_BH   20736
#define R_WO   20992
#define R_RED  21248
#define R_TOT  21504
#define R_SMEM (R_TOT * 4)

__global__ void __launch_bounds__(256, 1)
k_readout(const float* __restrict__ Wh, const float* __restrict__ bh,
          const float* __restrict__ Wout, const float* __restrict__ bout) {
    int tid = threadIdx.x, wid = tid >> 5, lane = tid & 31;
    uint32_t* smu = (uint32_t*)sm;
    for (int i = tid; i < 16384; i += 256) {
        int wc0 = i >> 12, rem = i & 4095;
        int c = rem & 1, idx = rem >> 1;
        int ln = idx & 31, ksj = idx >> 5;
        int ks = ksj >> 3, j = ksj & 7;
        int tg = ln & 3, gp = ln >> 2;
        int n = wc0 * 64 + j * 8 + gp;
        int k2 = ks * 8 + c * 4 + tg;
        smu[R_W + i] = packh2(Wh[(2 * k2) * HDIM + n], Wh[(2 * k2 + 1) * HDIM + n]);
    }
    sm[R_BH + tid] = bh[tid];
    sm[R_WO + tid] = Wout[tid];
    __syncthreads();

    int wr = wid >> 2, wc = wid & 3;
    int tig = lane & 3, grp = lane >> 2;
    float b0 = bout[0];
    float bhr[8][2], wor[8][2];
    #pragma unroll
    for (int j = 0; j < 8; j++) {
        int n0 = wc * 64 + j * 8 + 2 * tig;
        bhr[j][0] = sm[R_BH + n0]; bhr[j][1] = sm[R_BH + n0 + 1];
        wor[j][0] = sm[R_WO + n0]; wor[j][1] = sm[R_WO + n0 + 1];
    }

    for (int t = blockIdx.x; t < ATILE; t += gridDim.x) {
        #pragma unroll
        for (int q = 0; q < 16; q++) {
            int i = tid + q * 256;
            int r = i >> 6, k2 = i & 63;
            float2 f2 = *(const float2*)&g_x[(size_t)(t * 64 + r) * FDIM + 2 * k2];
            smu[R_A + r * 68 + k2] = packh2(f2.x, f2.y);
        }
        __syncthreads();

        float c[2][8][4] = {};
        #pragma unroll
        for (int ks = 0; ks < 8; ks++) {
            int k0 = ks * 8;
            uint32_t a[2][4];
            #pragma unroll
            for (int rt = 0; rt < 2; rt++) {
                int r = wr * 32 + rt * 16 + grp;
                a[rt][0] = smu[R_A + r * 68 + k0 + tig];
                a[rt][1] = smu[R_A + (r + 8) * 68 + k0 + tig];
                a[rt][2] = smu[R_A + r * 68 + k0 + 4 + tig];
                a[rt][3] = smu[R_A + (r + 8) * 68 + k0 + 4 + tig];
            }
            #pragma unroll
            for (int j = 0; j < 8; j++) {
                uint2 Bf = *(const uint2*)&smu[R_W + wc * 4096 + ((ks * 8 + j) * 32 + lane) * 2];
                #pragma unroll
                for (int rt = 0; rt < 2; rt++)
                    mma_f16(c[rt][j], a[rt][0], a[rt][1], a[rt][2], a[rt][3], Bf.x, Bf.y);
            }
        }

        #pragma unroll
        for (int rt = 0; rt < 2; rt++) {
            float p0 = 0.f, p1 = 0.f;
            #pragma unroll
            for (int j = 0; j < 8; j++) {
                p0 += spf(c[rt][j][0] + bhr[j][0]) * wor[j][0]
                    + spf(c[rt][j][1] + bhr[j][1]) * wor[j][1];
                p1 += spf(c[rt][j][2] + bhr[j][0]) * wor[j][0]
                    + spf(c[rt][j][3] + bhr[j][1]) * wor[j][1];
            }
            p0 += __shfl_xor_sync(0xffffffffu, p0, 1);
            p0 += __shfl_xor_sync(0xffffffffu, p0, 2);
            p1 += __shfl_xor_sync(0xffffffffu, p1, 1);
            p1 += __shfl_xor_sync(0xffffffffu, p1, 2);
            if (tig == 0) {
                int r = wr * 32 + rt * 16 + grp;
                sm[R_RED + r * 4 + wc]       = p0;
                sm[R_RED + (r + 8) * 4 + wc] = p1;
            }
        }
        __syncthreads();
        if (tid < 64) {
            float4 s4 = *(const float4*)&sm[R_RED + tid * 4];
            g_site[t * 64 + tid] = s4.x + s4.y + s4.z + s4.w + b0;
        }
        __syncthreads();
    }
}

// ============================================================================
// Kernel 5: per-crystal sum
// ============================================================================
__global__ void k_crystal(float* __restrict__ out) {
    __shared__ float red[8];
    int c = blockIdx.x, tid = threadIdx.x;
    float v = g_site[c * APC + tid];
    #pragma unroll
    for (int o = 16; o > 0; o >>= 1)
        v += __shfl_xor_sync(0xffffffffu, v, o);
    if ((tid & 31) == 0) red[tid >> 5] = v;
    __syncthreads();
    if (tid == 0) {
        float s = 0.f;
        #pragma unroll
        for (int i = 0; i < 8; i++) s += red[i];
        out[c] = s;
    }
}

// ============================================================================
extern "C" void kernel_launch(void* const* d_in, const int* in_sizes, int n_in,
                              void* d_out, int out_size) {
    const float* atom_fea = (const float*)d_in[0];
    const float* nbr_fea  = (const float*)d_in[1];
    const int*   nbr_idx  = (const int*)  d_in[2];
    const float* W_embed  = (const float*)d_in[3];
    const float* b_embed  = (const float*)d_in[4];
    const float* W_center = (const float*)d_in[5];
    const float* b_center = (const float*)d_in[6];
    const float* W_nbr    = (const float*)d_in[7];
    const float* b_nbr    = (const float*)d_in[8];
    const float* W_edge   = (const float*)d_in[9];
    const float* b_edge   = (const float*)d_in[10];
    const float* W_gate   = (const float*)d_in[11];
    const float* b_gate   = (const float*)d_in[12];
    const float* W_mag    = (const float*)d_in[13];
    const float* b_mag    = (const float*)d_in[14];
    const float* ln_scale = (const float*)d_in[15];
    const float* ln_bias  = (const float*)d_in[16];
    const float* W_h      = (const float*)d_in[17];
    const float* b_h      = (const float*)d_in[18];
    const float* W_out    = (const float*)d_in[19];
    const float* b_out    = (const float*)d_in[20];
    float* out = (float*)d_out;

    cudaFuncSetAttribute(k_embed,   cudaFuncAttributeMaxDynamicSharedMemorySize, E_SMEM);
    cudaFuncSetAttribute(k_convA,   cudaFuncAttributeMaxDynamicSharedMemorySize, CA_SMEM);
    cudaFuncSetAttribute(k_conv,    cudaFuncAttributeMaxDynamicSharedMemorySize, CV_SMEM);
    cudaFuncSetAttribute(k_readout, cudaFuncAttributeMaxDynamicSharedMemorySize, R_SMEM);

    k_pack<<<2048, 256>>>(nbr_fea);
    k_embed<<<148, 256, E_SMEM>>>(atom_fea, W_embed, b_embed);
    for (int l = 0; l < NCONV; l++) {
        k_convA<<<148, 256, CA_SMEM>>>(W_center + l * FDIM * FDIM, b_center + l * FDIM,
                                       W_nbr    + l * FDIM * FDIM, b_nbr    + l * FDIM);
        k_conv<<<148, CV_THREADS, CV_SMEM>>>(nbr_idx,
                                      W_gate + l * FDIM * FDIM, b_gate + l * FDIM,
                                      W_mag  + l * FDIM * FDIM, b_mag  + l * FDIM,
                                      W_edge + l * EDGE * FDIM, b_edge + l * FDIM,
                                      ln_scale + l * FDIM, ln_bias + l * FDIM);
    }
    k_readout<<<148, 256, R_SMEM>>>(W_h, b_h, W_out, b_out);
    k_crystal<<<NCRY, 256>>>(out);
}

// round 14
// speedup vs baseline: 5.6516x; 1.0571x over previous
#include <cuda_runtime.h>
#include <cuda_fp16.h>
#include <math.h>
#include <cstdint>

#define N_ATOMS 32768
#define MNBR    12
#define PROWS   16
#define ORIG    92
#define EDGE    41
#define FDIM    128
#define HDIM    256
#define NCONV   3
#define NCRY    128
#define APC     256
#define NT2     (N_ATOMS / 2)             // 16384 atom-pair tiles
#define ATILE   (N_ATOMS / 64)            // 512

// ---- scratch ----
__device__ float    g_x [N_ATOMS * FDIM];
__device__ uint32_t g_pc[N_ATOMS * 64];    // half2-packed phi_c
__device__ uint32_t g_yn[N_ATOMS * 64];    // half2-packed y_nbr
__device__ uint32_t g_nbrh[NT2 * 768];     // fp16 edge features, fragment order
__device__ float    g_site[N_ATOMS];

__device__ __forceinline__ uint32_t smem_u32(const void* p) {
    uint32_t a;
    asm("{ .reg .u64 t; cvta.to.shared.u64 t, %1; cvt.u32.u64 %0, t; }" : "=r"(a) : "l"(p));
    return a;
}
__device__ __forceinline__ uint32_t packh2(float a, float b) {
    __half2 h = __floats2half2_rn(a, b);
    return *(uint32_t*)&h;
}
__device__ __forceinline__ float2 unpackh2(uint32_t u) {
    return __half22float2(*(__half2*)&u);
}
__device__ __forceinline__ void mma_f16(float c[4], uint32_t a0, uint32_t a1,
                                        uint32_t a2, uint32_t a3,
                                        uint32_t b0, uint32_t b1) {
    asm volatile("mma.sync.aligned.m16n8k16.row.col.f32.f16.f16.f32 "
        "{%0,%1,%2,%3}, {%4,%5,%6,%7}, {%8,%9}, {%0,%1,%2,%3};"
        : "+f"(c[0]), "+f"(c[1]), "+f"(c[2]), "+f"(c[3])
        : "r"(a0), "r"(a1), "r"(a2), "r"(a3), "r"(b0), "r"(b1));
}
__device__ __forceinline__ float act(float g, float m) {
    float sig = __fdividef(1.f, 1.f + __expf(-g));
    float sp  = fmaxf(m, 0.f) + __logf(1.f + __expf(-fabsf(m)));
    return sig * sp;
}
__device__ __forceinline__ float spf(float x) {
    return fmaxf(x, 0.f) + __logf(1.f + __expf(-fabsf(x)));
}

extern __shared__ float sm[];

// ============================================================================
// Kernel 0: pack nbr_fea -> fp16 FRAGMENT-ORDER per 2-atom tile (768 u32)
// ============================================================================
__global__ void k_pack(const float* __restrict__ nbr_fea) {
    int total = NT2 * 768;
    for (int idx = blockIdx.x * 256 + threadIdx.x; idx < total; idx += gridDim.x * 256) {
        int s = idx / 768, f = idx - s * 768;
        int c = f & 3, q = f >> 2;
        int lane = q & 31, rks = q >> 5;
        int rt = rks / 3, ks = rks - rt * 3;
        int tig = lane & 3, grp = lane >> 2;
        int slot = c >> 1, rowbit = c & 1;
        int m = grp + rowbit * 8;
        int k2 = ks * 8 + slot * 4 + tig;
        float v0 = 0.f, v1 = 0.f;
        if (m < MNBR) {
            size_t base = ((size_t)(s * 2 + rt) * MNBR + m) * EDGE;
            if (2 * k2     < EDGE) v0 = nbr_fea[base + 2 * k2];
            if (2 * k2 + 1 < EDGE) v1 = nbr_fea[base + 2 * k2 + 1];
        }
        g_nbrh[idx] = packh2(v0, v1);
    }
}

// ============================================================================
// Kernel 1: k_embed — fp16 mma GEMM: x = atom_fea @ W_embed + b
// ============================================================================
#define E_W    0
#define E_A    6144
#define E_BIAS 9472
#define E_TOT  9600
#define E_SMEM (E_TOT * 4)

__global__ void __launch_bounds__(256, 1)
k_embed(const float* __restrict__ atom_fea,
        const float* __restrict__ W, const float* __restrict__ b) {
    int tid = threadIdx.x, wid = tid >> 5, lane = tid & 31;
    uint32_t* smu = (uint32_t*)sm;
    for (int i = tid; i < 6144; i += 256) {
        int wc0 = i / 1536, rem = i - wc0 * 1536;
        int c = rem & 1, idx = rem >> 1;
        int ln = idx & 31, ksj = idx >> 5;
        int ks = ksj >> 2, j = ksj & 3;
        int tg = ln & 3, gp = ln >> 2;
        int n = wc0 * 32 + j * 8 + gp;
        int k2 = ks * 8 + c * 4 + tg;
        float v0 = (2 * k2     < ORIG) ? W[(2 * k2) * FDIM + n]     : 0.f;
        float v1 = (2 * k2 + 1 < ORIG) ? W[(2 * k2 + 1) * FDIM + n] : 0.f;
        smu[E_W + i] = packh2(v0, v1);
    }
    if (tid < FDIM) sm[E_BIAS + tid] = b[tid];
    __syncthreads();

    int wr = wid >> 2, wc = wid & 3;
    int tig = lane & 3, grp = lane >> 2;
    float br[4][2];
    #pragma unroll
    for (int j = 0; j < 4; j++) {
        int n0 = wc * 32 + j * 8 + 2 * tig;
        br[j][0] = sm[E_BIAS + n0]; br[j][1] = sm[E_BIAS + n0 + 1];
    }

    for (int t = blockIdx.x; t < ATILE; t += gridDim.x) {
        #pragma unroll
        for (int q = 0; q < 12; q++) {
            int i = tid + q * 256;
            int r = i / 48, k2 = i - r * 48;
            uint32_t v = 0u;
            if (k2 < 46) {
                float2 f2 = *(const float2*)&atom_fea[(size_t)(t * 64 + r) * ORIG + 2 * k2];
                v = packh2(f2.x, f2.y);
            }
            smu[E_A + r * 52 + k2] = v;
        }
        __syncthreads();

        float c[2][4][4] = {};
        #pragma unroll
        for (int ks = 0; ks < 6; ks++) {
            int k0 = ks * 8;
            uint32_t a[2][4];
            #pragma unroll
            for (int rt = 0; rt < 2; rt++) {
                int r = wr * 32 + rt * 16 + grp;
                a[rt][0] = smu[E_A + r * 52 + k0 + tig];
                a[rt][1] = smu[E_A + (r + 8) * 52 + k0 + tig];
                a[rt][2] = smu[E_A + r * 52 + k0 + 4 + tig];
                a[rt][3] = smu[E_A + (r + 8) * 52 + k0 + 4 + tig];
            }
            #pragma unroll
            for (int j = 0; j < 4; j++) {
                uint2 Bf = *(const uint2*)&smu[E_W + wc * 1536 + ((ks * 4 + j) * 32 + lane) * 2];
                #pragma unroll
                for (int rt = 0; rt < 2; rt++)
                    mma_f16(c[rt][j], a[rt][0], a[rt][1], a[rt][2], a[rt][3], Bf.x, Bf.y);
            }
        }

        #pragma unroll
        for (int rt = 0; rt < 2; rt++) {
            int r0 = t * 64 + wr * 32 + rt * 16 + grp;
            #pragma unroll
            for (int j = 0; j < 4; j++) {
                int n0 = wc * 32 + j * 8 + 2 * tig;
                *(float2*)&g_x[r0 * FDIM + n0] =
                    make_float2(c[rt][j][0] + br[j][0], c[rt][j][1] + br[j][1]);
                *(float2*)&g_x[(r0 + 8) * FDIM + n0] =
                    make_float2(c[rt][j][2] + br[j][0], c[rt][j][3] + br[j][1]);
            }
        }
        __syncthreads();
    }
}

// ============================================================================
// Kernel 2: k_convA — fp16 mma GEMM: [phi_c|y_nbr] = x @ [Wc|Wn] + bias
//   Output packed half2 into g_pc / g_yn.
// ============================================================================
#define CA_W    0
#define CA_A    16384
#define CA_BIAS 20736
#define CA_TOT  20992
#define CA_SMEM (CA_TOT * 4)

__global__ void __launch_bounds__(256, 1)
k_convA(const float* __restrict__ Wc, const float* __restrict__ bc,
        const float* __restrict__ Wn, const float* __restrict__ bn) {
    int tid = threadIdx.x, wid = tid >> 5, lane = tid & 31;
    uint32_t* smu = (uint32_t*)sm;
    for (int i = tid; i < 16384; i += 256) {
        int wc0 = i >> 12, rem = i & 4095;
        int c = rem & 3, idx4 = rem >> 2;
        int ln = idx4 & 31, ksj = idx4 >> 5;
        int ks = ksj >> 2, j = ksj & 3;
        int tg = ln & 3, gp = ln >> 2;
        int n = wc0 * 32 + j * 8 + gp;
        int k2 = ks * 8 + (c & 1) * 4 + tg;
        const float* W = (c < 2) ? Wc : Wn;
        smu[CA_W + i] = packh2(W[(2 * k2) * FDIM + n], W[(2 * k2 + 1) * FDIM + n]);
    }
    if (tid < 128) { sm[CA_BIAS + tid] = bc[tid]; sm[CA_BIAS + 128 + tid] = bn[tid]; }
    __syncthreads();

    int wr = wid >> 2, wc = wid & 3;
    int tig = lane & 3, grp = lane >> 2;
    float bcr[4][2], bnr[4][2];
    #pragma unroll
    for (int j = 0; j < 4; j++) {
        int f0 = wc * 32 + j * 8 + 2 * tig;
        bcr[j][0] = sm[CA_BIAS + f0];       bcr[j][1] = sm[CA_BIAS + f0 + 1];
        bnr[j][0] = sm[CA_BIAS + 128 + f0]; bnr[j][1] = sm[CA_BIAS + 128 + f0 + 1];
    }

    for (int t = blockIdx.x; t < ATILE; t += gridDim.x) {
        #pragma unroll
        for (int q = 0; q < 16; q++) {
            int i = tid + q * 256;
            int r = i >> 6, k2 = i & 63;
            float2 f2 = *(const float2*)&g_x[(size_t)(t * 64 + r) * FDIM + 2 * k2];
            smu[CA_A + r * 68 + k2] = packh2(f2.x, f2.y);
        }
        __syncthreads();

        float cpc[2][4][4] = {}, cyn[2][4][4] = {};
        #pragma unroll
        for (int ks = 0; ks < 8; ks++) {
            int k0 = ks * 8;
            uint32_t a[2][4];
            #pragma unroll
            for (int rt = 0; rt < 2; rt++) {
                int r = wr * 32 + rt * 16 + grp;
                a[rt][0] = smu[CA_A + r * 68 + k0 + tig];
                a[rt][1] = smu[CA_A + (r + 8) * 68 + k0 + tig];
                a[rt][2] = smu[CA_A + r * 68 + k0 + 4 + tig];
                a[rt][3] = smu[CA_A + (r + 8) * 68 + k0 + 4 + tig];
            }
            #pragma unroll
            for (int j = 0; j < 4; j++) {
                uint4 Bf = *(const uint4*)&smu[CA_W + wc * 4096 + ((ks * 4 + j) * 32 + lane) * 4];
                #pragma unroll
                for (int rt = 0; rt < 2; rt++) {
                    mma_f16(cpc[rt][j], a[rt][0], a[rt][1], a[rt][2], a[rt][3], Bf.x, Bf.y);
                    mma_f16(cyn[rt][j], a[rt][0], a[rt][1], a[rt][2], a[rt][3], Bf.z, Bf.w);
                }
            }
        }

        #pragma unroll
        for (int rt = 0; rt < 2; rt++) {
            int r0 = t * 64 + wr * 32 + rt * 16 + grp;
            #pragma unroll
            for (int j = 0; j < 4; j++) {
                int h0 = wc * 16 + j * 4 + tig;      // f0/2
                g_pc[r0 * 64 + h0] =
                    packh2(cpc[rt][j][0] + bcr[j][0], cpc[rt][j][1] + bcr[j][1]);
                g_pc[(r0 + 8) * 64 + h0] =
                    packh2(cpc[rt][j][2] + bcr[j][0], cpc[rt][j][3] + bcr[j][1]);
                g_yn[r0 * 64 + h0] =
                    packh2(cyn[rt][j][0] + bnr[j][0], cyn[rt][j][1] + bnr[j][1]);
                g_yn[(r0 + 8) * 64 + h0] =
                    packh2(cyn[rt][j][2] + bnr[j][0], cyn[rt][j][3] + bnr[j][1]);
            }
        }
        __syncthreads();
    }
}

// ============================================================================
// Kernel 3: k_conv — fused conv layer; yn/pc staged as half2 (pitch 68)
// ============================================================================
#define S_W     0          // 16384
#define S_WE    16384      //  3072
#define S_BIAS  19456      //   640
#define S_GRP   20096
#define GP_AGM  0          // 2048
#define GP_AE   2048       // 3 x 768 = 2304
#define GP_YN   4352       // 2 x (26x68=1768) = 3536
#define GP_RED  7888       //  256
#define GP_IDX  8144       //  96
#define GRPSZ   8240
#define S_TOT   (S_GRP + 2 * GRPSZ)     // 36576 words = 146.3 KB
#define CV_SMEM (S_TOT * 4)
#define CV_THREADS 512

__device__ __forceinline__ void stage_ae_h(uint32_t dstbase, const char* __restrict__ src,
                                           int gtid) {
    if (gtid < 192) {
        asm volatile("cp.async.ca.shared.global [%0], [%1], 16;"
                     :: "r"(dstbase + (uint32_t)gtid * 16),
                        "l"(src + (size_t)gtid * 16) : "memory");
    }
}

// stage 24 yn rows (gathered, half2) + 2 pc rows into [26][68] u32 smem tile
__device__ __forceinline__ void stage_yn(uint32_t dstbase, const int* __restrict__ sx,
                                         int tn, int gtid) {
    #pragma unroll
    for (int q = 0; q < 2; q++) {
        int i = gtid + q * 256;                    // 416 chunks of 16B
        if (i < 416) {
            int row = i >> 4, c = i & 15;
            const char* src = (row < 24)
                ? (const char*)(g_yn + (size_t)sx[row] * 64) + c * 16
                : (const char*)(g_pc + ((size_t)tn * 2 + (row - 24)) * 64) + c * 16;
            uint32_t d = dstbase + (uint32_t)(row * 68 + c * 4) * 4;
            asm volatile("cp.async.ca.shared.global [%0], [%1], 16;"
                         :: "r"(d), "l"(src) : "memory");
        }
    }
}

__global__ void __launch_bounds__(CV_THREADS, 1)
k_conv(const int* __restrict__ nbr_idx,
       const float* __restrict__ Wg, const float* __restrict__ bg,
       const float* __restrict__ Wm, const float* __restrict__ bm,
       const float* __restrict__ We, const float* __restrict__ be,
       const float* __restrict__ lns, const float* __restrict__ lnb) {
    int tid = threadIdx.x, wid = tid >> 5, lane = tid & 31;
    int half = wid >> 3, wg = wid & 7, gtid = tid & 255;
    uint32_t* smu = (uint32_t*)sm;

    for (int i = tid; i < 16384; i += CV_THREADS) {
        int wgo = i >> 11, rem = i & 2047;
        int c = rem & 3, idx4 = rem >> 2;
        int ln = idx4 & 31, ksj = idx4 >> 5;
        int ks = ksj >> 1, j = ksj & 1;
        int tg = ln & 3, gp = ln >> 2;
        int n = wgo * 16 + j * 8 + gp;
        int k2 = ks * 8 + (c & 1) * 4 + tg;
        const float* W = (c < 2) ? Wg : Wm;
        smu[S_W + i] = packh2(W[(2 * k2) * FDIM + n], W[(2 * k2 + 1) * FDIM + n]);
    }
    for (int i = tid; i < 3072; i += CV_THREADS) {
        int wgo = i / 384, rem = i - wgo * 384;
        int c = rem & 1, idx2 = rem >> 1;
        int ln = idx2 & 31, ksj = idx2 >> 5;
        int ks = ksj >> 1, j = ksj & 1;
        int tg = ln & 3, gp = ln >> 2;
        int n = wgo * 16 + j * 8 + gp;
        int k2 = ks * 8 + c * 4 + tg;
        float v0 = (2 * k2     < EDGE) ? We[(2 * k2) * FDIM + n]     : 0.f;
        float v1 = (2 * k2 + 1 < EDGE) ? We[(2 * k2 + 1) * FDIM + n] : 0.f;
        smu[S_WE + i] = packh2(v0, v1);
    }
    if (tid < FDIM) {
        sm[S_BIAS + tid]       = bg[tid];
        sm[S_BIAS + 128 + tid] = bm[tid];
        sm[S_BIAS + 256 + tid] = lns[tid];
        sm[S_BIAS + 384 + tid] = lnb[tid];
        sm[S_BIAS + 512 + tid] = be[tid];
    }

    int gbase = S_GRP + half * GRPSZ;
    int* sidx3 = (int*)(sm + gbase + GP_IDX);
    uint32_t aeRaw = smem_u32(sm + gbase + GP_AE);
    uint32_t ynRaw = smem_u32(sm + gbase + GP_YN);
    int tig = lane & 3, grp = lane >> 2;
    bool notpad = (grp < 4);
    int barid = half + 1;

    int stride = 2 * gridDim.x;
    int s0 = blockIdx.x * 2 + half;

    __syncthreads();

    if (gtid < 24) {
        sidx3[gtid] = nbr_idx[s0 * 24 + gtid];
        if (s0 + stride < NT2)
            sidx3[24 + gtid] = nbr_idx[(s0 + stride) * 24 + gtid];
    }
    stage_ae_h(aeRaw, (const char*)(g_nbrh + (size_t)s0 * 768), gtid);
    if (s0 + stride < NT2)
        stage_ae_h(aeRaw + 768u * 4, (const char*)(g_nbrh + (size_t)(s0 + stride) * 768), gtid);
    asm volatile("cp.async.commit_group;" ::: "memory");
    asm volatile("cp.async.wait_group 0;" ::: "memory");
    asm volatile("bar.sync %0, %1;" :: "r"(barid), "r"(256) : "memory");

    stage_yn(ynRaw, sidx3, s0, gtid);
    asm volatile("cp.async.commit_group;" ::: "memory");
    asm volatile("cp.async.wait_group 0;" ::: "memory");
    asm volatile("bar.sync %0, %1;" :: "r"(barid), "r"(256) : "memory");

    float bgr[2][2], bmr[2][2], ber[2][2];
    #pragma unroll
    for (int j = 0; j < 2; j++) {
        int f0 = wg * 16 + j * 8 + 2 * tig;
        bgr[j][0] = sm[S_BIAS + f0];        bgr[j][1] = sm[S_BIAS + f0 + 1];
        bmr[j][0] = sm[S_BIAS + 128 + f0];  bmr[j][1] = sm[S_BIAS + 128 + f0 + 1];
        ber[j][0] = sm[S_BIAS + 512 + f0];  ber[j][1] = sm[S_BIAS + 512 + f0 + 1];
    }
    float4 lns4 = *(const float4*)&sm[S_BIAS + 256 + lane * 4];
    float4 lnb4 = *(const float4*)&sm[S_BIAS + 384 + lane * 4];

    int b2 = 0, b3 = 0;
    for (int t = s0; t < NT2; t += stride) {
        int aeB = gbase + GP_AE + b3 * 768;
        int ynB = gbase + GP_YN + b2 * 1768;

        if (t + stride < NT2)
            stage_yn(ynRaw + (uint32_t)(b2 ^ 1) * 1768 * 4,
                     sidx3 + ((b3 + 1) % 3) * 24, t + stride, gtid);
        asm volatile("cp.async.commit_group;" ::: "memory");

        int t2 = t + 2 * stride;
        if (t2 < NT2) {
            int ib = (b3 + 2) % 3;
            if (gtid < 24) sidx3[ib * 24 + gtid] = nbr_idx[t2 * 24 + gtid];
            stage_ae_h(aeRaw + (uint32_t)ib * 768 * 4,
                       (const char*)(g_nbrh + (size_t)t2 * 768), gtid);
        }
        asm volatile("cp.async.commit_group;" ::: "memory");

        // ---- phi_e mma ----
        float ce[2][2][4] = {};
        #pragma unroll
        for (int ks = 0; ks < 3; ks++) {
            uint4 A[2];
            #pragma unroll
            for (int rt = 0; rt < 2; rt++)
                A[rt] = *(const uint4*)&smu[aeB + ((rt * 3 + ks) * 32 + lane) * 4];
            #pragma unroll
            for (int j = 0; j < 2; j++) {
                uint2 Bf = *(const uint2*)&smu[S_WE + wg * 384 + ((ks * 2 + j) * 32 + lane) * 2];
                #pragma unroll
                for (int rt = 0; rt < 2; rt++)
                    mma_f16(ce[rt][j], A[rt].x, A[rt].y, A[rt].z, A[rt].w, Bf.x, Bf.y);
            }
        }

        // ---- build inter tile (yn/pc half2 from smem) ----
        #pragma unroll
        for (int rt = 0; rt < 2; rt++) {
            int yr0 = ynB + (rt * 12 + grp) * 68;
            int pr  = ynB + (24 + rt) * 68;
            #pragma unroll
            for (int j = 0; j < 2; j++) {
                int h0 = wg * 8 + j * 4 + tig;       // f0/2
                float2 pc2 = unpackh2(smu[pr + h0]);
                float2 y0  = unpackh2(smu[yr0 + h0]);
                uint32_t lo = packh2(pc2.x * y0.x * (ce[rt][j][0] + ber[j][0]),
                                     pc2.y * y0.y * (ce[rt][j][1] + ber[j][1]));
                uint32_t hi = 0u;
                if (notpad) {
                    float2 y1 = unpackh2(smu[yr0 + 8 * 68 + h0]);
                    hi = packh2(pc2.x * y1.x * (ce[rt][j][2] + ber[j][0]),
                                pc2.y * y1.y * (ce[rt][j][3] + ber[j][1]));
                }
                *(uint2*)&smu[gbase + GP_AGM + ((rt * 8 + wg) * 32 + lane) * 4 + j * 2] =
                    make_uint2(lo, hi);
            }
        }
        asm volatile("bar.sync %0, %1;" :: "r"(barid), "r"(256) : "memory");

        // ---- gate/mag mma ----
        float cg[2][2][4] = {}, cmm[2][2][4] = {};
        #pragma unroll
        for (int ks = 0; ks < 8; ks++) {
            uint4 A[2];
            #pragma unroll
            for (int rt = 0; rt < 2; rt++)
                A[rt] = *(const uint4*)&smu[gbase + GP_AGM + ((rt * 8 + ks) * 32 + lane) * 4];
            #pragma unroll
            for (int j = 0; j < 2; j++) {
                uint4 Bf = *(const uint4*)&smu[S_W + wg * 2048 + ((ks * 2 + j) * 32 + lane) * 4];
                #pragma unroll
                for (int rt = 0; rt < 2; rt++) {
                    mma_f16(cg[rt][j],  A[rt].x, A[rt].y, A[rt].z, A[rt].w, Bf.x, Bf.y);
                    mma_f16(cmm[rt][j], A[rt].x, A[rt].y, A[rt].z, A[rt].w, Bf.z, Bf.w);
                }
            }
        }

        // ---- activation + masked per-atom column sums ----
        #pragma unroll
        for (int rt = 0; rt < 2; rt++) {
            #pragma unroll
            for (int j = 0; j < 2; j++) {
                float p0 = act(cg[rt][j][0] + bgr[j][0], cmm[rt][j][0] + bmr[j][0]);
                float p1 = act(cg[rt][j][1] + bgr[j][1], cmm[rt][j][1] + bmr[j][1]);
                if (notpad) {
                    p0 += act(cg[rt][j][2] + bgr[j][0], cmm[rt][j][2] + bmr[j][0]);
                    p1 += act(cg[rt][j][3] + bgr[j][1], cmm[rt][j][3] + bmr[j][1]);
                }
                #pragma unroll
                for (int o = 4; o < 32; o <<= 1) {
                    p0 += __shfl_xor_sync(0xffffffffu, p0, o);
                    p1 += __shfl_xor_sync(0xffffffffu, p1, o);
                }
                if (grp == 0) {
                    int f0 = wg * 16 + j * 8 + 2 * tig;
                    sm[gbase + GP_RED + rt * 128 + f0]     = p0;
                    sm[gbase + GP_RED + rt * 128 + f0 + 1] = p1;
                }
            }
        }
        asm volatile("cp.async.wait_group 1;" ::: "memory");
        asm volatile("bar.sync %0, %1;" :: "r"(barid), "r"(256) : "memory");

        if (wg < 2) {
            float4 v = *(const float4*)&sm[gbase + GP_RED + wg * 128 + lane * 4];
            float s = v.x + v.y + v.z + v.w;
            float q = v.x*v.x + v.y*v.y + v.z*v.z + v.w*v.w;
            #pragma unroll
            for (int o = 16; o > 0; o >>= 1) {
                s += __shfl_xor_sync(0xffffffffu, s, o);
                q += __shfl_xor_sync(0xffffffffu, q, o);
            }
            float mu = s * (1.f / FDIM);
            float var = q * (1.f / FDIM) - mu * mu;
            float rstd = rsqrtf(var + 1e-6f);
            int n = t * 2 + wg;
            float4 x = *(float4*)&g_x[n * FDIM + lane * 4];
            x.x += (v.x - mu) * rstd * lns4.x + lnb4.x;
            x.y += (v.y - mu) * rstd * lns4.y + lnb4.y;
            x.z += (v.z - mu) * rstd * lns4.z + lnb4.z;
            x.w += (v.w - mu) * rstd * lns4.w + lnb4.w;
            *(float4*)&g_x[n * FDIM + lane * 4] = x;
        }
        b2 ^= 1;
        b3 = (b3 + 1) % 3;
    }
}

// ============================================================================
// Kernel 4: k_readout — fp16 mma GEMM + fused softplus.Wout
// ============================================================================
#define R_W    0
#define R_A    16384
#define R_BH   20736
#define R_WO   20992
#define R_RED  21248
#define R_TOT  21504
#define R_SMEM (R_TOT * 4)

__global__ void __launch_bounds__(256, 1)
k_readout(const float* __restrict__ Wh, const float* __restrict__ bh,
          const float* __restrict__ Wout, const float* __restrict__ bout) {
    int tid = threadIdx.x, wid = tid >> 5, lane = tid & 31;
    uint32_t* smu = (uint32_t*)sm;
    for (int i = tid; i < 16384; i += 256) {
        int wc0 = i >> 12, rem = i & 4095;
        int c = rem & 1, idx = rem >> 1;
        int ln = idx & 31, ksj = idx >> 5;
        int ks = ksj >> 3, j = ksj & 7;
        int tg = ln & 3, gp = ln >> 2;
        int n = wc0 * 64 + j * 8 + gp;
        int k2 = ks * 8 + c * 4 + tg;
        smu[R_W + i] = packh2(Wh[(2 * k2) * HDIM + n], Wh[(2 * k2 + 1) * HDIM + n]);
    }
    sm[R_BH + tid] = bh[tid];
    sm[R_WO + tid] = Wout[tid];
    __syncthreads();

    int wr = wid >> 2, wc = wid & 3;
    int tig = lane & 3, grp = lane >> 2;
    float b0 = bout[0];
    float bhr[8][2], wor[8][2];
    #pragma unroll
    for (int j = 0; j < 8; j++) {
        int n0 = wc * 64 + j * 8 + 2 * tig;
        bhr[j][0] = sm[R_BH + n0]; bhr[j][1] = sm[R_BH + n0 + 1];
        wor[j][0] = sm[R_WO + n0]; wor[j][1] = sm[R_WO + n0 + 1];
    }

    for (int t = blockIdx.x; t < ATILE; t += gridDim.x) {
        #pragma unroll
        for (int q = 0; q < 16; q++) {
            int i = tid + q * 256;
            int r = i >> 6, k2 = i & 63;
            float2 f2 = *(const float2*)&g_x[(size_t)(t * 64 + r) * FDIM + 2 * k2];
            smu[R_A + r * 68 + k2] = packh2(f2.x, f2.y);
        }
        __syncthreads();

        float c[2][8][4] = {};
        #pragma unroll
        for (int ks = 0; ks < 8; ks++) {
            int k0 = ks * 8;
            uint32_t a[2][4];
            #pragma unroll
            for (int rt = 0; rt < 2; rt++) {
                int r = wr * 32 + rt * 16 + grp;
                a[rt][0] = smu[R_A + r * 68 + k0 + tig];
                a[rt][1] = smu[R_A + (r + 8) * 68 + k0 + tig];
                a[rt][2] = smu[R_A + r * 68 + k0 + 4 + tig];
                a[rt][3] = smu[R_A + (r + 8) * 68 + k0 + 4 + tig];
            }
            #pragma unroll
            for (int j = 0; j < 8; j++) {
                uint2 Bf = *(const uint2*)&smu[R_W + wc * 4096 + ((ks * 8 + j) * 32 + lane) * 2];
                #pragma unroll
                for (int rt = 0; rt < 2; rt++)
                    mma_f16(c[rt][j], a[rt][0], a[rt][1], a[rt][2], a[rt][3], Bf.x, Bf.y);
            }
        }

        #pragma unroll
        for (int rt = 0; rt < 2; rt++) {
            float p0 = 0.f, p1 = 0.f;
            #pragma unroll
            for (int j = 0; j < 8; j++) {
                p0 += spf(c[rt][j][0] + bhr[j][0]) * wor[j][0]
                    + spf(c[rt][j][1] + bhr[j][1]) * wor[j][1];
                p1 += spf(c[rt][j][2] + bhr[j][0]) * wor[j][0]
                    + spf(c[rt][j][3] + bhr[j][1]) * wor[j][1];
            }
            p0 += __shfl_xor_sync(0xffffffffu, p0, 1);
            p0 += __shfl_xor_sync(0xffffffffu, p0, 2);
            p1 += __shfl_xor_sync(0xffffffffu, p1, 1);
            p1 += __shfl_xor_sync(0xffffffffu, p1, 2);
            if (tig == 0) {
                int r = wr * 32 + rt * 16 + grp;
                sm[R_RED + r * 4 + wc]       = p0;
                sm[R_RED + (r + 8) * 4 + wc] = p1;
            }
        }
        __syncthreads();
        if (tid < 64) {
            float4 s4 = *(const float4*)&sm[R_RED + tid * 4];
            g_site[t * 64 + tid] = s4.x + s4.y + s4.z + s4.w + b0;
        }
        __syncthreads();
    }
}

// ============================================================================
// Kernel 5: per-crystal sum
// ============================================================================
__global__ void k_crystal(float* __restrict__ out) {
    __shared__ float red[8];
    int c = blockIdx.x, tid = threadIdx.x;
    float v = g_site[c * APC + tid];
    #pragma unroll
    for (int o = 16; o > 0; o >>= 1)
        v += __shfl_xor_sync(0xffffffffu, v, o);
    if ((tid & 31) == 0) red[tid >> 5] = v;
    __syncthreads();
    if (tid == 0) {
        float s = 0.f;
        #pragma unroll
        for (int i = 0; i < 8; i++) s += red[i];
        out[c] = s;
    }
}

// ============================================================================
extern "C" void kernel_launch(void* const* d_in, const int* in_sizes, int n_in,
                              void* d_out, int out_size) {
    const float* atom_fea = (const float*)d_in[0];
    const float* nbr_fea  = (const float*)d_in[1];
    const int*   nbr_idx  = (const int*)  d_in[2];
    const float* W_embed  = (const float*)d_in[3];
    const float* b_embed  = (const float*)d_in[4];
    const float* W_center = (const float*)d_in[5];
    const float* b_center = (const float*)d_in[6];
    const float* W_nbr    = (const float*)d_in[7];
    const float* b_nbr    = (const float*)d_in[8];
    const float* W_edge   = (const float*)d_in[9];
    const float* b_edge   = (const float*)d_in[10];
    const float* W_gate   = (const float*)d_in[11];
    const float* b_gate   = (const float*)d_in[12];
    const float* W_mag    = (const float*)d_in[13];
    const float* b_mag    = (const float*)d_in[14];
    const float* ln_scale = (const float*)d_in[15];
    const float* ln_bias  = (const float*)d_in[16];
    const float* W_h      = (const float*)d_in[17];
    const float* b_h      = (const float*)d_in[18];
    const float* W_out    = (const float*)d_in[19];
    const float* b_out    = (const float*)d_in[20];
    float* out = (float*)d_out;

    cudaFuncSetAttribute(k_embed,   cudaFuncAttributeMaxDynamicSharedMemorySize, E_SMEM);
    cudaFuncSetAttribute(k_convA,   cudaFuncAttributeMaxDynamicSharedMemorySize, CA_SMEM);
    cudaFuncSetAttribute(k_conv,    cudaFuncAttributeMaxDynamicSharedMemorySize, CV_SMEM);
    cudaFuncSetAttribute(k_readout, cudaFuncAttributeMaxDynamicSharedMemorySize, R_SMEM);

    k_pack<<<2048, 256>>>(nbr_fea);
    k_embed<<<148, 256, E_SMEM>>>(atom_fea, W_embed, b_embed);
    for (int l = 0; l < NCONV; l++) {
        k_convA<<<148, 256, CA_SMEM>>>(W_center + l * FDIM * FDIM, b_center + l * FDIM,
                                       W_nbr    + l * FDIM * FDIM, b_nbr    + l * FDIM);
        k_conv<<<148, CV_THREADS, CV_SMEM>>>(nbr_idx,
                                      W_gate + l * FDIM * FDIM, b_gate + l * FDIM,
                                      W_mag  + l * FDIM * FDIM, b_mag  + l * FDIM,
                                      W_edge + l * EDGE * FDIM, b_edge + l * FDIM,
                                      ln_scale + l * FDIM, ln_bias + l * FDIM);
    }
    k_readout<<<148, 256, R_SMEM>>>(W_h, b_h, W_out, b_out);
    k_crystal<<<NCRY, 256>>>(out);
}

// round 15
// speedup vs baseline: 5.7641x; 1.0199x over previous
#include <cuda_runtime.h>
#include <cuda_fp16.h>
#include <math.h>
#include <cstdint>

#define N_ATOMS 32768
#define MNBR    12
#define PROWS   16
#define ORIG    92
#define EDGE    41
#define FDIM    128
#define HDIM    256
#define NCONV   3
#define NCRY    128
#define APC     256
#define NT2     (N_ATOMS / 2)             // 16384 atom-pair tiles
#define ATILE   (N_ATOMS / 64)            // 512

// ---- scratch ----
__device__ float    g_x [N_ATOMS * FDIM];
__device__ uint32_t g_pc[N_ATOMS * 64];    // half2-packed phi_c
__device__ uint32_t g_yn[N_ATOMS * 64];    // half2-packed y_nbr
__device__ uint32_t g_nbrh[NT2 * 768];     // fp16 edge features, fragment order
__device__ float    g_site[N_ATOMS];

__device__ __forceinline__ uint32_t smem_u32(const void* p) {
    uint32_t a;
    asm("{ .reg .u64 t; cvta.to.shared.u64 t, %1; cvt.u32.u64 %0, t; }" : "=r"(a) : "l"(p));
    return a;
}
__device__ __forceinline__ uint32_t packh2(float a, float b) {
    __half2 h = __floats2half2_rn(a, b);
    return *(uint32_t*)&h;
}
__device__ __forceinline__ float2 unpackh2(uint32_t u) {
    return __half22float2(*(__half2*)&u);
}
__device__ __forceinline__ void mma_f16(float c[4], uint32_t a0, uint32_t a1,
                                        uint32_t a2, uint32_t a3,
                                        uint32_t b0, uint32_t b1) {
    asm volatile("mma.sync.aligned.m16n8k16.row.col.f32.f16.f16.f32 "
        "{%0,%1,%2,%3}, {%4,%5,%6,%7}, {%8,%9}, {%0,%1,%2,%3};"
        : "+f"(c[0]), "+f"(c[1]), "+f"(c[2]), "+f"(c[3])
        : "r"(a0), "r"(a1), "r"(a2), "r"(a3), "r"(b0), "r"(b1));
}
__device__ __forceinline__ float act(float g, float m) {
    float sig = __fdividef(1.f, 1.f + __expf(-g));
    float sp  = fmaxf(m, 0.f) + __logf(1.f + __expf(-fabsf(m)));
    return sig * sp;
}
__device__ __forceinline__ float spf(float x) {
    return fmaxf(x, 0.f) + __logf(1.f + __expf(-fabsf(x)));
}

extern __shared__ float sm[];

// ============================================================================
// Kernel 0: pack nbr_fea -> fp16 FRAGMENT-ORDER per 2-atom tile (768 u32)
// ============================================================================
__global__ void k_pack(const float* __restrict__ nbr_fea) {
    int total = NT2 * 768;
    for (int idx = blockIdx.x * 256 + threadIdx.x; idx < total; idx += gridDim.x * 256) {
        int s = idx / 768, f = idx - s * 768;
        int c = f & 3, q = f >> 2;
        int lane = q & 31, rks = q >> 5;
        int rt = rks / 3, ks = rks - rt * 3;
        int tig = lane & 3, grp = lane >> 2;
        int slot = c >> 1, rowbit = c & 1;
        int m = grp + rowbit * 8;
        int k2 = ks * 8 + slot * 4 + tig;
        float v0 = 0.f, v1 = 0.f;
        if (m < MNBR) {
            size_t base = ((size_t)(s * 2 + rt) * MNBR + m) * EDGE;
            if (2 * k2     < EDGE) v0 = nbr_fea[base + 2 * k2];
            if (2 * k2 + 1 < EDGE) v1 = nbr_fea[base + 2 * k2 + 1];
        }
        g_nbrh[idx] = packh2(v0, v1);
    }
}

// ============================================================================
// Kernel 1: k_embed — fp16 mma GEMM: x = atom_fea @ W_embed + b
// ============================================================================
#define E_W    0
#define E_A    6144
#define E_BIAS 9472
#define E_TOT  9600
#define E_SMEM (E_TOT * 4)

__global__ void __launch_bounds__(256, 1)
k_embed(const float* __restrict__ atom_fea,
        const float* __restrict__ W, const float* __restrict__ b) {
    int tid = threadIdx.x, wid = tid >> 5, lane = tid & 31;
    uint32_t* smu = (uint32_t*)sm;
    for (int i = tid; i < 6144; i += 256) {
        int wc0 = i / 1536, rem = i - wc0 * 1536;
        int c = rem & 1, idx = rem >> 1;
        int ln = idx & 31, ksj = idx >> 5;
        int ks = ksj >> 2, j = ksj & 3;
        int tg = ln & 3, gp = ln >> 2;
        int n = wc0 * 32 + j * 8 + gp;
        int k2 = ks * 8 + c * 4 + tg;
        float v0 = (2 * k2     < ORIG) ? W[(2 * k2) * FDIM + n]     : 0.f;
        float v1 = (2 * k2 + 1 < ORIG) ? W[(2 * k2 + 1) * FDIM + n] : 0.f;
        smu[E_W + i] = packh2(v0, v1);
    }
    if (tid < FDIM) sm[E_BIAS + tid] = b[tid];
    __syncthreads();

    int wr = wid >> 2, wc = wid & 3;
    int tig = lane & 3, grp = lane >> 2;
    float br[4][2];
    #pragma unroll
    for (int j = 0; j < 4; j++) {
        int n0 = wc * 32 + j * 8 + 2 * tig;
        br[j][0] = sm[E_BIAS + n0]; br[j][1] = sm[E_BIAS + n0 + 1];
    }

    for (int t = blockIdx.x; t < ATILE; t += gridDim.x) {
        #pragma unroll
        for (int q = 0; q < 12; q++) {
            int i = tid + q * 256;
            int r = i / 48, k2 = i - r * 48;
            uint32_t v = 0u;
            if (k2 < 46) {
                float2 f2 = *(const float2*)&atom_fea[(size_t)(t * 64 + r) * ORIG + 2 * k2];
                v = packh2(f2.x, f2.y);
            }
            smu[E_A + r * 52 + k2] = v;
        }
        __syncthreads();

        float c[2][4][4] = {};
        #pragma unroll
        for (int ks = 0; ks < 6; ks++) {
            int k0 = ks * 8;
            uint32_t a[2][4];
            #pragma unroll
            for (int rt = 0; rt < 2; rt++) {
                int r = wr * 32 + rt * 16 + grp;
                a[rt][0] = smu[E_A + r * 52 + k0 + tig];
                a[rt][1] = smu[E_A + (r + 8) * 52 + k0 + tig];
                a[rt][2] = smu[E_A + r * 52 + k0 + 4 + tig];
                a[rt][3] = smu[E_A + (r + 8) * 52 + k0 + 4 + tig];
            }
            #pragma unroll
            for (int j = 0; j < 4; j++) {
                uint2 Bf = *(const uint2*)&smu[E_W + wc * 1536 + ((ks * 4 + j) * 32 + lane) * 2];
                #pragma unroll
                for (int rt = 0; rt < 2; rt++)
                    mma_f16(c[rt][j], a[rt][0], a[rt][1], a[rt][2], a[rt][3], Bf.x, Bf.y);
            }
        }

        #pragma unroll
        for (int rt = 0; rt < 2; rt++) {
            int r0 = t * 64 + wr * 32 + rt * 16 + grp;
            #pragma unroll
            for (int j = 0; j < 4; j++) {
                int n0 = wc * 32 + j * 8 + 2 * tig;
                *(float2*)&g_x[r0 * FDIM + n0] =
                    make_float2(c[rt][j][0] + br[j][0], c[rt][j][1] + br[j][1]);
                *(float2*)&g_x[(r0 + 8) * FDIM + n0] =
                    make_float2(c[rt][j][2] + br[j][0], c[rt][j][3] + br[j][1]);
            }
        }
        __syncthreads();
    }
}

// ============================================================================
// Kernel 2: k_convA — fp16 mma GEMM: [phi_c|y_nbr] = x @ [Wc|Wn] + bias
// ============================================================================
#define CA_W    0
#define CA_A    16384
#define CA_BIAS 20736
#define CA_TOT  20992
#define CA_SMEM (CA_TOT * 4)

__global__ void __launch_bounds__(256, 1)
k_convA(const float* __restrict__ Wc, const float* __restrict__ bc,
        const float* __restrict__ Wn, const float* __restrict__ bn) {
    int tid = threadIdx.x, wid = tid >> 5, lane = tid & 31;
    uint32_t* smu = (uint32_t*)sm;
    for (int i = tid; i < 16384; i += 256) {
        int wc0 = i >> 12, rem = i & 4095;
        int c = rem & 3, idx4 = rem >> 2;
        int ln = idx4 & 31, ksj = idx4 >> 5;
        int ks = ksj >> 2, j = ksj & 3;
        int tg = ln & 3, gp = ln >> 2;
        int n = wc0 * 32 + j * 8 + gp;
        int k2 = ks * 8 + (c & 1) * 4 + tg;
        const float* W = (c < 2) ? Wc : Wn;
        smu[CA_W + i] = packh2(W[(2 * k2) * FDIM + n], W[(2 * k2 + 1) * FDIM + n]);
    }
    if (tid < 128) { sm[CA_BIAS + tid] = bc[tid]; sm[CA_BIAS + 128 + tid] = bn[tid]; }
    __syncthreads();

    int wr = wid >> 2, wc = wid & 3;
    int tig = lane & 3, grp = lane >> 2;
    float bcr[4][2], bnr[4][2];
    #pragma unroll
    for (int j = 0; j < 4; j++) {
        int f0 = wc * 32 + j * 8 + 2 * tig;
        bcr[j][0] = sm[CA_BIAS + f0];       bcr[j][1] = sm[CA_BIAS + f0 + 1];
        bnr[j][0] = sm[CA_BIAS + 128 + f0]; bnr[j][1] = sm[CA_BIAS + 128 + f0 + 1];
    }

    for (int t = blockIdx.x; t < ATILE; t += gridDim.x) {
        #pragma unroll
        for (int q = 0; q < 16; q++) {
            int i = tid + q * 256;
            int r = i >> 6, k2 = i & 63;
            float2 f2 = *(const float2*)&g_x[(size_t)(t * 64 + r) * FDIM + 2 * k2];
            smu[CA_A + r * 68 + k2] = packh2(f2.x, f2.y);
        }
        __syncthreads();

        float cpc[2][4][4] = {}, cyn[2][4][4] = {};
        #pragma unroll
        for (int ks = 0; ks < 8; ks++) {
            int k0 = ks * 8;
            uint32_t a[2][4];
            #pragma unroll
            for (int rt = 0; rt < 2; rt++) {
                int r = wr * 32 + rt * 16 + grp;
                a[rt][0] = smu[CA_A + r * 68 + k0 + tig];
                a[rt][1] = smu[CA_A + (r + 8) * 68 + k0 + tig];
                a[rt][2] = smu[CA_A + r * 68 + k0 + 4 + tig];
                a[rt][3] = smu[CA_A + (r + 8) * 68 + k0 + 4 + tig];
            }
            #pragma unroll
            for (int j = 0; j < 4; j++) {
                uint4 Bf = *(const uint4*)&smu[CA_W + wc * 4096 + ((ks * 4 + j) * 32 + lane) * 4];
                #pragma unroll
                for (int rt = 0; rt < 2; rt++) {
                    mma_f16(cpc[rt][j], a[rt][0], a[rt][1], a[rt][2], a[rt][3], Bf.x, Bf.y);
                    mma_f16(cyn[rt][j], a[rt][0], a[rt][1], a[rt][2], a[rt][3], Bf.z, Bf.w);
                }
            }
        }

        #pragma unroll
        for (int rt = 0; rt < 2; rt++) {
            int r0 = t * 64 + wr * 32 + rt * 16 + grp;
            #pragma unroll
            for (int j = 0; j < 4; j++) {
                int h0 = wc * 16 + j * 4 + tig;
                g_pc[r0 * 64 + h0] =
                    packh2(cpc[rt][j][0] + bcr[j][0], cpc[rt][j][1] + bcr[j][1]);
                g_pc[(r0 + 8) * 64 + h0] =
                    packh2(cpc[rt][j][2] + bcr[j][0], cpc[rt][j][3] + bcr[j][1]);
                g_yn[r0 * 64 + h0] =
                    packh2(cyn[rt][j][0] + bnr[j][0], cyn[rt][j][1] + bnr[j][1]);
                g_yn[(r0 + 8) * 64 + h0] =
                    packh2(cyn[rt][j][2] + bnr[j][0], cyn[rt][j][3] + bnr[j][1]);
            }
        }
        __syncthreads();
    }
}

// ============================================================================
// Kernel 3: k_conv — fused conv layer, ONE barrier per tile.
//   AGM and RED double-buffered; LN of tile t deferred into iteration t+1.
// ============================================================================
#define S_W     0          // 16384
#define S_WE    16384      //  3072
#define S_BIAS  19456      //   640
#define S_GRP   20096
#define GP_AGM  0          // 2 x 2048 = 4096
#define GP_AE   4096       // 3 x 768  = 2304
#define GP_YN   6400       // 2 x 1768 = 3536
#define GP_RED  9936       // 2 x 256  =  512
#define GP_IDX  10448      // 96
#define GRPSZ   10544
#define S_TOT   (S_GRP + 2 * GRPSZ)     // 41184 words = 164.7 KB
#define CV_SMEM (S_TOT * 4)
#define CV_THREADS 512

__device__ __forceinline__ void stage_ae_h(uint32_t dstbase, const char* __restrict__ src,
                                           int gtid) {
    if (gtid < 192) {
        asm volatile("cp.async.ca.shared.global [%0], [%1], 16;"
                     :: "r"(dstbase + (uint32_t)gtid * 16),
                        "l"(src + (size_t)gtid * 16) : "memory");
    }
}

__device__ __forceinline__ void stage_yn(uint32_t dstbase, const int* __restrict__ sx,
                                         int tn, int gtid) {
    #pragma unroll
    for (int q = 0; q < 2; q++) {
        int i = gtid + q * 256;
        if (i < 416) {
            int row = i >> 4, c = i & 15;
            const char* src = (row < 24)
                ? (const char*)(g_yn + (size_t)sx[row] * 64) + c * 16
                : (const char*)(g_pc + ((size_t)tn * 2 + (row - 24)) * 64) + c * 16;
            uint32_t d = dstbase + (uint32_t)(row * 68 + c * 4) * 4;
            asm volatile("cp.async.ca.shared.global [%0], [%1], 16;"
                         :: "r"(d), "l"(src) : "memory");
        }
    }
}

__global__ void __launch_bounds__(CV_THREADS, 1)
k_conv(const int* __restrict__ nbr_idx,
       const float* __restrict__ Wg, const float* __restrict__ bg,
       const float* __restrict__ Wm, const float* __restrict__ bm,
       const float* __restrict__ We, const float* __restrict__ be,
       const float* __restrict__ lns, const float* __restrict__ lnb) {
    int tid = threadIdx.x, wid = tid >> 5, lane = tid & 31;
    int half = wid >> 3, wg = wid & 7, gtid = tid & 255;
    uint32_t* smu = (uint32_t*)sm;

    for (int i = tid; i < 16384; i += CV_THREADS) {
        int wgo = i >> 11, rem = i & 2047;
        int c = rem & 3, idx4 = rem >> 2;
        int ln = idx4 & 31, ksj = idx4 >> 5;
        int ks = ksj >> 1, j = ksj & 1;
        int tg = ln & 3, gp = ln >> 2;
        int n = wgo * 16 + j * 8 + gp;
        int k2 = ks * 8 + (c & 1) * 4 + tg;
        const float* W = (c < 2) ? Wg : Wm;
        smu[S_W + i] = packh2(W[(2 * k2) * FDIM + n], W[(2 * k2 + 1) * FDIM + n]);
    }
    for (int i = tid; i < 3072; i += CV_THREADS) {
        int wgo = i / 384, rem = i - wgo * 384;
        int c = rem & 1, idx2 = rem >> 1;
        int ln = idx2 & 31, ksj = idx2 >> 5;
        int ks = ksj >> 1, j = ksj & 1;
        int tg = ln & 3, gp = ln >> 2;
        int n = wgo * 16 + j * 8 + gp;
        int k2 = ks * 8 + c * 4 + tg;
        float v0 = (2 * k2     < EDGE) ? We[(2 * k2) * FDIM + n]     : 0.f;
        float v1 = (2 * k2 + 1 < EDGE) ? We[(2 * k2 + 1) * FDIM + n] : 0.f;
        smu[S_WE + i] = packh2(v0, v1);
    }
    if (tid < FDIM) {
        sm[S_BIAS + tid]       = bg[tid];
        sm[S_BIAS + 128 + tid] = bm[tid];
        sm[S_BIAS + 256 + tid] = lns[tid];
        sm[S_BIAS + 384 + tid] = lnb[tid];
        sm[S_BIAS + 512 + tid] = be[tid];
    }

    int gbase = S_GRP + half * GRPSZ;
    int* sidx3 = (int*)(sm + gbase + GP_IDX);
    uint32_t aeRaw = smem_u32(sm + gbase + GP_AE);
    uint32_t ynRaw = smem_u32(sm + gbase + GP_YN);
    int tig = lane & 3, grp = lane >> 2;
    bool notpad = (grp < 4);
    int barid = half + 1;

    int stride = 2 * gridDim.x;
    int s0 = blockIdx.x * 2 + half;

    __syncthreads();

    // ---- prologue: sidx/AE for s0 and s0+stride, then YN for s0 ----
    if (gtid < 24) {
        sidx3[gtid] = nbr_idx[s0 * 24 + gtid];
        if (s0 + stride < NT2)
            sidx3[24 + gtid] = nbr_idx[(s0 + stride) * 24 + gtid];
    }
    stage_ae_h(aeRaw, (const char*)(g_nbrh + (size_t)s0 * 768), gtid);
    if (s0 + stride < NT2)
        stage_ae_h(aeRaw + 768u * 4, (const char*)(g_nbrh + (size_t)(s0 + stride) * 768), gtid);
    asm volatile("cp.async.commit_group;" ::: "memory");
    asm volatile("cp.async.wait_group 0;" ::: "memory");
    asm volatile("bar.sync %0, %1;" :: "r"(barid), "r"(256) : "memory");

    stage_yn(ynRaw, sidx3, s0, gtid);
    asm volatile("cp.async.commit_group;" ::: "memory");
    asm volatile("cp.async.wait_group 0;" ::: "memory");
    asm volatile("bar.sync %0, %1;" :: "r"(barid), "r"(256) : "memory");

    float bgr[2][2], bmr[2][2], ber[2][2];
    #pragma unroll
    for (int j = 0; j < 2; j++) {
        int f0 = wg * 16 + j * 8 + 2 * tig;
        bgr[j][0] = sm[S_BIAS + f0];        bgr[j][1] = sm[S_BIAS + f0 + 1];
        bmr[j][0] = sm[S_BIAS + 128 + f0];  bmr[j][1] = sm[S_BIAS + 128 + f0 + 1];
        ber[j][0] = sm[S_BIAS + 512 + f0];  ber[j][1] = sm[S_BIAS + 512 + f0 + 1];
    }
    float4 lns4 = *(const float4*)&sm[S_BIAS + 256 + lane * 4];
    float4 lnb4 = *(const float4*)&sm[S_BIAS + 384 + lane * 4];

    int b2 = 0, b3 = 0, bA = 0, bR = 0;
    int tprev = -1;
    for (int t = s0; t < NT2; t += stride) {
        int aeB  = gbase + GP_AE + b3 * 768;
        int ynB  = gbase + GP_YN + b2 * 1768;
        int agmB = gbase + GP_AGM + bA * 2048;

        // commit A: yn for t+stride (sidx already resident)
        if (t + stride < NT2)
            stage_yn(ynRaw + (uint32_t)(b2 ^ 1) * 1768 * 4,
                     sidx3 + ((b3 + 1) % 3) * 24, t + stride, gtid);
        asm volatile("cp.async.commit_group;" ::: "memory");

        // commit B: sidx/AE for t+2*stride
        int t2 = t + 2 * stride;
        if (t2 < NT2) {
            int ib = (b3 + 2) % 3;
            if (gtid < 24) sidx3[ib * 24 + gtid] = nbr_idx[t2 * 24 + gtid];
            stage_ae_h(aeRaw + (uint32_t)ib * 768 * 4,
                       (const char*)(g_nbrh + (size_t)t2 * 768), gtid);
        }
        asm volatile("cp.async.commit_group;" ::: "memory");

        // ---- phi_e mma ----
        float ce[2][2][4] = {};
        #pragma unroll
        for (int ks = 0; ks < 3; ks++) {
            uint4 A[2];
            #pragma unroll
            for (int rt = 0; rt < 2; rt++)
                A[rt] = *(const uint4*)&smu[aeB + ((rt * 3 + ks) * 32 + lane) * 4];
            #pragma unroll
            for (int j = 0; j < 2; j++) {
                uint2 Bf = *(const uint2*)&smu[S_WE + wg * 384 + ((ks * 2 + j) * 32 + lane) * 2];
                #pragma unroll
                for (int rt = 0; rt < 2; rt++)
                    mma_f16(ce[rt][j], A[rt].x, A[rt].y, A[rt].z, A[rt].w, Bf.x, Bf.y);
            }
        }

        // ---- build inter tile into AGM[bA] ----
        #pragma unroll
        for (int rt = 0; rt < 2; rt++) {
            int yr0 = ynB + (rt * 12 + grp) * 68;
            int pr  = ynB + (24 + rt) * 68;
            #pragma unroll
            for (int j = 0; j < 2; j++) {
                int h0 = wg * 8 + j * 4 + tig;
                float2 pc2 = unpackh2(smu[pr + h0]);
                float2 y0  = unpackh2(smu[yr0 + h0]);
                uint32_t lo = packh2(pc2.x * y0.x * (ce[rt][j][0] + ber[j][0]),
                                     pc2.y * y0.y * (ce[rt][j][1] + ber[j][1]));
                uint32_t hi = 0u;
                if (notpad) {
                    float2 y1 = unpackh2(smu[yr0 + 8 * 68 + h0]);
                    hi = packh2(pc2.x * y1.x * (ce[rt][j][2] + ber[j][0]),
                                pc2.y * y1.y * (ce[rt][j][3] + ber[j][1]));
                }
                *(uint2*)&smu[agmB + ((rt * 8 + wg) * 32 + lane) * 4 + j * 2] =
                    make_uint2(lo, hi);
            }
        }

        // ---- THE barrier (AGM visibility + staged-data visibility) ----
        asm volatile("cp.async.wait_group 1;" ::: "memory");
        asm volatile("bar.sync %0, %1;" :: "r"(barid), "r"(256) : "memory");

        // ---- gate/mag mma from AGM[bA] ----
        float cg[2][2][4] = {}, cmm[2][2][4] = {};
        #pragma unroll
        for (int ks = 0; ks < 8; ks++) {
            uint4 A[2];
            #pragma unroll
            for (int rt = 0; rt < 2; rt++)
                A[rt] = *(const uint4*)&smu[agmB + ((rt * 8 + ks) * 32 + lane) * 4];
            #pragma unroll
            for (int j = 0; j < 2; j++) {
                uint4 Bf = *(const uint4*)&smu[S_W + wg * 2048 + ((ks * 2 + j) * 32 + lane) * 4];
                #pragma unroll
                for (int rt = 0; rt < 2; rt++) {
                    mma_f16(cg[rt][j],  A[rt].x, A[rt].y, A[rt].z, A[rt].w, Bf.x, Bf.y);
                    mma_f16(cmm[rt][j], A[rt].x, A[rt].y, A[rt].z, A[rt].w, Bf.z, Bf.w);
                }
            }
        }

        // ---- deferred LayerNorm + residual for PREVIOUS tile ----
        if (tprev >= 0 && wg < 2) {
            float4 v = *(const float4*)&sm[gbase + GP_RED + (bR ^ 1) * 256 + wg * 128 + lane * 4];
            float s = v.x + v.y + v.z + v.w;
            float q = v.x*v.x + v.y*v.y + v.z*v.z + v.w*v.w;
            #pragma unroll
            for (int o = 16; o > 0; o >>= 1) {
                s += __shfl_xor_sync(0xffffffffu, s, o);
                q += __shfl_xor_sync(0xffffffffu, q, o);
            }
            float mu = s * (1.f / FDIM);
            float var = q * (1.f / FDIM) - mu * mu;
            float rstd = rsqrtf(var + 1e-6f);
            int n = tprev * 2 + wg;
            float4 x = *(float4*)&g_x[n * FDIM + lane * 4];
            x.x += (v.x - mu) * rstd * lns4.x + lnb4.x;
            x.y += (v.y - mu) * rstd * lns4.y + lnb4.y;
            x.z += (v.z - mu) * rstd * lns4.z + lnb4.z;
            x.w += (v.w - mu) * rstd * lns4.w + lnb4.w;
            *(float4*)&g_x[n * FDIM + lane * 4] = x;
        }

        // ---- activation + masked per-atom column sums into RED[bR] ----
        #pragma unroll
        for (int rt = 0; rt < 2; rt++) {
            #pragma unroll
            for (int j = 0; j < 2; j++) {
                float p0 = act(cg[rt][j][0] + bgr[j][0], cmm[rt][j][0] + bmr[j][0]);
                float p1 = act(cg[rt][j][1] + bgr[j][1], cmm[rt][j][1] + bmr[j][1]);
                if (notpad) {
                    p0 += act(cg[rt][j][2] + bgr[j][0], cmm[rt][j][2] + bmr[j][0]);
                    p1 += act(cg[rt][j][3] + bgr[j][1], cmm[rt][j][3] + bmr[j][1]);
                }
                #pragma unroll
                for (int o = 4; o < 32; o <<= 1) {
                    p0 += __shfl_xor_sync(0xffffffffu, p0, o);
                    p1 += __shfl_xor_sync(0xffffffffu, p1, o);
                }
                if (grp == 0) {
                    int f0 = wg * 16 + j * 8 + 2 * tig;
                    sm[gbase + GP_RED + bR * 256 + rt * 128 + f0]     = p0;
                    sm[gbase + GP_RED + bR * 256 + rt * 128 + f0 + 1] = p1;
                }
            }
        }

        tprev = t;
        bA ^= 1; bR ^= 1; b2 ^= 1; b3 = (b3 + 1) % 3;
    }

    // ---- epilogue: final LN for last tile ----
    asm volatile("bar.sync %0, %1;" :: "r"(barid), "r"(256) : "memory");
    if (tprev >= 0 && wg < 2) {
        float4 v = *(const float4*)&sm[gbase + GP_RED + (bR ^ 1) * 256 + wg * 128 + lane * 4];
        float s = v.x + v.y + v.z + v.w;
        float q = v.x*v.x + v.y*v.y + v.z*v.z + v.w*v.w;
        #pragma unroll
        for (int o = 16; o > 0; o >>= 1) {
            s += __shfl_xor_sync(0xffffffffu, s, o);
            q += __shfl_xor_sync(0xffffffffu, q, o);
        }
        float mu = s * (1.f / FDIM);
        float var = q * (1.f / FDIM) - mu * mu;
        float rstd = rsqrtf(var + 1e-6f);
        int n = tprev * 2 + wg;
        float4 x = *(float4*)&g_x[n * FDIM + lane * 4];
        x.x += (v.x - mu) * rstd * lns4.x + lnb4.x;
        x.y += (v.y - mu) * rstd * lns4.y + lnb4.y;
        x.z += (v.z - mu) * rstd * lns4.z + lnb4.z;
        x.w += (v.w - mu) * rstd * lns4.w + lnb4.w;
        *(float4*)&g_x[n * FDIM + lane * 4] = x;
    }
}

// ============================================================================
// Kernel 4: k_readout — fp16 mma GEMM + fused softplus.Wout
// ============================================================================
#define R_W    0
#define R_A    16384
#define R_BH   20736
#define R_WO   20992
#define R_RED  21248
#define R_TOT  21504
#define R_SMEM (R_TOT * 4)

__global__ void __launch_bounds__(256, 1)
k_readout(const float* __restrict__ Wh, const float* __restrict__ bh,
          const float* __restrict__ Wout, const float* __restrict__ bout) {
    int tid = threadIdx.x, wid = tid >> 5, lane = tid & 31;
    uint32_t* smu = (uint32_t*)sm;
    for (int i = tid; i < 16384; i += 256) {
        int wc0 = i >> 12, rem = i & 4095;
        int c = rem & 1, idx = rem >> 1;
        int ln = idx & 31, ksj = idx >> 5;
        int ks = ksj >> 3, j = ksj & 7;
        int tg = ln & 3, gp = ln >> 2;
        int n = wc0 * 64 + j * 8 + gp;
        int k2 = ks * 8 + c * 4 + tg;
        smu[R_W + i] = packh2(Wh[(2 * k2) * HDIM + n], Wh[(2 * k2 + 1) * HDIM + n]);
    }
    sm[R_BH + tid] = bh[tid];
    sm[R_WO + tid] = Wout[tid];
    __syncthreads();

    int wr = wid >> 2, wc = wid & 3;
    int tig = lane & 3, grp = lane >> 2;
    float b0 = bout[0];
    float bhr[8][2], wor[8][2];
    #pragma unroll
    for (int j = 0; j < 8; j++) {
        int n0 = wc * 64 + j * 8 + 2 * tig;
        bhr[j][0] = sm[R_BH + n0]; bhr[j][1] = sm[R_BH + n0 + 1];
        wor[j][0] = sm[R_WO + n0]; wor[j][1] = sm[R_WO + n0 + 1];
    }

    for (int t = blockIdx.x; t < ATILE; t += gridDim.x) {
        #pragma unroll
        for (int q = 0; q < 16; q++) {
            int i = tid + q * 256;
            int r = i >> 6, k2 = i & 63;
            float2 f2 = *(const float2*)&g_x[(size_t)(t * 64 + r) * FDIM + 2 * k2];
            smu[R_A + r * 68 + k2] = packh2(f2.x, f2.y);
        }
        __syncthreads();

        float c[2][8][4] = {};
        #pragma unroll
        for (int ks = 0; ks < 8; ks++) {
            int k0 = ks * 8;
            uint32_t a[2][4];
            #pragma unroll
            for (int rt = 0; rt < 2; rt++) {
                int r = wr * 32 + rt * 16 + grp;
                a[rt][0] = smu[R_A + r * 68 + k0 + tig];
                a[rt][1] = smu[R_A + (r + 8) * 68 + k0 + tig];
                a[rt][2] = smu[R_A + r * 68 + k0 + 4 + tig];
                a[rt][3] = smu[R_A + (r + 8) * 68 + k0 + 4 + tig];
            }
            #pragma unroll
            for (int j = 0; j < 8; j++) {
                uint2 Bf = *(const uint2*)&smu[R_W + wc * 4096 + ((ks * 8 + j) * 32 + lane) * 2];
                #pragma unroll
                for (int rt = 0; rt < 2; rt++)
                    mma_f16(c[rt][j], a[rt][0], a[rt][1], a[rt][2], a[rt][3], Bf.x, Bf.y);
            }
        }

        #pragma unroll
        for (int rt = 0; rt < 2; rt++) {
            float p0 = 0.f, p1 = 0.f;
            #pragma unroll
            for (int j = 0; j < 8; j++) {
                p0 += spf(c[rt][j][0] + bhr[j][0]) * wor[j][0]
                    + spf(c[rt][j][1] + bhr[j][1]) * wor[j][1];
                p1 += spf(c[rt][j][2] + bhr[j][0]) * wor[j][0]
                    + spf(c[rt][j][3] + bhr[j][1]) * wor[j][1];
            }
            p0 += __shfl_xor_sync(0xffffffffu, p0, 1);
            p0 += __shfl_xor_sync(0xffffffffu, p0, 2);
            p1 += __shfl_xor_sync(0xffffffffu, p1, 1);
            p1 += __shfl_xor_sync(0xffffffffu, p1, 2);
            if (tig == 0) {
                int r = wr * 32 + rt * 16 + grp;
                sm[R_RED + r * 4 + wc]       = p0;
                sm[R_RED + (r + 8) * 4 + wc] = p1;
            }
        }
        __syncthreads();
        if (tid < 64) {
            float4 s4 = *(const float4*)&sm[R_RED + tid * 4];
            g_site[t * 64 + tid] = s4.x + s4.y + s4.z + s4.w + b0;
        }
        __syncthreads();
    }
}

// ============================================================================
// Kernel 5: per-crystal sum
// ============================================================================
__global__ void k_crystal(float* __restrict__ out) {
    __shared__ float red[8];
    int c = blockIdx.x, tid = threadIdx.x;
    float v = g_site[c * APC + tid];
    #pragma unroll
    for (int o = 16; o > 0; o >>= 1)
        v += __shfl_xor_sync(0xffffffffu, v, o);
    if ((tid & 31) == 0) red[tid >> 5] = v;
    __syncthreads();
    if (tid == 0) {
        float s = 0.f;
        #pragma unroll
        for (int i = 0; i < 8; i++) s += red[i];
        out[c] = s;
    }
}

// ============================================================================
extern "C" void kernel_launch(void* const* d_in, const int* in_sizes, int n_in,
                              void* d_out, int out_size) {
    const float* atom_fea = (const float*)d_in[0];
    const float* nbr_fea  = (const float*)d_in[1];
    const int*   nbr_idx  = (const int*)  d_in[2];
    const float* W_embed  = (const float*)d_in[3];
    const float* b_embed  = (const float*)d_in[4];
    const float* W_center = (const float*)d_in[5];
    const float* b_center = (const float*)d_in[6];
    const float* W_nbr    = (const float*)d_in[7];
    const float* b_nbr    = (const float*)d_in[8];
    const float* W_edge   = (const float*)d_in[9];
    const float* b_edge   = (const float*)d_in[10];
    const float* W_gate   = (const float*)d_in[11];
    const float* b_gate   = (const float*)d_in[12];
    const float* W_mag    = (const float*)d_in[13];
    const float* b_mag    = (const float*)d_in[14];
    const float* ln_scale = (const float*)d_in[15];
    const float* ln_bias  = (const float*)d_in[16];
    const float* W_h      = (const float*)d_in[17];
    const float* b_h      = (const float*)d_in[18];
    const float* W_out    = (const float*)d_in[19];
    const float* b_out    = (const float*)d_in[20];
    float* out = (float*)d_out;

    cudaFuncSetAttribute(k_embed,   cudaFuncAttributeMaxDynamicSharedMemorySize, E_SMEM);
    cudaFuncSetAttribute(k_convA,   cudaFuncAttributeMaxDynamicSharedMemorySize, CA_SMEM);
    cudaFuncSetAttribute(k_conv,    cudaFuncAttributeMaxDynamicSharedMemorySize, CV_SMEM);
    cudaFuncSetAttribute(k_readout, cudaFuncAttributeMaxDynamicSharedMemorySize, R_SMEM);

    k_pack<<<2048, 256>>>(nbr_fea);
    k_embed<<<148, 256, E_SMEM>>>(atom_fea, W_embed, b_embed);
    for (int l = 0; l < NCONV; l++) {
        k_convA<<<148, 256, CA_SMEM>>>(W_center + l * FDIM * FDIM, b_center + l * FDIM,
                                       W_nbr    + l * FDIM * FDIM, b_nbr    + l * FDIM);
        k_conv<<<148, CV_THREADS, CV_SMEM>>>(nbr_idx,
                                      W_gate + l * FDIM * FDIM, b_gate + l * FDIM,
                                      W_mag  + l * FDIM * FDIM, b_mag  + l * FDIM,
                                      W_edge + l * EDGE * FDIM, b_edge + l * FDIM,
                                      ln_scale + l * FDIM, ln_bias + l * FDIM);
    }
    k_readout<<<148, 256, R_SMEM>>>(W_h, b_h, W_out, b_out);
    k_crystal<<<NCRY, 256>>>(out);
}

// round 16
// speedup vs baseline: 5.7971x; 1.0057x over previous
#include <cuda_runtime.h>
#include <cuda_fp16.h>
#include <math.h>
#include <cstdint>

#define N_ATOMS 32768
#define MNBR    12
#define PROWS   16
#define ORIG    92
#define EDGE    41
#define FDIM    128
#define HDIM    256
#define NCONV   3
#define NCRY    128
#define APC     256
#define NT2     (N_ATOMS / 2)             // 16384 atom-pair tiles
#define ATILE   (N_ATOMS / 64)            // 512

// ---- scratch ----
__device__ float    g_x [N_ATOMS * FDIM];
__device__ uint32_t g_pc[N_ATOMS * 64];    // half2-packed phi_c
__device__ uint32_t g_yn[N_ATOMS * 64];    // half2-packed y_nbr
__device__ uint32_t g_nbrh[NT2 * 768];     // fp16 edge features, fragment order
__device__ float    g_site[N_ATOMS];

__device__ __forceinline__ uint32_t smem_u32(const void* p) {
    uint32_t a;
    asm("{ .reg .u64 t; cvta.to.shared.u64 t, %1; cvt.u32.u64 %0, t; }" : "=r"(a) : "l"(p));
    return a;
}
__device__ __forceinline__ uint32_t packh2(float a, float b) {
    __half2 h = __floats2half2_rn(a, b);
    return *(uint32_t*)&h;
}
__device__ __forceinline__ float2 unpackh2(uint32_t u) {
    return __half22float2(*(__half2*)&u);
}
__device__ __forceinline__ void mma_f16(float c[4], uint32_t a0, uint32_t a1,
                                        uint32_t a2, uint32_t a3,
                                        uint32_t b0, uint32_t b1) {
    asm volatile("mma.sync.aligned.m16n8k16.row.col.f32.f16.f16.f32 "
        "{%0,%1,%2,%3}, {%4,%5,%6,%7}, {%8,%9}, {%0,%1,%2,%3};"
        : "+f"(c[0]), "+f"(c[1]), "+f"(c[2]), "+f"(c[3])
        : "r"(a0), "r"(a1), "r"(a2), "r"(a3), "r"(b0), "r"(b1));
}
__device__ __forceinline__ float act(float g, float m) {
    float sig = __fdividef(1.f, 1.f + __expf(-g));
    float sp  = fmaxf(m, 0.f) + __logf(1.f + __expf(-fabsf(m)));
    return sig * sp;
}
__device__ __forceinline__ float spf(float x) {
    return fmaxf(x, 0.f) + __logf(1.f + __expf(-fabsf(x)));
}

extern __shared__ float sm[];

// ============================================================================
// Kernel 0: pack nbr_fea -> fp16 FRAGMENT-ORDER per 2-atom tile (768 u32)
// ============================================================================
__global__ void k_pack(const float* __restrict__ nbr_fea) {
    int total = NT2 * 768;
    for (int idx = blockIdx.x * 256 + threadIdx.x; idx < total; idx += gridDim.x * 256) {
        int s = idx / 768, f = idx - s * 768;
        int c = f & 3, q = f >> 2;
        int lane = q & 31, rks = q >> 5;
        int rt = rks / 3, ks = rks - rt * 3;
        int tig = lane & 3, grp = lane >> 2;
        int slot = c >> 1, rowbit = c & 1;
        int m = grp + rowbit * 8;
        int k2 = ks * 8 + slot * 4 + tig;
        float v0 = 0.f, v1 = 0.f;
        if (m < MNBR) {
            size_t base = ((size_t)(s * 2 + rt) * MNBR + m) * EDGE;
            if (2 * k2     < EDGE) v0 = nbr_fea[base + 2 * k2];
            if (2 * k2 + 1 < EDGE) v1 = nbr_fea[base + 2 * k2 + 1];
        }
        g_nbrh[idx] = packh2(v0, v1);
    }
}

// ============================================================================
// Kernel 1: k_embed — fp16 mma GEMM: x = atom_fea @ W_embed + b
// ============================================================================
#define E_W    0
#define E_A    6144
#define E_BIAS 9472
#define E_TOT  9600
#define E_SMEM (E_TOT * 4)

__global__ void __launch_bounds__(256, 1)
k_embed(const float* __restrict__ atom_fea,
        const float* __restrict__ W, const float* __restrict__ b) {
    int tid = threadIdx.x, wid = tid >> 5, lane = tid & 31;
    uint32_t* smu = (uint32_t*)sm;
    for (int i = tid; i < 6144; i += 256) {
        int wc0 = i / 1536, rem = i - wc0 * 1536;
        int c = rem & 1, idx = rem >> 1;
        int ln = idx & 31, ksj = idx >> 5;
        int ks = ksj >> 2, j = ksj & 3;
        int tg = ln & 3, gp = ln >> 2;
        int n = wc0 * 32 + j * 8 + gp;
        int k2 = ks * 8 + c * 4 + tg;
        float v0 = (2 * k2     < ORIG) ? W[(2 * k2) * FDIM + n]     : 0.f;
        float v1 = (2 * k2 + 1 < ORIG) ? W[(2 * k2 + 1) * FDIM + n] : 0.f;
        smu[E_W + i] = packh2(v0, v1);
    }
    if (tid < FDIM) sm[E_BIAS + tid] = b[tid];
    __syncthreads();

    int wr = wid >> 2, wc = wid & 3;
    int tig = lane & 3, grp = lane >> 2;
    float br[4][2];
    #pragma unroll
    for (int j = 0; j < 4; j++) {
        int n0 = wc * 32 + j * 8 + 2 * tig;
        br[j][0] = sm[E_BIAS + n0]; br[j][1] = sm[E_BIAS + n0 + 1];
    }

    for (int t = blockIdx.x; t < ATILE; t += gridDim.x) {
        #pragma unroll
        for (int q = 0; q < 12; q++) {
            int i = tid + q * 256;
            int r = i / 48, k2 = i - r * 48;
            uint32_t v = 0u;
            if (k2 < 46) {
                float2 f2 = *(const float2*)&atom_fea[(size_t)(t * 64 + r) * ORIG + 2 * k2];
                v = packh2(f2.x, f2.y);
            }
            smu[E_A + r * 52 + k2] = v;
        }
        __syncthreads();

        float c[2][4][4] = {};
        #pragma unroll
        for (int ks = 0; ks < 6; ks++) {
            int k0 = ks * 8;
            uint32_t a[2][4];
            #pragma unroll
            for (int rt = 0; rt < 2; rt++) {
                int r = wr * 32 + rt * 16 + grp;
                a[rt][0] = smu[E_A + r * 52 + k0 + tig];
                a[rt][1] = smu[E_A + (r + 8) * 52 + k0 + tig];
                a[rt][2] = smu[E_A + r * 52 + k0 + 4 + tig];
                a[rt][3] = smu[E_A + (r + 8) * 52 + k0 + 4 + tig];
            }
            #pragma unroll
            for (int j = 0; j < 4; j++) {
                uint2 Bf = *(const uint2*)&smu[E_W + wc * 1536 + ((ks * 4 + j) * 32 + lane) * 2];
                #pragma unroll
                for (int rt = 0; rt < 2; rt++)
                    mma_f16(c[rt][j], a[rt][0], a[rt][1], a[rt][2], a[rt][3], Bf.x, Bf.y);
            }
        }

        #pragma unroll
        for (int rt = 0; rt < 2; rt++) {
            int r0 = t * 64 + wr * 32 + rt * 16 + grp;
            #pragma unroll
            for (int j = 0; j < 4; j++) {
                int n0 = wc * 32 + j * 8 + 2 * tig;
                *(float2*)&g_x[r0 * FDIM + n0] =
                    make_float2(c[rt][j][0] + br[j][0], c[rt][j][1] + br[j][1]);
                *(float2*)&g_x[(r0 + 8) * FDIM + n0] =
                    make_float2(c[rt][j][2] + br[j][0], c[rt][j][3] + br[j][1]);
            }
        }
        __syncthreads();
    }
}

// ============================================================================
// Kernel 2: k_convA — fp16 mma GEMM: [phi_c|y_nbr] = x @ [Wc|Wn] + bias
// ============================================================================
#define CA_W    0
#define CA_A    16384
#define CA_BIAS 20736
#define CA_TOT  20992
#define CA_SMEM (CA_TOT * 4)

__global__ void __launch_bounds__(256, 1)
k_convA(const float* __restrict__ Wc, const float* __restrict__ bc,
        const float* __restrict__ Wn, const float* __restrict__ bn) {
    int tid = threadIdx.x, wid = tid >> 5, lane = tid & 31;
    uint32_t* smu = (uint32_t*)sm;
    for (int i = tid; i < 16384; i += 256) {
        int wc0 = i >> 12, rem = i & 4095;
        int c = rem & 3, idx4 = rem >> 2;
        int ln = idx4 & 31, ksj = idx4 >> 5;
        int ks = ksj >> 2, j = ksj & 3;
        int tg = ln & 3, gp = ln >> 2;
        int n = wc0 * 32 + j * 8 + gp;
        int k2 = ks * 8 + (c & 1) * 4 + tg;
        const float* W = (c < 2) ? Wc : Wn;
        smu[CA_W + i] = packh2(W[(2 * k2) * FDIM + n], W[(2 * k2 + 1) * FDIM + n]);
    }
    if (tid < 128) { sm[CA_BIAS + tid] = bc[tid]; sm[CA_BIAS + 128 + tid] = bn[tid]; }
    __syncthreads();

    int wr = wid >> 2, wc = wid & 3;
    int tig = lane & 3, grp = lane >> 2;
    float bcr[4][2], bnr[4][2];
    #pragma unroll
    for (int j = 0; j < 4; j++) {
        int f0 = wc * 32 + j * 8 + 2 * tig;
        bcr[j][0] = sm[CA_BIAS + f0];       bcr[j][1] = sm[CA_BIAS + f0 + 1];
        bnr[j][0] = sm[CA_BIAS + 128 + f0]; bnr[j][1] = sm[CA_BIAS + 128 + f0 + 1];
    }

    for (int t = blockIdx.x; t < ATILE; t += gridDim.x) {
        #pragma unroll
        for (int q = 0; q < 16; q++) {
            int i = tid + q * 256;
            int r = i >> 6, k2 = i & 63;
            float2 f2 = *(const float2*)&g_x[(size_t)(t * 64 + r) * FDIM + 2 * k2];
            smu[CA_A + r * 68 + k2] = packh2(f2.x, f2.y);
        }
        __syncthreads();

        float cpc[2][4][4] = {}, cyn[2][4][4] = {};
        #pragma unroll
        for (int ks = 0; ks < 8; ks++) {
            int k0 = ks * 8;
            uint32_t a[2][4];
            #pragma unroll
            for (int rt = 0; rt < 2; rt++) {
                int r = wr * 32 + rt * 16 + grp;
                a[rt][0] = smu[CA_A + r * 68 + k0 + tig];
                a[rt][1] = smu[CA_A + (r + 8) * 68 + k0 + tig];
                a[rt][2] = smu[CA_A + r * 68 + k0 + 4 + tig];
                a[rt][3] = smu[CA_A + (r + 8) * 68 + k0 + 4 + tig];
            }
            #pragma unroll
            for (int j = 0; j < 4; j++) {
                uint4 Bf = *(const uint4*)&smu[CA_W + wc * 4096 + ((ks * 4 + j) * 32 + lane) * 4];
                #pragma unroll
                for (int rt = 0; rt < 2; rt++) {
                    mma_f16(cpc[rt][j], a[rt][0], a[rt][1], a[rt][2], a[rt][3], Bf.x, Bf.y);
                    mma_f16(cyn[rt][j], a[rt][0], a[rt][1], a[rt][2], a[rt][3], Bf.z, Bf.w);
                }
            }
        }

        #pragma unroll
        for (int rt = 0; rt < 2; rt++) {
            int r0 = t * 64 + wr * 32 + rt * 16 + grp;
            #pragma unroll
            for (int j = 0; j < 4; j++) {
                int h0 = wc * 16 + j * 4 + tig;
                g_pc[r0 * 64 + h0] =
                    packh2(cpc[rt][j][0] + bcr[j][0], cpc[rt][j][1] + bcr[j][1]);
                g_pc[(r0 + 8) * 64 + h0] =
                    packh2(cpc[rt][j][2] + bcr[j][0], cpc[rt][j][3] + bcr[j][1]);
                g_yn[r0 * 64 + h0] =
                    packh2(cyn[rt][j][0] + bnr[j][0], cyn[rt][j][1] + bnr[j][1]);
                g_yn[(r0 + 8) * 64 + h0] =
                    packh2(cyn[rt][j][2] + bnr[j][0], cyn[rt][j][3] + bnr[j][1]);
            }
        }
        __syncthreads();
    }
}

// ============================================================================
// Kernel 3: k_conv — fused conv layer, one barrier per tile.
//   Register relief: ber / lns4 / lnb4 no longer live in registers across the
//   loop; re-read from smem at use sites so ptxas can pipeline fragment loads.
// ============================================================================
#define S_W     0          // 16384
#define S_WE    16384      //  3072
#define S_BIAS  19456      //   640
#define S_GRP   20096
#define GP_AGM  0          // 2 x 2048 = 4096
#define GP_AE   4096       // 3 x 768  = 2304
#define GP_YN   6400       // 2 x 1768 = 3536
#define GP_RED  9936       // 2 x 256  =  512
#define GP_IDX  10448      // 96
#define GRPSZ   10544
#define S_TOT   (S_GRP + 2 * GRPSZ)     // 41184 words = 164.7 KB
#define CV_SMEM (S_TOT * 4)
#define CV_THREADS 512

__device__ __forceinline__ void stage_ae_h(uint32_t dstbase, const char* __restrict__ src,
                                           int gtid) {
    if (gtid < 192) {
        asm volatile("cp.async.ca.shared.global [%0], [%1], 16;"
                     :: "r"(dstbase + (uint32_t)gtid * 16),
                        "l"(src + (size_t)gtid * 16) : "memory");
    }
}

__device__ __forceinline__ void stage_yn(uint32_t dstbase, const int* __restrict__ sx,
                                         int tn, int gtid) {
    #pragma unroll
    for (int q = 0; q < 2; q++) {
        int i = gtid + q * 256;
        if (i < 416) {
            int row = i >> 4, c = i & 15;
            const char* src = (row < 24)
                ? (const char*)(g_yn + (size_t)sx[row] * 64) + c * 16
                : (const char*)(g_pc + ((size_t)tn * 2 + (row - 24)) * 64) + c * 16;
            uint32_t d = dstbase + (uint32_t)(row * 68 + c * 4) * 4;
            asm volatile("cp.async.ca.shared.global [%0], [%1], 16;"
                         :: "r"(d), "l"(src) : "memory");
        }
    }
}

__global__ void __launch_bounds__(CV_THREADS, 1)
k_conv(const int* __restrict__ nbr_idx,
       const float* __restrict__ Wg, const float* __restrict__ bg,
       const float* __restrict__ Wm, const float* __restrict__ bm,
       const float* __restrict__ We, const float* __restrict__ be,
       const float* __restrict__ lns, const float* __restrict__ lnb) {
    int tid = threadIdx.x, wid = tid >> 5, lane = tid & 31;
    int half = wid >> 3, wg = wid & 7, gtid = tid & 255;
    uint32_t* smu = (uint32_t*)sm;

    for (int i = tid; i < 16384; i += CV_THREADS) {
        int wgo = i >> 11, rem = i & 2047;
        int c = rem & 3, idx4 = rem >> 2;
        int ln = idx4 & 31, ksj = idx4 >> 5;
        int ks = ksj >> 1, j = ksj & 1;
        int tg = ln & 3, gp = ln >> 2;
        int n = wgo * 16 + j * 8 + gp;
        int k2 = ks * 8 + (c & 1) * 4 + tg;
        const float* W = (c < 2) ? Wg : Wm;
        smu[S_W + i] = packh2(W[(2 * k2) * FDIM + n], W[(2 * k2 + 1) * FDIM + n]);
    }
    for (int i = tid; i < 3072; i += CV_THREADS) {
        int wgo = i / 384, rem = i - wgo * 384;
        int c = rem & 1, idx2 = rem >> 1;
        int ln = idx2 & 31, ksj = idx2 >> 5;
        int ks = ksj >> 1, j = ksj & 1;
        int tg = ln & 3, gp = ln >> 2;
        int n = wgo * 16 + j * 8 + gp;
        int k2 = ks * 8 + c * 4 + tg;
        float v0 = (2 * k2     < EDGE) ? We[(2 * k2) * FDIM + n]     : 0.f;
        float v1 = (2 * k2 + 1 < EDGE) ? We[(2 * k2 + 1) * FDIM + n] : 0.f;
        smu[S_WE + i] = packh2(v0, v1);
    }
    if (tid < FDIM) {
        sm[S_BIAS + tid]       = bg[tid];
        sm[S_BIAS + 128 + tid] = bm[tid];
        sm[S_BIAS + 256 + tid] = lns[tid];
        sm[S_BIAS + 384 + tid] = lnb[tid];
        sm[S_BIAS + 512 + tid] = be[tid];
    }

    int gbase = S_GRP + half * GRPSZ;
    int* sidx3 = (int*)(sm + gbase + GP_IDX);
    uint32_t aeRaw = smem_u32(sm + gbase + GP_AE);
    uint32_t ynRaw = smem_u32(sm + gbase + GP_YN);
    int tig = lane & 3, grp = lane >> 2;
    bool notpad = (grp < 4);
    int barid = half + 1;

    int stride = 2 * gridDim.x;
    int s0 = blockIdx.x * 2 + half;

    __syncthreads();

    // ---- prologue ----
    if (gtid < 24) {
        sidx3[gtid] = nbr_idx[s0 * 24 + gtid];
        if (s0 + stride < NT2)
            sidx3[24 + gtid] = nbr_idx[(s0 + stride) * 24 + gtid];
    }
    stage_ae_h(aeRaw, (const char*)(g_nbrh + (size_t)s0 * 768), gtid);
    if (s0 + stride < NT2)
        stage_ae_h(aeRaw + 768u * 4, (const char*)(g_nbrh + (size_t)(s0 + stride) * 768), gtid);
    asm volatile("cp.async.commit_group;" ::: "memory");
    asm volatile("cp.async.wait_group 0;" ::: "memory");
    asm volatile("bar.sync %0, %1;" :: "r"(barid), "r"(256) : "memory");

    stage_yn(ynRaw, sidx3, s0, gtid);
    asm volatile("cp.async.commit_group;" ::: "memory");
    asm volatile("cp.async.wait_group 0;" ::: "memory");
    asm volatile("bar.sync %0, %1;" :: "r"(barid), "r"(256) : "memory");

    // hot-loop register bias state: gate/mag only (ber/lns/lnb read from smem)
    float bgr[2][2], bmr[2][2];
    #pragma unroll
    for (int j = 0; j < 2; j++) {
        int f0 = wg * 16 + j * 8 + 2 * tig;
        bgr[j][0] = sm[S_BIAS + f0];        bgr[j][1] = sm[S_BIAS + f0 + 1];
        bmr[j][0] = sm[S_BIAS + 128 + f0];  bmr[j][1] = sm[S_BIAS + 128 + f0 + 1];
    }

    int b2 = 0, b3 = 0, bA = 0, bR = 0;
    int tprev = -1;
    for (int t = s0; t < NT2; t += stride) {
        int aeB  = gbase + GP_AE + b3 * 768;
        int ynB  = gbase + GP_YN + b2 * 1768;
        int agmB = gbase + GP_AGM + bA * 2048;

        if (t + stride < NT2)
            stage_yn(ynRaw + (uint32_t)(b2 ^ 1) * 1768 * 4,
                     sidx3 + ((b3 + 1) % 3) * 24, t + stride, gtid);
        asm volatile("cp.async.commit_group;" ::: "memory");

        int t2 = t + 2 * stride;
        if (t2 < NT2) {
            int ib = (b3 + 2) % 3;
            if (gtid < 24) sidx3[ib * 24 + gtid] = nbr_idx[t2 * 24 + gtid];
            stage_ae_h(aeRaw + (uint32_t)ib * 768 * 4,
                       (const char*)(g_nbrh + (size_t)t2 * 768), gtid);
        }
        asm volatile("cp.async.commit_group;" ::: "memory");

        // ---- phi_e mma ----
        float ce[2][2][4] = {};
        #pragma unroll
        for (int ks = 0; ks < 3; ks++) {
            uint4 A[2];
            #pragma unroll
            for (int rt = 0; rt < 2; rt++)
                A[rt] = *(const uint4*)&smu[aeB + ((rt * 3 + ks) * 32 + lane) * 4];
            #pragma unroll
            for (int j = 0; j < 2; j++) {
                uint2 Bf = *(const uint2*)&smu[S_WE + wg * 384 + ((ks * 2 + j) * 32 + lane) * 2];
                #pragma unroll
                for (int rt = 0; rt < 2; rt++)
                    mma_f16(ce[rt][j], A[rt].x, A[rt].y, A[rt].z, A[rt].w, Bf.x, Bf.y);
            }
        }

        // ---- build inter tile into AGM[bA]; be read from smem ----
        #pragma unroll
        for (int rt = 0; rt < 2; rt++) {
            int yr0 = ynB + (rt * 12 + grp) * 68;
            int pr  = ynB + (24 + rt) * 68;
            #pragma unroll
            for (int j = 0; j < 2; j++) {
                int f0 = wg * 16 + j * 8 + 2 * tig;
                int h0 = wg * 8 + j * 4 + tig;
                float2 be2 = *(const float2*)&sm[S_BIAS + 512 + f0];
                float2 pc2 = unpackh2(smu[pr + h0]);
                float2 y0  = unpackh2(smu[yr0 + h0]);
                uint32_t lo = packh2(pc2.x * y0.x * (ce[rt][j][0] + be2.x),
                                     pc2.y * y0.y * (ce[rt][j][1] + be2.y));
                uint32_t hi = 0u;
                if (notpad) {
                    float2 y1 = unpackh2(smu[yr0 + 8 * 68 + h0]);
                    hi = packh2(pc2.x * y1.x * (ce[rt][j][2] + be2.x),
                                pc2.y * y1.y * (ce[rt][j][3] + be2.y));
                }
                *(uint2*)&smu[agmB + ((rt * 8 + wg) * 32 + lane) * 4 + j * 2] =
                    make_uint2(lo, hi);
            }
        }

        // ---- THE barrier ----
        asm volatile("cp.async.wait_group 1;" ::: "memory");
        asm volatile("bar.sync %0, %1;" :: "r"(barid), "r"(256) : "memory");

        // ---- gate/mag mma from AGM[bA] ----
        float cg[2][2][4] = {}, cmm[2][2][4] = {};
        #pragma unroll
        for (int ks = 0; ks < 8; ks++) {
            uint4 A[2];
            #pragma unroll
            for (int rt = 0; rt < 2; rt++)
                A[rt] = *(const uint4*)&smu[agmB + ((rt * 8 + ks) * 32 + lane) * 4];
            #pragma unroll
            for (int j = 0; j < 2; j++) {
                uint4 Bf = *(const uint4*)&smu[S_W + wg * 2048 + ((ks * 2 + j) * 32 + lane) * 4];
                #pragma unroll
                for (int rt = 0; rt < 2; rt++) {
                    mma_f16(cg[rt][j],  A[rt].x, A[rt].y, A[rt].z, A[rt].w, Bf.x, Bf.y);
                    mma_f16(cmm[rt][j], A[rt].x, A[rt].y, A[rt].z, A[rt].w, Bf.z, Bf.w);
                }
            }
        }

        // ---- deferred LayerNorm + residual for previous tile ----
        if (tprev >= 0 && wg < 2) {
            float4 v = *(const float4*)&sm[gbase + GP_RED + (bR ^ 1) * 256 + wg * 128 + lane * 4];
            float4 lns4 = *(const float4*)&sm[S_BIAS + 256 + lane * 4];
            float4 lnb4 = *(const float4*)&sm[S_BIAS + 384 + lane * 4];
            float s = v.x + v.y + v.z + v.w;
            float q = v.x*v.x + v.y*v.y + v.z*v.z + v.w*v.w;
            #pragma unroll
            for (int o = 16; o > 0; o >>= 1) {
                s += __shfl_xor_sync(0xffffffffu, s, o);
                q += __shfl_xor_sync(0xffffffffu, q, o);
            }
            float mu = s * (1.f / FDIM);
            float var = q * (1.f / FDIM) - mu * mu;
            float rstd = rsqrtf(var + 1e-6f);
            int n = tprev * 2 + wg;
            float4 x = *(float4*)&g_x[n * FDIM + lane * 4];
            x.x += (v.x - mu) * rstd * lns4.x + lnb4.x;
            x.y += (v.y - mu) * rstd * lns4.y + lnb4.y;
            x.z += (v.z - mu) * rstd * lns4.z + lnb4.z;
            x.w += (v.w - mu) * rstd * lns4.w + lnb4.w;
            *(float4*)&g_x[n * FDIM + lane * 4] = x;
        }

        // ---- activation + masked per-atom column sums into RED[bR] ----
        #pragma unroll
        for (int rt = 0; rt < 2; rt++) {
            #pragma unroll
            for (int j = 0; j < 2; j++) {
                float p0 = act(cg[rt][j][0] + bgr[j][0], cmm[rt][j][0] + bmr[j][0]);
                float p1 = act(cg[rt][j][1] + bgr[j][1], cmm[rt][j][1] + bmr[j][1]);
                if (notpad) {
                    p0 += act(cg[rt][j][2] + bgr[j][0], cmm[rt][j][2] + bmr[j][0]);
                    p1 += act(cg[rt][j][3] + bgr[j][1], cmm[rt][j][3] + bmr[j][1]);
                }
                #pragma unroll
                for (int o = 4; o < 32; o <<= 1) {
                    p0 += __shfl_xor_sync(0xffffffffu, p0, o);
                    p1 += __shfl_xor_sync(0xffffffffu, p1, o);
                }
                if (grp == 0) {
                    int f0 = wg * 16 + j * 8 + 2 * tig;
                    sm[gbase + GP_RED + bR * 256 + rt * 128 + f0]     = p0;
                    sm[gbase + GP_RED + bR * 256 + rt * 128 + f0 + 1] = p1;
                }
            }
        }

        tprev = t;
        bA ^= 1; bR ^= 1; b2 ^= 1; b3 = (b3 + 1) % 3;
    }

    // ---- epilogue: final LN for last tile ----
    asm volatile("bar.sync %0, %1;" :: "r"(barid), "r"(256) : "memory");
    if (tprev >= 0 && wg < 2) {
        float4 v = *(const float4*)&sm[gbase + GP_RED + (bR ^ 1) * 256 + wg * 128 + lane * 4];
        float4 lns4 = *(const float4*)&sm[S_BIAS + 256 + lane * 4];
        float4 lnb4 = *(const float4*)&sm[S_BIAS + 384 + lane * 4];
        float s = v.x + v.y + v.z + v.w;
        float q = v.x*v.x + v.y*v.y + v.z*v.z + v.w*v.w;
        #pragma unroll
        for (int o = 16; o > 0; o >>= 1) {
            s += __shfl_xor_sync(0xffffffffu, s, o);
            q += __shfl_xor_sync(0xffffffffu, q, o);
        }
        float mu = s * (1.f / FDIM);
        float var = q * (1.f / FDIM) - mu * mu;
        float rstd = rsqrtf(var + 1e-6f);
        int n = tprev * 2 + wg;
        float4 x = *(float4*)&g_x[n * FDIM + lane * 4];
        x.x += (v.x - mu) * rstd * lns4.x + lnb4.x;
        x.y += (v.y - mu) * rstd * lns4.y + lnb4.y;
        x.z += (v.z - mu) * rstd * lns4.z + lnb4.z;
        x.w += (v.w - mu) * rstd * lns4.w + lnb4.w;
        *(float4*)&g_x[n * FDIM + lane * 4] = x;
    }
}

// ============================================================================
// Kernel 4: k_readout — fp16 mma GEMM + fused softplus.Wout
// ============================================================================
#define R_W    0
#define R_A    16384
#define R_BH   20736
#define R_WO   20992
#define R_RED  21248
#define R_TOT  21504
#define R_SMEM (R_TOT * 4)

__global__ void __launch_bounds__(256, 1)
k_readout(const float* __restrict__ Wh, const float* __restrict__ bh,
          const float* __restrict__ Wout, const float* __restrict__ bout) {
    int tid = threadIdx.x, wid = tid >> 5, lane = tid & 31;
    uint32_t* smu = (uint32_t*)sm;
    for (int i = tid; i < 16384; i += 256) {
        int wc0 = i >> 12, rem = i & 4095;
        int c = rem & 1, idx = rem >> 1;
        int ln = idx & 31, ksj = idx >> 5;
        int ks = ksj >> 3, j = ksj & 7;
        int tg = ln & 3, gp = ln >> 2;
        int n = wc0 * 64 + j * 8 + gp;
        int k2 = ks * 8 + c * 4 + tg;
        smu[R_W + i] = packh2(Wh[(2 * k2) * HDIM + n], Wh[(2 * k2 + 1) * HDIM + n]);
    }
    sm[R_BH + tid] = bh[tid];
    sm[R_WO + tid] = Wout[tid];
    __syncthreads();

    int wr = wid >> 2, wc = wid & 3;
    int tig = lane & 3, grp = lane >> 2;
    float b0 = bout[0];
    float bhr[8][2], wor[8][2];
    #pragma unroll
    for (int j = 0; j < 8; j++) {
        int n0 = wc * 64 + j * 8 + 2 * tig;
        bhr[j][0] = sm[R_BH + n0]; bhr[j][1] = sm[R_BH + n0 + 1];
        wor[j][0] = sm[R_WO + n0]; wor[j][1] = sm[R_WO + n0 + 1];
    }

    for (int t = blockIdx.x; t < ATILE; t += gridDim.x) {
        #pragma unroll
        for (int q = 0; q < 16; q++) {
            int i = tid + q * 256;
            int r = i >> 6, k2 = i & 63;
            float2 f2 = *(const float2*)&g_x[(size_t)(t * 64 + r) * FDIM + 2 * k2];
            smu[R_A + r * 68 + k2] = packh2(f2.x, f2.y);
        }
        __syncthreads();

        float c[2][8][4] = {};
        #pragma unroll
        for (int ks = 0; ks < 8; ks++) {
            int k0 = ks * 8;
            uint32_t a[2][4];
            #pragma unroll
            for (int rt = 0; rt < 2; rt++) {
                int r = wr * 32 + rt * 16 + grp;
                a[rt][0] = smu[R_A + r * 68 + k0 + tig];
                a[rt][1] = smu[R_A + (r + 8) * 68 + k0 + tig];
                a[rt][2] = smu[R_A + r * 68 + k0 + 4 + tig];
                a[rt][3] = smu[R_A + (r + 8) * 68 + k0 + 4 + tig];
            }
            #pragma unroll
            for (int j = 0; j < 8; j++) {
                uint2 Bf = *(const uint2*)&smu[R_W + wc * 4096 + ((ks * 8 + j) * 32 + lane) * 2];
                #pragma unroll
                for (int rt = 0; rt < 2; rt++)
                    mma_f16(c[rt][j], a[rt][0], a[rt][1], a[rt][2], a[rt][3], Bf.x, Bf.y);
            }
        }

        #pragma unroll
        for (int rt = 0; rt < 2; rt++) {
            float p0 = 0.f, p1 = 0.f;
            #pragma unroll
            for (int j = 0; j < 8; j++) {
                p0 += spf(c[rt][j][0] + bhr[j][0]) * wor[j][0]
                    + spf(c[rt][j][1] + bhr[j][1]) * wor[j][1];
                p1 += spf(c[rt][j][2] + bhr[j][0]) * wor[j][0]
                    + spf(c[rt][j][3] + bhr[j][1]) * wor[j][1];
            }
            p0 += __shfl_xor_sync(0xffffffffu, p0, 1);
            p0 += __shfl_xor_sync(0xffffffffu, p0, 2);
            p1 += __shfl_xor_sync(0xffffffffu, p1, 1);
            p1 += __shfl_xor_sync(0xffffffffu, p1, 2);
            if (tig == 0) {
                int r = wr * 32 + rt * 16 + grp;
                sm[R_RED + r * 4 + wc]       = p0;
                sm[R_RED + (r + 8) * 4 + wc] = p1;
            }
        }
        __syncthreads();
        if (tid < 64) {
            float4 s4 = *(const float4*)&sm[R_RED + tid * 4];
            g_site[t * 64 + tid] = s4.x + s4.y + s4.z + s4.w + b0;
        }
        __syncthreads();
    }
}

// ============================================================================
// Kernel 5: per-crystal sum
// ============================================================================
__global__ void k_crystal(float* __restrict__ out) {
    __shared__ float red[8];
    int c = blockIdx.x, tid = threadIdx.x;
    float v = g_site[c * APC + tid];
    #pragma unroll
    for (int o = 16; o > 0; o >>= 1)
        v += __shfl_xor_sync(0xffffffffu, v, o);
    if ((tid & 31) == 0) red[tid >> 5] = v;
    __syncthreads();
    if (tid == 0) {
        float s = 0.f;
        #pragma unroll
        for (int i = 0; i < 8; i++) s += red[i];
        out[c] = s;
    }
}

// ============================================================================
extern "C" void kernel_launch(void* const* d_in, const int* in_sizes, int n_in,
                              void* d_out, int out_size) {
    const float* atom_fea = (const float*)d_in[0];
    const float* nbr_fea  = (const float*)d_in[1];
    const int*   nbr_idx  = (const int*)  d_in[2];
    const float* W_embed  = (const float*)d_in[3];
    const float* b_embed  = (const float*)d_in[4];
    const float* W_center = (const float*)d_in[5];
    const float* b_center = (const float*)d_in[6];
    const float* W_nbr    = (const float*)d_in[7];
    const float* b_nbr    = (const float*)d_in[8];
    const float* W_edge   = (const float*)d_in[9];
    const float* b_edge   = (const float*)d_in[10];
    const float* W_gate   = (const float*)d_in[11];
    const float* b_gate   = (const float*)d_in[12];
    const float* W_mag    = (const float*)d_in[13];
    const float* b_mag    = (const float*)d_in[14];
    const float* ln_scale = (const float*)d_in[15];
    const float* ln_bias  = (const float*)d_in[16];
    const float* W_h      = (const float*)d_in[17];
    const float* b_h      = (const float*)d_in[18];
    const float* W_out    = (const float*)d_in[19];
    const float* b_out    = (const float*)d_in[20];
    float* out = (float*)d_out;

    cudaFuncSetAttribute(k_embed,   cudaFuncAttributeMaxDynamicSharedMemorySize, E_SMEM);
    cudaFuncSetAttribute(k_convA,   cudaFuncAttributeMaxDynamicSharedMemorySize, CA_SMEM);
    cudaFuncSetAttribute(k_conv,    cudaFuncAttributeMaxDynamicSharedMemorySize, CV_SMEM);
    cudaFuncSetAttribute(k_readout, cudaFuncAttributeMaxDynamicSharedMemorySize, R_SMEM);

    k_pack<<<2048, 256>>>(nbr_fea);
    k_embed<<<148, 256, E_SMEM>>>(atom_fea, W_embed, b_embed);
    for (int l = 0; l < NCONV; l++) {
        k_convA<<<148, 256, CA_SMEM>>>(W_center + l * FDIM * FDIM, b_center + l * FDIM,
                                       W_nbr    + l * FDIM * FDIM, b_nbr    + l * FDIM);
        k_conv<<<148, CV_THREADS, CV_SMEM>>>(nbr_idx,
                                      W_gate + l * FDIM * FDIM, b_gate + l * FDIM,
                                      W_mag  + l * FDIM * FDIM, b_mag  + l * FDIM,
                                      W_edge + l * EDGE * FDIM, b_edge + l * FDIM,
                                      ln_scale + l * FDIM, ln_bias + l * FDIM);
    }
    k_readout<<<148, 256, R_SMEM>>>(W_h, b_h, W_out, b_out);
    k_crystal<<<NCRY, 256>>>(out);
}